// round 1
// baseline (speedup 1.0000x reference)
#include <cuda_runtime.h>
#include <math.h>

#define Bx 2
#define Sx 4096
#define Dx 768
#define NHx 12
#define HDx 64
#define BSx 64
#define NBx 64
#define FFx 3072
#define Rx 3
#define NGx 8
#define NMID 62
#define TOK (Bx*Sx)

// ---------------- scratch (static device memory; no allocations) ----------------
__device__ float g_h[(size_t)TOK*Dx];
__device__ float g_res[(size_t)TOK*Dx];
__device__ float g_q[(size_t)TOK*Dx];
__device__ float g_k[(size_t)TOK*Dx];
__device__ float g_v[(size_t)TOK*Dx];
__device__ float g_ctx[(size_t)TOK*Dx];
__device__ float g_ff[(size_t)TOK*FFx];
__device__ float g_smid[(size_t)Bx*NHx*NMID*BSx*NGx*BSx];   // [b,h,n-1,qi, g*64+ki]
__device__ float g_sedge[(size_t)Bx*NHx*2*BSx*Sx];          // [b,h,e,qi, pos]

// ---------------- block reductions ----------------
__device__ __forceinline__ float blk_sum(float v) {
    __shared__ float red[33];
    #pragma unroll
    for (int o = 16; o; o >>= 1) v += __shfl_down_sync(0xffffffffu, v, o);
    int lane = threadIdx.x & 31, w = threadIdx.x >> 5;
    __syncthreads();
    if (lane == 0) red[w] = v;
    __syncthreads();
    if (w == 0) {
        float x = (lane < ((blockDim.x + 31) >> 5)) ? red[lane] : 0.f;
        #pragma unroll
        for (int o = 16; o; o >>= 1) x += __shfl_down_sync(0xffffffffu, x, o);
        if (lane == 0) red[32] = x;
    }
    __syncthreads();
    return red[32];
}

__device__ __forceinline__ float blk_max(float v) {
    __shared__ float redm[33];
    #pragma unroll
    for (int o = 16; o; o >>= 1) v = fmaxf(v, __shfl_down_sync(0xffffffffu, v, o));
    int lane = threadIdx.x & 31, w = threadIdx.x >> 5;
    __syncthreads();
    if (lane == 0) redm[w] = v;
    __syncthreads();
    if (w == 0) {
        float x = (lane < ((blockDim.x + 31) >> 5)) ? redm[lane] : -3.4e38f;
        #pragma unroll
        for (int o = 16; o; o >>= 1) x = fmaxf(x, __shfl_down_sync(0xffffffffu, x, o));
        if (lane == 0) redm[32] = x;
    }
    __syncthreads();
    return redm[32];
}

// ---------------- embeddings + LN ----------------
__global__ void embed_ln_kernel(const int* __restrict__ ids, const int* __restrict__ tt,
                                const float* __restrict__ wemb, const float* __restrict__ temb,
                                const float* __restrict__ pemb,
                                const float* __restrict__ lns, const float* __restrict__ lnb) {
    int tok = blockIdx.x;
    int pos = tok % Sx;
    const float* w = wemb + (size_t)ids[tok] * Dx;
    const float* t = temb + (size_t)tt[tok] * Dx;
    const float* p = pemb + (size_t)pos * Dx;
    __shared__ float buf[Dx];
    float ls = 0.f, lq = 0.f;
    for (int i = threadIdx.x; i < Dx; i += blockDim.x) {
        float x = w[i] + t[i] + p[i];
        buf[i] = x; ls += x; lq += x * x;
    }
    float sum = blk_sum(ls);
    float sq  = blk_sum(lq);
    float mu = sum * (1.f / Dx);
    float var = sq * (1.f / Dx) - mu * mu;
    float inv = rsqrtf(var + 1e-12f);
    for (int i = threadIdx.x; i < Dx; i += blockDim.x)
        g_h[(size_t)tok * Dx + i] = lns[i] * (buf[i] - mu) * inv + lnb[i];
}

// ---------------- residual add + LN (in-place on h) ----------------
__global__ void add_ln_kernel(float* __restrict__ h, const float* __restrict__ r,
                              const float* __restrict__ lns, const float* __restrict__ lnb) {
    int tok = blockIdx.x;
    __shared__ float buf[Dx];
    float ls = 0.f, lq = 0.f;
    for (int i = threadIdx.x; i < Dx; i += blockDim.x) {
        float x = h[(size_t)tok * Dx + i] + r[(size_t)tok * Dx + i];
        buf[i] = x; ls += x; lq += x * x;
    }
    float sum = blk_sum(ls);
    float sq  = blk_sum(lq);
    float mu = sum * (1.f / Dx);
    float var = sq * (1.f / Dx) - mu * mu;
    float inv = rsqrtf(var + 1e-12f);
    for (int i = threadIdx.x; i < Dx; i += blockDim.x)
        h[(size_t)tok * Dx + i] = lns[i] * (buf[i] - mu) * inv + lnb[i];
}

// ---------------- dense SGEMM: C = act(A[M,K] @ W[K,N] + bias) ----------------
// M % 128 == 0, N % 128 == 0, K % 8 == 0 (guaranteed by shapes used)
template<int GELU>
__global__ void __launch_bounds__(256) sgemm_kernel(
    const float* __restrict__ A, const float* __restrict__ W,
    const float* __restrict__ bias, float* __restrict__ C,
    int M, int N, int K)
{
    __shared__ float As[8][128];
    __shared__ float Bs[8][128];
    int tid = threadIdx.x;
    int bx = blockIdx.x, by = blockIdx.y;
    int tx = tid & 15, ty = tid >> 4;

    int arow = tid >> 1, acol = (tid & 1) << 2;
    int brow = tid >> 5, bcol = (tid & 31) << 2;
    const float* Aptr = A + (size_t)(by * 128 + arow) * K + acol;
    const float* Wptr = W + (size_t)brow * N + bx * 128 + bcol;

    float acc[8][8];
    #pragma unroll
    for (int i = 0; i < 8; i++)
        #pragma unroll
        for (int j = 0; j < 8; j++) acc[i][j] = 0.f;

    for (int k0 = 0; k0 < K; k0 += 8) {
        float4 a = *(const float4*)Aptr;  Aptr += 8;
        float4 w = *(const float4*)Wptr;  Wptr += (size_t)8 * N;
        __syncthreads();
        As[acol + 0][arow] = a.x; As[acol + 1][arow] = a.y;
        As[acol + 2][arow] = a.z; As[acol + 3][arow] = a.w;
        *(float4*)&Bs[brow][bcol] = w;
        __syncthreads();
        #pragma unroll
        for (int kk = 0; kk < 8; kk++) {
            float ar[8], br[8];
            *(float4*)(ar)     = *(const float4*)&As[kk][ty * 8];
            *(float4*)(ar + 4) = *(const float4*)&As[kk][ty * 8 + 4];
            *(float4*)(br)     = *(const float4*)&Bs[kk][tx * 8];
            *(float4*)(br + 4) = *(const float4*)&Bs[kk][tx * 8 + 4];
            #pragma unroll
            for (int i = 0; i < 8; i++)
                #pragma unroll
                for (int j = 0; j < 8; j++) acc[i][j] += ar[i] * br[j];
        }
    }
    int row0 = by * 128 + ty * 8, col0 = bx * 128 + tx * 8;
    #pragma unroll
    for (int i = 0; i < 8; i++) {
        #pragma unroll
        for (int j = 0; j < 8; j++) {
            float v = acc[i][j] + bias[col0 + j];
            if (GELU) v = 0.5f * v * (1.f + erff(v * 0.70710678118654752f));
            C[(size_t)(row0 + i) * N + col0 + j] = v;
        }
    }
}

// ---------------- helpers for block indices ----------------
__device__ __forceinline__ int mid_block_idx(int n, int g, const int* __restrict__ randb) {
    if (g == 0) return 0;
    if (g == 1) return NBx - 1;
    if (g < 5)  return n - 3 + g;          // g=2 -> n-1, g=3 -> n, g=4 -> n+1
    return randb[(n - 1) * Rx + (g - 5)];
}

// ---------------- middle-block scores: smid = QK^T*scale + mask ----------------
__global__ void __launch_bounds__(256) mid_scores_kernel(
    const float* __restrict__ q, const float* __restrict__ k,
    const int* __restrict__ randb, const int* __restrict__ amask,
    float* __restrict__ smid)
{
    int n = blockIdx.x + 1;
    int h = blockIdx.y;
    int b = blockIdx.z;
    __shared__ float Qs[64][65];   // [d][qi]
    __shared__ float Ks[64][65];   // [d][ki]
    int tid = threadIdx.x;
    int tx = tid & 15, ty = tid >> 4;

    const float* qbase = q + ((size_t)b * Sx + n * 64) * Dx + h * 64;
    for (int f = tid; f < 1024; f += 256) {
        int qi = f >> 4, d4 = (f & 15) << 2;
        float4 v = *(const float4*)(qbase + (size_t)qi * Dx + d4);
        Qs[d4 + 0][qi] = v.x; Qs[d4 + 1][qi] = v.y;
        Qs[d4 + 2][qi] = v.z; Qs[d4 + 3][qi] = v.w;
    }
    float* out = smid + (((size_t)(b * NHx + h) * NMID + (n - 1)) << 15);

    for (int g = 0; g < NGx; g++) {
        int kb = mid_block_idx(n, g, randb);
        const float* kbase = k + ((size_t)b * Sx + kb * 64) * Dx + h * 64;
        __syncthreads();
        for (int f = tid; f < 1024; f += 256) {
            int ki = f >> 4, d4 = (f & 15) << 2;
            float4 v = *(const float4*)(kbase + (size_t)ki * Dx + d4);
            Ks[d4 + 0][ki] = v.x; Ks[d4 + 1][ki] = v.y;
            Ks[d4 + 2][ki] = v.z; Ks[d4 + 3][ki] = v.w;
        }
        __syncthreads();
        float acc[4][4] = {};
        #pragma unroll 16
        for (int d = 0; d < 64; d++) {
            float ar[4], br[4];
            #pragma unroll
            for (int i = 0; i < 4; i++) ar[i] = Qs[d][ty * 4 + i];
            #pragma unroll
            for (int j = 0; j < 4; j++) br[j] = Ks[d][tx * 4 + j];
            #pragma unroll
            for (int i = 0; i < 4; i++)
                #pragma unroll
                for (int j = 0; j < 4; j++) acc[i][j] += ar[i] * br[j];
        }
        #pragma unroll
        for (int j = 0; j < 4; j++) {
            int ki = tx * 4 + j;
            float madd = (1.0f - (float)amask[b * Sx + kb * 64 + ki]) * -1e9f;
            #pragma unroll
            for (int i = 0; i < 4; i++) {
                int qi = ty * 4 + i;
                out[(size_t)qi * (NGx * 64) + g * 64 + ki] = acc[i][j] * 0.125f + madd;
            }
        }
    }
}

// ---------------- middle-block PV: ctx_mid = P @ Vgathered ----------------
__global__ void __launch_bounds__(256) mid_pv_kernel(
    const float* __restrict__ p, const float* __restrict__ v,
    const int* __restrict__ randb, float* __restrict__ ctx)
{
    int n = blockIdx.x + 1;
    int h = blockIdx.y;
    int b = blockIdx.z;
    __shared__ float Ps[64][65];   // [ki][qi]
    __shared__ float Vs[64][65];   // [ki][d]
    int tid = threadIdx.x;
    int tx = tid & 15, ty = tid >> 4;

    const float* prow = p + (((size_t)(b * NHx + h) * NMID + (n - 1)) << 15);
    float acc[4][4] = {};

    for (int g = 0; g < NGx; g++) {
        int kb = mid_block_idx(n, g, randb);
        const float* vbase = v + ((size_t)b * Sx + kb * 64) * Dx + h * 64;
        __syncthreads();
        for (int f = tid; f < 1024; f += 256) {
            int qi = f >> 4, k4 = (f & 15) << 2;
            float4 t = *(const float4*)(prow + (size_t)qi * (NGx * 64) + g * 64 + k4);
            Ps[k4 + 0][qi] = t.x; Ps[k4 + 1][qi] = t.y;
            Ps[k4 + 2][qi] = t.z; Ps[k4 + 3][qi] = t.w;
        }
        for (int f = tid; f < 1024; f += 256) {
            int ki = f >> 4, d4 = (f & 15) << 2;
            float4 t = *(const float4*)(vbase + (size_t)ki * Dx + d4);
            Vs[ki][d4 + 0] = t.x; Vs[ki][d4 + 1] = t.y;
            Vs[ki][d4 + 2] = t.z; Vs[ki][d4 + 3] = t.w;
        }
        __syncthreads();
        #pragma unroll 16
        for (int kk = 0; kk < 64; kk++) {
            float ar[4], br[4];
            #pragma unroll
            for (int i = 0; i < 4; i++) ar[i] = Ps[kk][ty * 4 + i];
            #pragma unroll
            for (int j = 0; j < 4; j++) br[j] = Vs[kk][tx * 4 + j];
            #pragma unroll
            for (int i = 0; i < 4; i++)
                #pragma unroll
                for (int j = 0; j < 4; j++) acc[i][j] += ar[i] * br[j];
        }
    }
    float* cbase = ctx + ((size_t)b * Sx + n * 64) * Dx + h * 64;
    #pragma unroll
    for (int i = 0; i < 4; i++)
        #pragma unroll
        for (int j = 0; j < 4; j++)
            cbase[(size_t)(ty * 4 + i) * Dx + tx * 4 + j] = acc[i][j];
}

// ---------------- edge scores: dense over all keys ----------------
__global__ void __launch_bounds__(256) edge_scores_kernel(
    const float* __restrict__ q, const float* __restrict__ k,
    const int* __restrict__ amask, float* __restrict__ sedge)
{
    int kb = blockIdx.x;          // key block
    int h  = blockIdx.y;
    int e  = blockIdx.z & 1;
    int b  = blockIdx.z >> 1;
    int qb = e ? (NBx - 1) : 0;
    __shared__ float Qs[64][65];
    __shared__ float Ks[64][65];
    int tid = threadIdx.x;
    int tx = tid & 15, ty = tid >> 4;

    const float* qbase = q + ((size_t)b * Sx + qb * 64) * Dx + h * 64;
    const float* kbase = k + ((size_t)b * Sx + kb * 64) * Dx + h * 64;
    for (int f = tid; f < 1024; f += 256) {
        int r = f >> 4, d4 = (f & 15) << 2;
        float4 a = *(const float4*)(qbase + (size_t)r * Dx + d4);
        Qs[d4 + 0][r] = a.x; Qs[d4 + 1][r] = a.y; Qs[d4 + 2][r] = a.z; Qs[d4 + 3][r] = a.w;
        float4 c = *(const float4*)(kbase + (size_t)r * Dx + d4);
        Ks[d4 + 0][r] = c.x; Ks[d4 + 1][r] = c.y; Ks[d4 + 2][r] = c.z; Ks[d4 + 3][r] = c.w;
    }
    __syncthreads();
    float acc[4][4] = {};
    #pragma unroll 16
    for (int d = 0; d < 64; d++) {
        float ar[4], br[4];
        #pragma unroll
        for (int i = 0; i < 4; i++) ar[i] = Qs[d][ty * 4 + i];
        #pragma unroll
        for (int j = 0; j < 4; j++) br[j] = Ks[d][tx * 4 + j];
        #pragma unroll
        for (int i = 0; i < 4; i++)
            #pragma unroll
            for (int j = 0; j < 4; j++) acc[i][j] += ar[i] * br[j];
    }
    float* out = sedge + ((size_t)((b * NHx + h) * 2 + e)) * (64 * Sx);
    #pragma unroll
    for (int j = 0; j < 4; j++) {
        int ki = tx * 4 + j;
        float madd = (1.0f - (float)amask[b * Sx + kb * 64 + ki]) * -1e9f;
        #pragma unroll
        for (int i = 0; i < 4; i++) {
            int qi = ty * 4 + i;
            out[(size_t)qi * Sx + kb * 64 + ki] = acc[i][j] * 0.125f + madd;
        }
    }
}

// ---------------- edge PV ----------------
__global__ void __launch_bounds__(256) edge_pv_kernel(
    const float* __restrict__ p, const float* __restrict__ v, float* __restrict__ ctx)
{
    int h = blockIdx.x;
    int e = blockIdx.y & 1;
    int b = blockIdx.y >> 1;
    int qb = e ? (NBx - 1) : 0;
    __shared__ float Ps[64][65];
    __shared__ float Vs[64][65];
    int tid = threadIdx.x;
    int tx = tid & 15, ty = tid >> 4;

    const float* prow = p + ((size_t)((b * NHx + h) * 2 + e)) * (64 * Sx);
    float acc[4][4] = {};
    for (int kb = 0; kb < NBx; kb++) {
        const float* vbase = v + ((size_t)b * Sx + kb * 64) * Dx + h * 64;
        __syncthreads();
        for (int f = tid; f < 1024; f += 256) {
            int qi = f >> 4, k4 = (f & 15) << 2;
            float4 t = *(const float4*)(prow + (size_t)qi * Sx + kb * 64 + k4);
            Ps[k4 + 0][qi] = t.x; Ps[k4 + 1][qi] = t.y;
            Ps[k4 + 2][qi] = t.z; Ps[k4 + 3][qi] = t.w;
        }
        for (int f = tid; f < 1024; f += 256) {
            int ki = f >> 4, d4 = (f & 15) << 2;
            float4 t = *(const float4*)(vbase + (size_t)ki * Dx + d4);
            Vs[ki][d4 + 0] = t.x; Vs[ki][d4 + 1] = t.y;
            Vs[ki][d4 + 2] = t.z; Vs[ki][d4 + 3] = t.w;
        }
        __syncthreads();
        #pragma unroll 16
        for (int kk = 0; kk < 64; kk++) {
            float ar[4], br[4];
            #pragma unroll
            for (int i = 0; i < 4; i++) ar[i] = Ps[kk][ty * 4 + i];
            #pragma unroll
            for (int j = 0; j < 4; j++) br[j] = Vs[kk][tx * 4 + j];
            #pragma unroll
            for (int i = 0; i < 4; i++)
                #pragma unroll
                for (int j = 0; j < 4; j++) acc[i][j] += ar[i] * br[j];
        }
    }
    float* cbase = ctx + ((size_t)b * Sx + qb * 64) * Dx + h * 64;
    #pragma unroll
    for (int i = 0; i < 4; i++)
        #pragma unroll
        for (int j = 0; j < 4; j++)
            cbase[(size_t)(ty * 4 + i) * Dx + tx * 4 + j] = acc[i][j];
}

// ---------------- row softmax (in-place), row length L ----------------
__global__ void softmax_kernel(float* __restrict__ s, int L) {
    extern __shared__ float buf[];
    size_t base = (size_t)blockIdx.x * L;
    float m = -3.4e38f;
    for (int i = threadIdx.x; i < L; i += blockDim.x) {
        float x = s[base + i];
        buf[i] = x;
        m = fmaxf(m, x);
    }
    m = blk_max(m);
    float lsum = 0.f;
    for (int i = threadIdx.x; i < L; i += blockDim.x) {
        float e = expf(buf[i] - m);
        buf[i] = e;
        lsum += e;
    }
    float sum = blk_sum(lsum);
    float inv = 1.f / sum;
    for (int i = threadIdx.x; i < L; i += blockDim.x)
        s[base + i] = buf[i] * inv;
}

// ---------------- pooler: out = tanh(h[:,0,:] @ pool_w + pool_b) ----------------
__global__ void pooler_kernel(const float* __restrict__ h, const float* __restrict__ pw,
                              const float* __restrict__ pb, float* __restrict__ out) {
    int j = blockIdx.x * blockDim.x + threadIdx.x;
    int b = blockIdx.y;
    if (j >= Dx) return;
    const float* hr = h + (size_t)b * Sx * Dx;  // token 0
    float acc = pb[j];
    for (int kI = 0; kI < Dx; kI++) acc += hr[kI] * pw[(size_t)kI * Dx + j];
    out[b * Dx + j] = tanhf(acc);
}

// ---------------- host launcher ----------------
extern "C" void kernel_launch(void* const* d_in, const int* in_sizes, int n_in,
                              void* d_out, int out_size) {
    const int*   input_ids = (const int*)d_in[0];
    const int*   attn_mask = (const int*)d_in[1];
    const int*   tok_type  = (const int*)d_in[2];
    const int*   rand_blk  = (const int*)d_in[3];
    const float* word_emb  = (const float*)d_in[4];
    const float* type_emb  = (const float*)d_in[5];
    const float* pos_emb   = (const float*)d_in[6];
    const float* emb_ln_s  = (const float*)d_in[7];
    const float* emb_ln_b  = (const float*)d_in[8];
    const float* Wq = (const float*)d_in[9];  const float* bq = (const float*)d_in[10];
    const float* Wk = (const float*)d_in[11]; const float* bk = (const float*)d_in[12];
    const float* Wv = (const float*)d_in[13]; const float* bv = (const float*)d_in[14];
    const float* Wo = (const float*)d_in[15]; const float* bo = (const float*)d_in[16];
    const float* ln1_s = (const float*)d_in[17]; const float* ln1_b = (const float*)d_in[18];
    const float* W1 = (const float*)d_in[19]; const float* b1 = (const float*)d_in[20];
    const float* W2 = (const float*)d_in[21]; const float* b2 = (const float*)d_in[22];
    const float* ln2_s = (const float*)d_in[23]; const float* ln2_b = (const float*)d_in[24];
    const float* pool_w = (const float*)d_in[25]; const float* pool_b = (const float*)d_in[26];
    float* out = (float*)d_out;

    float *p_h, *p_res, *p_q, *p_k, *p_v, *p_ctx, *p_ff, *p_smid, *p_sedge;
    cudaGetSymbolAddress((void**)&p_h,     g_h);
    cudaGetSymbolAddress((void**)&p_res,   g_res);
    cudaGetSymbolAddress((void**)&p_q,     g_q);
    cudaGetSymbolAddress((void**)&p_k,     g_k);
    cudaGetSymbolAddress((void**)&p_v,     g_v);
    cudaGetSymbolAddress((void**)&p_ctx,   g_ctx);
    cudaGetSymbolAddress((void**)&p_ff,    g_ff);
    cudaGetSymbolAddress((void**)&p_smid,  g_smid);
    cudaGetSymbolAddress((void**)&p_sedge, g_sedge);

    const int M = TOK;  // 8192

    embed_ln_kernel<<<TOK, 256>>>(input_ids, tok_type, word_emb, type_emb, pos_emb,
                                  emb_ln_s, emb_ln_b);

    for (int l = 0; l < 2; l++) {
        const float* wq = Wq + (size_t)l * Dx * Dx;  const float* bql = bq + (size_t)l * Dx;
        const float* wk = Wk + (size_t)l * Dx * Dx;  const float* bkl = bk + (size_t)l * Dx;
        const float* wv = Wv + (size_t)l * Dx * Dx;  const float* bvl = bv + (size_t)l * Dx;
        const float* wo = Wo + (size_t)l * Dx * Dx;  const float* bol = bo + (size_t)l * Dx;
        const float* w1 = W1 + (size_t)l * Dx * FFx; const float* b1l = b1 + (size_t)l * FFx;
        const float* w2 = W2 + (size_t)l * FFx * Dx; const float* b2l = b2 + (size_t)l * Dx;
        const float* l1s = ln1_s + (size_t)l * Dx; const float* l1b = ln1_b + (size_t)l * Dx;
        const float* l2s = ln2_s + (size_t)l * Dx; const float* l2b = ln2_b + (size_t)l * Dx;

        sgemm_kernel<0><<<dim3(Dx / 128, M / 128), 256>>>(p_h, wq, bql, p_q, M, Dx, Dx);
        sgemm_kernel<0><<<dim3(Dx / 128, M / 128), 256>>>(p_h, wk, bkl, p_k, M, Dx, Dx);
        sgemm_kernel<0><<<dim3(Dx / 128, M / 128), 256>>>(p_h, wv, bvl, p_v, M, Dx, Dx);

        mid_scores_kernel<<<dim3(NMID, NHx, Bx), 256>>>(p_q, p_k, rand_blk, attn_mask, p_smid);
        softmax_kernel<<<Bx * NHx * NMID * BSx, 256, (NGx * 64) * sizeof(float)>>>(p_smid, NGx * 64);
        mid_pv_kernel<<<dim3(NMID, NHx, Bx), 256>>>(p_smid, p_v, rand_blk, p_ctx);

        edge_scores_kernel<<<dim3(NBx, NHx, Bx * 2), 256>>>(p_q, p_k, attn_mask, p_sedge);
        softmax_kernel<<<Bx * NHx * 2 * BSx, 256, Sx * sizeof(float)>>>(p_sedge, Sx);
        edge_pv_kernel<<<dim3(NHx, Bx * 2), 256>>>(p_sedge, p_v, p_ctx);

        sgemm_kernel<0><<<dim3(Dx / 128, M / 128), 256>>>(p_ctx, wo, bol, p_res, M, Dx, Dx);
        add_ln_kernel<<<TOK, 256>>>(p_h, p_res, l1s, l1b);

        sgemm_kernel<1><<<dim3(FFx / 128, M / 128), 256>>>(p_h, w1, b1l, p_ff, M, FFx, Dx);
        sgemm_kernel<0><<<dim3(Dx / 128, M / 128), 256>>>(p_ff, w2, b2l, p_res, M, Dx, FFx);
        add_ln_kernel<<<TOK, 256>>>(p_h, p_res, l2s, l2b);
    }

    pooler_kernel<<<dim3((Dx + 127) / 128, Bx), 128>>>(p_h, pool_w, pool_b, out);
}

// round 3
// speedup vs baseline: 1.5538x; 1.5538x over previous
#include <cuda_runtime.h>
#include <cuda_bf16.h>
#include <cstdint>
#include <math.h>

#define Bx 2
#define Sx 4096
#define Dx 768
#define NHx 12
#define HDx 64
#define BSx 64
#define NBx 64
#define FFx 3072
#define Rx 3
#define NGx 8
#define NMID 62
#define TOK (Bx*Sx)

// ---------------- scratch (static device memory; no allocations) ----------------
__device__ float g_h[(size_t)TOK*Dx];
__device__ float g_res[(size_t)TOK*Dx];
__device__ float g_q[(size_t)TOK*Dx];
__device__ float g_k[(size_t)TOK*Dx];
__device__ float g_v[(size_t)TOK*Dx];
__device__ float g_ctx[(size_t)TOK*Dx];
__device__ float g_ff[(size_t)TOK*FFx];
__device__ float g_smid[(size_t)Bx*NHx*NMID*BSx*NGx*BSx];
__device__ float g_sedge[(size_t)Bx*NHx*2*BSx*Sx];

// ---------------- block reductions ----------------
__device__ __forceinline__ float blk_sum(float v) {
    __shared__ float red[33];
    #pragma unroll
    for (int o = 16; o; o >>= 1) v += __shfl_down_sync(0xffffffffu, v, o);
    int lane = threadIdx.x & 31, w = threadIdx.x >> 5;
    __syncthreads();
    if (lane == 0) red[w] = v;
    __syncthreads();
    if (w == 0) {
        float x = (lane < ((blockDim.x + 31) >> 5)) ? red[lane] : 0.f;
        #pragma unroll
        for (int o = 16; o; o >>= 1) x += __shfl_down_sync(0xffffffffu, x, o);
        if (lane == 0) red[32] = x;
    }
    __syncthreads();
    return red[32];
}

__device__ __forceinline__ float blk_max(float v) {
    __shared__ float redm[33];
    #pragma unroll
    for (int o = 16; o; o >>= 1) v = fmaxf(v, __shfl_down_sync(0xffffffffu, v, o));
    int lane = threadIdx.x & 31, w = threadIdx.x >> 5;
    __syncthreads();
    if (lane == 0) redm[w] = v;
    __syncthreads();
    if (w == 0) {
        float x = (lane < ((blockDim.x + 31) >> 5)) ? redm[lane] : -3.4e38f;
        #pragma unroll
        for (int o = 16; o; o >>= 1) x = fmaxf(x, __shfl_down_sync(0xffffffffu, x, o));
        if (lane == 0) redm[32] = x;
    }
    __syncthreads();
    return redm[32];
}

// ---------------- embeddings + LN ----------------
__global__ void embed_ln_kernel(const int* __restrict__ ids, const int* __restrict__ tt,
                                const float* __restrict__ wemb, const float* __restrict__ temb,
                                const float* __restrict__ pemb,
                                const float* __restrict__ lns, const float* __restrict__ lnb) {
    int tok = blockIdx.x;
    int pos = tok % Sx;
    const float* w = wemb + (size_t)ids[tok] * Dx;
    const float* t = temb + (size_t)tt[tok] * Dx;
    const float* p = pemb + (size_t)pos * Dx;
    __shared__ float buf[Dx];
    float ls = 0.f, lq = 0.f;
    for (int i = threadIdx.x; i < Dx; i += blockDim.x) {
        float x = w[i] + t[i] + p[i];
        buf[i] = x; ls += x; lq += x * x;
    }
    float sum = blk_sum(ls);
    float sq  = blk_sum(lq);
    float mu = sum * (1.f / Dx);
    float var = sq * (1.f / Dx) - mu * mu;
    float inv = rsqrtf(var + 1e-12f);
    for (int i = threadIdx.x; i < Dx; i += blockDim.x)
        g_h[(size_t)tok * Dx + i] = lns[i] * (buf[i] - mu) * inv + lnb[i];
}

// ---------------- residual add + LN (in-place on h) ----------------
__global__ void add_ln_kernel(float* __restrict__ h, const float* __restrict__ r,
                              const float* __restrict__ lns, const float* __restrict__ lnb) {
    int tok = blockIdx.x;
    __shared__ float buf[Dx];
    float ls = 0.f, lq = 0.f;
    for (int i = threadIdx.x; i < Dx; i += blockDim.x) {
        float x = h[(size_t)tok * Dx + i] + r[(size_t)tok * Dx + i];
        buf[i] = x; ls += x; lq += x * x;
    }
    float sum = blk_sum(ls);
    float sq  = blk_sum(lq);
    float mu = sum * (1.f / Dx);
    float var = sq * (1.f / Dx) - mu * mu;
    float inv = rsqrtf(var + 1e-12f);
    for (int i = threadIdx.x; i < Dx; i += blockDim.x)
        h[(size_t)tok * Dx + i] = lns[i] * (buf[i] - mu) * inv + lnb[i];
}

// ---------------- tensor-core GEMM (split-bf16, fp32-accurate) ----------------
__device__ __forceinline__ void ldsm_x4(uint32_t* r, uint32_t addr) {
    asm volatile("ldmatrix.sync.aligned.m8n8.x4.shared.b16 {%0,%1,%2,%3}, [%4];"
                 : "=r"(r[0]), "=r"(r[1]), "=r"(r[2]), "=r"(r[3]) : "r"(addr));
}
__device__ __forceinline__ void ldsm_x4t(uint32_t* r, uint32_t addr) {
    asm volatile("ldmatrix.sync.aligned.m8n8.x4.trans.shared.b16 {%0,%1,%2,%3}, [%4];"
                 : "=r"(r[0]), "=r"(r[1]), "=r"(r[2]), "=r"(r[3]) : "r"(addr));
}
__device__ __forceinline__ void mma_bf16(float* c, const uint32_t* a, uint32_t b0, uint32_t b1) {
    asm volatile("mma.sync.aligned.m16n8k16.row.col.f32.bf16.bf16.f32 "
                 "{%0,%1,%2,%3}, {%4,%5,%6,%7}, {%8,%9}, {%0,%1,%2,%3};"
                 : "+f"(c[0]), "+f"(c[1]), "+f"(c[2]), "+f"(c[3])
                 : "r"(a[0]), "r"(a[1]), "r"(a[2]), "r"(a[3]), "r"(b0), "r"(b1));
}
__device__ __forceinline__ void split2(float x, __nv_bfloat16& hi, __nv_bfloat16& lo) {
    hi = __float2bfloat16_rn(x);
    lo = __float2bfloat16_rn(x - __bfloat162float(hi));
}

// C = act(A[M,K] @ W[K,N] + bias). Tile 128x128x32; 256 threads = 8 warps (4M x 2N).
template<int GELU>
__global__ void __launch_bounds__(256) bgemm_kernel(
    const float* __restrict__ A, const float* __restrict__ W,
    const float* __restrict__ bias, float* __restrict__ C,
    int M, int N, int K)
{
    __shared__ __nv_bfloat16 Ah[128][40];
    __shared__ __nv_bfloat16 Al[128][40];
    __shared__ __nv_bfloat16 Bh[32][136];
    __shared__ __nv_bfloat16 Bl[32][136];

    const int tid = threadIdx.x;
    const int lane = tid & 31;
    const int wid = tid >> 5;
    const int warp_m = wid & 3;
    const int warp_n = wid >> 2;
    const int bxb = blockIdx.x;
    const int byb = blockIdx.y;

    float4 areg[4];
    float4 wreg[4];
    #pragma unroll
    for (int i = 0; i < 4; i++) {
        int f = tid + i * 256;
        int rA = f >> 3, cA = (f & 7) << 2;
        int rB = f >> 5, cB = (f & 31) << 2;
        areg[i] = *(const float4*)(A + (size_t)(byb * 128 + rA) * K + cA);
        wreg[i] = *(const float4*)(W + (size_t)rB * N + bxb * 128 + cB);
    }

    float acc[2][8][4];
    #pragma unroll
    for (int mt = 0; mt < 2; mt++) {
        #pragma unroll
        for (int nt = 0; nt < 8; nt++) {
            acc[mt][nt][0] = 0.f; acc[mt][nt][1] = 0.f;
            acc[mt][nt][2] = 0.f; acc[mt][nt][3] = 0.f;
        }
    }

    const int a_tile = lane >> 3;
    const int a_rl = lane & 7;
    const int a_ldrow = warp_m * 32 + (a_tile & 1) * 8 + a_rl;
    const int a_ldcol = (a_tile >> 1) * 8;
    const int b_ldk = (a_tile & 1) * 8 + a_rl;
    const int b_ldn = warp_n * 64 + (a_tile >> 1) * 8;

    for (int k0 = 0; k0 < K; k0 += 32) {
        // stage current tile into smem (split hi/lo)
        #pragma unroll
        for (int i = 0; i < 4; i++) {
            int f = tid + i * 256;
            int rA = f >> 3, cA = (f & 7) << 2;
            split2(areg[i].x, Ah[rA][cA + 0], Al[rA][cA + 0]);
            split2(areg[i].y, Ah[rA][cA + 1], Al[rA][cA + 1]);
            split2(areg[i].z, Ah[rA][cA + 2], Al[rA][cA + 2]);
            split2(areg[i].w, Ah[rA][cA + 3], Al[rA][cA + 3]);
            int rB = f >> 5, cB = (f & 31) << 2;
            split2(wreg[i].x, Bh[rB][cB + 0], Bl[rB][cB + 0]);
            split2(wreg[i].y, Bh[rB][cB + 1], Bl[rB][cB + 1]);
            split2(wreg[i].z, Bh[rB][cB + 2], Bl[rB][cB + 2]);
            split2(wreg[i].w, Bh[rB][cB + 3], Bl[rB][cB + 3]);
        }
        __syncthreads();

        // prefetch next tile
        if (k0 + 32 < K) {
            #pragma unroll
            for (int i = 0; i < 4; i++) {
                int f = tid + i * 256;
                int rA = f >> 3, cA = (f & 7) << 2;
                int rB = f >> 5, cB = (f & 31) << 2;
                areg[i] = *(const float4*)(A + (size_t)(byb * 128 + rA) * K + k0 + 32 + cA);
                wreg[i] = *(const float4*)(W + (size_t)(k0 + 32 + rB) * N + bxb * 128 + cB);
            }
        }

        #pragma unroll
        for (int kk = 0; kk < 32; kk += 16) {
            uint32_t ah0[4], ah1[4], al0[4], al1[4];
            ldsm_x4(ah0, (uint32_t)__cvta_generic_to_shared(&Ah[a_ldrow][a_ldcol + kk]));
            ldsm_x4(ah1, (uint32_t)__cvta_generic_to_shared(&Ah[a_ldrow + 16][a_ldcol + kk]));
            ldsm_x4(al0, (uint32_t)__cvta_generic_to_shared(&Al[a_ldrow][a_ldcol + kk]));
            ldsm_x4(al1, (uint32_t)__cvta_generic_to_shared(&Al[a_ldrow + 16][a_ldcol + kk]));
            #pragma unroll
            for (int p = 0; p < 4; p++) {
                uint32_t bh4[4], bl4[4];
                ldsm_x4t(bh4, (uint32_t)__cvta_generic_to_shared(&Bh[kk + b_ldk][b_ldn + p * 16]));
                ldsm_x4t(bl4, (uint32_t)__cvta_generic_to_shared(&Bl[kk + b_ldk][b_ldn + p * 16]));
                int nt0 = p * 2;
                int nt1 = p * 2 + 1;
                mma_bf16(acc[0][nt0], ah0, bh4[0], bh4[1]);
                mma_bf16(acc[0][nt0], ah0, bl4[0], bl4[1]);
                mma_bf16(acc[0][nt0], al0, bh4[0], bh4[1]);
                mma_bf16(acc[0][nt1], ah0, bh4[2], bh4[3]);
                mma_bf16(acc[0][nt1], ah0, bl4[2], bl4[3]);
                mma_bf16(acc[0][nt1], al0, bh4[2], bh4[3]);
                mma_bf16(acc[1][nt0], ah1, bh4[0], bh4[1]);
                mma_bf16(acc[1][nt0], ah1, bl4[0], bl4[1]);
                mma_bf16(acc[1][nt0], al1, bh4[0], bh4[1]);
                mma_bf16(acc[1][nt1], ah1, bh4[2], bh4[3]);
                mma_bf16(acc[1][nt1], ah1, bl4[2], bl4[3]);
                mma_bf16(acc[1][nt1], al1, bh4[2], bh4[3]);
            }
        }
        __syncthreads();
    }

    // epilogue
    const int grp = lane >> 2;
    const int tig = lane & 3;
    #pragma unroll
    for (int mt = 0; mt < 2; mt++) {
        #pragma unroll
        for (int nt = 0; nt < 8; nt++) {
            int col = bxb * 128 + warp_n * 64 + nt * 8 + tig * 2;
            float b0 = bias[col];
            float b1 = bias[col + 1];
            #pragma unroll
            for (int half = 0; half < 2; half++) {
                int row = byb * 128 + warp_m * 32 + mt * 16 + grp + half * 8;
                float v0 = acc[mt][nt][half * 2 + 0] + b0;
                float v1 = acc[mt][nt][half * 2 + 1] + b1;
                if (GELU) {
                    v0 = 0.5f * v0 * (1.f + erff(v0 * 0.70710678118654752f));
                    v1 = 0.5f * v1 * (1.f + erff(v1 * 0.70710678118654752f));
                }
                C[(size_t)row * N + col] = v0;
                C[(size_t)row * N + col + 1] = v1;
            }
        }
    }
}

// ---------------- helpers for block indices ----------------
__device__ __forceinline__ int mid_block_idx(int n, int g, const int* __restrict__ randb) {
    if (g == 0) return 0;
    if (g == 1) return NBx - 1;
    if (g < 5)  return n - 3 + g;
    return randb[(n - 1) * Rx + (g - 5)];
}

// ---------------- middle-block scores ----------------
__global__ void __launch_bounds__(256) mid_scores_kernel(
    const float* __restrict__ q, const float* __restrict__ k,
    const int* __restrict__ randb, const int* __restrict__ amask,
    float* __restrict__ smid)
{
    int n = blockIdx.x + 1;
    int h = blockIdx.y;
    int b = blockIdx.z;
    __shared__ float Qs[64][65];
    __shared__ float Ks[64][65];
    int tid = threadIdx.x;
    int tx = tid & 15, ty = tid >> 4;

    const float* qbase = q + ((size_t)b * Sx + n * 64) * Dx + h * 64;
    for (int f = tid; f < 1024; f += 256) {
        int qi = f >> 4, d4 = (f & 15) << 2;
        float4 v = *(const float4*)(qbase + (size_t)qi * Dx + d4);
        Qs[d4 + 0][qi] = v.x; Qs[d4 + 1][qi] = v.y;
        Qs[d4 + 2][qi] = v.z; Qs[d4 + 3][qi] = v.w;
    }
    float* out = smid + (((size_t)(b * NHx + h) * NMID + (n - 1)) << 15);

    for (int g = 0; g < NGx; g++) {
        int kb = mid_block_idx(n, g, randb);
        const float* kbase = k + ((size_t)b * Sx + kb * 64) * Dx + h * 64;
        __syncthreads();
        for (int f = tid; f < 1024; f += 256) {
            int ki = f >> 4, d4 = (f & 15) << 2;
            float4 v = *(const float4*)(kbase + (size_t)ki * Dx + d4);
            Ks[d4 + 0][ki] = v.x; Ks[d4 + 1][ki] = v.y;
            Ks[d4 + 2][ki] = v.z; Ks[d4 + 3][ki] = v.w;
        }
        __syncthreads();
        float acc[4][4] = {};
        #pragma unroll 16
        for (int d = 0; d < 64; d++) {
            float ar[4], br[4];
            #pragma unroll
            for (int i = 0; i < 4; i++) ar[i] = Qs[d][ty * 4 + i];
            #pragma unroll
            for (int j = 0; j < 4; j++) br[j] = Ks[d][tx * 4 + j];
            #pragma unroll
            for (int i = 0; i < 4; i++) {
                #pragma unroll
                for (int j = 0; j < 4; j++) acc[i][j] += ar[i] * br[j];
            }
        }
        #pragma unroll
        for (int j = 0; j < 4; j++) {
            int ki = tx * 4 + j;
            float madd = (1.0f - (float)amask[b * Sx + kb * 64 + ki]) * -1e9f;
            #pragma unroll
            for (int i = 0; i < 4; i++) {
                int qi = ty * 4 + i;
                out[(size_t)qi * (NGx * 64) + g * 64 + ki] = acc[i][j] * 0.125f + madd;
            }
        }
    }
}

// ---------------- middle-block PV ----------------
__global__ void __launch_bounds__(256) mid_pv_kernel(
    const float* __restrict__ p, const float* __restrict__ v,
    const int* __restrict__ randb, float* __restrict__ ctx)
{
    int n = blockIdx.x + 1;
    int h = blockIdx.y;
    int b = blockIdx.z;
    __shared__ float Ps[64][65];
    __shared__ float Vs[64][65];
    int tid = threadIdx.x;
    int tx = tid & 15, ty = tid >> 4;

    const float* prow = p + (((size_t)(b * NHx + h) * NMID + (n - 1)) << 15);
    float acc[4][4] = {};

    for (int g = 0; g < NGx; g++) {
        int kb = mid_block_idx(n, g, randb);
        const float* vbase = v + ((size_t)b * Sx + kb * 64) * Dx + h * 64;
        __syncthreads();
        for (int f = tid; f < 1024; f += 256) {
            int qi = f >> 4, k4 = (f & 15) << 2;
            float4 t = *(const float4*)(prow + (size_t)qi * (NGx * 64) + g * 64 + k4);
            Ps[k4 + 0][qi] = t.x; Ps[k4 + 1][qi] = t.y;
            Ps[k4 + 2][qi] = t.z; Ps[k4 + 3][qi] = t.w;
        }
        for (int f = tid; f < 1024; f += 256) {
            int ki = f >> 4, d4 = (f & 15) << 2;
            float4 t = *(const float4*)(vbase + (size_t)ki * Dx + d4);
            Vs[ki][d4 + 0] = t.x; Vs[ki][d4 + 1] = t.y;
            Vs[ki][d4 + 2] = t.z; Vs[ki][d4 + 3] = t.w;
        }
        __syncthreads();
        #pragma unroll 16
        for (int kk = 0; kk < 64; kk++) {
            float ar[4], br[4];
            #pragma unroll
            for (int i = 0; i < 4; i++) ar[i] = Ps[kk][ty * 4 + i];
            #pragma unroll
            for (int j = 0; j < 4; j++) br[j] = Vs[kk][tx * 4 + j];
            #pragma unroll
            for (int i = 0; i < 4; i++) {
                #pragma unroll
                for (int j = 0; j < 4; j++) acc[i][j] += ar[i] * br[j];
            }
        }
    }
    float* cbase = ctx + ((size_t)b * Sx + n * 64) * Dx + h * 64;
    #pragma unroll
    for (int i = 0; i < 4; i++) {
        #pragma unroll
        for (int j = 0; j < 4; j++)
            cbase[(size_t)(ty * 4 + i) * Dx + tx * 4 + j] = acc[i][j];
    }
}

// ---------------- edge scores ----------------
__global__ void __launch_bounds__(256) edge_scores_kernel(
    const float* __restrict__ q, const float* __restrict__ k,
    const int* __restrict__ amask, float* __restrict__ sedge)
{
    int kb = blockIdx.x;
    int h  = blockIdx.y;
    int e  = blockIdx.z & 1;
    int b  = blockIdx.z >> 1;
    int qb = e ? (NBx - 1) : 0;
    __shared__ float Qs[64][65];
    __shared__ float Ks[64][65];
    int tid = threadIdx.x;
    int tx = tid & 15, ty = tid >> 4;

    const float* qbase = q + ((size_t)b * Sx + qb * 64) * Dx + h * 64;
    const float* kbase = k + ((size_t)b * Sx + kb * 64) * Dx + h * 64;
    for (int f = tid; f < 1024; f += 256) {
        int r = f >> 4, d4 = (f & 15) << 2;
        float4 a = *(const float4*)(qbase + (size_t)r * Dx + d4);
        Qs[d4 + 0][r] = a.x; Qs[d4 + 1][r] = a.y; Qs[d4 + 2][r] = a.z; Qs[d4 + 3][r] = a.w;
        float4 c = *(const float4*)(kbase + (size_t)r * Dx + d4);
        Ks[d4 + 0][r] = c.x; Ks[d4 + 1][r] = c.y; Ks[d4 + 2][r] = c.z; Ks[d4 + 3][r] = c.w;
    }
    __syncthreads();
    float acc[4][4] = {};
    #pragma unroll 16
    for (int d = 0; d < 64; d++) {
        float ar[4], br[4];
        #pragma unroll
        for (int i = 0; i < 4; i++) ar[i] = Qs[d][ty * 4 + i];
        #pragma unroll
        for (int j = 0; j < 4; j++) br[j] = Ks[d][tx * 4 + j];
        #pragma unroll
        for (int i = 0; i < 4; i++) {
            #pragma unroll
            for (int j = 0; j < 4; j++) acc[i][j] += ar[i] * br[j];
        }
    }
    float* out = sedge + ((size_t)((b * NHx + h) * 2 + e)) * (64 * Sx);
    #pragma unroll
    for (int j = 0; j < 4; j++) {
        int ki = tx * 4 + j;
        float madd = (1.0f - (float)amask[b * Sx + kb * 64 + ki]) * -1e9f;
        #pragma unroll
        for (int i = 0; i < 4; i++) {
            int qi = ty * 4 + i;
            out[(size_t)qi * Sx + kb * 64 + ki] = acc[i][j] * 0.125f + madd;
        }
    }
}

// ---------------- edge PV ----------------
__global__ void __launch_bounds__(256) edge_pv_kernel(
    const float* __restrict__ p, const float* __restrict__ v, float* __restrict__ ctx)
{
    int h = blockIdx.x;
    int e = blockIdx.y & 1;
    int b = blockIdx.y >> 1;
    int qb = e ? (NBx - 1) : 0;
    __shared__ float Ps[64][65];
    __shared__ float Vs[64][65];
    int tid = threadIdx.x;
    int tx = tid & 15, ty = tid >> 4;

    const float* prow = p + ((size_t)((b * NHx + h) * 2 + e)) * (64 * Sx);
    float acc[4][4] = {};
    for (int kb = 0; kb < NBx; kb++) {
        const float* vbase = v + ((size_t)b * Sx + kb * 64) * Dx + h * 64;
        __syncthreads();
        for (int f = tid; f < 1024; f += 256) {
            int qi = f >> 4, k4 = (f & 15) << 2;
            float4 t = *(const float4*)(prow + (size_t)qi * Sx + kb * 64 + k4);
            Ps[k4 + 0][qi] = t.x; Ps[k4 + 1][qi] = t.y;
            Ps[k4 + 2][qi] = t.z; Ps[k4 + 3][qi] = t.w;
        }
        for (int f = tid; f < 1024; f += 256) {
            int ki = f >> 4, d4 = (f & 15) << 2;
            float4 t = *(const float4*)(vbase + (size_t)ki * Dx + d4);
            Vs[ki][d4 + 0] = t.x; Vs[ki][d4 + 1] = t.y;
            Vs[ki][d4 + 2] = t.z; Vs[ki][d4 + 3] = t.w;
        }
        __syncthreads();
        #pragma unroll 16
        for (int kk = 0; kk < 64; kk++) {
            float ar[4], br[4];
            #pragma unroll
            for (int i = 0; i < 4; i++) ar[i] = Ps[kk][ty * 4 + i];
            #pragma unroll
            for (int j = 0; j < 4; j++) br[j] = Vs[kk][tx * 4 + j];
            #pragma unroll
            for (int i = 0; i < 4; i++) {
                #pragma unroll
                for (int j = 0; j < 4; j++) acc[i][j] += ar[i] * br[j];
            }
        }
    }
    float* cbase = ctx + ((size_t)b * Sx + qb * 64) * Dx + h * 64;
    #pragma unroll
    for (int i = 0; i < 4; i++) {
        #pragma unroll
        for (int j = 0; j < 4; j++)
            cbase[(size_t)(ty * 4 + i) * Dx + tx * 4 + j] = acc[i][j];
    }
}

// ---------------- row softmax (in-place), row length L ----------------
__global__ void softmax_kernel(float* __restrict__ s, int L) {
    extern __shared__ float buf[];
    size_t base = (size_t)blockIdx.x * L;
    float m = -3.4e38f;
    for (int i = threadIdx.x; i < L; i += blockDim.x) {
        float x = s[base + i];
        buf[i] = x;
        m = fmaxf(m, x);
    }
    m = blk_max(m);
    float lsum = 0.f;
    for (int i = threadIdx.x; i < L; i += blockDim.x) {
        float e = expf(buf[i] - m);
        buf[i] = e;
        lsum += e;
    }
    float sum = blk_sum(lsum);
    float inv = 1.f / sum;
    for (int i = threadIdx.x; i < L; i += blockDim.x)
        s[base + i] = buf[i] * inv;
}

// ---------------- pooler ----------------
__global__ void pooler_kernel(const float* __restrict__ h, const float* __restrict__ pw,
                              const float* __restrict__ pb, float* __restrict__ out) {
    int j = blockIdx.x * blockDim.x + threadIdx.x;
    int b = blockIdx.y;
    if (j >= Dx) return;
    const float* hr = h + (size_t)b * Sx * Dx;
    float acc = pb[j];
    for (int kI = 0; kI < Dx; kI++) acc += hr[kI] * pw[(size_t)kI * Dx + j];
    out[b * Dx + j] = tanhf(acc);
}

// ---------------- host launcher ----------------
extern "C" void kernel_launch(void* const* d_in, const int* in_sizes, int n_in,
                              void* d_out, int out_size) {
    const int*   input_ids = (const int*)d_in[0];
    const int*   attn_mask = (const int*)d_in[1];
    const int*   tok_type  = (const int*)d_in[2];
    const int*   rand_blk  = (const int*)d_in[3];
    const float* word_emb  = (const float*)d_in[4];
    const float* type_emb  = (const float*)d_in[5];
    const float* pos_emb   = (const float*)d_in[6];
    const float* emb_ln_s  = (const float*)d_in[7];
    const float* emb_ln_b  = (const float*)d_in[8];
    const float* Wq = (const float*)d_in[9];  const float* bq = (const float*)d_in[10];
    const float* Wk = (const float*)d_in[11]; const float* bk = (const float*)d_in[12];
    const float* Wv = (const float*)d_in[13]; const float* bv = (const float*)d_in[14];
    const float* Wo = (const float*)d_in[15]; const float* bo = (const float*)d_in[16];
    const float* ln1_s = (const float*)d_in[17]; const float* ln1_b = (const float*)d_in[18];
    const float* W1 = (const float*)d_in[19]; const float* b1 = (const float*)d_in[20];
    const float* W2 = (const float*)d_in[21]; const float* b2 = (const float*)d_in[22];
    const float* ln2_s = (const float*)d_in[23]; const float* ln2_b = (const float*)d_in[24];
    const float* pool_w = (const float*)d_in[25]; const float* pool_b = (const float*)d_in[26];
    float* out = (float*)d_out;

    float *p_h = 0, *p_res = 0, *p_q = 0, *p_k = 0, *p_v = 0, *p_ctx = 0, *p_ff = 0, *p_smid = 0, *p_sedge = 0;
    cudaGetSymbolAddress((void**)&p_h,     g_h);
    cudaGetSymbolAddress((void**)&p_res,   g_res);
    cudaGetSymbolAddress((void**)&p_q,     g_q);
    cudaGetSymbolAddress((void**)&p_k,     g_k);
    cudaGetSymbolAddress((void**)&p_v,     g_v);
    cudaGetSymbolAddress((void**)&p_ctx,   g_ctx);
    cudaGetSymbolAddress((void**)&p_ff,    g_ff);
    cudaGetSymbolAddress((void**)&p_smid,  g_smid);
    cudaGetSymbolAddress((void**)&p_sedge, g_sedge);

    const int M = TOK;

    embed_ln_kernel<<<TOK, 256>>>(input_ids, tok_type, word_emb, type_emb, pos_emb,
                                  emb_ln_s, emb_ln_b);

    for (int l = 0; l < 2; l++) {
        const float* wq = Wq + (size_t)l * Dx * Dx;  const float* bql = bq + (size_t)l * Dx;
        const float* wk = Wk + (size_t)l * Dx * Dx;  const float* bkl = bk + (size_t)l * Dx;
        const float* wv = Wv + (size_t)l * Dx * Dx;  const float* bvl = bv + (size_t)l * Dx;
        const float* wo = Wo + (size_t)l * Dx * Dx;  const float* bol = bo + (size_t)l * Dx;
        const float* w1 = W1 + (size_t)l * Dx * FFx; const float* b1l = b1 + (size_t)l * FFx;
        const float* w2 = W2 + (size_t)l * FFx * Dx; const float* b2l = b2 + (size_t)l * Dx;
        const float* l1s = ln1_s + (size_t)l * Dx; const float* l1b = ln1_b + (size_t)l * Dx;
        const float* l2s = ln2_s + (size_t)l * Dx; const float* l2b = ln2_b + (size_t)l * Dx;

        bgemm_kernel<0><<<dim3(Dx / 128, M / 128), 256>>>(p_h, wq, bql, p_q, M, Dx, Dx);
        bgemm_kernel<0><<<dim3(Dx / 128, M / 128), 256>>>(p_h, wk, bkl, p_k, M, Dx, Dx);
        bgemm_kernel<0><<<dim3(Dx / 128, M / 128), 256>>>(p_h, wv, bvl, p_v, M, Dx, Dx);

        mid_scores_kernel<<<dim3(NMID, NHx, Bx), 256>>>(p_q, p_k, rand_blk, attn_mask, p_smid);
        softmax_kernel<<<Bx * NHx * NMID * BSx, 256, (NGx * 64) * sizeof(float)>>>(p_smid, NGx * 64);
        mid_pv_kernel<<<dim3(NMID, NHx, Bx), 256>>>(p_smid, p_v, rand_blk, p_ctx);

        edge_scores_kernel<<<dim3(NBx, NHx, Bx * 2), 256>>>(p_q, p_k, attn_mask, p_sedge);
        softmax_kernel<<<Bx * NHx * 2 * BSx, 256, Sx * sizeof(float)>>>(p_sedge, Sx);
        edge_pv_kernel<<<dim3(NHx, Bx * 2), 256>>>(p_sedge, p_v, p_ctx);

        bgemm_kernel<0><<<dim3(Dx / 128, M / 128), 256>>>(p_ctx, wo, bol, p_res, M, Dx, Dx);
        add_ln_kernel<<<TOK, 256>>>(p_h, p_res, l1s, l1b);

        bgemm_kernel<1><<<dim3(FFx / 128, M / 128), 256>>>(p_h, w1, b1l, p_ff, M, FFx, Dx);
        bgemm_kernel<0><<<dim3(Dx / 128, M / 128), 256>>>(p_ff, w2, b2l, p_res, M, Dx, FFx);
        add_ln_kernel<<<TOK, 256>>>(p_h, p_res, l2s, l2b);
    }

    pooler_kernel<<<dim3((Dx + 127) / 128, Bx), 128>>>(p_h, pool_w, pool_b, out);
}

// round 4
// speedup vs baseline: 1.7524x; 1.1278x over previous
#include <cuda_runtime.h>
#include <cuda_bf16.h>
#include <cstdint>
#include <math.h>

#define Bx 2
#define Sx 4096
#define Dx 768
#define NHx 12
#define HDx 64
#define BSx 64
#define NBx 64
#define FFx 3072
#define Rx 3
#define NGx 8
#define NMID 62
#define TOK (Bx*Sx)

// ---------------- scratch (static device memory; no allocations) ----------------
__device__ float g_h[(size_t)TOK*Dx];
__device__ float g_res[(size_t)TOK*Dx];
__device__ float g_q[(size_t)TOK*Dx];
__device__ float g_k[(size_t)TOK*Dx];
__device__ float g_v[(size_t)TOK*Dx];
__device__ float g_ctx[(size_t)TOK*Dx];
__device__ float g_ff[(size_t)TOK*FFx];
__device__ float g_smid[(size_t)Bx*NHx*NMID*BSx*NGx*BSx];
__device__ float g_sedge[(size_t)Bx*NHx*2*BSx*Sx];
// bf16 hi/lo planes
__device__ __nv_bfloat16 g_act_hi[(size_t)TOK*FFx];
__device__ __nv_bfloat16 g_act_lo[(size_t)TOK*FFx];
__device__ __nv_bfloat16 g_w_hi[(size_t)Dx*FFx];
__device__ __nv_bfloat16 g_w_lo[(size_t)Dx*FFx];

// ---------------- block reductions ----------------
__device__ __forceinline__ float blk_sum(float v) {
    __shared__ float red[33];
    #pragma unroll
    for (int o = 16; o; o >>= 1) v += __shfl_down_sync(0xffffffffu, v, o);
    int lane = threadIdx.x & 31, w = threadIdx.x >> 5;
    __syncthreads();
    if (lane == 0) red[w] = v;
    __syncthreads();
    if (w == 0) {
        float x = (lane < ((blockDim.x + 31) >> 5)) ? red[lane] : 0.f;
        #pragma unroll
        for (int o = 16; o; o >>= 1) x += __shfl_down_sync(0xffffffffu, x, o);
        if (lane == 0) red[32] = x;
    }
    __syncthreads();
    return red[32];
}

__device__ __forceinline__ float blk_max(float v) {
    __shared__ float redm[33];
    #pragma unroll
    for (int o = 16; o; o >>= 1) v = fmaxf(v, __shfl_down_sync(0xffffffffu, v, o));
    int lane = threadIdx.x & 31, w = threadIdx.x >> 5;
    __syncthreads();
    if (lane == 0) redm[w] = v;
    __syncthreads();
    if (w == 0) {
        float x = (lane < ((blockDim.x + 31) >> 5)) ? redm[lane] : -3.4e38f;
        #pragma unroll
        for (int o = 16; o; o >>= 1) x = fmaxf(x, __shfl_down_sync(0xffffffffu, x, o));
        if (lane == 0) redm[32] = x;
    }
    __syncthreads();
    return redm[32];
}

// ---------------- fp32 -> (hi, lo) bf16 planes ----------------
__global__ void split_kernel(const float* __restrict__ in,
                             __nv_bfloat16* __restrict__ hi,
                             __nv_bfloat16* __restrict__ lo, int n4) {
    int i = blockIdx.x * blockDim.x + threadIdx.x;
    if (i >= n4) return;
    float4 v = ((const float4*)in)[i];
    __nv_bfloat16 h0 = __float2bfloat16_rn(v.x);
    __nv_bfloat16 h1 = __float2bfloat16_rn(v.y);
    __nv_bfloat16 h2 = __float2bfloat16_rn(v.z);
    __nv_bfloat16 h3 = __float2bfloat16_rn(v.w);
    __nv_bfloat16 l0 = __float2bfloat16_rn(v.x - __bfloat162float(h0));
    __nv_bfloat16 l1 = __float2bfloat16_rn(v.y - __bfloat162float(h1));
    __nv_bfloat16 l2 = __float2bfloat16_rn(v.z - __bfloat162float(h2));
    __nv_bfloat16 l3 = __float2bfloat16_rn(v.w - __bfloat162float(h3));
    ((__nv_bfloat162*)hi)[2*i]   = __halves2bfloat162(h0, h1);
    ((__nv_bfloat162*)hi)[2*i+1] = __halves2bfloat162(h2, h3);
    ((__nv_bfloat162*)lo)[2*i]   = __halves2bfloat162(l0, l1);
    ((__nv_bfloat162*)lo)[2*i+1] = __halves2bfloat162(l2, l3);
}

// ---------------- embeddings + LN ----------------
__global__ void embed_ln_kernel(const int* __restrict__ ids, const int* __restrict__ tt,
                                const float* __restrict__ wemb, const float* __restrict__ temb,
                                const float* __restrict__ pemb,
                                const float* __restrict__ lns, const float* __restrict__ lnb) {
    int tok = blockIdx.x;
    int pos = tok % Sx;
    const float* w = wemb + (size_t)ids[tok] * Dx;
    const float* t = temb + (size_t)tt[tok] * Dx;
    const float* p = pemb + (size_t)pos * Dx;
    __shared__ float buf[Dx];
    float ls = 0.f, lq = 0.f;
    for (int i = threadIdx.x; i < Dx; i += blockDim.x) {
        float x = w[i] + t[i] + p[i];
        buf[i] = x; ls += x; lq += x * x;
    }
    float sum = blk_sum(ls);
    float sq  = blk_sum(lq);
    float mu = sum * (1.f / Dx);
    float var = sq * (1.f / Dx) - mu * mu;
    float inv = rsqrtf(var + 1e-12f);
    for (int i = threadIdx.x; i < Dx; i += blockDim.x)
        g_h[(size_t)tok * Dx + i] = lns[i] * (buf[i] - mu) * inv + lnb[i];
}

// ---------------- residual add + LN (in-place on h) ----------------
__global__ void add_ln_kernel(float* __restrict__ h, const float* __restrict__ r,
                              const float* __restrict__ lns, const float* __restrict__ lnb) {
    int tok = blockIdx.x;
    __shared__ float buf[Dx];
    float ls = 0.f, lq = 0.f;
    for (int i = threadIdx.x; i < Dx; i += blockDim.x) {
        float x = h[(size_t)tok * Dx + i] + r[(size_t)tok * Dx + i];
        buf[i] = x; ls += x; lq += x * x;
    }
    float sum = blk_sum(ls);
    float sq  = blk_sum(lq);
    float mu = sum * (1.f / Dx);
    float var = sq * (1.f / Dx) - mu * mu;
    float inv = rsqrtf(var + 1e-12f);
    for (int i = threadIdx.x; i < Dx; i += blockDim.x)
        h[(size_t)tok * Dx + i] = lns[i] * (buf[i] - mu) * inv + lnb[i];
}

// ---------------- tensor-core GEMM primitives ----------------
__device__ __forceinline__ void ldsm_x4(uint32_t* r, uint32_t addr) {
    asm volatile("ldmatrix.sync.aligned.m8n8.x4.shared.b16 {%0,%1,%2,%3}, [%4];"
                 : "=r"(r[0]), "=r"(r[1]), "=r"(r[2]), "=r"(r[3]) : "r"(addr));
}
__device__ __forceinline__ void ldsm_x4t(uint32_t* r, uint32_t addr) {
    asm volatile("ldmatrix.sync.aligned.m8n8.x4.trans.shared.b16 {%0,%1,%2,%3}, [%4];"
                 : "=r"(r[0]), "=r"(r[1]), "=r"(r[2]), "=r"(r[3]) : "r"(addr));
}
__device__ __forceinline__ void mma_bf16(float* c, const uint32_t* a, uint32_t b0, uint32_t b1) {
    asm volatile("mma.sync.aligned.m16n8k16.row.col.f32.bf16.bf16.f32 "
                 "{%0,%1,%2,%3}, {%4,%5,%6,%7}, {%8,%9}, {%0,%1,%2,%3};"
                 : "+f"(c[0]), "+f"(c[1]), "+f"(c[2]), "+f"(c[3])
                 : "r"(a[0]), "r"(a[1]), "r"(a[2]), "r"(a[3]), "r"(b0), "r"(b1));
}
__device__ __forceinline__ void cp16(void* dst, const void* src) {
    uint32_t d = (uint32_t)__cvta_generic_to_shared(dst);
    asm volatile("cp.async.cg.shared.global [%0], [%1], 16;" :: "r"(d), "l"(src));
}

// smem stage layout (elements): Ah 128x40, Al 128x40, Bh 32x136, Bl 32x136
#define STAGE_ELT 18944
#define OFF_AL 5120
#define OFF_BH 10240
#define OFF_BL 14592
#define SMEM_BYTES (2 * STAGE_ELT * 2)

__device__ __forceinline__ void load_stage(
    __nv_bfloat16* sm, int s, int k0, int tid, int byb, int bxb,
    const __nv_bfloat16* Ahg, const __nv_bfloat16* Alg,
    const __nv_bfloat16* Whg, const __nv_bfloat16* Wlg, int N, int K)
{
    __nv_bfloat16* base = sm + s * STAGE_ELT;
    #pragma unroll
    for (int i = 0; i < 2; i++) {
        int idx = tid + i * 256;
        int rA = idx >> 2, cA = (idx & 3) * 8;
        size_t ga = (size_t)(byb * 128 + rA) * K + k0 + cA;
        cp16(base + rA * 40 + cA, Ahg + ga);
        cp16(base + OFF_AL + rA * 40 + cA, Alg + ga);
        int rB = idx >> 4, cB = (idx & 15) * 8;
        size_t gb = (size_t)(k0 + rB) * N + bxb * 128 + cB;
        cp16(base + OFF_BH + rB * 136 + cB, Whg + gb);
        cp16(base + OFF_BL + rB * 136 + cB, Wlg + gb);
    }
    asm volatile("cp.async.commit_group;");
}

// C = act(A[M,K] @ W[K,N] + bias), A/W given as bf16 hi/lo planes.
// Tile 128x128x32; 256 threads = 8 warps (4M x 2N). Double-buffered cp.async.
template<int GELU>
__global__ void __launch_bounds__(256) bgemm2_kernel(
    const __nv_bfloat16* __restrict__ Ahg, const __nv_bfloat16* __restrict__ Alg,
    const __nv_bfloat16* __restrict__ Whg, const __nv_bfloat16* __restrict__ Wlg,
    const float* __restrict__ bias, float* __restrict__ C,
    int M, int N, int K)
{
    extern __shared__ __align__(16) __nv_bfloat16 sm[];
    const int tid = threadIdx.x;
    const int lane = tid & 31;
    const int wid = tid >> 5;
    const int warp_m = wid & 3;
    const int warp_n = wid >> 2;
    const int bxb = blockIdx.x;
    const int byb = blockIdx.y;

    float acc[2][8][4];
    #pragma unroll
    for (int mt = 0; mt < 2; mt++) {
        #pragma unroll
        for (int nt = 0; nt < 8; nt++) {
            acc[mt][nt][0] = 0.f; acc[mt][nt][1] = 0.f;
            acc[mt][nt][2] = 0.f; acc[mt][nt][3] = 0.f;
        }
    }

    const int a_tile = lane >> 3;
    const int a_rl = lane & 7;
    const int a_ldrow = warp_m * 32 + (a_tile & 1) * 8 + a_rl;
    const int a_ldcol = (a_tile >> 1) * 8;
    const int b_ldk = (a_tile & 1) * 8 + a_rl;
    const int b_ldn = warp_n * 64 + (a_tile >> 1) * 8;

    const int nk = K >> 5;
    load_stage(sm, 0, 0, tid, byb, bxb, Ahg, Alg, Whg, Wlg, N, K);
    load_stage(sm, 1, 32, tid, byb, bxb, Ahg, Alg, Whg, Wlg, N, K);

    for (int kt = 0; kt < nk; kt++) {
        const int s = kt & 1;
        if (kt == nk - 1) asm volatile("cp.async.wait_group 0;");
        else              asm volatile("cp.async.wait_group 1;");
        __syncthreads();

        __nv_bfloat16* Ahs = sm + s * STAGE_ELT;
        __nv_bfloat16* Als = Ahs + OFF_AL;
        __nv_bfloat16* Bhs = sm + s * STAGE_ELT + OFF_BH;
        __nv_bfloat16* Bls = sm + s * STAGE_ELT + OFF_BL;

        #pragma unroll
        for (int kk = 0; kk < 32; kk += 16) {
            uint32_t ah0[4], ah1[4], al0[4], al1[4];
            ldsm_x4(ah0, (uint32_t)__cvta_generic_to_shared(Ahs + a_ldrow * 40 + a_ldcol + kk));
            ldsm_x4(ah1, (uint32_t)__cvta_generic_to_shared(Ahs + (a_ldrow + 16) * 40 + a_ldcol + kk));
            ldsm_x4(al0, (uint32_t)__cvta_generic_to_shared(Als + a_ldrow * 40 + a_ldcol + kk));
            ldsm_x4(al1, (uint32_t)__cvta_generic_to_shared(Als + (a_ldrow + 16) * 40 + a_ldcol + kk));
            #pragma unroll
            for (int p = 0; p < 4; p++) {
                uint32_t bh4[4], bl4[4];
                ldsm_x4t(bh4, (uint32_t)__cvta_generic_to_shared(Bhs + (kk + b_ldk) * 136 + b_ldn + p * 16));
                ldsm_x4t(bl4, (uint32_t)__cvta_generic_to_shared(Bls + (kk + b_ldk) * 136 + b_ldn + p * 16));
                int nt0 = p * 2;
                int nt1 = p * 2 + 1;
                mma_bf16(acc[0][nt0], ah0, bh4[0], bh4[1]);
                mma_bf16(acc[0][nt0], ah0, bl4[0], bl4[1]);
                mma_bf16(acc[0][nt0], al0, bh4[0], bh4[1]);
                mma_bf16(acc[0][nt1], ah0, bh4[2], bh4[3]);
                mma_bf16(acc[0][nt1], ah0, bl4[2], bl4[3]);
                mma_bf16(acc[0][nt1], al0, bh4[2], bh4[3]);
                mma_bf16(acc[1][nt0], ah1, bh4[0], bh4[1]);
                mma_bf16(acc[1][nt0], ah1, bl4[0], bl4[1]);
                mma_bf16(acc[1][nt0], al1, bh4[0], bh4[1]);
                mma_bf16(acc[1][nt1], ah1, bh4[2], bh4[3]);
                mma_bf16(acc[1][nt1], ah1, bl4[2], bl4[3]);
                mma_bf16(acc[1][nt1], al1, bh4[2], bh4[3]);
            }
        }
        __syncthreads();
        if (kt + 2 < nk)
            load_stage(sm, s, (kt + 2) * 32, tid, byb, bxb, Ahg, Alg, Whg, Wlg, N, K);
    }

    // epilogue
    const int grp = lane >> 2;
    const int tig = lane & 3;
    #pragma unroll
    for (int mt = 0; mt < 2; mt++) {
        #pragma unroll
        for (int nt = 0; nt < 8; nt++) {
            int col = bxb * 128 + warp_n * 64 + nt * 8 + tig * 2;
            float b0 = bias[col];
            float b1 = bias[col + 1];
            #pragma unroll
            for (int half = 0; half < 2; half++) {
                int row = byb * 128 + warp_m * 32 + mt * 16 + grp + half * 8;
                float v0 = acc[mt][nt][half * 2 + 0] + b0;
                float v1 = acc[mt][nt][half * 2 + 1] + b1;
                if (GELU) {
                    v0 = 0.5f * v0 * (1.f + erff(v0 * 0.70710678118654752f));
                    v1 = 0.5f * v1 * (1.f + erff(v1 * 0.70710678118654752f));
                }
                C[(size_t)row * N + col] = v0;
                C[(size_t)row * N + col + 1] = v1;
            }
        }
    }
}

// ---------------- helpers for block indices ----------------
__device__ __forceinline__ int mid_block_idx(int n, int g, const int* __restrict__ randb) {
    if (g == 0) return 0;
    if (g == 1) return NBx - 1;
    if (g < 5)  return n - 3 + g;
    return randb[(n - 1) * Rx + (g - 5)];
}

// ---------------- middle-block scores ----------------
__global__ void __launch_bounds__(256) mid_scores_kernel(
    const float* __restrict__ q, const float* __restrict__ k,
    const int* __restrict__ randb, const int* __restrict__ amask,
    float* __restrict__ smid)
{
    int n = blockIdx.x + 1;
    int h = blockIdx.y;
    int b = blockIdx.z;
    __shared__ float Qs[64][65];
    __shared__ float Ks[64][65];
    int tid = threadIdx.x;
    int tx = tid & 15, ty = tid >> 4;

    const float* qbase = q + ((size_t)b * Sx + n * 64) * Dx + h * 64;
    for (int f = tid; f < 1024; f += 256) {
        int qi = f >> 4, d4 = (f & 15) << 2;
        float4 v = *(const float4*)(qbase + (size_t)qi * Dx + d4);
        Qs[d4 + 0][qi] = v.x; Qs[d4 + 1][qi] = v.y;
        Qs[d4 + 2][qi] = v.z; Qs[d4 + 3][qi] = v.w;
    }
    float* out = smid + (((size_t)(b * NHx + h) * NMID + (n - 1)) << 15);

    for (int g = 0; g < NGx; g++) {
        int kb = mid_block_idx(n, g, randb);
        const float* kbase = k + ((size_t)b * Sx + kb * 64) * Dx + h * 64;
        __syncthreads();
        for (int f = tid; f < 1024; f += 256) {
            int ki = f >> 4, d4 = (f & 15) << 2;
            float4 v = *(const float4*)(kbase + (size_t)ki * Dx + d4);
            Ks[d4 + 0][ki] = v.x; Ks[d4 + 1][ki] = v.y;
            Ks[d4 + 2][ki] = v.z; Ks[d4 + 3][ki] = v.w;
        }
        __syncthreads();
        float acc[4][4] = {};
        #pragma unroll 16
        for (int d = 0; d < 64; d++) {
            float ar[4], br[4];
            #pragma unroll
            for (int i = 0; i < 4; i++) ar[i] = Qs[d][ty * 4 + i];
            #pragma unroll
            for (int j = 0; j < 4; j++) br[j] = Ks[d][tx * 4 + j];
            #pragma unroll
            for (int i = 0; i < 4; i++) {
                #pragma unroll
                for (int j = 0; j < 4; j++) acc[i][j] += ar[i] * br[j];
            }
        }
        #pragma unroll
        for (int j = 0; j < 4; j++) {
            int ki = tx * 4 + j;
            float madd = (1.0f - (float)amask[b * Sx + kb * 64 + ki]) * -1e9f;
            #pragma unroll
            for (int i = 0; i < 4; i++) {
                int qi = ty * 4 + i;
                out[(size_t)qi * (NGx * 64) + g * 64 + ki] = acc[i][j] * 0.125f + madd;
            }
        }
    }
}

// ---------------- middle-block PV ----------------
__global__ void __launch_bounds__(256) mid_pv_kernel(
    const float* __restrict__ p, const float* __restrict__ v,
    const int* __restrict__ randb, float* __restrict__ ctx)
{
    int n = blockIdx.x + 1;
    int h = blockIdx.y;
    int b = blockIdx.z;
    __shared__ float Ps[64][65];
    __shared__ float Vs[64][65];
    int tid = threadIdx.x;
    int tx = tid & 15, ty = tid >> 4;

    const float* prow = p + (((size_t)(b * NHx + h) * NMID + (n - 1)) << 15);
    float acc[4][4] = {};

    for (int g = 0; g < NGx; g++) {
        int kb = mid_block_idx(n, g, randb);
        const float* vbase = v + ((size_t)b * Sx + kb * 64) * Dx + h * 64;
        __syncthreads();
        for (int f = tid; f < 1024; f += 256) {
            int qi = f >> 4, k4 = (f & 15) << 2;
            float4 t = *(const float4*)(prow + (size_t)qi * (NGx * 64) + g * 64 + k4);
            Ps[k4 + 0][qi] = t.x; Ps[k4 + 1][qi] = t.y;
            Ps[k4 + 2][qi] = t.z; Ps[k4 + 3][qi] = t.w;
        }
        for (int f = tid; f < 1024; f += 256) {
            int ki = f >> 4, d4 = (f & 15) << 2;
            float4 t = *(const float4*)(vbase + (size_t)ki * Dx + d4);
            Vs[ki][d4 + 0] = t.x; Vs[ki][d4 + 1] = t.y;
            Vs[ki][d4 + 2] = t.z; Vs[ki][d4 + 3] = t.w;
        }
        __syncthreads();
        #pragma unroll 16
        for (int kk = 0; kk < 64; kk++) {
            float ar[4], br[4];
            #pragma unroll
            for (int i = 0; i < 4; i++) ar[i] = Ps[kk][ty * 4 + i];
            #pragma unroll
            for (int j = 0; j < 4; j++) br[j] = Vs[kk][tx * 4 + j];
            #pragma unroll
            for (int i = 0; i < 4; i++) {
                #pragma unroll
                for (int j = 0; j < 4; j++) acc[i][j] += ar[i] * br[j];
            }
        }
    }
    float* cbase = ctx + ((size_t)b * Sx + n * 64) * Dx + h * 64;
    #pragma unroll
    for (int i = 0; i < 4; i++) {
        #pragma unroll
        for (int j = 0; j < 4; j++)
            cbase[(size_t)(ty * 4 + i) * Dx + tx * 4 + j] = acc[i][j];
    }
}

// ---------------- edge scores ----------------
__global__ void __launch_bounds__(256) edge_scores_kernel(
    const float* __restrict__ q, const float* __restrict__ k,
    const int* __restrict__ amask, float* __restrict__ sedge)
{
    int kb = blockIdx.x;
    int h  = blockIdx.y;
    int e  = blockIdx.z & 1;
    int b  = blockIdx.z >> 1;
    int qb = e ? (NBx - 1) : 0;
    __shared__ float Qs[64][65];
    __shared__ float Ks[64][65];
    int tid = threadIdx.x;
    int tx = tid & 15, ty = tid >> 4;

    const float* qbase = q + ((size_t)b * Sx + qb * 64) * Dx + h * 64;
    const float* kbase = k + ((size_t)b * Sx + kb * 64) * Dx + h * 64;
    for (int f = tid; f < 1024; f += 256) {
        int r = f >> 4, d4 = (f & 15) << 2;
        float4 a = *(const float4*)(qbase + (size_t)r * Dx + d4);
        Qs[d4 + 0][r] = a.x; Qs[d4 + 1][r] = a.y; Qs[d4 + 2][r] = a.z; Qs[d4 + 3][r] = a.w;
        float4 c = *(const float4*)(kbase + (size_t)r * Dx + d4);
        Ks[d4 + 0][r] = c.x; Ks[d4 + 1][r] = c.y; Ks[d4 + 2][r] = c.z; Ks[d4 + 3][r] = c.w;
    }
    __syncthreads();
    float acc[4][4] = {};
    #pragma unroll 16
    for (int d = 0; d < 64; d++) {
        float ar[4], br[4];
        #pragma unroll
        for (int i = 0; i < 4; i++) ar[i] = Qs[d][ty * 4 + i];
        #pragma unroll
        for (int j = 0; j < 4; j++) br[j] = Ks[d][tx * 4 + j];
        #pragma unroll
        for (int i = 0; i < 4; i++) {
            #pragma unroll
            for (int j = 0; j < 4; j++) acc[i][j] += ar[i] * br[j];
        }
    }
    float* out = sedge + ((size_t)((b * NHx + h) * 2 + e)) * (64 * Sx);
    #pragma unroll
    for (int j = 0; j < 4; j++) {
        int ki = tx * 4 + j;
        float madd = (1.0f - (float)amask[b * Sx + kb * 64 + ki]) * -1e9f;
        #pragma unroll
        for (int i = 0; i < 4; i++) {
            int qi = ty * 4 + i;
            out[(size_t)qi * Sx + kb * 64 + ki] = acc[i][j] * 0.125f + madd;
        }
    }
}

// ---------------- edge PV ----------------
__global__ void __launch_bounds__(256) edge_pv_kernel(
    const float* __restrict__ p, const float* __restrict__ v, float* __restrict__ ctx)
{
    int h = blockIdx.x;
    int e = blockIdx.y & 1;
    int b = blockIdx.y >> 1;
    int qb = e ? (NBx - 1) : 0;
    __shared__ float Ps[64][65];
    __shared__ float Vs[64][65];
    int tid = threadIdx.x;
    int tx = tid & 15, ty = tid >> 4;

    const float* prow = p + ((size_t)((b * NHx + h) * 2 + e)) * (64 * Sx);
    float acc[4][4] = {};
    for (int kb = 0; kb < NBx; kb++) {
        const float* vbase = v + ((size_t)b * Sx + kb * 64) * Dx + h * 64;
        __syncthreads();
        for (int f = tid; f < 1024; f += 256) {
            int qi = f >> 4, k4 = (f & 15) << 2;
            float4 t = *(const float4*)(prow + (size_t)qi * Sx + kb * 64 + k4);
            Ps[k4 + 0][qi] = t.x; Ps[k4 + 1][qi] = t.y;
            Ps[k4 + 2][qi] = t.z; Ps[k4 + 3][qi] = t.w;
        }
        for (int f = tid; f < 1024; f += 256) {
            int ki = f >> 4, d4 = (f & 15) << 2;
            float4 t = *(const float4*)(vbase + (size_t)ki * Dx + d4);
            Vs[ki][d4 + 0] = t.x; Vs[ki][d4 + 1] = t.y;
            Vs[ki][d4 + 2] = t.z; Vs[ki][d4 + 3] = t.w;
        }
        __syncthreads();
        #pragma unroll 16
        for (int kk = 0; kk < 64; kk++) {
            float ar[4], br[4];
            #pragma unroll
            for (int i = 0; i < 4; i++) ar[i] = Ps[kk][ty * 4 + i];
            #pragma unroll
            for (int j = 0; j < 4; j++) br[j] = Vs[kk][tx * 4 + j];
            #pragma unroll
            for (int i = 0; i < 4; i++) {
                #pragma unroll
                for (int j = 0; j < 4; j++) acc[i][j] += ar[i] * br[j];
            }
        }
    }
    float* cbase = ctx + ((size_t)b * Sx + qb * 64) * Dx + h * 64;
    #pragma unroll
    for (int i = 0; i < 4; i++) {
        #pragma unroll
        for (int j = 0; j < 4; j++)
            cbase[(size_t)(ty * 4 + i) * Dx + tx * 4 + j] = acc[i][j];
    }
}

// ---------------- row softmax (in-place), row length L ----------------
__global__ void softmax_kernel(float* __restrict__ s, int L) {
    extern __shared__ float buf[];
    size_t base = (size_t)blockIdx.x * L;
    float m = -3.4e38f;
    for (int i = threadIdx.x; i < L; i += blockDim.x) {
        float x = s[base + i];
        buf[i] = x;
        m = fmaxf(m, x);
    }
    m = blk_max(m);
    float lsum = 0.f;
    for (int i = threadIdx.x; i < L; i += blockDim.x) {
        float e = expf(buf[i] - m);
        buf[i] = e;
        lsum += e;
    }
    float sum = blk_sum(lsum);
    float inv = 1.f / sum;
    for (int i = threadIdx.x; i < L; i += blockDim.x)
        s[base + i] = buf[i] * inv;
}

// ---------------- pooler ----------------
__global__ void pooler_kernel(const float* __restrict__ h, const float* __restrict__ pw,
                              const float* __restrict__ pb, float* __restrict__ out) {
    int j = blockIdx.x * blockDim.x + threadIdx.x;
    int b = blockIdx.y;
    if (j >= Dx) return;
    const float* hr = h + (size_t)b * Sx * Dx;
    float acc = pb[j];
    for (int kI = 0; kI < Dx; kI++) acc += hr[kI] * pw[(size_t)kI * Dx + j];
    out[b * Dx + j] = tanhf(acc);
}

// ---------------- host launcher ----------------
extern "C" void kernel_launch(void* const* d_in, const int* in_sizes, int n_in,
                              void* d_out, int out_size) {
    const int*   input_ids = (const int*)d_in[0];
    const int*   attn_mask = (const int*)d_in[1];
    const int*   tok_type  = (const int*)d_in[2];
    const int*   rand_blk  = (const int*)d_in[3];
    const float* word_emb  = (const float*)d_in[4];
    const float* type_emb  = (const float*)d_in[5];
    const float* pos_emb   = (const float*)d_in[6];
    const float* emb_ln_s  = (const float*)d_in[7];
    const float* emb_ln_b  = (const float*)d_in[8];
    const float* Wq = (const float*)d_in[9];  const float* bq = (const float*)d_in[10];
    const float* Wk = (const float*)d_in[11]; const float* bk = (const float*)d_in[12];
    const float* Wv = (const float*)d_in[13]; const float* bv = (const float*)d_in[14];
    const float* Wo = (const float*)d_in[15]; const float* bo = (const float*)d_in[16];
    const float* ln1_s = (const float*)d_in[17]; const float* ln1_b = (const float*)d_in[18];
    const float* W1 = (const float*)d_in[19]; const float* b1 = (const float*)d_in[20];
    const float* W2 = (const float*)d_in[21]; const float* b2 = (const float*)d_in[22];
    const float* ln2_s = (const float*)d_in[23]; const float* ln2_b = (const float*)d_in[24];
    const float* pool_w = (const float*)d_in[25]; const float* pool_b = (const float*)d_in[26];
    float* out = (float*)d_out;

    float *p_h = 0, *p_res = 0, *p_q = 0, *p_k = 0, *p_v = 0, *p_ctx = 0, *p_ff = 0, *p_smid = 0, *p_sedge = 0;
    __nv_bfloat16 *p_ahi = 0, *p_alo = 0, *p_whi = 0, *p_wlo = 0;
    cudaGetSymbolAddress((void**)&p_h,     g_h);
    cudaGetSymbolAddress((void**)&p_res,   g_res);
    cudaGetSymbolAddress((void**)&p_q,     g_q);
    cudaGetSymbolAddress((void**)&p_k,     g_k);
    cudaGetSymbolAddress((void**)&p_v,     g_v);
    cudaGetSymbolAddress((void**)&p_ctx,   g_ctx);
    cudaGetSymbolAddress((void**)&p_ff,    g_ff);
    cudaGetSymbolAddress((void**)&p_smid,  g_smid);
    cudaGetSymbolAddress((void**)&p_sedge, g_sedge);
    cudaGetSymbolAddress((void**)&p_ahi,   g_act_hi);
    cudaGetSymbolAddress((void**)&p_alo,   g_act_lo);
    cudaGetSymbolAddress((void**)&p_whi,   g_w_hi);
    cudaGetSymbolAddress((void**)&p_wlo,   g_w_lo);

    static bool attr_done = false;
    if (!attr_done) {
        cudaFuncSetAttribute(bgemm2_kernel<0>, cudaFuncAttributeMaxDynamicSharedMemorySize, SMEM_BYTES);
        cudaFuncSetAttribute(bgemm2_kernel<1>, cudaFuncAttributeMaxDynamicSharedMemorySize, SMEM_BYTES);
        attr_done = true;
    }

    const int M = TOK;
    const int nDD = Dx * Dx;
    const int nDF = Dx * FFx;
    const int nHD = TOK * Dx;
    const int nHF = TOK * FFx;

    auto split = [&](const float* src, __nv_bfloat16* hi, __nv_bfloat16* lo, int n) {
        split_kernel<<<(n / 4 + 255) / 256, 256>>>(src, hi, lo, n / 4);
    };

    embed_ln_kernel<<<TOK, 256>>>(input_ids, tok_type, word_emb, type_emb, pos_emb,
                                  emb_ln_s, emb_ln_b);

    for (int l = 0; l < 2; l++) {
        const float* wq = Wq + (size_t)l * nDD;  const float* bql = bq + (size_t)l * Dx;
        const float* wk = Wk + (size_t)l * nDD;  const float* bkl = bk + (size_t)l * Dx;
        const float* wv = Wv + (size_t)l * nDD;  const float* bvl = bv + (size_t)l * Dx;
        const float* wo = Wo + (size_t)l * nDD;  const float* bol = bo + (size_t)l * Dx;
        const float* w1 = W1 + (size_t)l * nDF;  const float* b1l = b1 + (size_t)l * FFx;
        const float* w2 = W2 + (size_t)l * nDF;  const float* b2l = b2 + (size_t)l * Dx;
        const float* l1s = ln1_s + (size_t)l * Dx; const float* l1b = ln1_b + (size_t)l * Dx;
        const float* l2s = ln2_s + (size_t)l * Dx; const float* l2b = ln2_b + (size_t)l * Dx;

        // QKV
        split(p_h, p_ahi, p_alo, nHD);
        split(wq, p_whi, p_wlo, nDD);
        bgemm2_kernel<0><<<dim3(Dx / 128, M / 128), 256, SMEM_BYTES>>>(
            p_ahi, p_alo, p_whi, p_wlo, bql, p_q, M, Dx, Dx);
        split(wk, p_whi, p_wlo, nDD);
        bgemm2_kernel<0><<<dim3(Dx / 128, M / 128), 256, SMEM_BYTES>>>(
            p_ahi, p_alo, p_whi, p_wlo, bkl, p_k, M, Dx, Dx);
        split(wv, p_whi, p_wlo, nDD);
        bgemm2_kernel<0><<<dim3(Dx / 128, M / 128), 256, SMEM_BYTES>>>(
            p_ahi, p_alo, p_whi, p_wlo, bvl, p_v, M, Dx, Dx);

        // attention (fp32)
        mid_scores_kernel<<<dim3(NMID, NHx, Bx), 256>>>(p_q, p_k, rand_blk, attn_mask, p_smid);
        softmax_kernel<<<Bx * NHx * NMID * BSx, 256, (NGx * 64) * sizeof(float)>>>(p_smid, NGx * 64);
        mid_pv_kernel<<<dim3(NMID, NHx, Bx), 256>>>(p_smid, p_v, rand_blk, p_ctx);

        edge_scores_kernel<<<dim3(NBx, NHx, Bx * 2), 256>>>(p_q, p_k, attn_mask, p_sedge);
        softmax_kernel<<<Bx * NHx * 2 * BSx, 256, Sx * sizeof(float)>>>(p_sedge, Sx);
        edge_pv_kernel<<<dim3(NHx, Bx * 2), 256>>>(p_sedge, p_v, p_ctx);

        // O-projection
        split(p_ctx, p_ahi, p_alo, nHD);
        split(wo, p_whi, p_wlo, nDD);
        bgemm2_kernel<0><<<dim3(Dx / 128, M / 128), 256, SMEM_BYTES>>>(
            p_ahi, p_alo, p_whi, p_wlo, bol, p_res, M, Dx, Dx);
        add_ln_kernel<<<TOK, 256>>>(p_h, p_res, l1s, l1b);

        // FFN
        split(p_h, p_ahi, p_alo, nHD);
        split(w1, p_whi, p_wlo, nDF);
        bgemm2_kernel<1><<<dim3(FFx / 128, M / 128), 256, SMEM_BYTES>>>(
            p_ahi, p_alo, p_whi, p_wlo, b1l, p_ff, M, FFx, Dx);
        split(p_ff, p_ahi, p_alo, nHF);
        split(w2, p_whi, p_wlo, nDF);
        bgemm2_kernel<0><<<dim3(Dx / 128, M / 128), 256, SMEM_BYTES>>>(
            p_ahi, p_alo, p_whi, p_wlo, b2l, p_res, M, Dx, FFx);
        add_ln_kernel<<<TOK, 256>>>(p_h, p_res, l2s, l2b);
    }

    pooler_kernel<<<dim3((Dx + 127) / 128, Bx), 128>>>(p_h, pool_w, pool_b, out);
}

// round 5
// speedup vs baseline: 2.3720x; 1.3536x over previous
#include <cuda_runtime.h>
#include <cuda_bf16.h>
#include <cstdint>
#include <math.h>

#define Bx 2
#define Sx 4096
#define Dx 768
#define NHx 12
#define HDx 64
#define BSx 64
#define NBx 64
#define FFx 3072
#define Rx 3
#define NGx 8
#define NMID 62
#define TOK (Bx*Sx)

// ---------------- scratch (static device memory; no allocations) ----------------
__device__ float g_h[(size_t)TOK*Dx];
__device__ float g_res[(size_t)TOK*Dx];
__device__ float g_ctx[(size_t)TOK*Dx];
__device__ float g_ff[(size_t)TOK*FFx];
__device__ float g_smid[(size_t)Bx*NHx*NMID*BSx*NGx*BSx];
__device__ float g_sedge[(size_t)Bx*NHx*2*BSx*Sx];
// bf16 hi/lo planes
__device__ __nv_bfloat16 g_act_hi[(size_t)TOK*FFx];
__device__ __nv_bfloat16 g_act_lo[(size_t)TOK*FFx];
__device__ __nv_bfloat16 g_w_hi[(size_t)Dx*FFx];
__device__ __nv_bfloat16 g_w_lo[(size_t)Dx*FFx];
__device__ __nv_bfloat16 g_qhi[(size_t)TOK*Dx];
__device__ __nv_bfloat16 g_qlo[(size_t)TOK*Dx];
__device__ __nv_bfloat16 g_khi[(size_t)TOK*Dx];
__device__ __nv_bfloat16 g_klo[(size_t)TOK*Dx];
__device__ __nv_bfloat16 g_vhi[(size_t)TOK*Dx];
__device__ __nv_bfloat16 g_vlo[(size_t)TOK*Dx];
__device__ __nv_bfloat16 g_pmid_hi[(size_t)Bx*NHx*NMID*BSx*NGx*BSx];
__device__ __nv_bfloat16 g_pmid_lo[(size_t)Bx*NHx*NMID*BSx*NGx*BSx];
__device__ __nv_bfloat16 g_pedge_hi[(size_t)Bx*NHx*2*BSx*Sx];
__device__ __nv_bfloat16 g_pedge_lo[(size_t)Bx*NHx*2*BSx*Sx];

// ---------------- block reductions ----------------
__device__ __forceinline__ float blk_sum(float v) {
    __shared__ float red[33];
    #pragma unroll
    for (int o = 16; o; o >>= 1) v += __shfl_down_sync(0xffffffffu, v, o);
    int lane = threadIdx.x & 31, w = threadIdx.x >> 5;
    __syncthreads();
    if (lane == 0) red[w] = v;
    __syncthreads();
    if (w == 0) {
        float x = (lane < ((blockDim.x + 31) >> 5)) ? red[lane] : 0.f;
        #pragma unroll
        for (int o = 16; o; o >>= 1) x += __shfl_down_sync(0xffffffffu, x, o);
        if (lane == 0) red[32] = x;
    }
    __syncthreads();
    return red[32];
}

__device__ __forceinline__ float blk_max(float v) {
    __shared__ float redm[33];
    #pragma unroll
    for (int o = 16; o; o >>= 1) v = fmaxf(v, __shfl_down_sync(0xffffffffu, v, o));
    int lane = threadIdx.x & 31, w = threadIdx.x >> 5;
    __syncthreads();
    if (lane == 0) redm[w] = v;
    __syncthreads();
    if (w == 0) {
        float x = (lane < ((blockDim.x + 31) >> 5)) ? redm[lane] : -3.4e38f;
        #pragma unroll
        for (int o = 16; o; o >>= 1) x = fmaxf(x, __shfl_down_sync(0xffffffffu, x, o));
        if (lane == 0) redm[32] = x;
    }
    __syncthreads();
    return redm[32];
}

// ---------------- fp32 -> (hi, lo) bf16 planes ----------------
__global__ void split_kernel(const float* __restrict__ in,
                             __nv_bfloat16* __restrict__ hi,
                             __nv_bfloat16* __restrict__ lo, int n4) {
    int i = blockIdx.x * blockDim.x + threadIdx.x;
    if (i >= n4) return;
    float4 v = ((const float4*)in)[i];
    __nv_bfloat16 h0 = __float2bfloat16_rn(v.x);
    __nv_bfloat16 h1 = __float2bfloat16_rn(v.y);
    __nv_bfloat16 h2 = __float2bfloat16_rn(v.z);
    __nv_bfloat16 h3 = __float2bfloat16_rn(v.w);
    __nv_bfloat16 l0 = __float2bfloat16_rn(v.x - __bfloat162float(h0));
    __nv_bfloat16 l1 = __float2bfloat16_rn(v.y - __bfloat162float(h1));
    __nv_bfloat16 l2 = __float2bfloat16_rn(v.z - __bfloat162float(h2));
    __nv_bfloat16 l3 = __float2bfloat16_rn(v.w - __bfloat162float(h3));
    ((__nv_bfloat162*)hi)[2*i]   = __halves2bfloat162(h0, h1);
    ((__nv_bfloat162*)hi)[2*i+1] = __halves2bfloat162(h2, h3);
    ((__nv_bfloat162*)lo)[2*i]   = __halves2bfloat162(l0, l1);
    ((__nv_bfloat162*)lo)[2*i+1] = __halves2bfloat162(l2, l3);
}

// ---------------- embeddings + LN ----------------
__global__ void embed_ln_kernel(const int* __restrict__ ids, const int* __restrict__ tt,
                                const float* __restrict__ wemb, const float* __restrict__ temb,
                                const float* __restrict__ pemb,
                                const float* __restrict__ lns, const float* __restrict__ lnb) {
    int tok = blockIdx.x;
    int pos = tok % Sx;
    const float* w = wemb + (size_t)ids[tok] * Dx;
    const float* t = temb + (size_t)tt[tok] * Dx;
    const float* p = pemb + (size_t)pos * Dx;
    __shared__ float buf[Dx];
    float ls = 0.f, lq = 0.f;
    for (int i = threadIdx.x; i < Dx; i += blockDim.x) {
        float x = w[i] + t[i] + p[i];
        buf[i] = x; ls += x; lq += x * x;
    }
    float sum = blk_sum(ls);
    float sq  = blk_sum(lq);
    float mu = sum * (1.f / Dx);
    float var = sq * (1.f / Dx) - mu * mu;
    float inv = rsqrtf(var + 1e-12f);
    for (int i = threadIdx.x; i < Dx; i += blockDim.x)
        g_h[(size_t)tok * Dx + i] = lns[i] * (buf[i] - mu) * inv + lnb[i];
}

// ---------------- residual add + LN (in-place on h) ----------------
__global__ void add_ln_kernel(float* __restrict__ h, const float* __restrict__ r,
                              const float* __restrict__ lns, const float* __restrict__ lnb) {
    int tok = blockIdx.x;
    __shared__ float buf[Dx];
    float ls = 0.f, lq = 0.f;
    for (int i = threadIdx.x; i < Dx; i += blockDim.x) {
        float x = h[(size_t)tok * Dx + i] + r[(size_t)tok * Dx + i];
        buf[i] = x; ls += x; lq += x * x;
    }
    float sum = blk_sum(ls);
    float sq  = blk_sum(lq);
    float mu = sum * (1.f / Dx);
    float var = sq * (1.f / Dx) - mu * mu;
    float inv = rsqrtf(var + 1e-12f);
    for (int i = threadIdx.x; i < Dx; i += blockDim.x)
        h[(size_t)tok * Dx + i] = lns[i] * (buf[i] - mu) * inv + lnb[i];
}

// ---------------- tensor-core primitives ----------------
__device__ __forceinline__ void ldsm_x4(uint32_t* r, uint32_t addr) {
    asm volatile("ldmatrix.sync.aligned.m8n8.x4.shared.b16 {%0,%1,%2,%3}, [%4];"
                 : "=r"(r[0]), "=r"(r[1]), "=r"(r[2]), "=r"(r[3]) : "r"(addr));
}
__device__ __forceinline__ void ldsm_x4t(uint32_t* r, uint32_t addr) {
    asm volatile("ldmatrix.sync.aligned.m8n8.x4.trans.shared.b16 {%0,%1,%2,%3}, [%4];"
                 : "=r"(r[0]), "=r"(r[1]), "=r"(r[2]), "=r"(r[3]) : "r"(addr));
}
__device__ __forceinline__ void mma_bf16(float* c, const uint32_t* a, uint32_t b0, uint32_t b1) {
    asm volatile("mma.sync.aligned.m16n8k16.row.col.f32.bf16.bf16.f32 "
                 "{%0,%1,%2,%3}, {%4,%5,%6,%7}, {%8,%9}, {%0,%1,%2,%3};"
                 : "+f"(c[0]), "+f"(c[1]), "+f"(c[2]), "+f"(c[3])
                 : "r"(a[0]), "r"(a[1]), "r"(a[2]), "r"(a[3]), "r"(b0), "r"(b1));
}
__device__ __forceinline__ void cp16(void* dst, const void* src) {
    uint32_t d = (uint32_t)__cvta_generic_to_shared(dst);
    asm volatile("cp.async.cg.shared.global [%0], [%1], 16;" :: "r"(d), "l"(src));
}

// ---------------- dense GEMM (bf16 hi/lo planes, double-buffered cp.async) ------
// MODE 0: fp32 out; MODE 1: fp32 GELU out; MODE 2: bf16 hi/lo out.
#define STAGE_ELT 18944
#define OFF_AL 5120
#define OFF_BH 10240
#define OFF_BL 14592
#define SMEM_BYTES (2 * STAGE_ELT * 2)

__device__ __forceinline__ void load_stage(
    __nv_bfloat16* sm, int s, int k0, int tid, int byb, int bxb,
    const __nv_bfloat16* Ahg, const __nv_bfloat16* Alg,
    const __nv_bfloat16* Whg, const __nv_bfloat16* Wlg, int N, int K)
{
    __nv_bfloat16* base = sm + s * STAGE_ELT;
    #pragma unroll
    for (int i = 0; i < 2; i++) {
        int idx = tid + i * 256;
        int rA = idx >> 2, cA = (idx & 3) * 8;
        size_t ga = (size_t)(byb * 128 + rA) * K + k0 + cA;
        cp16(base + rA * 40 + cA, Ahg + ga);
        cp16(base + OFF_AL + rA * 40 + cA, Alg + ga);
        int rB = idx >> 4, cB = (idx & 15) * 8;
        size_t gb = (size_t)(k0 + rB) * N + bxb * 128 + cB;
        cp16(base + OFF_BH + rB * 136 + cB, Whg + gb);
        cp16(base + OFF_BL + rB * 136 + cB, Wlg + gb);
    }
    asm volatile("cp.async.commit_group;");
}

template<int MODE>
__global__ void __launch_bounds__(256) bgemm2_kernel(
    const __nv_bfloat16* __restrict__ Ahg, const __nv_bfloat16* __restrict__ Alg,
    const __nv_bfloat16* __restrict__ Whg, const __nv_bfloat16* __restrict__ Wlg,
    const float* __restrict__ bias, float* __restrict__ C,
    __nv_bfloat16* __restrict__ Chi, __nv_bfloat16* __restrict__ Clo,
    int M, int N, int K)
{
    extern __shared__ __align__(16) __nv_bfloat16 sm[];
    const int tid = threadIdx.x;
    const int lane = tid & 31;
    const int wid = tid >> 5;
    const int warp_m = wid & 3;
    const int warp_n = wid >> 2;
    const int bxb = blockIdx.x;
    const int byb = blockIdx.y;

    float acc[2][8][4];
    #pragma unroll
    for (int mt = 0; mt < 2; mt++) {
        #pragma unroll
        for (int nt = 0; nt < 8; nt++) {
            acc[mt][nt][0] = 0.f; acc[mt][nt][1] = 0.f;
            acc[mt][nt][2] = 0.f; acc[mt][nt][3] = 0.f;
        }
    }

    const int a_tile = lane >> 3;
    const int a_rl = lane & 7;
    const int a_ldrow = warp_m * 32 + (a_tile & 1) * 8 + a_rl;
    const int a_ldcol = (a_tile >> 1) * 8;
    const int b_ldk = (a_tile & 1) * 8 + a_rl;
    const int b_ldn = warp_n * 64 + (a_tile >> 1) * 8;

    const int nk = K >> 5;
    load_stage(sm, 0, 0, tid, byb, bxb, Ahg, Alg, Whg, Wlg, N, K);
    load_stage(sm, 1, 32, tid, byb, bxb, Ahg, Alg, Whg, Wlg, N, K);

    for (int kt = 0; kt < nk; kt++) {
        const int s = kt & 1;
        if (kt == nk - 1) asm volatile("cp.async.wait_group 0;");
        else              asm volatile("cp.async.wait_group 1;");
        __syncthreads();

        __nv_bfloat16* Ahs = sm + s * STAGE_ELT;
        __nv_bfloat16* Als = Ahs + OFF_AL;
        __nv_bfloat16* Bhs = sm + s * STAGE_ELT + OFF_BH;
        __nv_bfloat16* Bls = sm + s * STAGE_ELT + OFF_BL;

        #pragma unroll
        for (int kk = 0; kk < 32; kk += 16) {
            uint32_t ah0[4], ah1[4], al0[4], al1[4];
            ldsm_x4(ah0, (uint32_t)__cvta_generic_to_shared(Ahs + a_ldrow * 40 + a_ldcol + kk));
            ldsm_x4(ah1, (uint32_t)__cvta_generic_to_shared(Ahs + (a_ldrow + 16) * 40 + a_ldcol + kk));
            ldsm_x4(al0, (uint32_t)__cvta_generic_to_shared(Als + a_ldrow * 40 + a_ldcol + kk));
            ldsm_x4(al1, (uint32_t)__cvta_generic_to_shared(Als + (a_ldrow + 16) * 40 + a_ldcol + kk));
            #pragma unroll
            for (int p = 0; p < 4; p++) {
                uint32_t bh4[4], bl4[4];
                ldsm_x4t(bh4, (uint32_t)__cvta_generic_to_shared(Bhs + (kk + b_ldk) * 136 + b_ldn + p * 16));
                ldsm_x4t(bl4, (uint32_t)__cvta_generic_to_shared(Bls + (kk + b_ldk) * 136 + b_ldn + p * 16));
                int nt0 = p * 2;
                int nt1 = p * 2 + 1;
                mma_bf16(acc[0][nt0], ah0, bh4[0], bh4[1]);
                mma_bf16(acc[0][nt0], ah0, bl4[0], bl4[1]);
                mma_bf16(acc[0][nt0], al0, bh4[0], bh4[1]);
                mma_bf16(acc[0][nt1], ah0, bh4[2], bh4[3]);
                mma_bf16(acc[0][nt1], ah0, bl4[2], bl4[3]);
                mma_bf16(acc[0][nt1], al0, bh4[2], bh4[3]);
                mma_bf16(acc[1][nt0], ah1, bh4[0], bh4[1]);
                mma_bf16(acc[1][nt0], ah1, bl4[0], bl4[1]);
                mma_bf16(acc[1][nt0], al1, bh4[0], bh4[1]);
                mma_bf16(acc[1][nt1], ah1, bh4[2], bh4[3]);
                mma_bf16(acc[1][nt1], ah1, bl4[2], bl4[3]);
                mma_bf16(acc[1][nt1], al1, bh4[2], bh4[3]);
            }
        }
        __syncthreads();
        if (kt + 2 < nk)
            load_stage(sm, s, (kt + 2) * 32, tid, byb, bxb, Ahg, Alg, Whg, Wlg, N, K);
    }

    const int grp = lane >> 2;
    const int tig = lane & 3;
    #pragma unroll
    for (int mt = 0; mt < 2; mt++) {
        #pragma unroll
        for (int nt = 0; nt < 8; nt++) {
            int col = bxb * 128 + warp_n * 64 + nt * 8 + tig * 2;
            float b0 = bias[col];
            float b1 = bias[col + 1];
            #pragma unroll
            for (int half = 0; half < 2; half++) {
                int row = byb * 128 + warp_m * 32 + mt * 16 + grp + half * 8;
                float v0 = acc[mt][nt][half * 2 + 0] + b0;
                float v1 = acc[mt][nt][half * 2 + 1] + b1;
                if (MODE == 1) {
                    v0 = 0.5f * v0 * (1.f + erff(v0 * 0.70710678118654752f));
                    v1 = 0.5f * v1 * (1.f + erff(v1 * 0.70710678118654752f));
                }
                if (MODE == 2) {
                    __nv_bfloat16 h0 = __float2bfloat16_rn(v0);
                    __nv_bfloat16 h1 = __float2bfloat16_rn(v1);
                    __nv_bfloat16 l0 = __float2bfloat16_rn(v0 - __bfloat162float(h0));
                    __nv_bfloat16 l1 = __float2bfloat16_rn(v1 - __bfloat162float(h1));
                    *(__nv_bfloat162*)&Chi[(size_t)row * N + col] = __halves2bfloat162(h0, h1);
                    *(__nv_bfloat162*)&Clo[(size_t)row * N + col] = __halves2bfloat162(l0, l1);
                } else {
                    C[(size_t)row * N + col] = v0;
                    C[(size_t)row * N + col + 1] = v1;
                }
            }
        }
    }
}

// ---------------- helpers ----------------
__device__ __forceinline__ int mid_block_idx(int n, int g, const int* __restrict__ randb) {
    if (g == 0) return 0;
    if (g == 1) return NBx - 1;
    if (g < 5)  return n - 3 + g;
    return randb[(n - 1) * Rx + (g - 5)];
}

// ---------------- attention: 64x64 score tile (MMA, split-bf16) -----------------
// Computes S = Q(64x64) @ K(64 keys x 64)^T * 0.125 + mask, writes to out[qi*ostride + ocol0 + ki].
// 8 warps: warp_m = wid&3 (16 q-rows), warp_n = wid>>2 (32 keys).
__device__ __forceinline__ void score_tile(
    const __nv_bfloat16 (*Qh)[72], const __nv_bfloat16 (*Ql)[72],
    const __nv_bfloat16 (*Kh)[72], const __nv_bfloat16 (*Kl)[72],
    const int* __restrict__ amask, int mask_base,
    float* __restrict__ out, int ostride, int ocol0,
    int lane, int warp_m, int warp_n)
{
    const int tile = lane >> 3;
    const int rl = lane & 7;
    const int ldrow = (tile & 1) * 8 + rl;
    const int ldcol = (tile >> 1) * 8;

    float acc[4][4];
    #pragma unroll
    for (int j = 0; j < 4; j++) {
        acc[j][0] = 0.f; acc[j][1] = 0.f; acc[j][2] = 0.f; acc[j][3] = 0.f;
    }

    #pragma unroll
    for (int kk = 0; kk < 64; kk += 16) {
        uint32_t ah[4], al[4];
        ldsm_x4(ah, (uint32_t)__cvta_generic_to_shared(&Qh[warp_m * 16 + ldrow][ldcol + kk]));
        ldsm_x4(al, (uint32_t)__cvta_generic_to_shared(&Ql[warp_m * 16 + ldrow][ldcol + kk]));
        #pragma unroll
        for (int j2 = 0; j2 < 2; j2++) {
            int n0 = warp_n * 32 + j2 * 16;
            uint32_t bh[4], bl[4];
            ldsm_x4(bh, (uint32_t)__cvta_generic_to_shared(&Kh[n0 + ldrow][ldcol + kk]));
            ldsm_x4(bl, (uint32_t)__cvta_generic_to_shared(&Kl[n0 + ldrow][ldcol + kk]));
            mma_bf16(acc[j2 * 2 + 0], ah, bh[0], bh[2]);
            mma_bf16(acc[j2 * 2 + 0], ah, bl[0], bl[2]);
            mma_bf16(acc[j2 * 2 + 0], al, bh[0], bh[2]);
            mma_bf16(acc[j2 * 2 + 1], ah, bh[1], bh[3]);
            mma_bf16(acc[j2 * 2 + 1], ah, bl[1], bl[3]);
            mma_bf16(acc[j2 * 2 + 1], al, bh[1], bh[3]);
        }
    }

    int r0 = warp_m * 16 + (lane >> 2);
    #pragma unroll
    for (int j = 0; j < 4; j++) {
        int ki = warp_n * 32 + j * 8 + (lane & 3) * 2;
        float m0 = (1.0f - (float)amask[mask_base + ki]) * -1e9f;
        float m1 = (1.0f - (float)amask[mask_base + ki + 1]) * -1e9f;
        out[(size_t)r0 * ostride + ocol0 + ki]           = acc[j][0] * 0.125f + m0;
        out[(size_t)r0 * ostride + ocol0 + ki + 1]       = acc[j][1] * 0.125f + m1;
        out[(size_t)(r0 + 8) * ostride + ocol0 + ki]     = acc[j][2] * 0.125f + m0;
        out[(size_t)(r0 + 8) * ostride + ocol0 + ki + 1] = acc[j][3] * 0.125f + m1;
    }
}

// Accumulate acc += P(64x64) @ V(64x64) for one key group.
__device__ __forceinline__ void pv_tile(
    const __nv_bfloat16 (*Ph)[72], const __nv_bfloat16 (*Pl)[72],
    const __nv_bfloat16 (*Vh)[72], const __nv_bfloat16 (*Vl)[72],
    float acc[4][4], int lane, int warp_m, int warp_n)
{
    const int tile = lane >> 3;
    const int rl = lane & 7;
    const int ldrow = (tile & 1) * 8 + rl;
    const int ldcol = (tile >> 1) * 8;
    const int b_ldk = (tile & 1) * 8 + rl;
    const int b_ldn = (tile >> 1) * 8;

    #pragma unroll
    for (int kk = 0; kk < 64; kk += 16) {
        uint32_t ah[4], al[4];
        ldsm_x4(ah, (uint32_t)__cvta_generic_to_shared(&Ph[warp_m * 16 + ldrow][ldcol + kk]));
        ldsm_x4(al, (uint32_t)__cvta_generic_to_shared(&Pl[warp_m * 16 + ldrow][ldcol + kk]));
        #pragma unroll
        for (int j2 = 0; j2 < 2; j2++) {
            int n0 = warp_n * 32 + j2 * 16;
            uint32_t bh4[4], bl4[4];
            ldsm_x4t(bh4, (uint32_t)__cvta_generic_to_shared(&Vh[kk + b_ldk][n0 + b_ldn]));
            ldsm_x4t(bl4, (uint32_t)__cvta_generic_to_shared(&Vl[kk + b_ldk][n0 + b_ldn]));
            mma_bf16(acc[j2 * 2 + 0], ah, bh4[0], bh4[1]);
            mma_bf16(acc[j2 * 2 + 0], ah, bl4[0], bl4[1]);
            mma_bf16(acc[j2 * 2 + 0], al, bh4[0], bh4[1]);
            mma_bf16(acc[j2 * 2 + 1], ah, bh4[2], bh4[3]);
            mma_bf16(acc[j2 * 2 + 1], ah, bl4[2], bl4[3]);
            mma_bf16(acc[j2 * 2 + 1], al, bh4[2], bh4[3]);
        }
    }
}

// load a 64x64 bf16 tile (row stride 'gstride' in gmem) into smem[64][72]
__device__ __forceinline__ void load_tile64(
    __nv_bfloat16 (*dst)[72], const __nv_bfloat16* __restrict__ src, int gstride, int tid)
{
    #pragma unroll
    for (int i = 0; i < 2; i++) {
        int idx = tid + i * 256;
        int r = idx >> 3, c = (idx & 7) * 8;
        *(uint4*)&dst[r][c] = *(const uint4*)(src + (size_t)r * gstride + c);
    }
}

// ---------------- middle-block scores ----------------
__global__ void __launch_bounds__(256) mid_scores_mma(
    const __nv_bfloat16* __restrict__ qhi, const __nv_bfloat16* __restrict__ qlo,
    const __nv_bfloat16* __restrict__ khi, const __nv_bfloat16* __restrict__ klo,
    const int* __restrict__ randb, const int* __restrict__ amask,
    float* __restrict__ smid)
{
    int n = blockIdx.x + 1, h = blockIdx.y, b = blockIdx.z;
    __shared__ __nv_bfloat16 Qh[64][72], Ql[64][72], Kh[64][72], Kl[64][72];
    int tid = threadIdx.x, lane = tid & 31, wid = tid >> 5;
    int warp_m = wid & 3, warp_n = wid >> 2;

    size_t qoff = ((size_t)b * Sx + n * 64) * Dx + h * 64;
    load_tile64(Qh, qhi + qoff, Dx, tid);
    load_tile64(Ql, qlo + qoff, Dx, tid);

    float* out = smid + (((size_t)(b * NHx + h) * NMID + (n - 1)) << 15);

    for (int g = 0; g < NGx; g++) {
        int kb = mid_block_idx(n, g, randb);
        size_t koff = ((size_t)b * Sx + kb * 64) * Dx + h * 64;
        __syncthreads();
        load_tile64(Kh, khi + koff, Dx, tid);
        load_tile64(Kl, klo + koff, Dx, tid);
        __syncthreads();
        score_tile(Qh, Ql, Kh, Kl, amask, b * Sx + kb * 64,
                   out, NGx * 64, g * 64, lane, warp_m, warp_n);
    }
}

// ---------------- middle-block PV ----------------
__global__ void __launch_bounds__(256) mid_pv_mma(
    const __nv_bfloat16* __restrict__ phi, const __nv_bfloat16* __restrict__ plo,
    const __nv_bfloat16* __restrict__ vhi, const __nv_bfloat16* __restrict__ vlo,
    const int* __restrict__ randb, float* __restrict__ ctx)
{
    int n = blockIdx.x + 1, h = blockIdx.y, b = blockIdx.z;
    __shared__ __nv_bfloat16 Ph[64][72], Pl[64][72], Vh[64][72], Vl[64][72];
    int tid = threadIdx.x, lane = tid & 31, wid = tid >> 5;
    int warp_m = wid & 3, warp_n = wid >> 2;

    const __nv_bfloat16* prow_h = phi + (((size_t)(b * NHx + h) * NMID + (n - 1)) << 15);
    const __nv_bfloat16* prow_l = plo + (((size_t)(b * NHx + h) * NMID + (n - 1)) << 15);

    float acc[4][4];
    #pragma unroll
    for (int j = 0; j < 4; j++) {
        acc[j][0] = 0.f; acc[j][1] = 0.f; acc[j][2] = 0.f; acc[j][3] = 0.f;
    }

    for (int g = 0; g < NGx; g++) {
        int kb = mid_block_idx(n, g, randb);
        size_t voff = ((size_t)b * Sx + kb * 64) * Dx + h * 64;
        __syncthreads();
        load_tile64(Ph, prow_h + g * 64, NGx * 64, tid);
        load_tile64(Pl, prow_l + g * 64, NGx * 64, tid);
        load_tile64(Vh, vhi + voff, Dx, tid);
        load_tile64(Vl, vlo + voff, Dx, tid);
        __syncthreads();
        pv_tile(Ph, Pl, Vh, Vl, acc, lane, warp_m, warp_n);
    }

    float* cbase = ctx + ((size_t)b * Sx + n * 64) * Dx + h * 64;
    int r0 = warp_m * 16 + (lane >> 2);
    #pragma unroll
    for (int j = 0; j < 4; j++) {
        int col = warp_n * 32 + j * 8 + (lane & 3) * 2;
        cbase[(size_t)r0 * Dx + col]           = acc[j][0];
        cbase[(size_t)r0 * Dx + col + 1]       = acc[j][1];
        cbase[(size_t)(r0 + 8) * Dx + col]     = acc[j][2];
        cbase[(size_t)(r0 + 8) * Dx + col + 1] = acc[j][3];
    }
}

// ---------------- edge scores ----------------
__global__ void __launch_bounds__(256) edge_scores_mma(
    const __nv_bfloat16* __restrict__ qhi, const __nv_bfloat16* __restrict__ qlo,
    const __nv_bfloat16* __restrict__ khi, const __nv_bfloat16* __restrict__ klo,
    const int* __restrict__ amask, float* __restrict__ sedge)
{
    int kb = blockIdx.x, h = blockIdx.y;
    int e = blockIdx.z & 1, b = blockIdx.z >> 1;
    int qb = e ? (NBx - 1) : 0;
    __shared__ __nv_bfloat16 Qh[64][72], Ql[64][72], Kh[64][72], Kl[64][72];
    int tid = threadIdx.x, lane = tid & 31, wid = tid >> 5;
    int warp_m = wid & 3, warp_n = wid >> 2;

    size_t qoff = ((size_t)b * Sx + qb * 64) * Dx + h * 64;
    size_t koff = ((size_t)b * Sx + kb * 64) * Dx + h * 64;
    load_tile64(Qh, qhi + qoff, Dx, tid);
    load_tile64(Ql, qlo + qoff, Dx, tid);
    load_tile64(Kh, khi + koff, Dx, tid);
    load_tile64(Kl, klo + koff, Dx, tid);
    __syncthreads();

    float* out = sedge + ((size_t)((b * NHx + h) * 2 + e)) * (64 * Sx);
    score_tile(Qh, Ql, Kh, Kl, amask, b * Sx + kb * 64,
               out, Sx, kb * 64, lane, warp_m, warp_n);
}

// ---------------- edge PV (chunked, atomic accumulate) ----------------
__global__ void __launch_bounds__(256) edge_pv_mma(
    const __nv_bfloat16* __restrict__ phi, const __nv_bfloat16* __restrict__ plo,
    const __nv_bfloat16* __restrict__ vhi, const __nv_bfloat16* __restrict__ vlo,
    float* __restrict__ ctx)
{
    int h = blockIdx.x;
    int e = blockIdx.y & 1, b = blockIdx.y >> 1;
    int chunk = blockIdx.z;
    int qb = e ? (NBx - 1) : 0;
    __shared__ __nv_bfloat16 Ph[64][72], Pl[64][72], Vh[64][72], Vl[64][72];
    int tid = threadIdx.x, lane = tid & 31, wid = tid >> 5;
    int warp_m = wid & 3, warp_n = wid >> 2;

    const __nv_bfloat16* prow_h = phi + ((size_t)((b * NHx + h) * 2 + e)) * (64 * Sx);
    const __nv_bfloat16* prow_l = plo + ((size_t)((b * NHx + h) * 2 + e)) * (64 * Sx);

    float acc[4][4];
    #pragma unroll
    for (int j = 0; j < 4; j++) {
        acc[j][0] = 0.f; acc[j][1] = 0.f; acc[j][2] = 0.f; acc[j][3] = 0.f;
    }

    for (int c8 = 0; c8 < 8; c8++) {
        int kb = chunk * 8 + c8;
        size_t voff = ((size_t)b * Sx + kb * 64) * Dx + h * 64;
        __syncthreads();
        load_tile64(Ph, prow_h + kb * 64, Sx, tid);
        load_tile64(Pl, prow_l + kb * 64, Sx, tid);
        load_tile64(Vh, vhi + voff, Dx, tid);
        load_tile64(Vl, vlo + voff, Dx, tid);
        __syncthreads();
        pv_tile(Ph, Pl, Vh, Vl, acc, lane, warp_m, warp_n);
    }

    float* cbase = ctx + ((size_t)b * Sx + qb * 64) * Dx + h * 64;
    int r0 = warp_m * 16 + (lane >> 2);
    #pragma unroll
    for (int j = 0; j < 4; j++) {
        int col = warp_n * 32 + j * 8 + (lane & 3) * 2;
        atomicAdd(&cbase[(size_t)r0 * Dx + col],           acc[j][0]);
        atomicAdd(&cbase[(size_t)r0 * Dx + col + 1],       acc[j][1]);
        atomicAdd(&cbase[(size_t)(r0 + 8) * Dx + col],     acc[j][2]);
        atomicAdd(&cbase[(size_t)(r0 + 8) * Dx + col + 1], acc[j][3]);
    }
}

// ---------------- zero edge ctx rows ----------------
__global__ void zero_edge_ctx(float* __restrict__ ctx) {
    int i = blockIdx.x * 256 + threadIdx.x;
    if (i >= Bx * 2 * 64 * Dx) return;
    int col = i % Dx;
    int t = i / Dx;
    int row = t % 64;  t /= 64;
    int e = t & 1;
    int b = t >> 1;
    int blk = e ? (NBx - 1) : 0;
    ctx[((size_t)b * Sx + blk * 64 + row) * Dx + col] = 0.f;
}

// ---------------- row softmax -> bf16 hi/lo planes ----------------
__global__ void softmax_split_kernel(const float* __restrict__ s,
                                     __nv_bfloat16* __restrict__ phi,
                                     __nv_bfloat16* __restrict__ plo, int L) {
    extern __shared__ float buf[];
    size_t base = (size_t)blockIdx.x * L;
    float m = -3.4e38f;
    for (int i = threadIdx.x; i < L; i += blockDim.x) {
        float x = s[base + i];
        buf[i] = x;
        m = fmaxf(m, x);
    }
    m = blk_max(m);
    float lsum = 0.f;
    for (int i = threadIdx.x; i < L; i += blockDim.x) {
        float e = expf(buf[i] - m);
        buf[i] = e;
        lsum += e;
    }
    float sum = blk_sum(lsum);
    float inv = 1.f / sum;
    for (int i = threadIdx.x; i < L; i += blockDim.x) {
        float p = buf[i] * inv;
        __nv_bfloat16 hi = __float2bfloat16_rn(p);
        __nv_bfloat16 lo = __float2bfloat16_rn(p - __bfloat162float(hi));
        phi[base + i] = hi;
        plo[base + i] = lo;
    }
}

// ---------------- pooler ----------------
__global__ void pooler_kernel(const float* __restrict__ h, const float* __restrict__ pw,
                              const float* __restrict__ pb, float* __restrict__ out) {
    int j = blockIdx.x * blockDim.x + threadIdx.x;
    int b = blockIdx.y;
    if (j >= Dx) return;
    const float* hr = h + (size_t)b * Sx * Dx;
    float acc = pb[j];
    for (int kI = 0; kI < Dx; kI++) acc += hr[kI] * pw[(size_t)kI * Dx + j];
    out[b * Dx + j] = tanhf(acc);
}

// ---------------- host launcher ----------------
extern "C" void kernel_launch(void* const* d_in, const int* in_sizes, int n_in,
                              void* d_out, int out_size) {
    const int*   input_ids = (const int*)d_in[0];
    const int*   attn_mask = (const int*)d_in[1];
    const int*   tok_type  = (const int*)d_in[2];
    const int*   rand_blk  = (const int*)d_in[3];
    const float* word_emb  = (const float*)d_in[4];
    const float* type_emb  = (const float*)d_in[5];
    const float* pos_emb   = (const float*)d_in[6];
    const float* emb_ln_s  = (const float*)d_in[7];
    const float* emb_ln_b  = (const float*)d_in[8];
    const float* Wq = (const float*)d_in[9];  const float* bq = (const float*)d_in[10];
    const float* Wk = (const float*)d_in[11]; const float* bk = (const float*)d_in[12];
    const float* Wv = (const float*)d_in[13]; const float* bv = (const float*)d_in[14];
    const float* Wo = (const float*)d_in[15]; const float* bo = (const float*)d_in[16];
    const float* ln1_s = (const float*)d_in[17]; const float* ln1_b = (const float*)d_in[18];
    const float* W1 = (const float*)d_in[19]; const float* b1 = (const float*)d_in[20];
    const float* W2 = (const float*)d_in[21]; const float* b2 = (const float*)d_in[22];
    const float* ln2_s = (const float*)d_in[23]; const float* ln2_b = (const float*)d_in[24];
    const float* pool_w = (const float*)d_in[25]; const float* pool_b = (const float*)d_in[26];
    float* out = (float*)d_out;

    float *p_h = 0, *p_res = 0, *p_ctx = 0, *p_ff = 0, *p_smid = 0, *p_sedge = 0;
    __nv_bfloat16 *p_ahi = 0, *p_alo = 0, *p_whi = 0, *p_wlo = 0;
    __nv_bfloat16 *p_qhi = 0, *p_qlo = 0, *p_khi = 0, *p_klo = 0, *p_vhi = 0, *p_vlo = 0;
    __nv_bfloat16 *p_pmh = 0, *p_pml = 0, *p_peh = 0, *p_pel = 0;
    cudaGetSymbolAddress((void**)&p_h,     g_h);
    cudaGetSymbolAddress((void**)&p_res,   g_res);
    cudaGetSymbolAddress((void**)&p_ctx,   g_ctx);
    cudaGetSymbolAddress((void**)&p_ff,    g_ff);
    cudaGetSymbolAddress((void**)&p_smid,  g_smid);
    cudaGetSymbolAddress((void**)&p_sedge, g_sedge);
    cudaGetSymbolAddress((void**)&p_ahi,   g_act_hi);
    cudaGetSymbolAddress((void**)&p_alo,   g_act_lo);
    cudaGetSymbolAddress((void**)&p_whi,   g_w_hi);
    cudaGetSymbolAddress((void**)&p_wlo,   g_w_lo);
    cudaGetSymbolAddress((void**)&p_qhi,   g_qhi);
    cudaGetSymbolAddress((void**)&p_qlo,   g_qlo);
    cudaGetSymbolAddress((void**)&p_khi,   g_khi);
    cudaGetSymbolAddress((void**)&p_klo,   g_klo);
    cudaGetSymbolAddress((void**)&p_vhi,   g_vhi);
    cudaGetSymbolAddress((void**)&p_vlo,   g_vlo);
    cudaGetSymbolAddress((void**)&p_pmh,   g_pmid_hi);
    cudaGetSymbolAddress((void**)&p_pml,   g_pmid_lo);
    cudaGetSymbolAddress((void**)&p_peh,   g_pedge_hi);
    cudaGetSymbolAddress((void**)&p_pel,   g_pedge_lo);

    static bool attr_done = false;
    if (!attr_done) {
        cudaFuncSetAttribute(bgemm2_kernel<0>, cudaFuncAttributeMaxDynamicSharedMemorySize, SMEM_BYTES);
        cudaFuncSetAttribute(bgemm2_kernel<1>, cudaFuncAttributeMaxDynamicSharedMemorySize, SMEM_BYTES);
        cudaFuncSetAttribute(bgemm2_kernel<2>, cudaFuncAttributeMaxDynamicSharedMemorySize, SMEM_BYTES);
        attr_done = true;
    }

    const int M = TOK;
    const int nDD = Dx * Dx;
    const int nDF = Dx * FFx;
    const int nHD = TOK * Dx;
    const int nHF = TOK * FFx;

    auto split = [&](const float* src, __nv_bfloat16* hi, __nv_bfloat16* lo, int n) {
        split_kernel<<<(n / 4 + 255) / 256, 256>>>(src, hi, lo, n / 4);
    };

    embed_ln_kernel<<<TOK, 256>>>(input_ids, tok_type, word_emb, type_emb, pos_emb,
                                  emb_ln_s, emb_ln_b);

    for (int l = 0; l < 2; l++) {
        const float* wq = Wq + (size_t)l * nDD;  const float* bql = bq + (size_t)l * Dx;
        const float* wk = Wk + (size_t)l * nDD;  const float* bkl = bk + (size_t)l * Dx;
        const float* wv = Wv + (size_t)l * nDD;  const float* bvl = bv + (size_t)l * Dx;
        const float* wo = Wo + (size_t)l * nDD;  const float* bol = bo + (size_t)l * Dx;
        const float* w1 = W1 + (size_t)l * nDF;  const float* b1l = b1 + (size_t)l * FFx;
        const float* w2 = W2 + (size_t)l * nDF;  const float* b2l = b2 + (size_t)l * Dx;
        const float* l1s = ln1_s + (size_t)l * Dx; const float* l1b = ln1_b + (size_t)l * Dx;
        const float* l2s = ln2_s + (size_t)l * Dx; const float* l2b = ln2_b + (size_t)l * Dx;

        // QKV -> bf16 hi/lo planes directly
        split(p_h, p_ahi, p_alo, nHD);
        split(wq, p_whi, p_wlo, nDD);
        bgemm2_kernel<2><<<dim3(Dx / 128, M / 128), 256, SMEM_BYTES>>>(
            p_ahi, p_alo, p_whi, p_wlo, bql, nullptr, p_qhi, p_qlo, M, Dx, Dx);
        split(wk, p_whi, p_wlo, nDD);
        bgemm2_kernel<2><<<dim3(Dx / 128, M / 128), 256, SMEM_BYTES>>>(
            p_ahi, p_alo, p_whi, p_wlo, bkl, nullptr, p_khi, p_klo, M, Dx, Dx);
        split(wv, p_whi, p_wlo, nDD);
        bgemm2_kernel<2><<<dim3(Dx / 128, M / 128), 256, SMEM_BYTES>>>(
            p_ahi, p_alo, p_whi, p_wlo, bvl, nullptr, p_vhi, p_vlo, M, Dx, Dx);

        // middle blocks
        mid_scores_mma<<<dim3(NMID, NHx, Bx), 256>>>(p_qhi, p_qlo, p_khi, p_klo,
                                                     rand_blk, attn_mask, p_smid);
        softmax_split_kernel<<<Bx * NHx * NMID * BSx, 256, (NGx * 64) * sizeof(float)>>>(
            p_smid, p_pmh, p_pml, NGx * 64);
        mid_pv_mma<<<dim3(NMID, NHx, Bx), 256>>>(p_pmh, p_pml, p_vhi, p_vlo, rand_blk, p_ctx);

        // edge blocks
        edge_scores_mma<<<dim3(NBx, NHx, Bx * 2), 256>>>(p_qhi, p_qlo, p_khi, p_klo,
                                                         attn_mask, p_sedge);
        softmax_split_kernel<<<Bx * NHx * 2 * BSx, 256, Sx * sizeof(float)>>>(
            p_sedge, p_peh, p_pel, Sx);
        zero_edge_ctx<<<(Bx * 2 * 64 * Dx + 255) / 256, 256>>>(p_ctx);
        edge_pv_mma<<<dim3(NHx, Bx * 2, 8), 256>>>(p_peh, p_pel, p_vhi, p_vlo, p_ctx);

        // O-projection + LN
        split(p_ctx, p_ahi, p_alo, nHD);
        split(wo, p_whi, p_wlo, nDD);
        bgemm2_kernel<0><<<dim3(Dx / 128, M / 128), 256, SMEM_BYTES>>>(
            p_ahi, p_alo, p_whi, p_wlo, bol, p_res, nullptr, nullptr, M, Dx, Dx);
        add_ln_kernel<<<TOK, 256>>>(p_h, p_res, l1s, l1b);

        // FFN
        split(p_h, p_ahi, p_alo, nHD);
        split(w1, p_whi, p_wlo, nDF);
        bgemm2_kernel<1><<<dim3(FFx / 128, M / 128), 256, SMEM_BYTES>>>(
            p_ahi, p_alo, p_whi, p_wlo, b1l, p_ff, nullptr, nullptr, M, FFx, Dx);
        split(p_ff, p_ahi, p_alo, nHF);
        split(w2, p_whi, p_wlo, nDF);
        bgemm2_kernel<0><<<dim3(Dx / 128, M / 128), 256, SMEM_BYTES>>>(
            p_ahi, p_alo, p_whi, p_wlo, b2l, p_res, nullptr, nullptr, M, Dx, FFx);
        add_ln_kernel<<<TOK, 256>>>(p_h, p_res, l2s, l2b);
    }

    pooler_kernel<<<dim3((Dx + 127) / 128, Bx), 128>>>(p_h, pool_w, pool_b, out);
}

// round 7
// speedup vs baseline: 2.6326x; 1.1099x over previous
#include <cuda_runtime.h>
#include <cuda_bf16.h>
#include <cstdint>
#include <math.h>

#define Bx 2
#define Sx 4096
#define Dx 768
#define NHx 12
#define HDx 64
#define BSx 64
#define NBx 64
#define FFx 3072
#define Rx 3
#define NGx 8
#define NMID 62
#define TOK (Bx*Sx)

// ---------------- scratch (static device memory; no allocations) ----------------
__device__ float g_h[(size_t)TOK*Dx];
__device__ float g_res[(size_t)TOK*Dx];
__device__ float g_ctx[(size_t)TOK*Dx];
__device__ float g_smid[(size_t)Bx*NHx*NMID*BSx*NGx*BSx];
__device__ float g_sedge[(size_t)Bx*NHx*2*BSx*Sx];
// bf16 hi/lo planes
__device__ __nv_bfloat16 g_act_hi[(size_t)TOK*Dx];
__device__ __nv_bfloat16 g_act_lo[(size_t)TOK*Dx];
__device__ __nv_bfloat16 g_ff_hi[(size_t)TOK*FFx];
__device__ __nv_bfloat16 g_ff_lo[(size_t)TOK*FFx];
__device__ __nv_bfloat16 g_w_hi[(size_t)Dx*FFx];
__device__ __nv_bfloat16 g_w_lo[(size_t)Dx*FFx];
__device__ __nv_bfloat16 g_qhi[(size_t)TOK*Dx];
__device__ __nv_bfloat16 g_qlo[(size_t)TOK*Dx];
__device__ __nv_bfloat16 g_khi[(size_t)TOK*Dx];
__device__ __nv_bfloat16 g_klo[(size_t)TOK*Dx];
__device__ __nv_bfloat16 g_vhi[(size_t)TOK*Dx];
__device__ __nv_bfloat16 g_vlo[(size_t)TOK*Dx];
__device__ __nv_bfloat16 g_pmid_hi[(size_t)Bx*NHx*NMID*BSx*NGx*BSx];
__device__ __nv_bfloat16 g_pmid_lo[(size_t)Bx*NHx*NMID*BSx*NGx*BSx];
__device__ __nv_bfloat16 g_pedge_hi[(size_t)Bx*NHx*2*BSx*Sx];
__device__ __nv_bfloat16 g_pedge_lo[(size_t)Bx*NHx*2*BSx*Sx];

// ---------------- block reductions ----------------
__device__ __forceinline__ float blk_sum(float v) {
    __shared__ float red[33];
    #pragma unroll
    for (int o = 16; o; o >>= 1) v += __shfl_down_sync(0xffffffffu, v, o);
    int lane = threadIdx.x & 31, w = threadIdx.x >> 5;
    __syncthreads();
    if (lane == 0) red[w] = v;
    __syncthreads();
    if (w == 0) {
        float x = (lane < ((blockDim.x + 31) >> 5)) ? red[lane] : 0.f;
        #pragma unroll
        for (int o = 16; o; o >>= 1) x += __shfl_down_sync(0xffffffffu, x, o);
        if (lane == 0) red[32] = x;
    }
    __syncthreads();
    return red[32];
}

__device__ __forceinline__ float blk_max(float v) {
    __shared__ float redm[33];
    #pragma unroll
    for (int o = 16; o; o >>= 1) v = fmaxf(v, __shfl_down_sync(0xffffffffu, v, o));
    int lane = threadIdx.x & 31, w = threadIdx.x >> 5;
    __syncthreads();
    if (lane == 0) redm[w] = v;
    __syncthreads();
    if (w == 0) {
        float x = (lane < ((blockDim.x + 31) >> 5)) ? redm[lane] : -3.4e38f;
        #pragma unroll
        for (int o = 16; o; o >>= 1) x = fmaxf(x, __shfl_down_sync(0xffffffffu, x, o));
        if (lane == 0) redm[32] = x;
    }
    __syncthreads();
    return redm[32];
}

// ---------------- fp32 -> (hi, lo) bf16 planes ----------------
__global__ void split_kernel(const float* __restrict__ in,
                             __nv_bfloat16* __restrict__ hi,
                             __nv_bfloat16* __restrict__ lo, int n4) {
    int i = blockIdx.x * blockDim.x + threadIdx.x;
    if (i >= n4) return;
    float4 v = ((const float4*)in)[i];
    __nv_bfloat16 h0 = __float2bfloat16_rn(v.x);
    __nv_bfloat16 h1 = __float2bfloat16_rn(v.y);
    __nv_bfloat16 h2 = __float2bfloat16_rn(v.z);
    __nv_bfloat16 h3 = __float2bfloat16_rn(v.w);
    __nv_bfloat16 l0 = __float2bfloat16_rn(v.x - __bfloat162float(h0));
    __nv_bfloat16 l1 = __float2bfloat16_rn(v.y - __bfloat162float(h1));
    __nv_bfloat16 l2 = __float2bfloat16_rn(v.z - __bfloat162float(h2));
    __nv_bfloat16 l3 = __float2bfloat16_rn(v.w - __bfloat162float(h3));
    ((__nv_bfloat162*)hi)[2*i]   = __halves2bfloat162(h0, h1);
    ((__nv_bfloat162*)hi)[2*i+1] = __halves2bfloat162(h2, h3);
    ((__nv_bfloat162*)lo)[2*i]   = __halves2bfloat162(l0, l1);
    ((__nv_bfloat162*)lo)[2*i+1] = __halves2bfloat162(l2, l3);
}

// ---------------- embeddings + LN ----------------
__global__ void embed_ln_kernel(const int* __restrict__ ids, const int* __restrict__ tt,
                                const float* __restrict__ wemb, const float* __restrict__ temb,
                                const float* __restrict__ pemb,
                                const float* __restrict__ lns, const float* __restrict__ lnb) {
    int tok = blockIdx.x;
    int pos = tok % Sx;
    const float* w = wemb + (size_t)ids[tok] * Dx;
    const float* t = temb + (size_t)tt[tok] * Dx;
    const float* p = pemb + (size_t)pos * Dx;
    __shared__ float buf[Dx];
    float ls = 0.f, lq = 0.f;
    for (int i = threadIdx.x; i < Dx; i += blockDim.x) {
        float x = w[i] + t[i] + p[i];
        buf[i] = x; ls += x; lq += x * x;
    }
    float sum = blk_sum(ls);
    float sq  = blk_sum(lq);
    float mu = sum * (1.f / Dx);
    float var = sq * (1.f / Dx) - mu * mu;
    float inv = rsqrtf(var + 1e-12f);
    for (int i = threadIdx.x; i < Dx; i += blockDim.x)
        g_h[(size_t)tok * Dx + i] = lns[i] * (buf[i] - mu) * inv + lnb[i];
}

// ---------------- residual add + LN (in-place on h) ----------------
__global__ void add_ln_kernel(float* __restrict__ h, const float* __restrict__ r,
                              const float* __restrict__ lns, const float* __restrict__ lnb) {
    int tok = blockIdx.x;
    __shared__ float buf[Dx];
    float ls = 0.f, lq = 0.f;
    for (int i = threadIdx.x; i < Dx; i += blockDim.x) {
        float x = h[(size_t)tok * Dx + i] + r[(size_t)tok * Dx + i];
        buf[i] = x; ls += x; lq += x * x;
    }
    float sum = blk_sum(ls);
    float sq  = blk_sum(lq);
    float mu = sum * (1.f / Dx);
    float var = sq * (1.f / Dx) - mu * mu;
    float inv = rsqrtf(var + 1e-12f);
    for (int i = threadIdx.x; i < Dx; i += blockDim.x)
        h[(size_t)tok * Dx + i] = lns[i] * (buf[i] - mu) * inv + lnb[i];
}

// ---------------- tensor-core primitives ----------------
__device__ __forceinline__ void ldsm_x4(uint32_t* r, uint32_t addr) {
    asm volatile("ldmatrix.sync.aligned.m8n8.x4.shared.b16 {%0,%1,%2,%3}, [%4];"
                 : "=r"(r[0]), "=r"(r[1]), "=r"(r[2]), "=r"(r[3]) : "r"(addr));
}
__device__ __forceinline__ void ldsm_x4t(uint32_t* r, uint32_t addr) {
    asm volatile("ldmatrix.sync.aligned.m8n8.x4.trans.shared.b16 {%0,%1,%2,%3}, [%4];"
                 : "=r"(r[0]), "=r"(r[1]), "=r"(r[2]), "=r"(r[3]) : "r"(addr));
}
__device__ __forceinline__ void mma_bf16(float* c, const uint32_t* a, uint32_t b0, uint32_t b1) {
    asm volatile("mma.sync.aligned.m16n8k16.row.col.f32.bf16.bf16.f32 "
                 "{%0,%1,%2,%3}, {%4,%5,%6,%7}, {%8,%9}, {%0,%1,%2,%3};"
                 : "+f"(c[0]), "+f"(c[1]), "+f"(c[2]), "+f"(c[3])
                 : "r"(a[0]), "r"(a[1]), "r"(a[2]), "r"(a[3]), "r"(b0), "r"(b1));
}
__device__ __forceinline__ void cp16(void* dst, const void* src) {
    uint32_t d = (uint32_t)__cvta_generic_to_shared(dst);
    asm volatile("cp.async.cg.shared.global [%0], [%1], 16;" :: "r"(d), "l"(src));
}

// ---------------- dense GEMM (bf16 hi/lo planes, double-buffered cp.async) ------
// MODE 0: fp32 out; MODE 2: bf16 hi/lo out; MODE 3: GELU + bf16 hi/lo out.
#define STAGE_ELT 18944
#define OFF_AL 5120
#define OFF_BH 10240
#define OFF_BL 14592
#define SMEM_BYTES (2 * STAGE_ELT * 2)

__device__ __forceinline__ void load_stage(
    __nv_bfloat16* sm, int s, int k0, int tid, int byb, int bxb,
    const __nv_bfloat16* Ahg, const __nv_bfloat16* Alg,
    const __nv_bfloat16* Whg, const __nv_bfloat16* Wlg, int N, int K)
{
    __nv_bfloat16* base = sm + s * STAGE_ELT;
    #pragma unroll
    for (int i = 0; i < 2; i++) {
        int idx = tid + i * 256;
        int rA = idx >> 2, cA = (idx & 3) * 8;
        size_t ga = (size_t)(byb * 128 + rA) * K + k0 + cA;
        cp16(base + rA * 40 + cA, Ahg + ga);
        cp16(base + OFF_AL + rA * 40 + cA, Alg + ga);
        int rB = idx >> 4, cB = (idx & 15) * 8;
        size_t gb = (size_t)(k0 + rB) * N + bxb * 128 + cB;
        cp16(base + OFF_BH + rB * 136 + cB, Whg + gb);
        cp16(base + OFF_BL + rB * 136 + cB, Wlg + gb);
    }
    asm volatile("cp.async.commit_group;");
}

template<int MODE>
__global__ void __launch_bounds__(256, 2) bgemm2_kernel(
    const __nv_bfloat16* __restrict__ Ahg, const __nv_bfloat16* __restrict__ Alg,
    const __nv_bfloat16* __restrict__ Whg, const __nv_bfloat16* __restrict__ Wlg,
    const float* __restrict__ bias, float* __restrict__ C,
    __nv_bfloat16* __restrict__ Chi, __nv_bfloat16* __restrict__ Clo,
    int M, int N, int K)
{
    extern __shared__ __align__(16) __nv_bfloat16 sm[];
    const int tid = threadIdx.x;
    const int lane = tid & 31;
    const int wid = tid >> 5;
    const int warp_m = wid & 3;
    const int warp_n = wid >> 2;
    const int bxb = blockIdx.x;
    const int byb = blockIdx.y;

    float acc[2][8][4];
    #pragma unroll
    for (int mt = 0; mt < 2; mt++) {
        #pragma unroll
        for (int nt = 0; nt < 8; nt++) {
            acc[mt][nt][0] = 0.f; acc[mt][nt][1] = 0.f;
            acc[mt][nt][2] = 0.f; acc[mt][nt][3] = 0.f;
        }
    }

    const int a_tile = lane >> 3;
    const int a_rl = lane & 7;
    const int a_ldrow = warp_m * 32 + (a_tile & 1) * 8 + a_rl;
    const int a_ldcol = (a_tile >> 1) * 8;
    const int b_ldk = (a_tile & 1) * 8 + a_rl;
    const int b_ldn = warp_n * 64 + (a_tile >> 1) * 8;

    const int nk = K >> 5;
    load_stage(sm, 0, 0, tid, byb, bxb, Ahg, Alg, Whg, Wlg, N, K);
    load_stage(sm, 1, 32, tid, byb, bxb, Ahg, Alg, Whg, Wlg, N, K);

    for (int kt = 0; kt < nk; kt++) {
        const int s = kt & 1;
        if (kt == nk - 1) asm volatile("cp.async.wait_group 0;");
        else              asm volatile("cp.async.wait_group 1;");
        __syncthreads();

        __nv_bfloat16* Ahs = sm + s * STAGE_ELT;
        __nv_bfloat16* Als = Ahs + OFF_AL;
        __nv_bfloat16* Bhs = sm + s * STAGE_ELT + OFF_BH;
        __nv_bfloat16* Bls = sm + s * STAGE_ELT + OFF_BL;

        #pragma unroll
        for (int kk = 0; kk < 32; kk += 16) {
            uint32_t ah0[4], ah1[4], al0[4], al1[4];
            ldsm_x4(ah0, (uint32_t)__cvta_generic_to_shared(Ahs + a_ldrow * 40 + a_ldcol + kk));
            ldsm_x4(ah1, (uint32_t)__cvta_generic_to_shared(Ahs + (a_ldrow + 16) * 40 + a_ldcol + kk));
            ldsm_x4(al0, (uint32_t)__cvta_generic_to_shared(Als + a_ldrow * 40 + a_ldcol + kk));
            ldsm_x4(al1, (uint32_t)__cvta_generic_to_shared(Als + (a_ldrow + 16) * 40 + a_ldcol + kk));
            #pragma unroll
            for (int p = 0; p < 4; p++) {
                uint32_t bh4[4], bl4[4];
                ldsm_x4t(bh4, (uint32_t)__cvta_generic_to_shared(Bhs + (kk + b_ldk) * 136 + b_ldn + p * 16));
                ldsm_x4t(bl4, (uint32_t)__cvta_generic_to_shared(Bls + (kk + b_ldk) * 136 + b_ldn + p * 16));
                int nt0 = p * 2;
                int nt1 = p * 2 + 1;
                mma_bf16(acc[0][nt0], ah0, bh4[0], bh4[1]);
                mma_bf16(acc[0][nt0], ah0, bl4[0], bl4[1]);
                mma_bf16(acc[0][nt0], al0, bh4[0], bh4[1]);
                mma_bf16(acc[0][nt1], ah0, bh4[2], bh4[3]);
                mma_bf16(acc[0][nt1], ah0, bl4[2], bl4[3]);
                mma_bf16(acc[0][nt1], al0, bh4[2], bh4[3]);
                mma_bf16(acc[1][nt0], ah1, bh4[0], bh4[1]);
                mma_bf16(acc[1][nt0], ah1, bl4[0], bl4[1]);
                mma_bf16(acc[1][nt0], al1, bh4[0], bh4[1]);
                mma_bf16(acc[1][nt1], ah1, bh4[2], bh4[3]);
                mma_bf16(acc[1][nt1], ah1, bl4[2], bl4[3]);
                mma_bf16(acc[1][nt1], al1, bh4[2], bh4[3]);
            }
        }
        __syncthreads();
        if (kt + 2 < nk)
            load_stage(sm, s, (kt + 2) * 32, tid, byb, bxb, Ahg, Alg, Whg, Wlg, N, K);
    }

    const int grp = lane >> 2;
    const int tig = lane & 3;
    #pragma unroll
    for (int mt = 0; mt < 2; mt++) {
        #pragma unroll
        for (int nt = 0; nt < 8; nt++) {
            int col = bxb * 128 + warp_n * 64 + nt * 8 + tig * 2;
            float b0 = bias[col];
            float b1 = bias[col + 1];
            #pragma unroll
            for (int half = 0; half < 2; half++) {
                int row = byb * 128 + warp_m * 32 + mt * 16 + grp + half * 8;
                float v0 = acc[mt][nt][half * 2 + 0] + b0;
                float v1 = acc[mt][nt][half * 2 + 1] + b1;
                if (MODE == 3) {
                    v0 = 0.5f * v0 * (1.f + erff(v0 * 0.70710678118654752f));
                    v1 = 0.5f * v1 * (1.f + erff(v1 * 0.70710678118654752f));
                }
                if (MODE == 2 || MODE == 3) {
                    __nv_bfloat16 h0 = __float2bfloat16_rn(v0);
                    __nv_bfloat16 h1 = __float2bfloat16_rn(v1);
                    __nv_bfloat16 l0 = __float2bfloat16_rn(v0 - __bfloat162float(h0));
                    __nv_bfloat16 l1 = __float2bfloat16_rn(v1 - __bfloat162float(h1));
                    *(__nv_bfloat162*)&Chi[(size_t)row * N + col] = __halves2bfloat162(h0, h1);
                    *(__nv_bfloat162*)&Clo[(size_t)row * N + col] = __halves2bfloat162(l0, l1);
                } else {
                    C[(size_t)row * N + col] = v0;
                    C[(size_t)row * N + col + 1] = v1;
                }
            }
        }
    }
}

// ---------------- helpers ----------------
__device__ __forceinline__ int mid_block_idx(int n, int g, const int* __restrict__ randb) {
    if (g == 0) return 0;
    if (g == 1) return NBx - 1;
    if (g < 5)  return n - 3 + g;
    return randb[(n - 1) * Rx + (g - 5)];
}

// ---------------- attention: 64x64 score tile (MMA, split-bf16) -----------------
__device__ __forceinline__ void score_tile(
    const __nv_bfloat16 (*Qh)[72], const __nv_bfloat16 (*Ql)[72],
    const __nv_bfloat16 (*Kh)[72], const __nv_bfloat16 (*Kl)[72],
    const int* __restrict__ amask, int mask_base,
    float* __restrict__ out, int ostride, int ocol0,
    int lane, int warp_m, int warp_n)
{
    const int tile = lane >> 3;
    const int rl = lane & 7;
    const int ldrow = (tile & 1) * 8 + rl;
    const int ldcol = (tile >> 1) * 8;

    float acc[4][4];
    #pragma unroll
    for (int j = 0; j < 4; j++) {
        acc[j][0] = 0.f; acc[j][1] = 0.f; acc[j][2] = 0.f; acc[j][3] = 0.f;
    }

    #pragma unroll
    for (int kk = 0; kk < 64; kk += 16) {
        uint32_t ah[4], al[4];
        ldsm_x4(ah, (uint32_t)__cvta_generic_to_shared(&Qh[warp_m * 16 + ldrow][ldcol + kk]));
        ldsm_x4(al, (uint32_t)__cvta_generic_to_shared(&Ql[warp_m * 16 + ldrow][ldcol + kk]));
        #pragma unroll
        for (int j2 = 0; j2 < 2; j2++) {
            int n0 = warp_n * 32 + j2 * 16;
            uint32_t bh[4], bl[4];
            ldsm_x4(bh, (uint32_t)__cvta_generic_to_shared(&Kh[n0 + ldrow][ldcol + kk]));
            ldsm_x4(bl, (uint32_t)__cvta_generic_to_shared(&Kl[n0 + ldrow][ldcol + kk]));
            mma_bf16(acc[j2 * 2 + 0], ah, bh[0], bh[2]);
            mma_bf16(acc[j2 * 2 + 0], ah, bl[0], bl[2]);
            mma_bf16(acc[j2 * 2 + 0], al, bh[0], bh[2]);
            mma_bf16(acc[j2 * 2 + 1], ah, bh[1], bh[3]);
            mma_bf16(acc[j2 * 2 + 1], ah, bl[1], bl[3]);
            mma_bf16(acc[j2 * 2 + 1], al, bh[1], bh[3]);
        }
    }

    int r0 = warp_m * 16 + (lane >> 2);
    #pragma unroll
    for (int j = 0; j < 4; j++) {
        int ki = warp_n * 32 + j * 8 + (lane & 3) * 2;
        float m0 = (1.0f - (float)amask[mask_base + ki]) * -1e9f;
        float m1 = (1.0f - (float)amask[mask_base + ki + 1]) * -1e9f;
        out[(size_t)r0 * ostride + ocol0 + ki]           = acc[j][0] * 0.125f + m0;
        out[(size_t)r0 * ostride + ocol0 + ki + 1]       = acc[j][1] * 0.125f + m1;
        out[(size_t)(r0 + 8) * ostride + ocol0 + ki]     = acc[j][2] * 0.125f + m0;
        out[(size_t)(r0 + 8) * ostride + ocol0 + ki + 1] = acc[j][3] * 0.125f + m1;
    }
}

__device__ __forceinline__ void pv_tile(
    const __nv_bfloat16 (*Ph)[72], const __nv_bfloat16 (*Pl)[72],
    const __nv_bfloat16 (*Vh)[72], const __nv_bfloat16 (*Vl)[72],
    float acc[4][4], int lane, int warp_m, int warp_n)
{
    const int tile = lane >> 3;
    const int rl = lane & 7;
    const int ldrow = (tile & 1) * 8 + rl;
    const int ldcol = (tile >> 1) * 8;
    const int b_ldk = (tile & 1) * 8 + rl;
    const int b_ldn = (tile >> 1) * 8;

    #pragma unroll
    for (int kk = 0; kk < 64; kk += 16) {
        uint32_t ah[4], al[4];
        ldsm_x4(ah, (uint32_t)__cvta_generic_to_shared(&Ph[warp_m * 16 + ldrow][ldcol + kk]));
        ldsm_x4(al, (uint32_t)__cvta_generic_to_shared(&Pl[warp_m * 16 + ldrow][ldcol + kk]));
        #pragma unroll
        for (int j2 = 0; j2 < 2; j2++) {
            int n0 = warp_n * 32 + j2 * 16;
            uint32_t bh4[4], bl4[4];
            ldsm_x4t(bh4, (uint32_t)__cvta_generic_to_shared(&Vh[kk + b_ldk][n0 + b_ldn]));
            ldsm_x4t(bl4, (uint32_t)__cvta_generic_to_shared(&Vl[kk + b_ldk][n0 + b_ldn]));
            mma_bf16(acc[j2 * 2 + 0], ah, bh4[0], bh4[1]);
            mma_bf16(acc[j2 * 2 + 0], ah, bl4[0], bl4[1]);
            mma_bf16(acc[j2 * 2 + 0], al, bh4[0], bh4[1]);
            mma_bf16(acc[j2 * 2 + 1], ah, bh4[2], bh4[3]);
            mma_bf16(acc[j2 * 2 + 1], ah, bl4[2], bl4[3]);
            mma_bf16(acc[j2 * 2 + 1], al, bh4[2], bh4[3]);
        }
    }
}

__device__ __forceinline__ void load_tile64(
    __nv_bfloat16 (*dst)[72], const __nv_bfloat16* __restrict__ src, int gstride, int tid)
{
    #pragma unroll
    for (int i = 0; i < 2; i++) {
        int idx = tid + i * 256;
        int r = idx >> 3, c = (idx & 7) * 8;
        *(uint4*)&dst[r][c] = *(const uint4*)(src + (size_t)r * gstride + c);
    }
}

// ---------------- middle-block scores ----------------
__global__ void __launch_bounds__(256) mid_scores_mma(
    const __nv_bfloat16* __restrict__ qhi, const __nv_bfloat16* __restrict__ qlo,
    const __nv_bfloat16* __restrict__ khi, const __nv_bfloat16* __restrict__ klo,
    const int* __restrict__ randb, const int* __restrict__ amask,
    float* __restrict__ smid)
{
    int n = blockIdx.x + 1, h = blockIdx.y, b = blockIdx.z;
    __shared__ __nv_bfloat16 Qh[64][72], Ql[64][72], Kh[64][72], Kl[64][72];
    int tid = threadIdx.x, lane = tid & 31, wid = tid >> 5;
    int warp_m = wid & 3, warp_n = wid >> 2;

    size_t qoff = ((size_t)b * Sx + n * 64) * Dx + h * 64;
    load_tile64(Qh, qhi + qoff, Dx, tid);
    load_tile64(Ql, qlo + qoff, Dx, tid);

    float* out = smid + (((size_t)(b * NHx + h) * NMID + (n - 1)) << 15);

    for (int g = 0; g < NGx; g++) {
        int kb = mid_block_idx(n, g, randb);
        size_t koff = ((size_t)b * Sx + kb * 64) * Dx + h * 64;
        __syncthreads();
        load_tile64(Kh, khi + koff, Dx, tid);
        load_tile64(Kl, klo + koff, Dx, tid);
        __syncthreads();
        score_tile(Qh, Ql, Kh, Kl, amask, b * Sx + kb * 64,
                   out, NGx * 64, g * 64, lane, warp_m, warp_n);
    }
}

// ---------------- middle-block PV ----------------
__global__ void __launch_bounds__(256) mid_pv_mma(
    const __nv_bfloat16* __restrict__ phi, const __nv_bfloat16* __restrict__ plo,
    const __nv_bfloat16* __restrict__ vhi, const __nv_bfloat16* __restrict__ vlo,
    const int* __restrict__ randb, float* __restrict__ ctx)
{
    int n = blockIdx.x + 1, h = blockIdx.y, b = blockIdx.z;
    __shared__ __nv_bfloat16 Ph[64][72], Pl[64][72], Vh[64][72], Vl[64][72];
    int tid = threadIdx.x, lane = tid & 31, wid = tid >> 5;
    int warp_m = wid & 3, warp_n = wid >> 2;

    const __nv_bfloat16* prow_h = phi + (((size_t)(b * NHx + h) * NMID + (n - 1)) << 15);
    const __nv_bfloat16* prow_l = plo + (((size_t)(b * NHx + h) * NMID + (n - 1)) << 15);

    float acc[4][4];
    #pragma unroll
    for (int j = 0; j < 4; j++) {
        acc[j][0] = 0.f; acc[j][1] = 0.f; acc[j][2] = 0.f; acc[j][3] = 0.f;
    }

    for (int g = 0; g < NGx; g++) {
        int kb = mid_block_idx(n, g, randb);
        size_t voff = ((size_t)b * Sx + kb * 64) * Dx + h * 64;
        __syncthreads();
        load_tile64(Ph, prow_h + g * 64, NGx * 64, tid);
        load_tile64(Pl, prow_l + g * 64, NGx * 64, tid);
        load_tile64(Vh, vhi + voff, Dx, tid);
        load_tile64(Vl, vlo + voff, Dx, tid);
        __syncthreads();
        pv_tile(Ph, Pl, Vh, Vl, acc, lane, warp_m, warp_n);
    }

    float* cbase = ctx + ((size_t)b * Sx + n * 64) * Dx + h * 64;
    int r0 = warp_m * 16 + (lane >> 2);
    #pragma unroll
    for (int j = 0; j < 4; j++) {
        int col = warp_n * 32 + j * 8 + (lane & 3) * 2;
        cbase[(size_t)r0 * Dx + col]           = acc[j][0];
        cbase[(size_t)r0 * Dx + col + 1]       = acc[j][1];
        cbase[(size_t)(r0 + 8) * Dx + col]     = acc[j][2];
        cbase[(size_t)(r0 + 8) * Dx + col + 1] = acc[j][3];
    }
}

// ---------------- edge scores ----------------
__global__ void __launch_bounds__(256) edge_scores_mma(
    const __nv_bfloat16* __restrict__ qhi, const __nv_bfloat16* __restrict__ qlo,
    const __nv_bfloat16* __restrict__ khi, const __nv_bfloat16* __restrict__ klo,
    const int* __restrict__ amask, float* __restrict__ sedge)
{
    int kb = blockIdx.x, h = blockIdx.y;
    int e = blockIdx.z & 1, b = blockIdx.z >> 1;
    int qb = e ? (NBx - 1) : 0;
    __shared__ __nv_bfloat16 Qh[64][72], Ql[64][72], Kh[64][72], Kl[64][72];
    int tid = threadIdx.x, lane = tid & 31, wid = tid >> 5;
    int warp_m = wid & 3, warp_n = wid >> 2;

    size_t qoff = ((size_t)b * Sx + qb * 64) * Dx + h * 64;
    size_t koff = ((size_t)b * Sx + kb * 64) * Dx + h * 64;
    load_tile64(Qh, qhi + qoff, Dx, tid);
    load_tile64(Ql, qlo + qoff, Dx, tid);
    load_tile64(Kh, khi + koff, Dx, tid);
    load_tile64(Kl, klo + koff, Dx, tid);
    __syncthreads();

    float* out = sedge + ((size_t)((b * NHx + h) * 2 + e)) * (64 * Sx);
    score_tile(Qh, Ql, Kh, Kl, amask, b * Sx + kb * 64,
               out, Sx, kb * 64, lane, warp_m, warp_n);
}

// ---------------- edge PV (chunked, atomic accumulate) ----------------
__global__ void __launch_bounds__(256) edge_pv_mma(
    const __nv_bfloat16* __restrict__ phi, const __nv_bfloat16* __restrict__ plo,
    const __nv_bfloat16* __restrict__ vhi, const __nv_bfloat16* __restrict__ vlo,
    float* __restrict__ ctx)
{
    int h = blockIdx.x;
    int e = blockIdx.y & 1, b = blockIdx.y >> 1;
    int chunk = blockIdx.z;
    int qb = e ? (NBx - 1) : 0;
    __shared__ __nv_bfloat16 Ph[64][72], Pl[64][72], Vh[64][72], Vl[64][72];
    int tid = threadIdx.x, lane = tid & 31, wid = tid >> 5;
    int warp_m = wid & 3, warp_n = wid >> 2;

    const __nv_bfloat16* prow_h = phi + ((size_t)((b * NHx + h) * 2 + e)) * (64 * Sx);
    const __nv_bfloat16* prow_l = plo + ((size_t)((b * NHx + h) * 2 + e)) * (64 * Sx);

    float acc[4][4];
    #pragma unroll
    for (int j = 0; j < 4; j++) {
        acc[j][0] = 0.f; acc[j][1] = 0.f; acc[j][2] = 0.f; acc[j][3] = 0.f;
    }

    for (int c8 = 0; c8 < 8; c8++) {
        int kb = chunk * 8 + c8;
        size_t voff = ((size_t)b * Sx + kb * 64) * Dx + h * 64;
        __syncthreads();
        load_tile64(Ph, prow_h + kb * 64, Sx, tid);
        load_tile64(Pl, prow_l + kb * 64, Sx, tid);
        load_tile64(Vh, vhi + voff, Dx, tid);
        load_tile64(Vl, vlo + voff, Dx, tid);
        __syncthreads();
        pv_tile(Ph, Pl, Vh, Vl, acc, lane, warp_m, warp_n);
    }

    float* cbase = ctx + ((size_t)b * Sx + qb * 64) * Dx + h * 64;
    int r0 = warp_m * 16 + (lane >> 2);
    #pragma unroll
    for (int j = 0; j < 4; j++) {
        int col = warp_n * 32 + j * 8 + (lane & 3) * 2;
        atomicAdd(&cbase[(size_t)r0 * Dx + col],           acc[j][0]);
        atomicAdd(&cbase[(size_t)r0 * Dx + col + 1],       acc[j][1]);
        atomicAdd(&cbase[(size_t)(r0 + 8) * Dx + col],     acc[j][2]);
        atomicAdd(&cbase[(size_t)(r0 + 8) * Dx + col + 1], acc[j][3]);
    }
}

// ---------------- zero edge ctx rows ----------------
__global__ void zero_edge_ctx(float* __restrict__ ctx) {
    int i = blockIdx.x * 256 + threadIdx.x;
    if (i >= Bx * 2 * 64 * Dx) return;
    int col = i % Dx;
    int t = i / Dx;
    int row = t % 64;  t /= 64;
    int e = t & 1;
    int b = t >> 1;
    int blk = e ? (NBx - 1) : 0;
    ctx[((size_t)b * Sx + blk * 64 + row) * Dx + col] = 0.f;
}

// ---------------- row softmax -> bf16 hi/lo planes ----------------
__global__ void softmax_split_kernel(const float* __restrict__ s,
                                     __nv_bfloat16* __restrict__ phi,
                                     __nv_bfloat16* __restrict__ plo, int L) {
    extern __shared__ float buf[];
    size_t base = (size_t)blockIdx.x * L;
    float m = -3.4e38f;
    for (int i = threadIdx.x; i < L; i += blockDim.x) {
        float x = s[base + i];
        buf[i] = x;
        m = fmaxf(m, x);
    }
    m = blk_max(m);
    float lsum = 0.f;
    for (int i = threadIdx.x; i < L; i += blockDim.x) {
        float e = expf(buf[i] - m);
        buf[i] = e;
        lsum += e;
    }
    float sum = blk_sum(lsum);
    float inv = 1.f / sum;
    for (int i = threadIdx.x; i < L; i += blockDim.x) {
        float p = buf[i] * inv;
        __nv_bfloat16 hi = __float2bfloat16_rn(p);
        __nv_bfloat16 lo = __float2bfloat16_rn(p - __bfloat162float(hi));
        phi[base + i] = hi;
        plo[base + i] = lo;
    }
}

// ---------------- pooler ----------------
__global__ void pooler_kernel(const float* __restrict__ h, const float* __restrict__ pw,
                              const float* __restrict__ pb, float* __restrict__ out) {
    int j = blockIdx.x * blockDim.x + threadIdx.x;
    int b = blockIdx.y;
    if (j >= Dx) return;
    const float* hr = h + (size_t)b * Sx * Dx;
    float acc = pb[j];
    for (int kI = 0; kI < Dx; kI++) acc += hr[kI] * pw[(size_t)kI * Dx + j];
    out[b * Dx + j] = tanhf(acc);
}

// ---------------- host launcher ----------------
extern "C" void kernel_launch(void* const* d_in, const int* in_sizes, int n_in,
                              void* d_out, int out_size) {
    const int*   input_ids = (const int*)d_in[0];
    const int*   attn_mask = (const int*)d_in[1];
    const int*   tok_type  = (const int*)d_in[2];
    const int*   rand_blk  = (const int*)d_in[3];
    const float* word_emb  = (const float*)d_in[4];
    const float* type_emb  = (const float*)d_in[5];
    const float* pos_emb   = (const float*)d_in[6];
    const float* emb_ln_s  = (const float*)d_in[7];
    const float* emb_ln_b  = (const float*)d_in[8];
    const float* Wq = (const float*)d_in[9];  const float* bq = (const float*)d_in[10];
    const float* Wk = (const float*)d_in[11]; const float* bk = (const float*)d_in[12];
    const float* Wv = (const float*)d_in[13]; const float* bv = (const float*)d_in[14];
    const float* Wo = (const float*)d_in[15]; const float* bo = (const float*)d_in[16];
    const float* ln1_s = (const float*)d_in[17]; const float* ln1_b = (const float*)d_in[18];
    const float* W1 = (const float*)d_in[19]; const float* b1 = (const float*)d_in[20];
    const float* W2 = (const float*)d_in[21]; const float* b2 = (const float*)d_in[22];
    const float* ln2_s = (const float*)d_in[23]; const float* ln2_b = (const float*)d_in[24];
    const float* pool_w = (const float*)d_in[25]; const float* pool_b = (const float*)d_in[26];
    float* out = (float*)d_out;

    float *p_h = 0, *p_res = 0, *p_ctx = 0, *p_smid = 0, *p_sedge = 0;
    __nv_bfloat16 *p_ahi = 0, *p_alo = 0, *p_ffh = 0, *p_ffl = 0, *p_whi = 0, *p_wlo = 0;
    __nv_bfloat16 *p_qhi = 0, *p_qlo = 0, *p_khi = 0, *p_klo = 0, *p_vhi = 0, *p_vlo = 0;
    __nv_bfloat16 *p_pmh = 0, *p_pml = 0, *p_peh = 0, *p_pel = 0;
    cudaGetSymbolAddress((void**)&p_h,     g_h);
    cudaGetSymbolAddress((void**)&p_res,   g_res);
    cudaGetSymbolAddress((void**)&p_ctx,   g_ctx);
    cudaGetSymbolAddress((void**)&p_smid,  g_smid);
    cudaGetSymbolAddress((void**)&p_sedge, g_sedge);
    cudaGetSymbolAddress((void**)&p_ahi,   g_act_hi);
    cudaGetSymbolAddress((void**)&p_alo,   g_act_lo);
    cudaGetSymbolAddress((void**)&p_ffh,   g_ff_hi);
    cudaGetSymbolAddress((void**)&p_ffl,   g_ff_lo);
    cudaGetSymbolAddress((void**)&p_whi,   g_w_hi);
    cudaGetSymbolAddress((void**)&p_wlo,   g_w_lo);
    cudaGetSymbolAddress((void**)&p_qhi,   g_qhi);
    cudaGetSymbolAddress((void**)&p_qlo,   g_qlo);
    cudaGetSymbolAddress((void**)&p_khi,   g_khi);
    cudaGetSymbolAddress((void**)&p_klo,   g_klo);
    cudaGetSymbolAddress((void**)&p_vhi,   g_vhi);
    cudaGetSymbolAddress((void**)&p_vlo,   g_vlo);
    cudaGetSymbolAddress((void**)&p_pmh,   g_pmid_hi);
    cudaGetSymbolAddress((void**)&p_pml,   g_pmid_lo);
    cudaGetSymbolAddress((void**)&p_peh,   g_pedge_hi);
    cudaGetSymbolAddress((void**)&p_pel,   g_pedge_lo);

    static bool attr_done = false;
    if (!attr_done) {
        cudaFuncSetAttribute(bgemm2_kernel<0>, cudaFuncAttributeMaxDynamicSharedMemorySize, SMEM_BYTES);
        cudaFuncSetAttribute(bgemm2_kernel<2>, cudaFuncAttributeMaxDynamicSharedMemorySize, SMEM_BYTES);
        cudaFuncSetAttribute(bgemm2_kernel<3>, cudaFuncAttributeMaxDynamicSharedMemorySize, SMEM_BYTES);
        attr_done = true;
    }

    const int M = TOK;
    const int nDD = Dx * Dx;
    const int nDF = Dx * FFx;
    const int nHD = TOK * Dx;

    auto split = [&](const float* src, __nv_bfloat16* hi, __nv_bfloat16* lo, int n) {
        split_kernel<<<(n / 4 + 255) / 256, 256>>>(src, hi, lo, n / 4);
    };

    embed_ln_kernel<<<TOK, 256>>>(input_ids, tok_type, word_emb, type_emb, pos_emb,
                                  emb_ln_s, emb_ln_b);

    for (int l = 0; l < 2; l++) {
        const float* wq = Wq + (size_t)l * nDD;  const float* bql = bq + (size_t)l * Dx;
        const float* wk = Wk + (size_t)l * nDD;  const float* bkl = bk + (size_t)l * Dx;
        const float* wv = Wv + (size_t)l * nDD;  const float* bvl = bv + (size_t)l * Dx;
        const float* wo = Wo + (size_t)l * nDD;  const float* bol = bo + (size_t)l * Dx;
        const float* w1 = W1 + (size_t)l * nDF;  const float* b1l = b1 + (size_t)l * FFx;
        const float* w2 = W2 + (size_t)l * nDF;  const float* b2l = b2 + (size_t)l * Dx;
        const float* l1s = ln1_s + (size_t)l * Dx; const float* l1b = ln1_b + (size_t)l * Dx;
        const float* l2s = ln2_s + (size_t)l * Dx; const float* l2b = ln2_b + (size_t)l * Dx;

        // QKV -> bf16 hi/lo planes directly
        split(p_h, p_ahi, p_alo, nHD);
        split(wq, p_whi, p_wlo, nDD);
        bgemm2_kernel<2><<<dim3(Dx / 128, M / 128), 256, SMEM_BYTES>>>(
            p_ahi, p_alo, p_whi, p_wlo, bql, nullptr, p_qhi, p_qlo, M, Dx, Dx);
        split(wk, p_whi, p_wlo, nDD);
        bgemm2_kernel<2><<<dim3(Dx / 128, M / 128), 256, SMEM_BYTES>>>(
            p_ahi, p_alo, p_whi, p_wlo, bkl, nullptr, p_khi, p_klo, M, Dx, Dx);
        split(wv, p_whi, p_wlo, nDD);
        bgemm2_kernel<2><<<dim3(Dx / 128, M / 128), 256, SMEM_BYTES>>>(
            p_ahi, p_alo, p_whi, p_wlo, bvl, nullptr, p_vhi, p_vlo, M, Dx, Dx);

        // middle blocks
        mid_scores_mma<<<dim3(NMID, NHx, Bx), 256>>>(p_qhi, p_qlo, p_khi, p_klo,
                                                     rand_blk, attn_mask, p_smid);
        softmax_split_kernel<<<Bx * NHx * NMID * BSx, 256, (NGx * 64) * sizeof(float)>>>(
            p_smid, p_pmh, p_pml, NGx * 64);
        mid_pv_mma<<<dim3(NMID, NHx, Bx), 256>>>(p_pmh, p_pml, p_vhi, p_vlo, rand_blk, p_ctx);

        // edge blocks
        edge_scores_mma<<<dim3(NBx, NHx, Bx * 2), 256>>>(p_qhi, p_qlo, p_khi, p_klo,
                                                         attn_mask, p_sedge);
        softmax_split_kernel<<<Bx * NHx * 2 * BSx, 256, Sx * sizeof(float)>>>(
            p_sedge, p_peh, p_pel, Sx);
        zero_edge_ctx<<<(Bx * 2 * 64 * Dx + 255) / 256, 256>>>(p_ctx);
        edge_pv_mma<<<dim3(NHx, Bx * 2, 8), 256>>>(p_peh, p_pel, p_vhi, p_vlo, p_ctx);

        // O-projection + LN
        split(p_ctx, p_ahi, p_alo, nHD);
        split(wo, p_whi, p_wlo, nDD);
        bgemm2_kernel<0><<<dim3(Dx / 128, M / 128), 256, SMEM_BYTES>>>(
            p_ahi, p_alo, p_whi, p_wlo, bol, p_res, nullptr, nullptr, M, Dx, Dx);
        add_ln_kernel<<<TOK, 256>>>(p_h, p_res, l1s, l1b);

        // FFN: h -> (GELU, split) -> ff planes -> res
        split(p_h, p_ahi, p_alo, nHD);
        split(w1, p_whi, p_wlo, nDF);
        bgemm2_kernel<3><<<dim3(FFx / 128, M / 128), 256, SMEM_BYTES>>>(
            p_ahi, p_alo, p_whi, p_wlo, b1l, nullptr, p_ffh, p_ffl, M, FFx, Dx);
        split(w2, p_whi, p_wlo, nDF);
        bgemm2_kernel<0><<<dim3(Dx / 128, M / 128), 256, SMEM_BYTES>>>(
            p_ffh, p_ffl, p_whi, p_wlo, b2l, p_res, nullptr, nullptr, M, Dx, FFx);
        add_ln_kernel<<<TOK, 256>>>(p_h, p_res, l2s, l2b);
    }

    pooler_kernel<<<dim3((Dx + 127) / 128, Bx), 128>>>(p_h, pool_w, pool_b, out);
}

// round 8
// speedup vs baseline: 2.6932x; 1.0230x over previous
#include <cuda_runtime.h>
#include <cuda_bf16.h>
#include <cstdint>
#include <math.h>

#define Bx 2
#define Sx 4096
#define Dx 768
#define NHx 12
#define HDx 64
#define BSx 64
#define NBx 64
#define FFx 3072
#define Rx 3
#define NGx 8
#define NMID 62
#define TOK (Bx*Sx)

// ---------------- scratch (static device memory; no allocations) ----------------
__device__ float g_h[(size_t)TOK*Dx];
__device__ float g_res[(size_t)TOK*Dx];
__device__ float g_ctx[(size_t)TOK*Dx];
__device__ float g_smid[(size_t)Bx*NHx*NMID*BSx*NGx*BSx];
__device__ float g_sedge[(size_t)Bx*NHx*2*BSx*Sx];
// bf16 hi/lo planes
__device__ __nv_bfloat16 g_act_hi[(size_t)TOK*Dx];
__device__ __nv_bfloat16 g_act_lo[(size_t)TOK*Dx];
__device__ __nv_bfloat16 g_ff_hi[(size_t)TOK*FFx];
__device__ __nv_bfloat16 g_ff_lo[(size_t)TOK*FFx];
__device__ __nv_bfloat16 g_w_hi[(size_t)Dx*FFx];
__device__ __nv_bfloat16 g_w_lo[(size_t)Dx*FFx];
__device__ __nv_bfloat16 g_qhi[(size_t)TOK*Dx];
__device__ __nv_bfloat16 g_qlo[(size_t)TOK*Dx];
__device__ __nv_bfloat16 g_khi[(size_t)TOK*Dx];
__device__ __nv_bfloat16 g_klo[(size_t)TOK*Dx];
__device__ __nv_bfloat16 g_vhi[(size_t)TOK*Dx];
__device__ __nv_bfloat16 g_vlo[(size_t)TOK*Dx];
__device__ __nv_bfloat16 g_pmid_hi[(size_t)Bx*NHx*NMID*BSx*NGx*BSx];
__device__ __nv_bfloat16 g_pmid_lo[(size_t)Bx*NHx*NMID*BSx*NGx*BSx];
__device__ __nv_bfloat16 g_pedge_hi[(size_t)Bx*NHx*2*BSx*Sx];
__device__ __nv_bfloat16 g_pedge_lo[(size_t)Bx*NHx*2*BSx*Sx];

// ---------------- block reductions ----------------
__device__ __forceinline__ float blk_sum(float v) {
    __shared__ float red[33];
    #pragma unroll
    for (int o = 16; o; o >>= 1) v += __shfl_down_sync(0xffffffffu, v, o);
    int lane = threadIdx.x & 31, w = threadIdx.x >> 5;
    __syncthreads();
    if (lane == 0) red[w] = v;
    __syncthreads();
    if (w == 0) {
        float x = (lane < ((blockDim.x + 31) >> 5)) ? red[lane] : 0.f;
        #pragma unroll
        for (int o = 16; o; o >>= 1) x += __shfl_down_sync(0xffffffffu, x, o);
        if (lane == 0) red[32] = x;
    }
    __syncthreads();
    return red[32];
}

__device__ __forceinline__ float blk_max(float v) {
    __shared__ float redm[33];
    #pragma unroll
    for (int o = 16; o; o >>= 1) v = fmaxf(v, __shfl_down_sync(0xffffffffu, v, o));
    int lane = threadIdx.x & 31, w = threadIdx.x >> 5;
    __syncthreads();
    if (lane == 0) redm[w] = v;
    __syncthreads();
    if (w == 0) {
        float x = (lane < ((blockDim.x + 31) >> 5)) ? redm[lane] : -3.4e38f;
        #pragma unroll
        for (int o = 16; o; o >>= 1) x = fmaxf(x, __shfl_down_sync(0xffffffffu, x, o));
        if (lane == 0) redm[32] = x;
    }
    __syncthreads();
    return redm[32];
}

__device__ __forceinline__ void split_store(float x, __nv_bfloat16* hi, __nv_bfloat16* lo) {
    __nv_bfloat16 h = __float2bfloat16_rn(x);
    *hi = h;
    *lo = __float2bfloat16_rn(x - __bfloat162float(h));
}

// ---------------- fp32 -> (hi, lo) bf16 planes ----------------
__global__ void split_kernel(const float* __restrict__ in,
                             __nv_bfloat16* __restrict__ hi,
                             __nv_bfloat16* __restrict__ lo, int n4) {
    int i = blockIdx.x * blockDim.x + threadIdx.x;
    if (i >= n4) return;
    float4 v = ((const float4*)in)[i];
    __nv_bfloat16 h0 = __float2bfloat16_rn(v.x);
    __nv_bfloat16 h1 = __float2bfloat16_rn(v.y);
    __nv_bfloat16 h2 = __float2bfloat16_rn(v.z);
    __nv_bfloat16 h3 = __float2bfloat16_rn(v.w);
    __nv_bfloat16 l0 = __float2bfloat16_rn(v.x - __bfloat162float(h0));
    __nv_bfloat16 l1 = __float2bfloat16_rn(v.y - __bfloat162float(h1));
    __nv_bfloat16 l2 = __float2bfloat16_rn(v.z - __bfloat162float(h2));
    __nv_bfloat16 l3 = __float2bfloat16_rn(v.w - __bfloat162float(h3));
    ((__nv_bfloat162*)hi)[2*i]   = __halves2bfloat162(h0, h1);
    ((__nv_bfloat162*)hi)[2*i+1] = __halves2bfloat162(h2, h3);
    ((__nv_bfloat162*)lo)[2*i]   = __halves2bfloat162(l0, l1);
    ((__nv_bfloat162*)lo)[2*i+1] = __halves2bfloat162(l2, l3);
}

// ---------------- embeddings + LN (also emits bf16 hi/lo planes) ----------------
__global__ void embed_ln_kernel(const int* __restrict__ ids, const int* __restrict__ tt,
                                const float* __restrict__ wemb, const float* __restrict__ temb,
                                const float* __restrict__ pemb,
                                const float* __restrict__ lns, const float* __restrict__ lnb,
                                __nv_bfloat16* __restrict__ hi, __nv_bfloat16* __restrict__ lo) {
    int tok = blockIdx.x;
    int pos = tok % Sx;
    const float* w = wemb + (size_t)ids[tok] * Dx;
    const float* t = temb + (size_t)tt[tok] * Dx;
    const float* p = pemb + (size_t)pos * Dx;
    __shared__ float buf[Dx];
    float ls = 0.f, lq = 0.f;
    for (int i = threadIdx.x; i < Dx; i += blockDim.x) {
        float x = w[i] + t[i] + p[i];
        buf[i] = x; ls += x; lq += x * x;
    }
    float sum = blk_sum(ls);
    float sq  = blk_sum(lq);
    float mu = sum * (1.f / Dx);
    float var = sq * (1.f / Dx) - mu * mu;
    float inv = rsqrtf(var + 1e-12f);
    for (int i = threadIdx.x; i < Dx; i += blockDim.x) {
        float y = lns[i] * (buf[i] - mu) * inv + lnb[i];
        size_t idx = (size_t)tok * Dx + i;
        g_h[idx] = y;
        split_store(y, hi + idx, lo + idx);
    }
}

// ---------------- residual add + LN (in-place on h; also emits planes) ----------
__global__ void add_ln_kernel(float* __restrict__ h, const float* __restrict__ r,
                              const float* __restrict__ lns, const float* __restrict__ lnb,
                              __nv_bfloat16* __restrict__ hi, __nv_bfloat16* __restrict__ lo) {
    int tok = blockIdx.x;
    __shared__ float buf[Dx];
    float ls = 0.f, lq = 0.f;
    for (int i = threadIdx.x; i < Dx; i += blockDim.x) {
        float x = h[(size_t)tok * Dx + i] + r[(size_t)tok * Dx + i];
        buf[i] = x; ls += x; lq += x * x;
    }
    float sum = blk_sum(ls);
    float sq  = blk_sum(lq);
    float mu = sum * (1.f / Dx);
    float var = sq * (1.f / Dx) - mu * mu;
    float inv = rsqrtf(var + 1e-12f);
    for (int i = threadIdx.x; i < Dx; i += blockDim.x) {
        float y = lns[i] * (buf[i] - mu) * inv + lnb[i];
        size_t idx = (size_t)tok * Dx + i;
        h[idx] = y;
        split_store(y, hi + idx, lo + idx);
    }
}

// ---------------- tensor-core primitives ----------------
__device__ __forceinline__ void ldsm_x4(uint32_t* r, uint32_t addr) {
    asm volatile("ldmatrix.sync.aligned.m8n8.x4.shared.b16 {%0,%1,%2,%3}, [%4];"
                 : "=r"(r[0]), "=r"(r[1]), "=r"(r[2]), "=r"(r[3]) : "r"(addr));
}
__device__ __forceinline__ void ldsm_x4t(uint32_t* r, uint32_t addr) {
    asm volatile("ldmatrix.sync.aligned.m8n8.x4.trans.shared.b16 {%0,%1,%2,%3}, [%4];"
                 : "=r"(r[0]), "=r"(r[1]), "=r"(r[2]), "=r"(r[3]) : "r"(addr));
}
__device__ __forceinline__ void mma_bf16(float* c, const uint32_t* a, uint32_t b0, uint32_t b1) {
    asm volatile("mma.sync.aligned.m16n8k16.row.col.f32.bf16.bf16.f32 "
                 "{%0,%1,%2,%3}, {%4,%5,%6,%7}, {%8,%9}, {%0,%1,%2,%3};"
                 : "+f"(c[0]), "+f"(c[1]), "+f"(c[2]), "+f"(c[3])
                 : "r"(a[0]), "r"(a[1]), "r"(a[2]), "r"(a[3]), "r"(b0), "r"(b1));
}
__device__ __forceinline__ void cp16(void* dst, const void* src) {
    uint32_t d = (uint32_t)__cvta_generic_to_shared(dst);
    asm volatile("cp.async.cg.shared.global [%0], [%1], 16;" :: "r"(d), "l"(src));
}

// ---------------- dense GEMM (bf16 hi/lo planes, double-buffered cp.async) ------
// MODE 0: fp32 out; MODE 2: bf16 hi/lo out; MODE 3: GELU + bf16 hi/lo out.
#define STAGE_ELT 18944
#define OFF_AL 5120
#define OFF_BH 10240
#define OFF_BL 14592
#define SMEM_BYTES (2 * STAGE_ELT * 2)

__device__ __forceinline__ void load_stage(
    __nv_bfloat16* sm, int s, int k0, int tid, int byb, int bxb,
    const __nv_bfloat16* Ahg, const __nv_bfloat16* Alg,
    const __nv_bfloat16* Whg, const __nv_bfloat16* Wlg, int N, int K)
{
    __nv_bfloat16* base = sm + s * STAGE_ELT;
    #pragma unroll
    for (int i = 0; i < 2; i++) {
        int idx = tid + i * 256;
        int rA = idx >> 2, cA = (idx & 3) * 8;
        size_t ga = (size_t)(byb * 128 + rA) * K + k0 + cA;
        cp16(base + rA * 40 + cA, Ahg + ga);
        cp16(base + OFF_AL + rA * 40 + cA, Alg + ga);
        int rB = idx >> 4, cB = (idx & 15) * 8;
        size_t gb = (size_t)(k0 + rB) * N + bxb * 128 + cB;
        cp16(base + OFF_BH + rB * 136 + cB, Whg + gb);
        cp16(base + OFF_BL + rB * 136 + cB, Wlg + gb);
    }
    asm volatile("cp.async.commit_group;");
}

// Core GEMM body shared by all variants.
template<int MODE>
__device__ __forceinline__ void gemm_body(
    const __nv_bfloat16* __restrict__ Ahg, const __nv_bfloat16* __restrict__ Alg,
    const __nv_bfloat16* __restrict__ Whg, const __nv_bfloat16* __restrict__ Wlg,
    const float* __restrict__ bias, float* __restrict__ C,
    __nv_bfloat16* __restrict__ Chi, __nv_bfloat16* __restrict__ Clo,
    int M, int N, int K, int bxb, int byb, __nv_bfloat16* sm)
{
    const int tid = threadIdx.x;
    const int lane = tid & 31;
    const int wid = tid >> 5;
    const int warp_m = wid & 3;
    const int warp_n = wid >> 2;

    float acc[2][8][4];
    #pragma unroll
    for (int mt = 0; mt < 2; mt++) {
        #pragma unroll
        for (int nt = 0; nt < 8; nt++) {
            acc[mt][nt][0] = 0.f; acc[mt][nt][1] = 0.f;
            acc[mt][nt][2] = 0.f; acc[mt][nt][3] = 0.f;
        }
    }

    const int a_tile = lane >> 3;
    const int a_rl = lane & 7;
    const int a_ldrow = warp_m * 32 + (a_tile & 1) * 8 + a_rl;
    const int a_ldcol = (a_tile >> 1) * 8;
    const int b_ldk = (a_tile & 1) * 8 + a_rl;
    const int b_ldn = warp_n * 64 + (a_tile >> 1) * 8;

    const int nk = K >> 5;
    load_stage(sm, 0, 0, tid, byb, bxb, Ahg, Alg, Whg, Wlg, N, K);
    load_stage(sm, 1, 32, tid, byb, bxb, Ahg, Alg, Whg, Wlg, N, K);

    for (int kt = 0; kt < nk; kt++) {
        const int s = kt & 1;
        if (kt == nk - 1) asm volatile("cp.async.wait_group 0;");
        else              asm volatile("cp.async.wait_group 1;");
        __syncthreads();

        __nv_bfloat16* Ahs = sm + s * STAGE_ELT;
        __nv_bfloat16* Als = Ahs + OFF_AL;
        __nv_bfloat16* Bhs = sm + s * STAGE_ELT + OFF_BH;
        __nv_bfloat16* Bls = sm + s * STAGE_ELT + OFF_BL;

        #pragma unroll
        for (int kk = 0; kk < 32; kk += 16) {
            uint32_t ah0[4], ah1[4], al0[4], al1[4];
            ldsm_x4(ah0, (uint32_t)__cvta_generic_to_shared(Ahs + a_ldrow * 40 + a_ldcol + kk));
            ldsm_x4(ah1, (uint32_t)__cvta_generic_to_shared(Ahs + (a_ldrow + 16) * 40 + a_ldcol + kk));
            ldsm_x4(al0, (uint32_t)__cvta_generic_to_shared(Als + a_ldrow * 40 + a_ldcol + kk));
            ldsm_x4(al1, (uint32_t)__cvta_generic_to_shared(Als + (a_ldrow + 16) * 40 + a_ldcol + kk));
            #pragma unroll
            for (int p = 0; p < 4; p++) {
                uint32_t bh4[4], bl4[4];
                ldsm_x4t(bh4, (uint32_t)__cvta_generic_to_shared(Bhs + (kk + b_ldk) * 136 + b_ldn + p * 16));
                ldsm_x4t(bl4, (uint32_t)__cvta_generic_to_shared(Bls + (kk + b_ldk) * 136 + b_ldn + p * 16));
                int nt0 = p * 2;
                int nt1 = p * 2 + 1;
                mma_bf16(acc[0][nt0], ah0, bh4[0], bh4[1]);
                mma_bf16(acc[0][nt0], ah0, bl4[0], bl4[1]);
                mma_bf16(acc[0][nt0], al0, bh4[0], bh4[1]);
                mma_bf16(acc[0][nt1], ah0, bh4[2], bh4[3]);
                mma_bf16(acc[0][nt1], ah0, bl4[2], bl4[3]);
                mma_bf16(acc[0][nt1], al0, bh4[2], bh4[3]);
                mma_bf16(acc[1][nt0], ah1, bh4[0], bh4[1]);
                mma_bf16(acc[1][nt0], ah1, bl4[0], bl4[1]);
                mma_bf16(acc[1][nt0], al1, bh4[0], bh4[1]);
                mma_bf16(acc[1][nt1], ah1, bh4[2], bh4[3]);
                mma_bf16(acc[1][nt1], ah1, bl4[2], bl4[3]);
                mma_bf16(acc[1][nt1], al1, bh4[2], bh4[3]);
            }
        }
        __syncthreads();
        if (kt + 2 < nk)
            load_stage(sm, s, (kt + 2) * 32, tid, byb, bxb, Ahg, Alg, Whg, Wlg, N, K);
    }

    const int grp = lane >> 2;
    const int tig = lane & 3;
    #pragma unroll
    for (int mt = 0; mt < 2; mt++) {
        #pragma unroll
        for (int nt = 0; nt < 8; nt++) {
            int col = bxb * 128 + warp_n * 64 + nt * 8 + tig * 2;
            float b0 = bias[col];
            float b1 = bias[col + 1];
            #pragma unroll
            for (int half = 0; half < 2; half++) {
                int row = byb * 128 + warp_m * 32 + mt * 16 + grp + half * 8;
                float v0 = acc[mt][nt][half * 2 + 0] + b0;
                float v1 = acc[mt][nt][half * 2 + 1] + b1;
                if (MODE == 3) {
                    v0 = 0.5f * v0 * (1.f + erff(v0 * 0.70710678118654752f));
                    v1 = 0.5f * v1 * (1.f + erff(v1 * 0.70710678118654752f));
                }
                if (MODE == 2 || MODE == 3) {
                    __nv_bfloat16 h0 = __float2bfloat16_rn(v0);
                    __nv_bfloat16 h1 = __float2bfloat16_rn(v1);
                    __nv_bfloat16 l0 = __float2bfloat16_rn(v0 - __bfloat162float(h0));
                    __nv_bfloat16 l1 = __float2bfloat16_rn(v1 - __bfloat162float(h1));
                    *(__nv_bfloat162*)&Chi[(size_t)row * N + col] = __halves2bfloat162(h0, h1);
                    *(__nv_bfloat162*)&Clo[(size_t)row * N + col] = __halves2bfloat162(l0, l1);
                } else {
                    C[(size_t)row * N + col] = v0;
                    C[(size_t)row * N + col + 1] = v1;
                }
            }
        }
    }
}

template<int MODE>
__global__ void __launch_bounds__(256, 2) bgemm2_kernel(
    const __nv_bfloat16* __restrict__ Ahg, const __nv_bfloat16* __restrict__ Alg,
    const __nv_bfloat16* __restrict__ Whg, const __nv_bfloat16* __restrict__ Wlg,
    const float* __restrict__ bias, float* __restrict__ C,
    __nv_bfloat16* __restrict__ Chi, __nv_bfloat16* __restrict__ Clo,
    int M, int N, int K)
{
    extern __shared__ __align__(16) __nv_bfloat16 sm[];
    gemm_body<MODE>(Ahg, Alg, Whg, Wlg, bias, C, Chi, Clo, M, N, K,
                    blockIdx.x, blockIdx.y, sm);
}

// Fused QKV: z = 0/1/2 selects weight plane offset, bias, output planes. MODE 2.
__global__ void __launch_bounds__(256, 2) qkv_gemm_kernel(
    const __nv_bfloat16* __restrict__ Ahg, const __nv_bfloat16* __restrict__ Alg,
    const __nv_bfloat16* __restrict__ Whg, const __nv_bfloat16* __restrict__ Wlg,
    const float* __restrict__ bq, const float* __restrict__ bk, const float* __restrict__ bv,
    __nv_bfloat16* __restrict__ qhi, __nv_bfloat16* __restrict__ qlo,
    __nv_bfloat16* __restrict__ khi, __nv_bfloat16* __restrict__ klo,
    __nv_bfloat16* __restrict__ vhi, __nv_bfloat16* __restrict__ vlo)
{
    extern __shared__ __align__(16) __nv_bfloat16 sm[];
    int z = blockIdx.z;
    size_t woff = (size_t)z * Dx * Dx;
    const float* bias = (z == 0) ? bq : (z == 1) ? bk : bv;
    __nv_bfloat16* chi = (z == 0) ? qhi : (z == 1) ? khi : vhi;
    __nv_bfloat16* clo = (z == 0) ? qlo : (z == 1) ? klo : vlo;
    gemm_body<2>(Ahg, Alg, Whg + woff, Wlg + woff, bias, nullptr, chi, clo,
                 TOK, Dx, Dx, blockIdx.x, blockIdx.y, sm);
}

// ---------------- helpers ----------------
__device__ __forceinline__ int mid_block_idx(int n, int g, const int* __restrict__ randb) {
    if (g == 0) return 0;
    if (g == 1) return NBx - 1;
    if (g < 5)  return n - 3 + g;
    return randb[(n - 1) * Rx + (g - 5)];
}

// ---------------- attention: 64x64 score tile (MMA, split-bf16) -----------------
__device__ __forceinline__ void score_tile(
    const __nv_bfloat16 (*Qh)[72], const __nv_bfloat16 (*Ql)[72],
    const __nv_bfloat16 (*Kh)[72], const __nv_bfloat16 (*Kl)[72],
    const int* __restrict__ amask, int mask_base,
    float* __restrict__ out, int ostride, int ocol0,
    int lane, int warp_m, int warp_n)
{
    const int tile = lane >> 3;
    const int rl = lane & 7;
    const int ldrow = (tile & 1) * 8 + rl;
    const int ldcol = (tile >> 1) * 8;

    float acc[4][4];
    #pragma unroll
    for (int j = 0; j < 4; j++) {
        acc[j][0] = 0.f; acc[j][1] = 0.f; acc[j][2] = 0.f; acc[j][3] = 0.f;
    }

    #pragma unroll
    for (int kk = 0; kk < 64; kk += 16) {
        uint32_t ah[4], al[4];
        ldsm_x4(ah, (uint32_t)__cvta_generic_to_shared(&Qh[warp_m * 16 + ldrow][ldcol + kk]));
        ldsm_x4(al, (uint32_t)__cvta_generic_to_shared(&Ql[warp_m * 16 + ldrow][ldcol + kk]));
        #pragma unroll
        for (int j2 = 0; j2 < 2; j2++) {
            int n0 = warp_n * 32 + j2 * 16;
            uint32_t bh[4], bl[4];
            ldsm_x4(bh, (uint32_t)__cvta_generic_to_shared(&Kh[n0 + ldrow][ldcol + kk]));
            ldsm_x4(bl, (uint32_t)__cvta_generic_to_shared(&Kl[n0 + ldrow][ldcol + kk]));
            mma_bf16(acc[j2 * 2 + 0], ah, bh[0], bh[2]);
            mma_bf16(acc[j2 * 2 + 0], ah, bl[0], bl[2]);
            mma_bf16(acc[j2 * 2 + 0], al, bh[0], bh[2]);
            mma_bf16(acc[j2 * 2 + 1], ah, bh[1], bh[3]);
            mma_bf16(acc[j2 * 2 + 1], ah, bl[1], bl[3]);
            mma_bf16(acc[j2 * 2 + 1], al, bh[1], bh[3]);
        }
    }

    int r0 = warp_m * 16 + (lane >> 2);
    #pragma unroll
    for (int j = 0; j < 4; j++) {
        int ki = warp_n * 32 + j * 8 + (lane & 3) * 2;
        float m0 = (1.0f - (float)amask[mask_base + ki]) * -1e9f;
        float m1 = (1.0f - (float)amask[mask_base + ki + 1]) * -1e9f;
        out[(size_t)r0 * ostride + ocol0 + ki]           = acc[j][0] * 0.125f + m0;
        out[(size_t)r0 * ostride + ocol0 + ki + 1]       = acc[j][1] * 0.125f + m1;
        out[(size_t)(r0 + 8) * ostride + ocol0 + ki]     = acc[j][2] * 0.125f + m0;
        out[(size_t)(r0 + 8) * ostride + ocol0 + ki + 1] = acc[j][3] * 0.125f + m1;
    }
}

__device__ __forceinline__ void pv_tile(
    const __nv_bfloat16 (*Ph)[72], const __nv_bfloat16 (*Pl)[72],
    const __nv_bfloat16 (*Vh)[72], const __nv_bfloat16 (*Vl)[72],
    float acc[4][4], int lane, int warp_m, int warp_n)
{
    const int tile = lane >> 3;
    const int rl = lane & 7;
    const int ldrow = (tile & 1) * 8 + rl;
    const int ldcol = (tile >> 1) * 8;
    const int b_ldk = (tile & 1) * 8 + rl;
    const int b_ldn = (tile >> 1) * 8;

    #pragma unroll
    for (int kk = 0; kk < 64; kk += 16) {
        uint32_t ah[4], al[4];
        ldsm_x4(ah, (uint32_t)__cvta_generic_to_shared(&Ph[warp_m * 16 + ldrow][ldcol + kk]));
        ldsm_x4(al, (uint32_t)__cvta_generic_to_shared(&Pl[warp_m * 16 + ldrow][ldcol + kk]));
        #pragma unroll
        for (int j2 = 0; j2 < 2; j2++) {
            int n0 = warp_n * 32 + j2 * 16;
            uint32_t bh4[4], bl4[4];
            ldsm_x4t(bh4, (uint32_t)__cvta_generic_to_shared(&Vh[kk + b_ldk][n0 + b_ldn]));
            ldsm_x4t(bl4, (uint32_t)__cvta_generic_to_shared(&Vl[kk + b_ldk][n0 + b_ldn]));
            mma_bf16(acc[j2 * 2 + 0], ah, bh4[0], bh4[1]);
            mma_bf16(acc[j2 * 2 + 0], ah, bl4[0], bl4[1]);
            mma_bf16(acc[j2 * 2 + 0], al, bh4[0], bh4[1]);
            mma_bf16(acc[j2 * 2 + 1], ah, bh4[2], bh4[3]);
            mma_bf16(acc[j2 * 2 + 1], ah, bl4[2], bl4[3]);
            mma_bf16(acc[j2 * 2 + 1], al, bh4[2], bh4[3]);
        }
    }
}

__device__ __forceinline__ void load_tile64(
    __nv_bfloat16 (*dst)[72], const __nv_bfloat16* __restrict__ src, int gstride, int tid)
{
    #pragma unroll
    for (int i = 0; i < 2; i++) {
        int idx = tid + i * 256;
        int r = idx >> 3, c = (idx & 7) * 8;
        *(uint4*)&dst[r][c] = *(const uint4*)(src + (size_t)r * gstride + c);
    }
}

// ---------------- middle-block scores ----------------
__global__ void __launch_bounds__(256) mid_scores_mma(
    const __nv_bfloat16* __restrict__ qhi, const __nv_bfloat16* __restrict__ qlo,
    const __nv_bfloat16* __restrict__ khi, const __nv_bfloat16* __restrict__ klo,
    const int* __restrict__ randb, const int* __restrict__ amask,
    float* __restrict__ smid)
{
    int n = blockIdx.x + 1, h = blockIdx.y, b = blockIdx.z;
    __shared__ __nv_bfloat16 Qh[64][72], Ql[64][72], Kh[64][72], Kl[64][72];
    int tid = threadIdx.x, lane = tid & 31, wid = tid >> 5;
    int warp_m = wid & 3, warp_n = wid >> 2;

    size_t qoff = ((size_t)b * Sx + n * 64) * Dx + h * 64;
    load_tile64(Qh, qhi + qoff, Dx, tid);
    load_tile64(Ql, qlo + qoff, Dx, tid);

    float* out = smid + (((size_t)(b * NHx + h) * NMID + (n - 1)) << 15);

    for (int g = 0; g < NGx; g++) {
        int kb = mid_block_idx(n, g, randb);
        size_t koff = ((size_t)b * Sx + kb * 64) * Dx + h * 64;
        __syncthreads();
        load_tile64(Kh, khi + koff, Dx, tid);
        load_tile64(Kl, klo + koff, Dx, tid);
        __syncthreads();
        score_tile(Qh, Ql, Kh, Kl, amask, b * Sx + kb * 64,
                   out, NGx * 64, g * 64, lane, warp_m, warp_n);
    }
}

// ---------------- middle-block PV ----------------
__global__ void __launch_bounds__(256) mid_pv_mma(
    const __nv_bfloat16* __restrict__ phi, const __nv_bfloat16* __restrict__ plo,
    const __nv_bfloat16* __restrict__ vhi, const __nv_bfloat16* __restrict__ vlo,
    const int* __restrict__ randb, float* __restrict__ ctx)
{
    int n = blockIdx.x + 1, h = blockIdx.y, b = blockIdx.z;
    __shared__ __nv_bfloat16 Ph[64][72], Pl[64][72], Vh[64][72], Vl[64][72];
    int tid = threadIdx.x, lane = tid & 31, wid = tid >> 5;
    int warp_m = wid & 3, warp_n = wid >> 2;

    const __nv_bfloat16* prow_h = phi + (((size_t)(b * NHx + h) * NMID + (n - 1)) << 15);
    const __nv_bfloat16* prow_l = plo + (((size_t)(b * NHx + h) * NMID + (n - 1)) << 15);

    float acc[4][4];
    #pragma unroll
    for (int j = 0; j < 4; j++) {
        acc[j][0] = 0.f; acc[j][1] = 0.f; acc[j][2] = 0.f; acc[j][3] = 0.f;
    }

    for (int g = 0; g < NGx; g++) {
        int kb = mid_block_idx(n, g, randb);
        size_t voff = ((size_t)b * Sx + kb * 64) * Dx + h * 64;
        __syncthreads();
        load_tile64(Ph, prow_h + g * 64, NGx * 64, tid);
        load_tile64(Pl, prow_l + g * 64, NGx * 64, tid);
        load_tile64(Vh, vhi + voff, Dx, tid);
        load_tile64(Vl, vlo + voff, Dx, tid);
        __syncthreads();
        pv_tile(Ph, Pl, Vh, Vl, acc, lane, warp_m, warp_n);
    }

    float* cbase = ctx + ((size_t)b * Sx + n * 64) * Dx + h * 64;
    int r0 = warp_m * 16 + (lane >> 2);
    #pragma unroll
    for (int j = 0; j < 4; j++) {
        int col = warp_n * 32 + j * 8 + (lane & 3) * 2;
        cbase[(size_t)r0 * Dx + col]           = acc[j][0];
        cbase[(size_t)r0 * Dx + col + 1]       = acc[j][1];
        cbase[(size_t)(r0 + 8) * Dx + col]     = acc[j][2];
        cbase[(size_t)(r0 + 8) * Dx + col + 1] = acc[j][3];
    }
}

// ---------------- edge scores ----------------
__global__ void __launch_bounds__(256) edge_scores_mma(
    const __nv_bfloat16* __restrict__ qhi, const __nv_bfloat16* __restrict__ qlo,
    const __nv_bfloat16* __restrict__ khi, const __nv_bfloat16* __restrict__ klo,
    const int* __restrict__ amask, float* __restrict__ sedge)
{
    int kb = blockIdx.x, h = blockIdx.y;
    int e = blockIdx.z & 1, b = blockIdx.z >> 1;
    int qb = e ? (NBx - 1) : 0;
    __shared__ __nv_bfloat16 Qh[64][72], Ql[64][72], Kh[64][72], Kl[64][72];
    int tid = threadIdx.x, lane = tid & 31, wid = tid >> 5;
    int warp_m = wid & 3, warp_n = wid >> 2;

    size_t qoff = ((size_t)b * Sx + qb * 64) * Dx + h * 64;
    size_t koff = ((size_t)b * Sx + kb * 64) * Dx + h * 64;
    load_tile64(Qh, qhi + qoff, Dx, tid);
    load_tile64(Ql, qlo + qoff, Dx, tid);
    load_tile64(Kh, khi + koff, Dx, tid);
    load_tile64(Kl, klo + koff, Dx, tid);
    __syncthreads();

    float* out = sedge + ((size_t)((b * NHx + h) * 2 + e)) * (64 * Sx);
    score_tile(Qh, Ql, Kh, Kl, amask, b * Sx + kb * 64,
               out, Sx, kb * 64, lane, warp_m, warp_n);
}

// ---------------- edge PV (chunked, atomic accumulate) ----------------
__global__ void __launch_bounds__(256) edge_pv_mma(
    const __nv_bfloat16* __restrict__ phi, const __nv_bfloat16* __restrict__ plo,
    const __nv_bfloat16* __restrict__ vhi, const __nv_bfloat16* __restrict__ vlo,
    float* __restrict__ ctx)
{
    int h = blockIdx.x;
    int e = blockIdx.y & 1, b = blockIdx.y >> 1;
    int chunk = blockIdx.z;
    int qb = e ? (NBx - 1) : 0;
    __shared__ __nv_bfloat16 Ph[64][72], Pl[64][72], Vh[64][72], Vl[64][72];
    int tid = threadIdx.x, lane = tid & 31, wid = tid >> 5;
    int warp_m = wid & 3, warp_n = wid >> 2;

    const __nv_bfloat16* prow_h = phi + ((size_t)((b * NHx + h) * 2 + e)) * (64 * Sx);
    const __nv_bfloat16* prow_l = plo + ((size_t)((b * NHx + h) * 2 + e)) * (64 * Sx);

    float acc[4][4];
    #pragma unroll
    for (int j = 0; j < 4; j++) {
        acc[j][0] = 0.f; acc[j][1] = 0.f; acc[j][2] = 0.f; acc[j][3] = 0.f;
    }

    for (int c8 = 0; c8 < 8; c8++) {
        int kb = chunk * 8 + c8;
        size_t voff = ((size_t)b * Sx + kb * 64) * Dx + h * 64;
        __syncthreads();
        load_tile64(Ph, prow_h + kb * 64, Sx, tid);
        load_tile64(Pl, prow_l + kb * 64, Sx, tid);
        load_tile64(Vh, vhi + voff, Dx, tid);
        load_tile64(Vl, vlo + voff, Dx, tid);
        __syncthreads();
        pv_tile(Ph, Pl, Vh, Vl, acc, lane, warp_m, warp_n);
    }

    float* cbase = ctx + ((size_t)b * Sx + qb * 64) * Dx + h * 64;
    int r0 = warp_m * 16 + (lane >> 2);
    #pragma unroll
    for (int j = 0; j < 4; j++) {
        int col = warp_n * 32 + j * 8 + (lane & 3) * 2;
        atomicAdd(&cbase[(size_t)r0 * Dx + col],           acc[j][0]);
        atomicAdd(&cbase[(size_t)r0 * Dx + col + 1],       acc[j][1]);
        atomicAdd(&cbase[(size_t)(r0 + 8) * Dx + col],     acc[j][2]);
        atomicAdd(&cbase[(size_t)(r0 + 8) * Dx + col + 1], acc[j][3]);
    }
}

// ---------------- zero edge ctx rows ----------------
__global__ void zero_edge_ctx(float* __restrict__ ctx) {
    int i = blockIdx.x * 256 + threadIdx.x;
    if (i >= Bx * 2 * 64 * Dx) return;
    int col = i % Dx;
    int t = i / Dx;
    int row = t % 64;  t /= 64;
    int e = t & 1;
    int b = t >> 1;
    int blk = e ? (NBx - 1) : 0;
    ctx[((size_t)b * Sx + blk * 64 + row) * Dx + col] = 0.f;
}

// ---------------- row softmax -> bf16 hi/lo planes ----------------
__global__ void softmax_split_kernel(const float* __restrict__ s,
                                     __nv_bfloat16* __restrict__ phi,
                                     __nv_bfloat16* __restrict__ plo, int L) {
    extern __shared__ float buf[];
    size_t base = (size_t)blockIdx.x * L;
    float m = -3.4e38f;
    for (int i = threadIdx.x; i < L; i += blockDim.x) {
        float x = s[base + i];
        buf[i] = x;
        m = fmaxf(m, x);
    }
    m = blk_max(m);
    float lsum = 0.f;
    for (int i = threadIdx.x; i < L; i += blockDim.x) {
        float e = expf(buf[i] - m);
        buf[i] = e;
        lsum += e;
    }
    float sum = blk_sum(lsum);
    float inv = 1.f / sum;
    for (int i = threadIdx.x; i < L; i += blockDim.x) {
        float p = buf[i] * inv;
        __nv_bfloat16 hi = __float2bfloat16_rn(p);
        __nv_bfloat16 lo = __float2bfloat16_rn(p - __bfloat162float(hi));
        phi[base + i] = hi;
        plo[base + i] = lo;
    }
}

// ---------------- pooler ----------------
__global__ void pooler_kernel(const float* __restrict__ h, const float* __restrict__ pw,
                              const float* __restrict__ pb, float* __restrict__ out) {
    int j = blockIdx.x * blockDim.x + threadIdx.x;
    int b = blockIdx.y;
    if (j >= Dx) return;
    const float* hr = h + (size_t)b * Sx * Dx;
    float acc = pb[j];
    for (int kI = 0; kI < Dx; kI++) acc += hr[kI] * pw[(size_t)kI * Dx + j];
    out[b * Dx + j] = tanhf(acc);
}

// ---------------- host launcher ----------------
extern "C" void kernel_launch(void* const* d_in, const int* in_sizes, int n_in,
                              void* d_out, int out_size) {
    const int*   input_ids = (const int*)d_in[0];
    const int*   attn_mask = (const int*)d_in[1];
    const int*   tok_type  = (const int*)d_in[2];
    const int*   rand_blk  = (const int*)d_in[3];
    const float* word_emb  = (const float*)d_in[4];
    const float* type_emb  = (const float*)d_in[5];
    const float* pos_emb   = (const float*)d_in[6];
    const float* emb_ln_s  = (const float*)d_in[7];
    const float* emb_ln_b  = (const float*)d_in[8];
    const float* Wq = (const float*)d_in[9];  const float* bq = (const float*)d_in[10];
    const float* Wk = (const float*)d_in[11]; const float* bk = (const float*)d_in[12];
    const float* Wv = (const float*)d_in[13]; const float* bv = (const float*)d_in[14];
    const float* Wo = (const float*)d_in[15]; const float* bo = (const float*)d_in[16];
    const float* ln1_s = (const float*)d_in[17]; const float* ln1_b = (const float*)d_in[18];
    const float* W1 = (const float*)d_in[19]; const float* b1 = (const float*)d_in[20];
    const float* W2 = (const float*)d_in[21]; const float* b2 = (const float*)d_in[22];
    const float* ln2_s = (const float*)d_in[23]; const float* ln2_b = (const float*)d_in[24];
    const float* pool_w = (const float*)d_in[25]; const float* pool_b = (const float*)d_in[26];
    float* out = (float*)d_out;

    float *p_h = 0, *p_res = 0, *p_ctx = 0, *p_smid = 0, *p_sedge = 0;
    __nv_bfloat16 *p_ahi = 0, *p_alo = 0, *p_ffh = 0, *p_ffl = 0, *p_whi = 0, *p_wlo = 0;
    __nv_bfloat16 *p_qhi = 0, *p_qlo = 0, *p_khi = 0, *p_klo = 0, *p_vhi = 0, *p_vlo = 0;
    __nv_bfloat16 *p_pmh = 0, *p_pml = 0, *p_peh = 0, *p_pel = 0;
    cudaGetSymbolAddress((void**)&p_h,     g_h);
    cudaGetSymbolAddress((void**)&p_res,   g_res);
    cudaGetSymbolAddress((void**)&p_ctx,   g_ctx);
    cudaGetSymbolAddress((void**)&p_smid,  g_smid);
    cudaGetSymbolAddress((void**)&p_sedge, g_sedge);
    cudaGetSymbolAddress((void**)&p_ahi,   g_act_hi);
    cudaGetSymbolAddress((void**)&p_alo,   g_act_lo);
    cudaGetSymbolAddress((void**)&p_ffh,   g_ff_hi);
    cudaGetSymbolAddress((void**)&p_ffl,   g_ff_lo);
    cudaGetSymbolAddress((void**)&p_whi,   g_w_hi);
    cudaGetSymbolAddress((void**)&p_wlo,   g_w_lo);
    cudaGetSymbolAddress((void**)&p_qhi,   g_qhi);
    cudaGetSymbolAddress((void**)&p_qlo,   g_qlo);
    cudaGetSymbolAddress((void**)&p_khi,   g_khi);
    cudaGetSymbolAddress((void**)&p_klo,   g_klo);
    cudaGetSymbolAddress((void**)&p_vhi,   g_vhi);
    cudaGetSymbolAddress((void**)&p_vlo,   g_vlo);
    cudaGetSymbolAddress((void**)&p_pmh,   g_pmid_hi);
    cudaGetSymbolAddress((void**)&p_pml,   g_pmid_lo);
    cudaGetSymbolAddress((void**)&p_peh,   g_pedge_hi);
    cudaGetSymbolAddress((void**)&p_pel,   g_pedge_lo);

    static bool attr_done = false;
    if (!attr_done) {
        cudaFuncSetAttribute(bgemm2_kernel<0>, cudaFuncAttributeMaxDynamicSharedMemorySize, SMEM_BYTES);
        cudaFuncSetAttribute(bgemm2_kernel<2>, cudaFuncAttributeMaxDynamicSharedMemorySize, SMEM_BYTES);
        cudaFuncSetAttribute(bgemm2_kernel<3>, cudaFuncAttributeMaxDynamicSharedMemorySize, SMEM_BYTES);
        cudaFuncSetAttribute(qkv_gemm_kernel, cudaFuncAttributeMaxDynamicSharedMemorySize, SMEM_BYTES);
        attr_done = true;
    }

    const int M = TOK;
    const int nDD = Dx * Dx;
    const int nDF = Dx * FFx;
    const int nHD = TOK * Dx;

    auto split = [&](const float* src, __nv_bfloat16* hi, __nv_bfloat16* lo, int n) {
        split_kernel<<<(n / 4 + 255) / 256, 256>>>(src, hi, lo, n / 4);
    };

    embed_ln_kernel<<<TOK, 256>>>(input_ids, tok_type, word_emb, type_emb, pos_emb,
                                  emb_ln_s, emb_ln_b, p_ahi, p_alo);

    for (int l = 0; l < 2; l++) {
        const float* wq = Wq + (size_t)l * nDD;  const float* bql = bq + (size_t)l * Dx;
        const float* wk = Wk + (size_t)l * nDD;  const float* bkl = bk + (size_t)l * Dx;
        const float* wv = Wv + (size_t)l * nDD;  const float* bvl = bv + (size_t)l * Dx;
        const float* wo = Wo + (size_t)l * nDD;  const float* bol = bo + (size_t)l * Dx;
        const float* w1 = W1 + (size_t)l * nDF;  const float* b1l = b1 + (size_t)l * FFx;
        const float* w2 = W2 + (size_t)l * nDF;  const float* b2l = b2 + (size_t)l * Dx;
        const float* l1s = ln1_s + (size_t)l * Dx; const float* l1b = ln1_b + (size_t)l * Dx;
        const float* l2s = ln2_s + (size_t)l * Dx; const float* l2b = ln2_b + (size_t)l * Dx;

        // QKV: fused single launch (act planes already current)
        split(wq, p_whi,           p_wlo,           nDD);
        split(wk, p_whi + nDD,     p_wlo + nDD,     nDD);
        split(wv, p_whi + 2 * nDD, p_wlo + 2 * nDD, nDD);
        qkv_gemm_kernel<<<dim3(Dx / 128, M / 128, 3), 256, SMEM_BYTES>>>(
            p_ahi, p_alo, p_whi, p_wlo, bql, bkl, bvl,
            p_qhi, p_qlo, p_khi, p_klo, p_vhi, p_vlo);

        // middle blocks
        mid_scores_mma<<<dim3(NMID, NHx, Bx), 256>>>(p_qhi, p_qlo, p_khi, p_klo,
                                                     rand_blk, attn_mask, p_smid);
        softmax_split_kernel<<<Bx * NHx * NMID * BSx, 256, (NGx * 64) * sizeof(float)>>>(
            p_smid, p_pmh, p_pml, NGx * 64);
        mid_pv_mma<<<dim3(NMID, NHx, Bx), 256>>>(p_pmh, p_pml, p_vhi, p_vlo, rand_blk, p_ctx);

        // edge blocks
        edge_scores_mma<<<dim3(NBx, NHx, Bx * 2), 256>>>(p_qhi, p_qlo, p_khi, p_klo,
                                                         attn_mask, p_sedge);
        softmax_split_kernel<<<Bx * NHx * 2 * BSx, 256, Sx * sizeof(float)>>>(
            p_sedge, p_peh, p_pel, Sx);
        zero_edge_ctx<<<(Bx * 2 * 64 * Dx + 255) / 256, 256>>>(p_ctx);
        edge_pv_mma<<<dim3(NHx, Bx * 2, 8), 256>>>(p_peh, p_pel, p_vhi, p_vlo, p_ctx);

        // O-projection + LN (LN emits act planes for FFN1)
        split(p_ctx, p_ahi, p_alo, nHD);
        split(wo, p_whi, p_wlo, nDD);
        bgemm2_kernel<0><<<dim3(Dx / 128, M / 128), 256, SMEM_BYTES>>>(
            p_ahi, p_alo, p_whi, p_wlo, bol, p_res, nullptr, nullptr, M, Dx, Dx);
        add_ln_kernel<<<TOK, 256>>>(p_h, p_res, l1s, l1b, p_ahi, p_alo);

        // FFN: act planes -> (GELU, split) -> ff planes -> res; LN emits next act planes
        split(w1, p_whi, p_wlo, nDF);
        bgemm2_kernel<3><<<dim3(FFx / 128, M / 128), 256, SMEM_BYTES>>>(
            p_ahi, p_alo, p_whi, p_wlo, b1l, nullptr, p_ffh, p_ffl, M, FFx, Dx);
        split(w2, p_whi, p_wlo, nDF);
        bgemm2_kernel<0><<<dim3(Dx / 128, M / 128), 256, SMEM_BYTES>>>(
            p_ffh, p_ffl, p_whi, p_wlo, b2l, p_res, nullptr, nullptr, M, Dx, FFx);
        add_ln_kernel<<<TOK, 256>>>(p_h, p_res, l2s, l2b, p_ahi, p_alo);
    }

    pooler_kernel<<<dim3((Dx + 127) / 128, Bx), 128>>>(p_h, pool_w, pool_b, out);
}

// round 10
// speedup vs baseline: 2.8878x; 1.0722x over previous
#include <cuda_runtime.h>
#include <cuda_bf16.h>
#include <cstdint>
#include <math.h>

#define Bx 2
#define Sx 4096
#define Dx 768
#define NHx 12
#define HDx 64
#define BSx 64
#define NBx 64
#define FFx 3072
#define Rx 3
#define NGx 8
#define NMID 62
#define TOK (Bx*Sx)

// ---------------- scratch ----------------
__device__ float g_h[(size_t)TOK*Dx];
__device__ float g_res[(size_t)TOK*Dx];
__device__ float g_ctx[(size_t)TOK*Dx];
__device__ float g_sedge[(size_t)Bx*NHx*2*BSx*Sx];
__device__ __nv_bfloat16 g_act_hi[(size_t)TOK*Dx];
__device__ __nv_bfloat16 g_act_lo[(size_t)TOK*Dx];
__device__ __nv_bfloat16 g_ff_hi[(size_t)TOK*FFx];
__device__ __nv_bfloat16 g_ff_lo[(size_t)TOK*FFx];
__device__ __nv_bfloat16 g_w_hi[(size_t)Dx*FFx];
__device__ __nv_bfloat16 g_w_lo[(size_t)Dx*FFx];
__device__ __nv_bfloat16 g_qhi[(size_t)TOK*Dx];
__device__ __nv_bfloat16 g_qlo[(size_t)TOK*Dx];
__device__ __nv_bfloat16 g_khi[(size_t)TOK*Dx];
__device__ __nv_bfloat16 g_klo[(size_t)TOK*Dx];
__device__ __nv_bfloat16 g_vhi[(size_t)TOK*Dx];
__device__ __nv_bfloat16 g_vlo[(size_t)TOK*Dx];
__device__ __nv_bfloat16 g_pedge_hi[(size_t)Bx*NHx*2*BSx*Sx];
__device__ __nv_bfloat16 g_pedge_lo[(size_t)Bx*NHx*2*BSx*Sx];

// ---------------- block reductions ----------------
__device__ __forceinline__ float blk_sum(float v) {
    __shared__ float red[33];
    #pragma unroll
    for (int o = 16; o; o >>= 1) v += __shfl_down_sync(0xffffffffu, v, o);
    int lane = threadIdx.x & 31, w = threadIdx.x >> 5;
    __syncthreads();
    if (lane == 0) red[w] = v;
    __syncthreads();
    if (w == 0) {
        float x = (lane < ((blockDim.x + 31) >> 5)) ? red[lane] : 0.f;
        #pragma unroll
        for (int o = 16; o; o >>= 1) x += __shfl_down_sync(0xffffffffu, x, o);
        if (lane == 0) red[32] = x;
    }
    __syncthreads();
    return red[32];
}

__device__ __forceinline__ float blk_max(float v) {
    __shared__ float redm[33];
    #pragma unroll
    for (int o = 16; o; o >>= 1) v = fmaxf(v, __shfl_down_sync(0xffffffffu, v, o));
    int lane = threadIdx.x & 31, w = threadIdx.x >> 5;
    __syncthreads();
    if (lane == 0) redm[w] = v;
    __syncthreads();
    if (w == 0) {
        float x = (lane < ((blockDim.x + 31) >> 5)) ? redm[lane] : -3.4e38f;
        #pragma unroll
        for (int o = 16; o; o >>= 1) x = fmaxf(x, __shfl_down_sync(0xffffffffu, x, o));
        if (lane == 0) redm[32] = x;
    }
    __syncthreads();
    return redm[32];
}

__device__ __forceinline__ void split_store(float x, __nv_bfloat16* hi, __nv_bfloat16* lo) {
    __nv_bfloat16 h = __float2bfloat16_rn(x);
    *hi = h;
    *lo = __float2bfloat16_rn(x - __bfloat162float(h));
}
__device__ __forceinline__ void pack2(float x, float y, uint32_t& hi, uint32_t& lo) {
    __nv_bfloat16 h0 = __float2bfloat16_rn(x);
    __nv_bfloat16 h1 = __float2bfloat16_rn(y);
    __nv_bfloat16 l0 = __float2bfloat16_rn(x - __bfloat162float(h0));
    __nv_bfloat16 l1 = __float2bfloat16_rn(y - __bfloat162float(h1));
    __nv_bfloat162 hh = __halves2bfloat162(h0, h1);
    __nv_bfloat162 ll = __halves2bfloat162(l0, l1);
    hi = *(uint32_t*)&hh;
    lo = *(uint32_t*)&ll;
}

// ---------------- fp32 -> (hi, lo) bf16 planes ----------------
__global__ void split_kernel(const float* __restrict__ in,
                             __nv_bfloat16* __restrict__ hi,
                             __nv_bfloat16* __restrict__ lo, int n4) {
    int i = blockIdx.x * blockDim.x + threadIdx.x;
    if (i >= n4) return;
    float4 v = ((const float4*)in)[i];
    __nv_bfloat16 h0 = __float2bfloat16_rn(v.x);
    __nv_bfloat16 h1 = __float2bfloat16_rn(v.y);
    __nv_bfloat16 h2 = __float2bfloat16_rn(v.z);
    __nv_bfloat16 h3 = __float2bfloat16_rn(v.w);
    __nv_bfloat16 l0 = __float2bfloat16_rn(v.x - __bfloat162float(h0));
    __nv_bfloat16 l1 = __float2bfloat16_rn(v.y - __bfloat162float(h1));
    __nv_bfloat16 l2 = __float2bfloat16_rn(v.z - __bfloat162float(h2));
    __nv_bfloat16 l3 = __float2bfloat16_rn(v.w - __bfloat162float(h3));
    ((__nv_bfloat162*)hi)[2*i]   = __halves2bfloat162(h0, h1);
    ((__nv_bfloat162*)hi)[2*i+1] = __halves2bfloat162(h2, h3);
    ((__nv_bfloat162*)lo)[2*i]   = __halves2bfloat162(l0, l1);
    ((__nv_bfloat162*)lo)[2*i+1] = __halves2bfloat162(l2, l3);
}

// ---------------- embeddings + LN (emits planes) ----------------
__global__ void embed_ln_kernel(const int* __restrict__ ids, const int* __restrict__ tt,
                                const float* __restrict__ wemb, const float* __restrict__ temb,
                                const float* __restrict__ pemb,
                                const float* __restrict__ lns, const float* __restrict__ lnb,
                                __nv_bfloat16* __restrict__ hi, __nv_bfloat16* __restrict__ lo) {
    int tok = blockIdx.x;
    int pos = tok % Sx;
    const float* w = wemb + (size_t)ids[tok] * Dx;
    const float* t = temb + (size_t)tt[tok] * Dx;
    const float* p = pemb + (size_t)pos * Dx;
    __shared__ float buf[Dx];
    float ls = 0.f, lq = 0.f;
    for (int i = threadIdx.x; i < Dx; i += blockDim.x) {
        float x = w[i] + t[i] + p[i];
        buf[i] = x; ls += x; lq += x * x;
    }
    float sum = blk_sum(ls);
    float sq  = blk_sum(lq);
    float mu = sum * (1.f / Dx);
    float var = sq * (1.f / Dx) - mu * mu;
    float inv = rsqrtf(var + 1e-12f);
    for (int i = threadIdx.x; i < Dx; i += blockDim.x) {
        float y = lns[i] * (buf[i] - mu) * inv + lnb[i];
        size_t idx = (size_t)tok * Dx + i;
        g_h[idx] = y;
        split_store(y, hi + idx, lo + idx);
    }
}

// ---------------- residual add + LN (emits planes) ----------
__global__ void add_ln_kernel(float* __restrict__ h, const float* __restrict__ r,
                              const float* __restrict__ lns, const float* __restrict__ lnb,
                              __nv_bfloat16* __restrict__ hi, __nv_bfloat16* __restrict__ lo) {
    int tok = blockIdx.x;
    __shared__ float buf[Dx];
    float ls = 0.f, lq = 0.f;
    for (int i = threadIdx.x; i < Dx; i += blockDim.x) {
        float x = h[(size_t)tok * Dx + i] + r[(size_t)tok * Dx + i];
        buf[i] = x; ls += x; lq += x * x;
    }
    float sum = blk_sum(ls);
    float sq  = blk_sum(lq);
    float mu = sum * (1.f / Dx);
    float var = sq * (1.f / Dx) - mu * mu;
    float inv = rsqrtf(var + 1e-12f);
    for (int i = threadIdx.x; i < Dx; i += blockDim.x) {
        float y = lns[i] * (buf[i] - mu) * inv + lnb[i];
        size_t idx = (size_t)tok * Dx + i;
        h[idx] = y;
        split_store(y, hi + idx, lo + idx);
    }
}

// ---------------- tensor-core primitives ----------------
__device__ __forceinline__ void ldsm_x4(uint32_t* r, uint32_t addr) {
    asm volatile("ldmatrix.sync.aligned.m8n8.x4.shared.b16 {%0,%1,%2,%3}, [%4];"
                 : "=r"(r[0]), "=r"(r[1]), "=r"(r[2]), "=r"(r[3]) : "r"(addr));
}
__device__ __forceinline__ void ldsm_x4t(uint32_t* r, uint32_t addr) {
    asm volatile("ldmatrix.sync.aligned.m8n8.x4.trans.shared.b16 {%0,%1,%2,%3}, [%4];"
                 : "=r"(r[0]), "=r"(r[1]), "=r"(r[2]), "=r"(r[3]) : "r"(addr));
}
__device__ __forceinline__ void mma_bf16(float* c, const uint32_t* a, uint32_t b0, uint32_t b1) {
    asm volatile("mma.sync.aligned.m16n8k16.row.col.f32.bf16.bf16.f32 "
                 "{%0,%1,%2,%3}, {%4,%5,%6,%7}, {%8,%9}, {%0,%1,%2,%3};"
                 : "+f"(c[0]), "+f"(c[1]), "+f"(c[2]), "+f"(c[3])
                 : "r"(a[0]), "r"(a[1]), "r"(a[2]), "r"(a[3]), "r"(b0), "r"(b1));
}
__device__ __forceinline__ void cp16(void* dst, const void* src) {
    uint32_t d = (uint32_t)__cvta_generic_to_shared(dst);
    asm volatile("cp.async.cg.shared.global [%0], [%1], 16;" :: "r"(d), "l"(src));
}

// ---------------- dense GEMM (bf16 hi/lo planes, double-buffered cp.async) ------
#define STAGE_ELT 18944
#define OFF_AL 5120
#define OFF_BH 10240
#define OFF_BL 14592
#define SMEM_BYTES (2 * STAGE_ELT * 2)

__device__ __forceinline__ void load_stage(
    __nv_bfloat16* sm, int s, int k0, int tid, int byb, int bxb,
    const __nv_bfloat16* Ahg, const __nv_bfloat16* Alg,
    const __nv_bfloat16* Whg, const __nv_bfloat16* Wlg, int N, int K)
{
    __nv_bfloat16* base = sm + s * STAGE_ELT;
    #pragma unroll
    for (int i = 0; i < 2; i++) {
        int idx = tid + i * 256;
        int rA = idx >> 2, cA = (idx & 3) * 8;
        size_t ga = (size_t)(byb * 128 + rA) * K + k0 + cA;
        cp16(base + rA * 40 + cA, Ahg + ga);
        cp16(base + OFF_AL + rA * 40 + cA, Alg + ga);
        int rB = idx >> 4, cB = (idx & 15) * 8;
        size_t gb = (size_t)(k0 + rB) * N + bxb * 128 + cB;
        cp16(base + OFF_BH + rB * 136 + cB, Whg + gb);
        cp16(base + OFF_BL + rB * 136 + cB, Wlg + gb);
    }
    asm volatile("cp.async.commit_group;");
}

template<int MODE>
__device__ __forceinline__ void gemm_body(
    const __nv_bfloat16* __restrict__ Ahg, const __nv_bfloat16* __restrict__ Alg,
    const __nv_bfloat16* __restrict__ Whg, const __nv_bfloat16* __restrict__ Wlg,
    const float* __restrict__ bias, float* __restrict__ C,
    __nv_bfloat16* __restrict__ Chi, __nv_bfloat16* __restrict__ Clo,
    int M, int N, int K, int bxb, int byb, __nv_bfloat16* sm)
{
    const int tid = threadIdx.x;
    const int lane = tid & 31;
    const int wid = tid >> 5;
    const int warp_m = wid & 3;
    const int warp_n = wid >> 2;

    float acc[2][8][4];
    #pragma unroll
    for (int mt = 0; mt < 2; mt++) {
        #pragma unroll
        for (int nt = 0; nt < 8; nt++) {
            acc[mt][nt][0] = 0.f; acc[mt][nt][1] = 0.f;
            acc[mt][nt][2] = 0.f; acc[mt][nt][3] = 0.f;
        }
    }

    const int a_tile = lane >> 3;
    const int a_rl = lane & 7;
    const int a_ldrow = warp_m * 32 + (a_tile & 1) * 8 + a_rl;
    const int a_ldcol = (a_tile >> 1) * 8;
    const int b_ldk = (a_tile & 1) * 8 + a_rl;
    const int b_ldn = warp_n * 64 + (a_tile >> 1) * 8;

    const int nk = K >> 5;
    load_stage(sm, 0, 0, tid, byb, bxb, Ahg, Alg, Whg, Wlg, N, K);
    load_stage(sm, 1, 32, tid, byb, bxb, Ahg, Alg, Whg, Wlg, N, K);

    for (int kt = 0; kt < nk; kt++) {
        const int s = kt & 1;
        if (kt == nk - 1) asm volatile("cp.async.wait_group 0;");
        else              asm volatile("cp.async.wait_group 1;");
        __syncthreads();

        __nv_bfloat16* Ahs = sm + s * STAGE_ELT;
        __nv_bfloat16* Als = Ahs + OFF_AL;
        __nv_bfloat16* Bhs = sm + s * STAGE_ELT + OFF_BH;
        __nv_bfloat16* Bls = sm + s * STAGE_ELT + OFF_BL;

        #pragma unroll
        for (int kk = 0; kk < 32; kk += 16) {
            uint32_t ah0[4], ah1[4], al0[4], al1[4];
            ldsm_x4(ah0, (uint32_t)__cvta_generic_to_shared(Ahs + a_ldrow * 40 + a_ldcol + kk));
            ldsm_x4(ah1, (uint32_t)__cvta_generic_to_shared(Ahs + (a_ldrow + 16) * 40 + a_ldcol + kk));
            ldsm_x4(al0, (uint32_t)__cvta_generic_to_shared(Als + a_ldrow * 40 + a_ldcol + kk));
            ldsm_x4(al1, (uint32_t)__cvta_generic_to_shared(Als + (a_ldrow + 16) * 40 + a_ldcol + kk));
            #pragma unroll
            for (int p = 0; p < 4; p++) {
                uint32_t bh4[4], bl4[4];
                ldsm_x4t(bh4, (uint32_t)__cvta_generic_to_shared(Bhs + (kk + b_ldk) * 136 + b_ldn + p * 16));
                ldsm_x4t(bl4, (uint32_t)__cvta_generic_to_shared(Bls + (kk + b_ldk) * 136 + b_ldn + p * 16));
                int nt0 = p * 2;
                int nt1 = p * 2 + 1;
                mma_bf16(acc[0][nt0], ah0, bh4[0], bh4[1]);
                mma_bf16(acc[0][nt0], ah0, bl4[0], bl4[1]);
                mma_bf16(acc[0][nt0], al0, bh4[0], bh4[1]);
                mma_bf16(acc[0][nt1], ah0, bh4[2], bh4[3]);
                mma_bf16(acc[0][nt1], ah0, bl4[2], bl4[3]);
                mma_bf16(acc[0][nt1], al0, bh4[2], bh4[3]);
                mma_bf16(acc[1][nt0], ah1, bh4[0], bh4[1]);
                mma_bf16(acc[1][nt0], ah1, bl4[0], bl4[1]);
                mma_bf16(acc[1][nt0], al1, bh4[0], bh4[1]);
                mma_bf16(acc[1][nt1], ah1, bh4[2], bh4[3]);
                mma_bf16(acc[1][nt1], ah1, bl4[2], bl4[3]);
                mma_bf16(acc[1][nt1], al1, bh4[2], bh4[3]);
            }
        }
        __syncthreads();
        if (kt + 2 < nk)
            load_stage(sm, s, (kt + 2) * 32, tid, byb, bxb, Ahg, Alg, Whg, Wlg, N, K);
    }

    const int grp = lane >> 2;
    const int tig = lane & 3;
    #pragma unroll
    for (int mt = 0; mt < 2; mt++) {
        #pragma unroll
        for (int nt = 0; nt < 8; nt++) {
            int col = bxb * 128 + warp_n * 64 + nt * 8 + tig * 2;
            float b0 = bias[col];
            float b1 = bias[col + 1];
            #pragma unroll
            for (int half = 0; half < 2; half++) {
                int row = byb * 128 + warp_m * 32 + mt * 16 + grp + half * 8;
                float v0 = acc[mt][nt][half * 2 + 0] + b0;
                float v1 = acc[mt][nt][half * 2 + 1] + b1;
                if (MODE == 3) {
                    v0 = 0.5f * v0 * (1.f + erff(v0 * 0.70710678118654752f));
                    v1 = 0.5f * v1 * (1.f + erff(v1 * 0.70710678118654752f));
                }
                if (MODE == 2 || MODE == 3) {
                    __nv_bfloat16 h0 = __float2bfloat16_rn(v0);
                    __nv_bfloat16 h1 = __float2bfloat16_rn(v1);
                    __nv_bfloat16 l0 = __float2bfloat16_rn(v0 - __bfloat162float(h0));
                    __nv_bfloat16 l1 = __float2bfloat16_rn(v1 - __bfloat162float(h1));
                    *(__nv_bfloat162*)&Chi[(size_t)row * N + col] = __halves2bfloat162(h0, h1);
                    *(__nv_bfloat162*)&Clo[(size_t)row * N + col] = __halves2bfloat162(l0, l1);
                } else {
                    C[(size_t)row * N + col] = v0;
                    C[(size_t)row * N + col + 1] = v1;
                }
            }
        }
    }
}

template<int MODE>
__global__ void __launch_bounds__(256, 2) bgemm2_kernel(
    const __nv_bfloat16* __restrict__ Ahg, const __nv_bfloat16* __restrict__ Alg,
    const __nv_bfloat16* __restrict__ Whg, const __nv_bfloat16* __restrict__ Wlg,
    const float* __restrict__ bias, float* __restrict__ C,
    __nv_bfloat16* __restrict__ Chi, __nv_bfloat16* __restrict__ Clo,
    int M, int N, int K)
{
    extern __shared__ __align__(16) __nv_bfloat16 sm[];
    gemm_body<MODE>(Ahg, Alg, Whg, Wlg, bias, C, Chi, Clo, M, N, K,
                    blockIdx.x, blockIdx.y, sm);
}

__global__ void __launch_bounds__(256, 2) qkv_gemm_kernel(
    const __nv_bfloat16* __restrict__ Ahg, const __nv_bfloat16* __restrict__ Alg,
    const __nv_bfloat16* __restrict__ Whg, const __nv_bfloat16* __restrict__ Wlg,
    const float* __restrict__ bq, const float* __restrict__ bk, const float* __restrict__ bv,
    __nv_bfloat16* __restrict__ qhi, __nv_bfloat16* __restrict__ qlo,
    __nv_bfloat16* __restrict__ khi, __nv_bfloat16* __restrict__ klo,
    __nv_bfloat16* __restrict__ vhi, __nv_bfloat16* __restrict__ vlo)
{
    extern __shared__ __align__(16) __nv_bfloat16 sm[];
    int z = blockIdx.z;
    size_t woff = (size_t)z * Dx * Dx;
    const float* bias = (z == 0) ? bq : (z == 1) ? bk : bv;
    __nv_bfloat16* chi = (z == 0) ? qhi : (z == 1) ? khi : vhi;
    __nv_bfloat16* clo = (z == 0) ? qlo : (z == 1) ? klo : vlo;
    gemm_body<2>(Ahg, Alg, Whg + woff, Wlg + woff, bias, nullptr, chi, clo,
                 TOK, Dx, Dx, blockIdx.x, blockIdx.y, sm);
}

// ---------------- helpers ----------------
__device__ __forceinline__ int mid_block_idx(int n, int g, const int* __restrict__ randb) {
    if (g == 0) return 0;
    if (g == 1) return NBx - 1;
    if (g < 5)  return n - 3 + g;
    return randb[(n - 1) * Rx + (g - 5)];
}

__device__ __forceinline__ void load_tile64(
    __nv_bfloat16 (*dst)[72], const __nv_bfloat16* __restrict__ src, int gstride, int tid)
{
    #pragma unroll
    for (int i = 0; i < 2; i++) {
        int idx = tid + i * 256;
        int r = idx >> 3, c = (idx & 7) * 8;
        *(uint4*)&dst[r][c] = *(const uint4*)(src + (size_t)r * gstride + c);
    }
}

// ---------------- fused middle-block attention ----------------
// One CTA per (mid block n, head h, batch b). Scores -> smem fp32, softmax in place,
// PV with on-the-fly fp32->bf16 hi/lo fragment build, ctx planes written directly.
#define SROW 516
#define MID_SMEM (64 * SROW * 4 + 4 * 64 * 72 * 2)

__global__ void __launch_bounds__(256, 1) mid_fused_kernel(
    const __nv_bfloat16* __restrict__ qhi, const __nv_bfloat16* __restrict__ qlo,
    const __nv_bfloat16* __restrict__ khi, const __nv_bfloat16* __restrict__ klo,
    const __nv_bfloat16* __restrict__ vhi, const __nv_bfloat16* __restrict__ vlo,
    const int* __restrict__ randb, const int* __restrict__ amask,
    __nv_bfloat16* __restrict__ chi, __nv_bfloat16* __restrict__ clo)
{
    extern __shared__ __align__(16) char smraw[];
    float (*Sf)[SROW] = (float(*)[SROW])smraw;
    __nv_bfloat16 (*Qh)[72] = (__nv_bfloat16(*)[72])(smraw + 64 * SROW * 4);
    __nv_bfloat16 (*Ql)[72] = (__nv_bfloat16(*)[72])(smraw + 64 * SROW * 4 + 9216);
    __nv_bfloat16 (*Kh)[72] = (__nv_bfloat16(*)[72])(smraw + 64 * SROW * 4 + 18432);
    __nv_bfloat16 (*Kl)[72] = (__nv_bfloat16(*)[72])(smraw + 64 * SROW * 4 + 27648);

    int n = blockIdx.x + 1, h = blockIdx.y, b = blockIdx.z;
    int tid = threadIdx.x, lane = tid & 31, wid = tid >> 5;
    int warp_m = wid & 3, warp_n = wid >> 2;

    const int tile = lane >> 3;
    const int rl = lane & 7;
    const int ldrow = (tile & 1) * 8 + rl;
    const int ldcol = (tile >> 1) * 8;
    const int b_ldk = (tile & 1) * 8 + rl;
    const int b_ldn = (tile >> 1) * 8;

    size_t qoff = ((size_t)b * Sx + n * 64) * Dx + h * 64;
    load_tile64(Qh, qhi + qoff, Dx, tid);
    load_tile64(Ql, qlo + qoff, Dx, tid);

    // --- phase 1: scores into Sf ---
    for (int g = 0; g < NGx; g++) {
        int kb = mid_block_idx(n, g, randb);
        size_t koff = ((size_t)b * Sx + kb * 64) * Dx + h * 64;
        __syncthreads();
        load_tile64(Kh, khi + koff, Dx, tid);
        load_tile64(Kl, klo + koff, Dx, tid);
        __syncthreads();

        float acc[4][4];
        #pragma unroll
        for (int j = 0; j < 4; j++) {
            acc[j][0] = 0.f; acc[j][1] = 0.f; acc[j][2] = 0.f; acc[j][3] = 0.f;
        }
        #pragma unroll
        for (int kk = 0; kk < 64; kk += 16) {
            uint32_t ah[4], al[4];
            ldsm_x4(ah, (uint32_t)__cvta_generic_to_shared(&Qh[warp_m * 16 + ldrow][ldcol + kk]));
            ldsm_x4(al, (uint32_t)__cvta_generic_to_shared(&Ql[warp_m * 16 + ldrow][ldcol + kk]));
            #pragma unroll
            for (int j2 = 0; j2 < 2; j2++) {
                int n0 = warp_n * 32 + j2 * 16;
                uint32_t bh[4], bl[4];
                ldsm_x4(bh, (uint32_t)__cvta_generic_to_shared(&Kh[n0 + ldrow][ldcol + kk]));
                ldsm_x4(bl, (uint32_t)__cvta_generic_to_shared(&Kl[n0 + ldrow][ldcol + kk]));
                mma_bf16(acc[j2 * 2 + 0], ah, bh[0], bh[2]);
                mma_bf16(acc[j2 * 2 + 0], ah, bl[0], bl[2]);
                mma_bf16(acc[j2 * 2 + 0], al, bh[0], bh[2]);
                mma_bf16(acc[j2 * 2 + 1], ah, bh[1], bh[3]);
                mma_bf16(acc[j2 * 2 + 1], ah, bl[1], bl[3]);
                mma_bf16(acc[j2 * 2 + 1], al, bh[1], bh[3]);
            }
        }
        int r0 = warp_m * 16 + (lane >> 2);
        int mask_base = b * Sx + kb * 64;
        #pragma unroll
        for (int j = 0; j < 4; j++) {
            int ki = warp_n * 32 + j * 8 + (lane & 3) * 2;
            float m0 = (1.0f - (float)amask[mask_base + ki]) * -1e9f;
            float m1 = (1.0f - (float)amask[mask_base + ki + 1]) * -1e9f;
            Sf[r0][g * 64 + ki]           = acc[j][0] * 0.125f + m0;
            Sf[r0][g * 64 + ki + 1]       = acc[j][1] * 0.125f + m1;
            Sf[r0 + 8][g * 64 + ki]       = acc[j][2] * 0.125f + m0;
            Sf[r0 + 8][g * 64 + ki + 1]   = acc[j][3] * 0.125f + m1;
        }
    }
    __syncthreads();

    // --- phase 2: softmax rows in place (warp wid handles rows wid*8..+7) ---
    for (int rr = 0; rr < 8; rr++) {
        int row = wid * 8 + rr;
        float v[16];
        float m = -3.4e38f;
        #pragma unroll
        for (int j = 0; j < 16; j++) {
            v[j] = Sf[row][lane + 32 * j];
            m = fmaxf(m, v[j]);
        }
        #pragma unroll
        for (int o = 16; o; o >>= 1) m = fmaxf(m, __shfl_xor_sync(0xffffffffu, m, o));
        float s = 0.f;
        #pragma unroll
        for (int j = 0; j < 16; j++) { v[j] = expf(v[j] - m); s += v[j]; }
        #pragma unroll
        for (int o = 16; o; o >>= 1) s += __shfl_xor_sync(0xffffffffu, s, o);
        float inv = 1.f / s;
        #pragma unroll
        for (int j = 0; j < 16; j++) Sf[row][lane + 32 * j] = v[j] * inv;
    }
    __syncthreads();

    // --- phase 3: PV (P fragments built on the fly from Sf) ---
    float acc[4][4];
    #pragma unroll
    for (int j = 0; j < 4; j++) {
        acc[j][0] = 0.f; acc[j][1] = 0.f; acc[j][2] = 0.f; acc[j][3] = 0.f;
    }
    int pr = warp_m * 16 + (lane >> 2);
    for (int g = 0; g < NGx; g++) {
        int kb = mid_block_idx(n, g, randb);
        size_t voff = ((size_t)b * Sx + kb * 64) * Dx + h * 64;
        __syncthreads();
        load_tile64(Kh, vhi + voff, Dx, tid);
        load_tile64(Kl, vlo + voff, Dx, tid);
        __syncthreads();
        #pragma unroll
        for (int kk = 0; kk < 64; kk += 16) {
            int cc = g * 64 + kk + (lane & 3) * 2;
            float2 p00 = *(const float2*)&Sf[pr][cc];
            float2 p10 = *(const float2*)&Sf[pr + 8][cc];
            float2 p01 = *(const float2*)&Sf[pr][cc + 8];
            float2 p11 = *(const float2*)&Sf[pr + 8][cc + 8];
            uint32_t ah[4], al[4];
            pack2(p00.x, p00.y, ah[0], al[0]);
            pack2(p10.x, p10.y, ah[1], al[1]);
            pack2(p01.x, p01.y, ah[2], al[2]);
            pack2(p11.x, p11.y, ah[3], al[3]);
            #pragma unroll
            for (int j2 = 0; j2 < 2; j2++) {
                int n0 = warp_n * 32 + j2 * 16;
                uint32_t bh4[4], bl4[4];
                ldsm_x4t(bh4, (uint32_t)__cvta_generic_to_shared(&Kh[kk + b_ldk][n0 + b_ldn]));
                ldsm_x4t(bl4, (uint32_t)__cvta_generic_to_shared(&Kl[kk + b_ldk][n0 + b_ldn]));
                mma_bf16(acc[j2 * 2 + 0], ah, bh4[0], bh4[1]);
                mma_bf16(acc[j2 * 2 + 0], ah, bl4[0], bl4[1]);
                mma_bf16(acc[j2 * 2 + 0], al, bh4[0], bh4[1]);
                mma_bf16(acc[j2 * 2 + 1], ah, bh4[2], bh4[3]);
                mma_bf16(acc[j2 * 2 + 1], ah, bl4[2], bl4[3]);
                mma_bf16(acc[j2 * 2 + 1], al, bh4[2], bh4[3]);
            }
        }
    }

    size_t cb = ((size_t)b * Sx + n * 64) * Dx + h * 64;
    #pragma unroll
    for (int j = 0; j < 4; j++) {
        int col = warp_n * 32 + j * 8 + (lane & 3) * 2;
        split_store(acc[j][0], chi + cb + (size_t)pr * Dx + col,           clo + cb + (size_t)pr * Dx + col);
        split_store(acc[j][1], chi + cb + (size_t)pr * Dx + col + 1,       clo + cb + (size_t)pr * Dx + col + 1);
        split_store(acc[j][2], chi + cb + (size_t)(pr + 8) * Dx + col,     clo + cb + (size_t)(pr + 8) * Dx + col);
        split_store(acc[j][3], chi + cb + (size_t)(pr + 8) * Dx + col + 1, clo + cb + (size_t)(pr + 8) * Dx + col + 1);
    }
}

// ---------------- edge scores ----------------
__device__ __forceinline__ void score_tile(
    const __nv_bfloat16 (*Qh)[72], const __nv_bfloat16 (*Ql)[72],
    const __nv_bfloat16 (*Kh)[72], const __nv_bfloat16 (*Kl)[72],
    const int* __restrict__ amask, int mask_base,
    float* __restrict__ out, int ostride, int ocol0,
    int lane, int warp_m, int warp_n)
{
    const int tile = lane >> 3;
    const int rl = lane & 7;
    const int ldrow = (tile & 1) * 8 + rl;
    const int ldcol = (tile >> 1) * 8;

    float acc[4][4];
    #pragma unroll
    for (int j = 0; j < 4; j++) {
        acc[j][0] = 0.f; acc[j][1] = 0.f; acc[j][2] = 0.f; acc[j][3] = 0.f;
    }

    #pragma unroll
    for (int kk = 0; kk < 64; kk += 16) {
        uint32_t ah[4], al[4];
        ldsm_x4(ah, (uint32_t)__cvta_generic_to_shared(&Qh[warp_m * 16 + ldrow][ldcol + kk]));
        ldsm_x4(al, (uint32_t)__cvta_generic_to_shared(&Ql[warp_m * 16 + ldrow][ldcol + kk]));
        #pragma unroll
        for (int j2 = 0; j2 < 2; j2++) {
            int n0 = warp_n * 32 + j2 * 16;
            uint32_t bh[4], bl[4];
            ldsm_x4(bh, (uint32_t)__cvta_generic_to_shared(&Kh[n0 + ldrow][ldcol + kk]));
            ldsm_x4(bl, (uint32_t)__cvta_generic_to_shared(&Kl[n0 + ldrow][ldcol + kk]));
            mma_bf16(acc[j2 * 2 + 0], ah, bh[0], bh[2]);
            mma_bf16(acc[j2 * 2 + 0], ah, bl[0], bl[2]);
            mma_bf16(acc[j2 * 2 + 0], al, bh[0], bh[2]);
            mma_bf16(acc[j2 * 2 + 1], ah, bh[1], bh[3]);
            mma_bf16(acc[j2 * 2 + 1], ah, bl[1], bl[3]);
            mma_bf16(acc[j2 * 2 + 1], al, bh[1], bh[3]);
        }
    }

    int r0 = warp_m * 16 + (lane >> 2);
    #pragma unroll
    for (int j = 0; j < 4; j++) {
        int ki = warp_n * 32 + j * 8 + (lane & 3) * 2;
        float m0 = (1.0f - (float)amask[mask_base + ki]) * -1e9f;
        float m1 = (1.0f - (float)amask[mask_base + ki + 1]) * -1e9f;
        out[(size_t)r0 * ostride + ocol0 + ki]           = acc[j][0] * 0.125f + m0;
        out[(size_t)r0 * ostride + ocol0 + ki + 1]       = acc[j][1] * 0.125f + m1;
        out[(size_t)(r0 + 8) * ostride + ocol0 + ki]     = acc[j][2] * 0.125f + m0;
        out[(size_t)(r0 + 8) * ostride + ocol0 + ki + 1] = acc[j][3] * 0.125f + m1;
    }
}

__device__ __forceinline__ void pv_tile(
    const __nv_bfloat16 (*Ph)[72], const __nv_bfloat16 (*Pl)[72],
    const __nv_bfloat16 (*Vh)[72], const __nv_bfloat16 (*Vl)[72],
    float acc[4][4], int lane, int warp_m, int warp_n)
{
    const int tile = lane >> 3;
    const int rl = lane & 7;
    const int ldrow = (tile & 1) * 8 + rl;
    const int ldcol = (tile >> 1) * 8;
    const int b_ldk = (tile & 1) * 8 + rl;
    const int b_ldn = (tile >> 1) * 8;

    #pragma unroll
    for (int kk = 0; kk < 64; kk += 16) {
        uint32_t ah[4], al[4];
        ldsm_x4(ah, (uint32_t)__cvta_generic_to_shared(&Ph[warp_m * 16 + ldrow][ldcol + kk]));
        ldsm_x4(al, (uint32_t)__cvta_generic_to_shared(&Pl[warp_m * 16 + ldrow][ldcol + kk]));
        #pragma unroll
        for (int j2 = 0; j2 < 2; j2++) {
            int n0 = warp_n * 32 + j2 * 16;
            uint32_t bh4[4], bl4[4];
            ldsm_x4t(bh4, (uint32_t)__cvta_generic_to_shared(&Vh[kk + b_ldk][n0 + b_ldn]));
            ldsm_x4t(bl4, (uint32_t)__cvta_generic_to_shared(&Vl[kk + b_ldk][n0 + b_ldn]));
            mma_bf16(acc[j2 * 2 + 0], ah, bh4[0], bh4[1]);
            mma_bf16(acc[j2 * 2 + 0], ah, bl4[0], bl4[1]);
            mma_bf16(acc[j2 * 2 + 0], al, bh4[0], bh4[1]);
            mma_bf16(acc[j2 * 2 + 1], ah, bh4[2], bh4[3]);
            mma_bf16(acc[j2 * 2 + 1], ah, bl4[2], bl4[3]);
            mma_bf16(acc[j2 * 2 + 1], al, bh4[2], bh4[3]);
        }
    }
}

__global__ void __launch_bounds__(256) edge_scores_mma(
    const __nv_bfloat16* __restrict__ qhi, const __nv_bfloat16* __restrict__ qlo,
    const __nv_bfloat16* __restrict__ khi, const __nv_bfloat16* __restrict__ klo,
    const int* __restrict__ amask, float* __restrict__ sedge)
{
    int kb = blockIdx.x, h = blockIdx.y;
    int e = blockIdx.z & 1, b = blockIdx.z >> 1;
    int qb = e ? (NBx - 1) : 0;
    __shared__ __nv_bfloat16 Qh[64][72], Ql[64][72], Kh[64][72], Kl[64][72];
    int tid = threadIdx.x, lane = tid & 31, wid = tid >> 5;
    int warp_m = wid & 3, warp_n = wid >> 2;

    size_t qoff = ((size_t)b * Sx + qb * 64) * Dx + h * 64;
    size_t koff = ((size_t)b * Sx + kb * 64) * Dx + h * 64;
    load_tile64(Qh, qhi + qoff, Dx, tid);
    load_tile64(Ql, qlo + qoff, Dx, tid);
    load_tile64(Kh, khi + koff, Dx, tid);
    load_tile64(Kl, klo + koff, Dx, tid);
    __syncthreads();

    float* out = sedge + ((size_t)((b * NHx + h) * 2 + e)) * (64 * Sx);
    score_tile(Qh, Ql, Kh, Kl, amask, b * Sx + kb * 64,
               out, Sx, kb * 64, lane, warp_m, warp_n);
}

__global__ void __launch_bounds__(256) edge_pv_mma(
    const __nv_bfloat16* __restrict__ phi, const __nv_bfloat16* __restrict__ plo,
    const __nv_bfloat16* __restrict__ vhi, const __nv_bfloat16* __restrict__ vlo,
    float* __restrict__ ctx)
{
    int h = blockIdx.x;
    int e = blockIdx.y & 1, b = blockIdx.y >> 1;
    int chunk = blockIdx.z;
    int qb = e ? (NBx - 1) : 0;
    __shared__ __nv_bfloat16 Ph[64][72], Pl[64][72], Vh[64][72], Vl[64][72];
    int tid = threadIdx.x, lane = tid & 31, wid = tid >> 5;
    int warp_m = wid & 3, warp_n = wid >> 2;

    const __nv_bfloat16* prow_h = phi + ((size_t)((b * NHx + h) * 2 + e)) * (64 * Sx);
    const __nv_bfloat16* prow_l = plo + ((size_t)((b * NHx + h) * 2 + e)) * (64 * Sx);

    float acc[4][4];
    #pragma unroll
    for (int j = 0; j < 4; j++) {
        acc[j][0] = 0.f; acc[j][1] = 0.f; acc[j][2] = 0.f; acc[j][3] = 0.f;
    }

    for (int c8 = 0; c8 < 8; c8++) {
        int kb = chunk * 8 + c8;
        size_t voff = ((size_t)b * Sx + kb * 64) * Dx + h * 64;
        __syncthreads();
        load_tile64(Ph, prow_h + kb * 64, Sx, tid);
        load_tile64(Pl, prow_l + kb * 64, Sx, tid);
        load_tile64(Vh, vhi + voff, Dx, tid);
        load_tile64(Vl, vlo + voff, Dx, tid);
        __syncthreads();
        pv_tile(Ph, Pl, Vh, Vl, acc, lane, warp_m, warp_n);
    }

    float* cbase = ctx + ((size_t)b * Sx + qb * 64) * Dx + h * 64;
    int r0 = warp_m * 16 + (lane >> 2);
    #pragma unroll
    for (int j = 0; j < 4; j++) {
        int col = warp_n * 32 + j * 8 + (lane & 3) * 2;
        atomicAdd(&cbase[(size_t)r0 * Dx + col],           acc[j][0]);
        atomicAdd(&cbase[(size_t)r0 * Dx + col + 1],       acc[j][1]);
        atomicAdd(&cbase[(size_t)(r0 + 8) * Dx + col],     acc[j][2]);
        atomicAdd(&cbase[(size_t)(r0 + 8) * Dx + col + 1], acc[j][3]);
    }
}

__global__ void zero_edge_ctx(float* __restrict__ ctx) {
    int i = blockIdx.x * 256 + threadIdx.x;
    if (i >= Bx * 2 * 64 * Dx) return;
    int col = i % Dx;
    int t = i / Dx;
    int row = t % 64;  t /= 64;
    int e = t & 1;
    int b = t >> 1;
    int blk = e ? (NBx - 1) : 0;
    ctx[((size_t)b * Sx + blk * 64 + row) * Dx + col] = 0.f;
}

__global__ void split_edge_kernel(const float* __restrict__ ctx,
                                  __nv_bfloat16* __restrict__ hi,
                                  __nv_bfloat16* __restrict__ lo) {
    int i = blockIdx.x * 256 + threadIdx.x;
    if (i >= Bx * 2 * 64 * Dx) return;
    int col = i % Dx;
    int t = i / Dx;
    int row = t % 64;  t /= 64;
    int e = t & 1;
    int b = t >> 1;
    int blk = e ? (NBx - 1) : 0;
    size_t idx = ((size_t)b * Sx + blk * 64 + row) * Dx + col;
    split_store(ctx[idx], hi + idx, lo + idx);
}

// ---------------- row softmax -> bf16 hi/lo planes (edge) ----------------
__global__ void softmax_split_kernel(const float* __restrict__ s,
                                     __nv_bfloat16* __restrict__ phi,
                                     __nv_bfloat16* __restrict__ plo, int L) {
    extern __shared__ float buf[];
    size_t base = (size_t)blockIdx.x * L;
    float m = -3.4e38f;
    for (int i = threadIdx.x; i < L; i += blockDim.x) {
        float x = s[base + i];
        buf[i] = x;
        m = fmaxf(m, x);
    }
    m = blk_max(m);
    float lsum = 0.f;
    for (int i = threadIdx.x; i < L; i += blockDim.x) {
        float e = expf(buf[i] - m);
        buf[i] = e;
        lsum += e;
    }
    float sum = blk_sum(lsum);
    float inv = 1.f / sum;
    for (int i = threadIdx.x; i < L; i += blockDim.x) {
        float p = buf[i] * inv;
        split_store(p, phi + base + i, plo + base + i);
    }
}

// ---------------- pooler ----------------
__global__ void pooler_kernel(const float* __restrict__ h, const float* __restrict__ pw,
                              const float* __restrict__ pb, float* __restrict__ out) {
    int j = blockIdx.x * blockDim.x + threadIdx.x;
    int b = blockIdx.y;
    if (j >= Dx) return;
    const float* hr = h + (size_t)b * Sx * Dx;
    float acc = pb[j];
    for (int kI = 0; kI < Dx; kI++) acc += hr[kI] * pw[(size_t)kI * Dx + j];
    out[b * Dx + j] = tanhf(acc);
}

// ---------------- host launcher ----------------
extern "C" void kernel_launch(void* const* d_in, const int* in_sizes, int n_in,
                              void* d_out, int out_size) {
    const int*   input_ids = (const int*)d_in[0];
    const int*   attn_mask = (const int*)d_in[1];
    const int*   tok_type  = (const int*)d_in[2];
    const int*   rand_blk  = (const int*)d_in[3];
    const float* word_emb  = (const float*)d_in[4];
    const float* type_emb  = (const float*)d_in[5];
    const float* pos_emb   = (const float*)d_in[6];
    const float* emb_ln_s  = (const float*)d_in[7];
    const float* emb_ln_b  = (const float*)d_in[8];
    const float* Wq = (const float*)d_in[9];  const float* bq = (const float*)d_in[10];
    const float* Wk = (const float*)d_in[11]; const float* bk = (const float*)d_in[12];
    const float* Wv = (const float*)d_in[13]; const float* bv = (const float*)d_in[14];
    const float* Wo = (const float*)d_in[15]; const float* bo = (const float*)d_in[16];
    const float* ln1_s = (const float*)d_in[17]; const float* ln1_b = (const float*)d_in[18];
    const float* W1 = (const float*)d_in[19]; const float* b1 = (const float*)d_in[20];
    const float* W2 = (const float*)d_in[21]; const float* b2 = (const float*)d_in[22];
    const float* ln2_s = (const float*)d_in[23]; const float* ln2_b = (const float*)d_in[24];
    const float* pool_w = (const float*)d_in[25]; const float* pool_b = (const float*)d_in[26];
    float* out = (float*)d_out;

    float *p_h = 0, *p_res = 0, *p_ctx = 0, *p_sedge = 0;
    __nv_bfloat16 *p_ahi = 0, *p_alo = 0, *p_ffh = 0, *p_ffl = 0, *p_whi = 0, *p_wlo = 0;
    __nv_bfloat16 *p_qhi = 0, *p_qlo = 0, *p_khi = 0, *p_klo = 0, *p_vhi = 0, *p_vlo = 0;
    __nv_bfloat16 *p_peh = 0, *p_pel = 0;
    cudaGetSymbolAddress((void**)&p_h,     g_h);
    cudaGetSymbolAddress((void**)&p_res,   g_res);
    cudaGetSymbolAddress((void**)&p_ctx,   g_ctx);
    cudaGetSymbolAddress((void**)&p_sedge, g_sedge);
    cudaGetSymbolAddress((void**)&p_ahi,   g_act_hi);
    cudaGetSymbolAddress((void**)&p_alo,   g_act_lo);
    cudaGetSymbolAddress((void**)&p_ffh,   g_ff_hi);
    cudaGetSymbolAddress((void**)&p_ffl,   g_ff_lo);
    cudaGetSymbolAddress((void**)&p_whi,   g_w_hi);
    cudaGetSymbolAddress((void**)&p_wlo,   g_w_lo);
    cudaGetSymbolAddress((void**)&p_qhi,   g_qhi);
    cudaGetSymbolAddress((void**)&p_qlo,   g_qlo);
    cudaGetSymbolAddress((void**)&p_khi,   g_khi);
    cudaGetSymbolAddress((void**)&p_klo,   g_klo);
    cudaGetSymbolAddress((void**)&p_vhi,   g_vhi);
    cudaGetSymbolAddress((void**)&p_vlo,   g_vlo);
    cudaGetSymbolAddress((void**)&p_peh,   g_pedge_hi);
    cudaGetSymbolAddress((void**)&p_pel,   g_pedge_lo);

    static bool attr_done = false;
    if (!attr_done) {
        cudaFuncSetAttribute(bgemm2_kernel<0>, cudaFuncAttributeMaxDynamicSharedMemorySize, SMEM_BYTES);
        cudaFuncSetAttribute(bgemm2_kernel<2>, cudaFuncAttributeMaxDynamicSharedMemorySize, SMEM_BYTES);
        cudaFuncSetAttribute(bgemm2_kernel<3>, cudaFuncAttributeMaxDynamicSharedMemorySize, SMEM_BYTES);
        cudaFuncSetAttribute(qkv_gemm_kernel, cudaFuncAttributeMaxDynamicSharedMemorySize, SMEM_BYTES);
        cudaFuncSetAttribute(mid_fused_kernel, cudaFuncAttributeMaxDynamicSharedMemorySize, MID_SMEM);
        attr_done = true;
    }

    const int M = TOK;
    const int nDD = Dx * Dx;
    const int nDF = Dx * FFx;

    auto split = [&](const float* src, __nv_bfloat16* hi, __nv_bfloat16* lo, int n) {
        split_kernel<<<(n / 4 + 255) / 256, 256>>>(src, hi, lo, n / 4);
    };

    embed_ln_kernel<<<TOK, 256>>>(input_ids, tok_type, word_emb, type_emb, pos_emb,
                                  emb_ln_s, emb_ln_b, p_ahi, p_alo);

    for (int l = 0; l < 2; l++) {
        const float* wq = Wq + (size_t)l * nDD;  const float* bql = bq + (size_t)l * Dx;
        const float* wk = Wk + (size_t)l * nDD;  const float* bkl = bk + (size_t)l * Dx;
        const float* wv = Wv + (size_t)l * nDD;  const float* bvl = bv + (size_t)l * Dx;
        const float* wo = Wo + (size_t)l * nDD;  const float* bol = bo + (size_t)l * Dx;
        const float* w1 = W1 + (size_t)l * nDF;  const float* b1l = b1 + (size_t)l * FFx;
        const float* w2 = W2 + (size_t)l * nDF;  const float* b2l = b2 + (size_t)l * Dx;
        const float* l1s = ln1_s + (size_t)l * Dx; const float* l1b = ln1_b + (size_t)l * Dx;
        const float* l2s = ln2_s + (size_t)l * Dx; const float* l2b = ln2_b + (size_t)l * Dx;

        // QKV: fused single launch (act planes current)
        split(wq, p_whi,           p_wlo,           nDD);
        split(wk, p_whi + nDD,     p_wlo + nDD,     nDD);
        split(wv, p_whi + 2 * nDD, p_wlo + 2 * nDD, nDD);
        qkv_gemm_kernel<<<dim3(Dx / 128, M / 128, 3), 256, SMEM_BYTES>>>(
            p_ahi, p_alo, p_whi, p_wlo, bql, bkl, bvl,
            p_qhi, p_qlo, p_khi, p_klo, p_vhi, p_vlo);

        // middle blocks: fused scores+softmax+PV; writes ctx planes into act buffers
        mid_fused_kernel<<<dim3(NMID, NHx, Bx), 256, MID_SMEM>>>(
            p_qhi, p_qlo, p_khi, p_klo, p_vhi, p_vlo, rand_blk, attn_mask,
            p_ahi, p_alo);

        // edge blocks (dense rows, gmem scores)
        edge_scores_mma<<<dim3(NBx, NHx, Bx * 2), 256>>>(p_qhi, p_qlo, p_khi, p_klo,
                                                         attn_mask, p_sedge);
        softmax_split_kernel<<<Bx * NHx * 2 * BSx, 256, Sx * sizeof(float)>>>(
            p_sedge, p_peh, p_pel, Sx);
        zero_edge_ctx<<<(Bx * 2 * 64 * Dx + 255) / 256, 256>>>(p_ctx);
        edge_pv_mma<<<dim3(NHx, Bx * 2, 8), 256>>>(p_peh, p_pel, p_vhi, p_vlo, p_ctx);
        split_edge_kernel<<<(Bx * 2 * 64 * Dx + 255) / 256, 256>>>(p_ctx, p_ahi, p_alo);

        // O-projection + LN (LN emits act planes for FFN1)
        split(wo, p_whi, p_wlo, nDD);
        bgemm2_kernel<0><<<dim3(Dx / 128, M / 128), 256, SMEM_BYTES>>>(
            p_ahi, p_alo, p_whi, p_wlo, bol, p_res, nullptr, nullptr, M, Dx, Dx);
        add_ln_kernel<<<TOK, 256>>>(p_h, p_res, l1s, l1b, p_ahi, p_alo);

        // FFN
        split(w1, p_whi, p_wlo, nDF);
        bgemm2_kernel<3><<<dim3(FFx / 128, M / 128), 256, SMEM_BYTES>>>(
            p_ahi, p_alo, p_whi, p_wlo, b1l, nullptr, p_ffh, p_ffl, M, FFx, Dx);
        split(w2, p_whi, p_wlo, nDF);
        bgemm2_kernel<0><<<dim3(Dx / 128, M / 128), 256, SMEM_BYTES>>>(
            p_ffh, p_ffl, p_whi, p_wlo, b2l, p_res, nullptr, nullptr, M, Dx, FFx);
        add_ln_kernel<<<TOK, 256>>>(p_h, p_res, l2s, l2b, p_ahi, p_alo);
    }

    pooler_kernel<<<dim3((Dx + 127) / 128, Bx), 128>>>(p_h, pool_w, pool_b, out);
}

// round 11
// speedup vs baseline: 2.8973x; 1.0033x over previous
#include <cuda_runtime.h>
#include <cuda_bf16.h>
#include <cstdint>
#include <math.h>

#define Bx 2
#define Sx 4096
#define Dx 768
#define NHx 12
#define HDx 64
#define BSx 64
#define NBx 64
#define FFx 3072
#define Rx 3
#define NGx 8
#define NMID 62
#define TOK (Bx*Sx)

// ---------------- scratch ----------------
__device__ float g_h[(size_t)TOK*Dx];
__device__ float g_res[(size_t)TOK*Dx];
__device__ float g_ctx[(size_t)TOK*Dx];
__device__ float g_sedge[(size_t)Bx*NHx*2*BSx*Sx];
__device__ __nv_bfloat16 g_act_hi[(size_t)TOK*Dx];
__device__ __nv_bfloat16 g_act_lo[(size_t)TOK*Dx];
__device__ __nv_bfloat16 g_ff_hi[(size_t)TOK*FFx];
__device__ __nv_bfloat16 g_ff_lo[(size_t)TOK*FFx];
__device__ __nv_bfloat16 g_w_hi[(size_t)Dx*FFx];
__device__ __nv_bfloat16 g_w_lo[(size_t)Dx*FFx];
__device__ __nv_bfloat16 g_qhi[(size_t)TOK*Dx];
__device__ __nv_bfloat16 g_qlo[(size_t)TOK*Dx];
__device__ __nv_bfloat16 g_khi[(size_t)TOK*Dx];
__device__ __nv_bfloat16 g_klo[(size_t)TOK*Dx];
__device__ __nv_bfloat16 g_vhi[(size_t)TOK*Dx];
__device__ __nv_bfloat16 g_vlo[(size_t)TOK*Dx];
__device__ __nv_bfloat16 g_pedge_hi[(size_t)Bx*NHx*2*BSx*Sx];
__device__ __nv_bfloat16 g_pedge_lo[(size_t)Bx*NHx*2*BSx*Sx];

// ---------------- fast exp on the FMA pipe ----------------
__device__ __forceinline__ float fexp(float x) {
    x = fmaxf(x, -80.f);
    float t = fmaf(x, 1.4426950408889634f, 12582912.0f);
    float i = t - 12582912.0f;
    float f = fmaf(x, 1.4426950408889634f, -i);
    float pr = 1.5403530e-4f;
    pr = fmaf(pr, f, 1.3333558e-3f);
    pr = fmaf(pr, f, 9.6181291e-3f);
    pr = fmaf(pr, f, 5.5504109e-2f);
    pr = fmaf(pr, f, 2.4022651e-1f);
    pr = fmaf(pr, f, 6.9314718e-1f);
    pr = fmaf(pr, f, 1.0f);
    int ii = (int)i;
    float sc = __int_as_float((ii + 127) << 23);
    return pr * sc;
}

// ---------------- block reductions ----------------
__device__ __forceinline__ float blk_sum(float v) {
    __shared__ float red[33];
    #pragma unroll
    for (int o = 16; o; o >>= 1) v += __shfl_down_sync(0xffffffffu, v, o);
    int lane = threadIdx.x & 31, w = threadIdx.x >> 5;
    __syncthreads();
    if (lane == 0) red[w] = v;
    __syncthreads();
    if (w == 0) {
        float x = (lane < ((blockDim.x + 31) >> 5)) ? red[lane] : 0.f;
        #pragma unroll
        for (int o = 16; o; o >>= 1) x += __shfl_down_sync(0xffffffffu, x, o);
        if (lane == 0) red[32] = x;
    }
    __syncthreads();
    return red[32];
}

__device__ __forceinline__ float blk_max(float v) {
    __shared__ float redm[33];
    #pragma unroll
    for (int o = 16; o; o >>= 1) v = fmaxf(v, __shfl_down_sync(0xffffffffu, v, o));
    int lane = threadIdx.x & 31, w = threadIdx.x >> 5;
    __syncthreads();
    if (lane == 0) redm[w] = v;
    __syncthreads();
    if (w == 0) {
        float x = (lane < ((blockDim.x + 31) >> 5)) ? redm[lane] : -3.4e38f;
        #pragma unroll
        for (int o = 16; o; o >>= 1) x = fmaxf(x, __shfl_down_sync(0xffffffffu, x, o));
        if (lane == 0) redm[32] = x;
    }
    __syncthreads();
    return redm[32];
}

__device__ __forceinline__ void split_store(float x, __nv_bfloat16* hi, __nv_bfloat16* lo) {
    __nv_bfloat16 h = __float2bfloat16_rn(x);
    *hi = h;
    *lo = __float2bfloat16_rn(x - __bfloat162float(h));
}
__device__ __forceinline__ void pack2(float x, float y, uint32_t& hi, uint32_t& lo) {
    __nv_bfloat16 h0 = __float2bfloat16_rn(x);
    __nv_bfloat16 h1 = __float2bfloat16_rn(y);
    __nv_bfloat16 l0 = __float2bfloat16_rn(x - __bfloat162float(h0));
    __nv_bfloat16 l1 = __float2bfloat16_rn(y - __bfloat162float(h1));
    __nv_bfloat162 hh = __halves2bfloat162(h0, h1);
    __nv_bfloat162 ll = __halves2bfloat162(l0, l1);
    hi = *(uint32_t*)&hh;
    lo = *(uint32_t*)&ll;
}

// ---------------- fp32 -> (hi, lo) bf16 planes ----------------
__global__ void split_kernel(const float* __restrict__ in,
                             __nv_bfloat16* __restrict__ hi,
                             __nv_bfloat16* __restrict__ lo, int n4) {
    int i = blockIdx.x * blockDim.x + threadIdx.x;
    if (i >= n4) return;
    float4 v = ((const float4*)in)[i];
    __nv_bfloat16 h0 = __float2bfloat16_rn(v.x);
    __nv_bfloat16 h1 = __float2bfloat16_rn(v.y);
    __nv_bfloat16 h2 = __float2bfloat16_rn(v.z);
    __nv_bfloat16 h3 = __float2bfloat16_rn(v.w);
    __nv_bfloat16 l0 = __float2bfloat16_rn(v.x - __bfloat162float(h0));
    __nv_bfloat16 l1 = __float2bfloat16_rn(v.y - __bfloat162float(h1));
    __nv_bfloat16 l2 = __float2bfloat16_rn(v.z - __bfloat162float(h2));
    __nv_bfloat16 l3 = __float2bfloat16_rn(v.w - __bfloat162float(h3));
    ((__nv_bfloat162*)hi)[2*i]   = __halves2bfloat162(h0, h1);
    ((__nv_bfloat162*)hi)[2*i+1] = __halves2bfloat162(h2, h3);
    ((__nv_bfloat162*)lo)[2*i]   = __halves2bfloat162(l0, l1);
    ((__nv_bfloat162*)lo)[2*i+1] = __halves2bfloat162(l2, l3);
}

// ---------------- embeddings + LN (emits planes) ----------------
__global__ void embed_ln_kernel(const int* __restrict__ ids, const int* __restrict__ tt,
                                const float* __restrict__ wemb, const float* __restrict__ temb,
                                const float* __restrict__ pemb,
                                const float* __restrict__ lns, const float* __restrict__ lnb,
                                __nv_bfloat16* __restrict__ hi, __nv_bfloat16* __restrict__ lo) {
    int tok = blockIdx.x;
    int pos = tok % Sx;
    const float* w = wemb + (size_t)ids[tok] * Dx;
    const float* t = temb + (size_t)tt[tok] * Dx;
    const float* p = pemb + (size_t)pos * Dx;
    __shared__ float buf[Dx];
    float ls = 0.f, lq = 0.f;
    for (int i = threadIdx.x; i < Dx; i += blockDim.x) {
        float x = w[i] + t[i] + p[i];
        buf[i] = x; ls += x; lq += x * x;
    }
    float sum = blk_sum(ls);
    float sq  = blk_sum(lq);
    float mu = sum * (1.f / Dx);
    float var = sq * (1.f / Dx) - mu * mu;
    float inv = rsqrtf(var + 1e-12f);
    for (int i = threadIdx.x; i < Dx; i += blockDim.x) {
        float y = lns[i] * (buf[i] - mu) * inv + lnb[i];
        size_t idx = (size_t)tok * Dx + i;
        g_h[idx] = y;
        split_store(y, hi + idx, lo + idx);
    }
}

// ---------------- residual add + LN (emits planes) ----------
__global__ void add_ln_kernel(float* __restrict__ h, const float* __restrict__ r,
                              const float* __restrict__ lns, const float* __restrict__ lnb,
                              __nv_bfloat16* __restrict__ hi, __nv_bfloat16* __restrict__ lo) {
    int tok = blockIdx.x;
    __shared__ float buf[Dx];
    float ls = 0.f, lq = 0.f;
    for (int i = threadIdx.x; i < Dx; i += blockDim.x) {
        float x = h[(size_t)tok * Dx + i] + r[(size_t)tok * Dx + i];
        buf[i] = x; ls += x; lq += x * x;
    }
    float sum = blk_sum(ls);
    float sq  = blk_sum(lq);
    float mu = sum * (1.f / Dx);
    float var = sq * (1.f / Dx) - mu * mu;
    float inv = rsqrtf(var + 1e-12f);
    for (int i = threadIdx.x; i < Dx; i += blockDim.x) {
        float y = lns[i] * (buf[i] - mu) * inv + lnb[i];
        size_t idx = (size_t)tok * Dx + i;
        h[idx] = y;
        split_store(y, hi + idx, lo + idx);
    }
}

// ---------------- tensor-core primitives ----------------
__device__ __forceinline__ void ldsm_x4(uint32_t* r, uint32_t addr) {
    asm volatile("ldmatrix.sync.aligned.m8n8.x4.shared.b16 {%0,%1,%2,%3}, [%4];"
                 : "=r"(r[0]), "=r"(r[1]), "=r"(r[2]), "=r"(r[3]) : "r"(addr));
}
__device__ __forceinline__ void ldsm_x4t(uint32_t* r, uint32_t addr) {
    asm volatile("ldmatrix.sync.aligned.m8n8.x4.trans.shared.b16 {%0,%1,%2,%3}, [%4];"
                 : "=r"(r[0]), "=r"(r[1]), "=r"(r[2]), "=r"(r[3]) : "r"(addr));
}
__device__ __forceinline__ void mma_bf16(float* c, const uint32_t* a, uint32_t b0, uint32_t b1) {
    asm volatile("mma.sync.aligned.m16n8k16.row.col.f32.bf16.bf16.f32 "
                 "{%0,%1,%2,%3}, {%4,%5,%6,%7}, {%8,%9}, {%0,%1,%2,%3};"
                 : "+f"(c[0]), "+f"(c[1]), "+f"(c[2]), "+f"(c[3])
                 : "r"(a[0]), "r"(a[1]), "r"(a[2]), "r"(a[3]), "r"(b0), "r"(b1));
}
__device__ __forceinline__ void cp16(void* dst, const void* src) {
    uint32_t d = (uint32_t)__cvta_generic_to_shared(dst);
    asm volatile("cp.async.cg.shared.global [%0], [%1], 16;" :: "r"(d), "l"(src));
}

// ---------------- dense GEMM (bf16 hi/lo planes, single-sync pipeline) ------
#define STAGE_ELT 18944
#define OFF_AL 5120
#define OFF_BH 10240
#define OFF_BL 14592
#define SMEM_BYTES (2 * STAGE_ELT * 2)

__device__ __forceinline__ void load_stage(
    __nv_bfloat16* sm, int s, int k0, int tid, int byb, int bxb,
    const __nv_bfloat16* Ahg, const __nv_bfloat16* Alg,
    const __nv_bfloat16* Whg, const __nv_bfloat16* Wlg, int N, int K)
{
    __nv_bfloat16* base = sm + s * STAGE_ELT;
    #pragma unroll
    for (int i = 0; i < 2; i++) {
        int idx = tid + i * 256;
        int rA = idx >> 2, cA = (idx & 3) * 8;
        size_t ga = (size_t)(byb * 128 + rA) * K + k0 + cA;
        cp16(base + rA * 40 + cA, Ahg + ga);
        cp16(base + OFF_AL + rA * 40 + cA, Alg + ga);
        int rB = idx >> 4, cB = (idx & 15) * 8;
        size_t gb = (size_t)(k0 + rB) * N + bxb * 128 + cB;
        cp16(base + OFF_BH + rB * 136 + cB, Whg + gb);
        cp16(base + OFF_BL + rB * 136 + cB, Wlg + gb);
    }
    asm volatile("cp.async.commit_group;");
}

template<int MODE>
__device__ __forceinline__ void gemm_body(
    const __nv_bfloat16* __restrict__ Ahg, const __nv_bfloat16* __restrict__ Alg,
    const __nv_bfloat16* __restrict__ Whg, const __nv_bfloat16* __restrict__ Wlg,
    const float* __restrict__ bias, float* __restrict__ C,
    __nv_bfloat16* __restrict__ Chi, __nv_bfloat16* __restrict__ Clo,
    int M, int N, int K, int bxb, int byb, __nv_bfloat16* sm)
{
    const int tid = threadIdx.x;
    const int lane = tid & 31;
    const int wid = tid >> 5;
    const int warp_m = wid & 3;
    const int warp_n = wid >> 2;

    float acc[2][8][4];
    #pragma unroll
    for (int mt = 0; mt < 2; mt++) {
        #pragma unroll
        for (int nt = 0; nt < 8; nt++) {
            acc[mt][nt][0] = 0.f; acc[mt][nt][1] = 0.f;
            acc[mt][nt][2] = 0.f; acc[mt][nt][3] = 0.f;
        }
    }

    const int a_tile = lane >> 3;
    const int a_rl = lane & 7;
    const int a_ldrow = warp_m * 32 + (a_tile & 1) * 8 + a_rl;
    const int a_ldcol = (a_tile >> 1) * 8;
    const int b_ldk = (a_tile & 1) * 8 + a_rl;
    const int b_ldn = warp_n * 64 + (a_tile >> 1) * 8;

    const int nk = K >> 5;
    load_stage(sm, 0, 0, tid, byb, bxb, Ahg, Alg, Whg, Wlg, N, K);

    for (int kt = 0; kt < nk; kt++) {
        const int s = kt & 1;
        asm volatile("cp.async.wait_group 0;");
        __syncthreads();
        // all warps finished reading buffer s^1 (their kt-1 compute) -> safe to refill it
        if (kt + 1 < nk)
            load_stage(sm, s ^ 1, (kt + 1) * 32, tid, byb, bxb, Ahg, Alg, Whg, Wlg, N, K);

        __nv_bfloat16* Ahs = sm + s * STAGE_ELT;
        __nv_bfloat16* Als = Ahs + OFF_AL;
        __nv_bfloat16* Bhs = sm + s * STAGE_ELT + OFF_BH;
        __nv_bfloat16* Bls = sm + s * STAGE_ELT + OFF_BL;

        #pragma unroll
        for (int kk = 0; kk < 32; kk += 16) {
            uint32_t ah0[4], ah1[4], al0[4], al1[4];
            ldsm_x4(ah0, (uint32_t)__cvta_generic_to_shared(Ahs + a_ldrow * 40 + a_ldcol + kk));
            ldsm_x4(ah1, (uint32_t)__cvta_generic_to_shared(Ahs + (a_ldrow + 16) * 40 + a_ldcol + kk));
            ldsm_x4(al0, (uint32_t)__cvta_generic_to_shared(Als + a_ldrow * 40 + a_ldcol + kk));
            ldsm_x4(al1, (uint32_t)__cvta_generic_to_shared(Als + (a_ldrow + 16) * 40 + a_ldcol + kk));
            #pragma unroll
            for (int p = 0; p < 4; p++) {
                uint32_t bh4[4], bl4[4];
                ldsm_x4t(bh4, (uint32_t)__cvta_generic_to_shared(Bhs + (kk + b_ldk) * 136 + b_ldn + p * 16));
                ldsm_x4t(bl4, (uint32_t)__cvta_generic_to_shared(Bls + (kk + b_ldk) * 136 + b_ldn + p * 16));
                int nt0 = p * 2;
                int nt1 = p * 2 + 1;
                mma_bf16(acc[0][nt0], ah0, bh4[0], bh4[1]);
                mma_bf16(acc[0][nt0], ah0, bl4[0], bl4[1]);
                mma_bf16(acc[0][nt0], al0, bh4[0], bh4[1]);
                mma_bf16(acc[0][nt1], ah0, bh4[2], bh4[3]);
                mma_bf16(acc[0][nt1], ah0, bl4[2], bl4[3]);
                mma_bf16(acc[0][nt1], al0, bh4[2], bh4[3]);
                mma_bf16(acc[1][nt0], ah1, bh4[0], bh4[1]);
                mma_bf16(acc[1][nt0], ah1, bl4[0], bl4[1]);
                mma_bf16(acc[1][nt0], al1, bh4[0], bh4[1]);
                mma_bf16(acc[1][nt1], ah1, bh4[2], bh4[3]);
                mma_bf16(acc[1][nt1], ah1, bl4[2], bl4[3]);
                mma_bf16(acc[1][nt1], al1, bh4[2], bh4[3]);
            }
        }
    }

    const int grp = lane >> 2;
    const int tig = lane & 3;
    #pragma unroll
    for (int mt = 0; mt < 2; mt++) {
        #pragma unroll
        for (int nt = 0; nt < 8; nt++) {
            int col = bxb * 128 + warp_n * 64 + nt * 8 + tig * 2;
            float b0 = bias[col];
            float b1 = bias[col + 1];
            #pragma unroll
            for (int half = 0; half < 2; half++) {
                int row = byb * 128 + warp_m * 32 + mt * 16 + grp + half * 8;
                float v0 = acc[mt][nt][half * 2 + 0] + b0;
                float v1 = acc[mt][nt][half * 2 + 1] + b1;
                if (MODE == 3) {
                    v0 = 0.5f * v0 * (1.f + erff(v0 * 0.70710678118654752f));
                    v1 = 0.5f * v1 * (1.f + erff(v1 * 0.70710678118654752f));
                }
                if (MODE == 2 || MODE == 3) {
                    __nv_bfloat16 h0 = __float2bfloat16_rn(v0);
                    __nv_bfloat16 h1 = __float2bfloat16_rn(v1);
                    __nv_bfloat16 l0 = __float2bfloat16_rn(v0 - __bfloat162float(h0));
                    __nv_bfloat16 l1 = __float2bfloat16_rn(v1 - __bfloat162float(h1));
                    *(__nv_bfloat162*)&Chi[(size_t)row * N + col] = __halves2bfloat162(h0, h1);
                    *(__nv_bfloat162*)&Clo[(size_t)row * N + col] = __halves2bfloat162(l0, l1);
                } else {
                    C[(size_t)row * N + col] = v0;
                    C[(size_t)row * N + col + 1] = v1;
                }
            }
        }
    }
}

template<int MODE>
__global__ void __launch_bounds__(256, 2) bgemm2_kernel(
    const __nv_bfloat16* __restrict__ Ahg, const __nv_bfloat16* __restrict__ Alg,
    const __nv_bfloat16* __restrict__ Whg, const __nv_bfloat16* __restrict__ Wlg,
    const float* __restrict__ bias, float* __restrict__ C,
    __nv_bfloat16* __restrict__ Chi, __nv_bfloat16* __restrict__ Clo,
    int M, int N, int K)
{
    extern __shared__ __align__(16) __nv_bfloat16 sm[];
    gemm_body<MODE>(Ahg, Alg, Whg, Wlg, bias, C, Chi, Clo, M, N, K,
                    blockIdx.x, blockIdx.y, sm);
}

__global__ void __launch_bounds__(256, 2) qkv_gemm_kernel(
    const __nv_bfloat16* __restrict__ Ahg, const __nv_bfloat16* __restrict__ Alg,
    const __nv_bfloat16* __restrict__ Whg, const __nv_bfloat16* __restrict__ Wlg,
    const float* __restrict__ bq, const float* __restrict__ bk, const float* __restrict__ bv,
    __nv_bfloat16* __restrict__ qhi, __nv_bfloat16* __restrict__ qlo,
    __nv_bfloat16* __restrict__ khi, __nv_bfloat16* __restrict__ klo,
    __nv_bfloat16* __restrict__ vhi, __nv_bfloat16* __restrict__ vlo)
{
    extern __shared__ __align__(16) __nv_bfloat16 sm[];
    int z = blockIdx.z;
    size_t woff = (size_t)z * Dx * Dx;
    const float* bias = (z == 0) ? bq : (z == 1) ? bk : bv;
    __nv_bfloat16* chi = (z == 0) ? qhi : (z == 1) ? khi : vhi;
    __nv_bfloat16* clo = (z == 0) ? qlo : (z == 1) ? klo : vlo;
    gemm_body<2>(Ahg, Alg, Whg + woff, Wlg + woff, bias, nullptr, chi, clo,
                 TOK, Dx, Dx, blockIdx.x, blockIdx.y, sm);
}

// ---------------- helpers ----------------
__device__ __forceinline__ int mid_block_idx(int n, int g, const int* __restrict__ randb) {
    if (g == 0) return 0;
    if (g == 1) return NBx - 1;
    if (g < 5)  return n - 3 + g;
    return randb[(n - 1) * Rx + (g - 5)];
}

__device__ __forceinline__ void load_tile64(
    __nv_bfloat16 (*dst)[72], const __nv_bfloat16* __restrict__ src, int gstride, int tid)
{
    #pragma unroll
    for (int i = 0; i < 2; i++) {
        int idx = tid + i * 256;
        int r = idx >> 3, c = (idx & 7) * 8;
        *(uint4*)&dst[r][c] = *(const uint4*)(src + (size_t)r * gstride + c);
    }
}

// ---------------- fused middle-block attention ----------------
#define SROW 516
#define MID_SMEM (64 * SROW * 4 + 4 * 64 * 72 * 2)

__global__ void __launch_bounds__(256, 1) mid_fused_kernel(
    const __nv_bfloat16* __restrict__ qhi, const __nv_bfloat16* __restrict__ qlo,
    const __nv_bfloat16* __restrict__ khi, const __nv_bfloat16* __restrict__ klo,
    const __nv_bfloat16* __restrict__ vhi, const __nv_bfloat16* __restrict__ vlo,
    const int* __restrict__ randb, const int* __restrict__ amask,
    __nv_bfloat16* __restrict__ chi, __nv_bfloat16* __restrict__ clo)
{
    extern __shared__ __align__(16) char smraw[];
    float (*Sf)[SROW] = (float(*)[SROW])smraw;
    __nv_bfloat16 (*Qh)[72] = (__nv_bfloat16(*)[72])(smraw + 64 * SROW * 4);
    __nv_bfloat16 (*Ql)[72] = (__nv_bfloat16(*)[72])(smraw + 64 * SROW * 4 + 9216);
    __nv_bfloat16 (*Kh)[72] = (__nv_bfloat16(*)[72])(smraw + 64 * SROW * 4 + 18432);
    __nv_bfloat16 (*Kl)[72] = (__nv_bfloat16(*)[72])(smraw + 64 * SROW * 4 + 27648);

    int n = blockIdx.x + 1, h = blockIdx.y, b = blockIdx.z;
    int tid = threadIdx.x, lane = tid & 31, wid = tid >> 5;
    int warp_m = wid & 3, warp_n = wid >> 2;

    const int tile = lane >> 3;
    const int rl = lane & 7;
    const int ldrow = (tile & 1) * 8 + rl;
    const int ldcol = (tile >> 1) * 8;
    const int b_ldk = (tile & 1) * 8 + rl;
    const int b_ldn = (tile >> 1) * 8;

    size_t qoff = ((size_t)b * Sx + n * 64) * Dx + h * 64;
    load_tile64(Qh, qhi + qoff, Dx, tid);
    load_tile64(Ql, qlo + qoff, Dx, tid);

    // --- phase 1: scores into Sf ---
    for (int g = 0; g < NGx; g++) {
        int kb = mid_block_idx(n, g, randb);
        size_t koff = ((size_t)b * Sx + kb * 64) * Dx + h * 64;
        __syncthreads();
        load_tile64(Kh, khi + koff, Dx, tid);
        load_tile64(Kl, klo + koff, Dx, tid);
        __syncthreads();

        float acc[4][4];
        #pragma unroll
        for (int j = 0; j < 4; j++) {
            acc[j][0] = 0.f; acc[j][1] = 0.f; acc[j][2] = 0.f; acc[j][3] = 0.f;
        }
        #pragma unroll
        for (int kk = 0; kk < 64; kk += 16) {
            uint32_t ah[4], al[4];
            ldsm_x4(ah, (uint32_t)__cvta_generic_to_shared(&Qh[warp_m * 16 + ldrow][ldcol + kk]));
            ldsm_x4(al, (uint32_t)__cvta_generic_to_shared(&Ql[warp_m * 16 + ldrow][ldcol + kk]));
            #pragma unroll
            for (int j2 = 0; j2 < 2; j2++) {
                int n0 = warp_n * 32 + j2 * 16;
                uint32_t bh[4], bl[4];
                ldsm_x4(bh, (uint32_t)__cvta_generic_to_shared(&Kh[n0 + ldrow][ldcol + kk]));
                ldsm_x4(bl, (uint32_t)__cvta_generic_to_shared(&Kl[n0 + ldrow][ldcol + kk]));
                mma_bf16(acc[j2 * 2 + 0], ah, bh[0], bh[2]);
                mma_bf16(acc[j2 * 2 + 0], ah, bl[0], bl[2]);
                mma_bf16(acc[j2 * 2 + 0], al, bh[0], bh[2]);
                mma_bf16(acc[j2 * 2 + 1], ah, bh[1], bh[3]);
                mma_bf16(acc[j2 * 2 + 1], ah, bl[1], bl[3]);
                mma_bf16(acc[j2 * 2 + 1], al, bh[1], bh[3]);
            }
        }
        int r0 = warp_m * 16 + (lane >> 2);
        int mask_base = b * Sx + kb * 64;
        #pragma unroll
        for (int j = 0; j < 4; j++) {
            int ki = warp_n * 32 + j * 8 + (lane & 3) * 2;
            float m0 = (1.0f - (float)amask[mask_base + ki]) * -1e9f;
            float m1 = (1.0f - (float)amask[mask_base + ki + 1]) * -1e9f;
            Sf[r0][g * 64 + ki]           = acc[j][0] * 0.125f + m0;
            Sf[r0][g * 64 + ki + 1]       = acc[j][1] * 0.125f + m1;
            Sf[r0 + 8][g * 64 + ki]       = acc[j][2] * 0.125f + m0;
            Sf[r0 + 8][g * 64 + ki + 1]   = acc[j][3] * 0.125f + m1;
        }
    }
    __syncthreads();

    // --- phase 2: softmax rows in place (fexp on the FMA pipe) ---
    for (int rr = 0; rr < 8; rr++) {
        int row = wid * 8 + rr;
        float v[16];
        float m = -3.4e38f;
        #pragma unroll
        for (int j = 0; j < 16; j++) {
            v[j] = Sf[row][lane + 32 * j];
            m = fmaxf(m, v[j]);
        }
        #pragma unroll
        for (int o = 16; o; o >>= 1) m = fmaxf(m, __shfl_xor_sync(0xffffffffu, m, o));
        float s = 0.f;
        #pragma unroll
        for (int j = 0; j < 16; j++) { v[j] = fexp(v[j] - m); s += v[j]; }
        #pragma unroll
        for (int o = 16; o; o >>= 1) s += __shfl_xor_sync(0xffffffffu, s, o);
        float inv = 1.f / s;
        #pragma unroll
        for (int j = 0; j < 16; j++) Sf[row][lane + 32 * j] = v[j] * inv;
    }
    __syncthreads();

    // --- phase 3: PV (P fragments built on the fly from Sf) ---
    float acc[4][4];
    #pragma unroll
    for (int j = 0; j < 4; j++) {
        acc[j][0] = 0.f; acc[j][1] = 0.f; acc[j][2] = 0.f; acc[j][3] = 0.f;
    }
    int pr = warp_m * 16 + (lane >> 2);
    for (int g = 0; g < NGx; g++) {
        int kb = mid_block_idx(n, g, randb);
        size_t voff = ((size_t)b * Sx + kb * 64) * Dx + h * 64;
        __syncthreads();
        load_tile64(Kh, vhi + voff, Dx, tid);
        load_tile64(Kl, vlo + voff, Dx, tid);
        __syncthreads();
        #pragma unroll
        for (int kk = 0; kk < 64; kk += 16) {
            int cc = g * 64 + kk + (lane & 3) * 2;
            float2 p00 = *(const float2*)&Sf[pr][cc];
            float2 p10 = *(const float2*)&Sf[pr + 8][cc];
            float2 p01 = *(const float2*)&Sf[pr][cc + 8];
            float2 p11 = *(const float2*)&Sf[pr + 8][cc + 8];
            uint32_t ah[4], al[4];
            pack2(p00.x, p00.y, ah[0], al[0]);
            pack2(p10.x, p10.y, ah[1], al[1]);
            pack2(p01.x, p01.y, ah[2], al[2]);
            pack2(p11.x, p11.y, ah[3], al[3]);
            #pragma unroll
            for (int j2 = 0; j2 < 2; j2++) {
                int n0 = warp_n * 32 + j2 * 16;
                uint32_t bh4[4], bl4[4];
                ldsm_x4t(bh4, (uint32_t)__cvta_generic_to_shared(&Kh[kk + b_ldk][n0 + b_ldn]));
                ldsm_x4t(bl4, (uint32_t)__cvta_generic_to_shared(&Kl[kk + b_ldk][n0 + b_ldn]));
                mma_bf16(acc[j2 * 2 + 0], ah, bh4[0], bh4[1]);
                mma_bf16(acc[j2 * 2 + 0], ah, bl4[0], bl4[1]);
                mma_bf16(acc[j2 * 2 + 0], al, bh4[0], bh4[1]);
                mma_bf16(acc[j2 * 2 + 1], ah, bh4[2], bh4[3]);
                mma_bf16(acc[j2 * 2 + 1], ah, bl4[2], bl4[3]);
                mma_bf16(acc[j2 * 2 + 1], al, bh4[2], bh4[3]);
            }
        }
    }

    size_t cb = ((size_t)b * Sx + n * 64) * Dx + h * 64;
    #pragma unroll
    for (int j = 0; j < 4; j++) {
        int col = warp_n * 32 + j * 8 + (lane & 3) * 2;
        split_store(acc[j][0], chi + cb + (size_t)pr * Dx + col,           clo + cb + (size_t)pr * Dx + col);
        split_store(acc[j][1], chi + cb + (size_t)pr * Dx + col + 1,       clo + cb + (size_t)pr * Dx + col + 1);
        split_store(acc[j][2], chi + cb + (size_t)(pr + 8) * Dx + col,     clo + cb + (size_t)(pr + 8) * Dx + col);
        split_store(acc[j][3], chi + cb + (size_t)(pr + 8) * Dx + col + 1, clo + cb + (size_t)(pr + 8) * Dx + col + 1);
    }
}

// ---------------- edge scores ----------------
__device__ __forceinline__ void score_tile(
    const __nv_bfloat16 (*Qh)[72], const __nv_bfloat16 (*Ql)[72],
    const __nv_bfloat16 (*Kh)[72], const __nv_bfloat16 (*Kl)[72],
    const int* __restrict__ amask, int mask_base,
    float* __restrict__ out, int ostride, int ocol0,
    int lane, int warp_m, int warp_n)
{
    const int tile = lane >> 3;
    const int rl = lane & 7;
    const int ldrow = (tile & 1) * 8 + rl;
    const int ldcol = (tile >> 1) * 8;

    float acc[4][4];
    #pragma unroll
    for (int j = 0; j < 4; j++) {
        acc[j][0] = 0.f; acc[j][1] = 0.f; acc[j][2] = 0.f; acc[j][3] = 0.f;
    }

    #pragma unroll
    for (int kk = 0; kk < 64; kk += 16) {
        uint32_t ah[4], al[4];
        ldsm_x4(ah, (uint32_t)__cvta_generic_to_shared(&Qh[warp_m * 16 + ldrow][ldcol + kk]));
        ldsm_x4(al, (uint32_t)__cvta_generic_to_shared(&Ql[warp_m * 16 + ldrow][ldcol + kk]));
        #pragma unroll
        for (int j2 = 0; j2 < 2; j2++) {
            int n0 = warp_n * 32 + j2 * 16;
            uint32_t bh[4], bl[4];
            ldsm_x4(bh, (uint32_t)__cvta_generic_to_shared(&Kh[n0 + ldrow][ldcol + kk]));
            ldsm_x4(bl, (uint32_t)__cvta_generic_to_shared(&Kl[n0 + ldrow][ldcol + kk]));
            mma_bf16(acc[j2 * 2 + 0], ah, bh[0], bh[2]);
            mma_bf16(acc[j2 * 2 + 0], ah, bl[0], bl[2]);
            mma_bf16(acc[j2 * 2 + 0], al, bh[0], bh[2]);
            mma_bf16(acc[j2 * 2 + 1], ah, bh[1], bh[3]);
            mma_bf16(acc[j2 * 2 + 1], ah, bl[1], bl[3]);
            mma_bf16(acc[j2 * 2 + 1], al, bh[1], bh[3]);
        }
    }

    int r0 = warp_m * 16 + (lane >> 2);
    #pragma unroll
    for (int j = 0; j < 4; j++) {
        int ki = warp_n * 32 + j * 8 + (lane & 3) * 2;
        float m0 = (1.0f - (float)amask[mask_base + ki]) * -1e9f;
        float m1 = (1.0f - (float)amask[mask_base + ki + 1]) * -1e9f;
        out[(size_t)r0 * ostride + ocol0 + ki]           = acc[j][0] * 0.125f + m0;
        out[(size_t)r0 * ostride + ocol0 + ki + 1]       = acc[j][1] * 0.125f + m1;
        out[(size_t)(r0 + 8) * ostride + ocol0 + ki]     = acc[j][2] * 0.125f + m0;
        out[(size_t)(r0 + 8) * ostride + ocol0 + ki + 1] = acc[j][3] * 0.125f + m1;
    }
}

__device__ __forceinline__ void pv_tile(
    const __nv_bfloat16 (*Ph)[72], const __nv_bfloat16 (*Pl)[72],
    const __nv_bfloat16 (*Vh)[72], const __nv_bfloat16 (*Vl)[72],
    float acc[4][4], int lane, int warp_m, int warp_n)
{
    const int tile = lane >> 3;
    const int rl = lane & 7;
    const int ldrow = (tile & 1) * 8 + rl;
    const int ldcol = (tile >> 1) * 8;
    const int b_ldk = (tile & 1) * 8 + rl;
    const int b_ldn = (tile >> 1) * 8;

    #pragma unroll
    for (int kk = 0; kk < 64; kk += 16) {
        uint32_t ah[4], al[4];
        ldsm_x4(ah, (uint32_t)__cvta_generic_to_shared(&Ph[warp_m * 16 + ldrow][ldcol + kk]));
        ldsm_x4(al, (uint32_t)__cvta_generic_to_shared(&Pl[warp_m * 16 + ldrow][ldcol + kk]));
        #pragma unroll
        for (int j2 = 0; j2 < 2; j2++) {
            int n0 = warp_n * 32 + j2 * 16;
            uint32_t bh4[4], bl4[4];
            ldsm_x4t(bh4, (uint32_t)__cvta_generic_to_shared(&Vh[kk + b_ldk][n0 + b_ldn]));
            ldsm_x4t(bl4, (uint32_t)__cvta_generic_to_shared(&Vl[kk + b_ldk][n0 + b_ldn]));
            mma_bf16(acc[j2 * 2 + 0], ah, bh4[0], bh4[1]);
            mma_bf16(acc[j2 * 2 + 0], ah, bl4[0], bl4[1]);
            mma_bf16(acc[j2 * 2 + 0], al, bh4[0], bh4[1]);
            mma_bf16(acc[j2 * 2 + 1], ah, bh4[2], bh4[3]);
            mma_bf16(acc[j2 * 2 + 1], ah, bl4[2], bl4[3]);
            mma_bf16(acc[j2 * 2 + 1], al, bh4[2], bh4[3]);
        }
    }
}

__global__ void __launch_bounds__(256) edge_scores_mma(
    const __nv_bfloat16* __restrict__ qhi, const __nv_bfloat16* __restrict__ qlo,
    const __nv_bfloat16* __restrict__ khi, const __nv_bfloat16* __restrict__ klo,
    const int* __restrict__ amask, float* __restrict__ sedge)
{
    int kb = blockIdx.x, h = blockIdx.y;
    int e = blockIdx.z & 1, b = blockIdx.z >> 1;
    int qb = e ? (NBx - 1) : 0;
    __shared__ __nv_bfloat16 Qh[64][72], Ql[64][72], Kh[64][72], Kl[64][72];
    int tid = threadIdx.x, lane = tid & 31, wid = tid >> 5;
    int warp_m = wid & 3, warp_n = wid >> 2;

    size_t qoff = ((size_t)b * Sx + qb * 64) * Dx + h * 64;
    size_t koff = ((size_t)b * Sx + kb * 64) * Dx + h * 64;
    load_tile64(Qh, qhi + qoff, Dx, tid);
    load_tile64(Ql, qlo + qoff, Dx, tid);
    load_tile64(Kh, khi + koff, Dx, tid);
    load_tile64(Kl, klo + koff, Dx, tid);
    __syncthreads();

    float* out = sedge + ((size_t)((b * NHx + h) * 2 + e)) * (64 * Sx);
    score_tile(Qh, Ql, Kh, Kl, amask, b * Sx + kb * 64,
               out, Sx, kb * 64, lane, warp_m, warp_n);
}

__global__ void __launch_bounds__(256) edge_pv_mma(
    const __nv_bfloat16* __restrict__ phi, const __nv_bfloat16* __restrict__ plo,
    const __nv_bfloat16* __restrict__ vhi, const __nv_bfloat16* __restrict__ vlo,
    float* __restrict__ ctx)
{
    int h = blockIdx.x;
    int e = blockIdx.y & 1, b = blockIdx.y >> 1;
    int chunk = blockIdx.z;
    int qb = e ? (NBx - 1) : 0;
    __shared__ __nv_bfloat16 Ph[64][72], Pl[64][72], Vh[64][72], Vl[64][72];
    int tid = threadIdx.x, lane = tid & 31, wid = tid >> 5;
    int warp_m = wid & 3, warp_n = wid >> 2;

    const __nv_bfloat16* prow_h = phi + ((size_t)((b * NHx + h) * 2 + e)) * (64 * Sx);
    const __nv_bfloat16* prow_l = plo + ((size_t)((b * NHx + h) * 2 + e)) * (64 * Sx);

    float acc[4][4];
    #pragma unroll
    for (int j = 0; j < 4; j++) {
        acc[j][0] = 0.f; acc[j][1] = 0.f; acc[j][2] = 0.f; acc[j][3] = 0.f;
    }

    for (int c8 = 0; c8 < 8; c8++) {
        int kb = chunk * 8 + c8;
        size_t voff = ((size_t)b * Sx + kb * 64) * Dx + h * 64;
        __syncthreads();
        load_tile64(Ph, prow_h + kb * 64, Sx, tid);
        load_tile64(Pl, prow_l + kb * 64, Sx, tid);
        load_tile64(Vh, vhi + voff, Dx, tid);
        load_tile64(Vl, vlo + voff, Dx, tid);
        __syncthreads();
        pv_tile(Ph, Pl, Vh, Vl, acc, lane, warp_m, warp_n);
    }

    float* cbase = ctx + ((size_t)b * Sx + qb * 64) * Dx + h * 64;
    int r0 = warp_m * 16 + (lane >> 2);
    #pragma unroll
    for (int j = 0; j < 4; j++) {
        int col = warp_n * 32 + j * 8 + (lane & 3) * 2;
        atomicAdd(&cbase[(size_t)r0 * Dx + col],           acc[j][0]);
        atomicAdd(&cbase[(size_t)r0 * Dx + col + 1],       acc[j][1]);
        atomicAdd(&cbase[(size_t)(r0 + 8) * Dx + col],     acc[j][2]);
        atomicAdd(&cbase[(size_t)(r0 + 8) * Dx + col + 1], acc[j][3]);
    }
}

__global__ void zero_edge_ctx(float* __restrict__ ctx) {
    int i = blockIdx.x * 256 + threadIdx.x;
    if (i >= Bx * 2 * 64 * Dx) return;
    int col = i % Dx;
    int t = i / Dx;
    int row = t % 64;  t /= 64;
    int e = t & 1;
    int b = t >> 1;
    int blk = e ? (NBx - 1) : 0;
    ctx[((size_t)b * Sx + blk * 64 + row) * Dx + col] = 0.f;
}

__global__ void split_edge_kernel(const float* __restrict__ ctx,
                                  __nv_bfloat16* __restrict__ hi,
                                  __nv_bfloat16* __restrict__ lo) {
    int i = blockIdx.x * 256 + threadIdx.x;
    if (i >= Bx * 2 * 64 * Dx) return;
    int col = i % Dx;
    int t = i / Dx;
    int row = t % 64;  t /= 64;
    int e = t & 1;
    int b = t >> 1;
    int blk = e ? (NBx - 1) : 0;
    size_t idx = ((size_t)b * Sx + blk * 64 + row) * Dx + col;
    split_store(ctx[idx], hi + idx, lo + idx);
}

// ---------------- row softmax -> bf16 hi/lo planes (edge) ----------------
__global__ void softmax_split_kernel(const float* __restrict__ s,
                                     __nv_bfloat16* __restrict__ phi,
                                     __nv_bfloat16* __restrict__ plo, int L) {
    extern __shared__ float buf[];
    size_t base = (size_t)blockIdx.x * L;
    float m = -3.4e38f;
    for (int i = threadIdx.x; i < L; i += blockDim.x) {
        float x = s[base + i];
        buf[i] = x;
        m = fmaxf(m, x);
    }
    m = blk_max(m);
    float lsum = 0.f;
    for (int i = threadIdx.x; i < L; i += blockDim.x) {
        float e = fexp(buf[i] - m);
        buf[i] = e;
        lsum += e;
    }
    float sum = blk_sum(lsum);
    float inv = 1.f / sum;
    for (int i = threadIdx.x; i < L; i += blockDim.x) {
        float p = buf[i] * inv;
        split_store(p, phi + base + i, plo + base + i);
    }
}

// ---------------- pooler ----------------
__global__ void pooler_kernel(const float* __restrict__ h, const float* __restrict__ pw,
                              const float* __restrict__ pb, float* __restrict__ out) {
    int j = blockIdx.x * blockDim.x + threadIdx.x;
    int b = blockIdx.y;
    if (j >= Dx) return;
    const float* hr = h + (size_t)b * Sx * Dx;
    float acc = pb[j];
    for (int kI = 0; kI < Dx; kI++) acc += hr[kI] * pw[(size_t)kI * Dx + j];
    out[b * Dx + j] = tanhf(acc);
}

// ---------------- host launcher ----------------
extern "C" void kernel_launch(void* const* d_in, const int* in_sizes, int n_in,
                              void* d_out, int out_size) {
    const int*   input_ids = (const int*)d_in[0];
    const int*   attn_mask = (const int*)d_in[1];
    const int*   tok_type  = (const int*)d_in[2];
    const int*   rand_blk  = (const int*)d_in[3];
    const float* word_emb  = (const float*)d_in[4];
    const float* type_emb  = (const float*)d_in[5];
    const float* pos_emb   = (const float*)d_in[6];
    const float* emb_ln_s  = (const float*)d_in[7];
    const float* emb_ln_b  = (const float*)d_in[8];
    const float* Wq = (const float*)d_in[9];  const float* bq = (const float*)d_in[10];
    const float* Wk = (const float*)d_in[11]; const float* bk = (const float*)d_in[12];
    const float* Wv = (const float*)d_in[13]; const float* bv = (const float*)d_in[14];
    const float* Wo = (const float*)d_in[15]; const float* bo = (const float*)d_in[16];
    const float* ln1_s = (const float*)d_in[17]; const float* ln1_b = (const float*)d_in[18];
    const float* W1 = (const float*)d_in[19]; const float* b1 = (const float*)d_in[20];
    const float* W2 = (const float*)d_in[21]; const float* b2 = (const float*)d_in[22];
    const float* ln2_s = (const float*)d_in[23]; const float* ln2_b = (const float*)d_in[24];
    const float* pool_w = (const float*)d_in[25]; const float* pool_b = (const float*)d_in[26];
    float* out = (float*)d_out;

    float *p_h = 0, *p_res = 0, *p_ctx = 0, *p_sedge = 0;
    __nv_bfloat16 *p_ahi = 0, *p_alo = 0, *p_ffh = 0, *p_ffl = 0, *p_whi = 0, *p_wlo = 0;
    __nv_bfloat16 *p_qhi = 0, *p_qlo = 0, *p_khi = 0, *p_klo = 0, *p_vhi = 0, *p_vlo = 0;
    __nv_bfloat16 *p_peh = 0, *p_pel = 0;
    cudaGetSymbolAddress((void**)&p_h,     g_h);
    cudaGetSymbolAddress((void**)&p_res,   g_res);
    cudaGetSymbolAddress((void**)&p_ctx,   g_ctx);
    cudaGetSymbolAddress((void**)&p_sedge, g_sedge);
    cudaGetSymbolAddress((void**)&p_ahi,   g_act_hi);
    cudaGetSymbolAddress((void**)&p_alo,   g_act_lo);
    cudaGetSymbolAddress((void**)&p_ffh,   g_ff_hi);
    cudaGetSymbolAddress((void**)&p_ffl,   g_ff_lo);
    cudaGetSymbolAddress((void**)&p_whi,   g_w_hi);
    cudaGetSymbolAddress((void**)&p_wlo,   g_w_lo);
    cudaGetSymbolAddress((void**)&p_qhi,   g_qhi);
    cudaGetSymbolAddress((void**)&p_qlo,   g_qlo);
    cudaGetSymbolAddress((void**)&p_khi,   g_khi);
    cudaGetSymbolAddress((void**)&p_klo,   g_klo);
    cudaGetSymbolAddress((void**)&p_vhi,   g_vhi);
    cudaGetSymbolAddress((void**)&p_vlo,   g_vlo);
    cudaGetSymbolAddress((void**)&p_peh,   g_pedge_hi);
    cudaGetSymbolAddress((void**)&p_pel,   g_pedge_lo);

    static bool attr_done = false;
    if (!attr_done) {
        cudaFuncSetAttribute(bgemm2_kernel<0>, cudaFuncAttributeMaxDynamicSharedMemorySize, SMEM_BYTES);
        cudaFuncSetAttribute(bgemm2_kernel<2>, cudaFuncAttributeMaxDynamicSharedMemorySize, SMEM_BYTES);
        cudaFuncSetAttribute(bgemm2_kernel<3>, cudaFuncAttributeMaxDynamicSharedMemorySize, SMEM_BYTES);
        cudaFuncSetAttribute(qkv_gemm_kernel, cudaFuncAttributeMaxDynamicSharedMemorySize, SMEM_BYTES);
        cudaFuncSetAttribute(mid_fused_kernel, cudaFuncAttributeMaxDynamicSharedMemorySize, MID_SMEM);
        attr_done = true;
    }

    const int M = TOK;
    const int nDD = Dx * Dx;
    const int nDF = Dx * FFx;

    auto split = [&](const float* src, __nv_bfloat16* hi, __nv_bfloat16* lo, int n) {
        split_kernel<<<(n / 4 + 255) / 256, 256>>>(src, hi, lo, n / 4);
    };

    embed_ln_kernel<<<TOK, 256>>>(input_ids, tok_type, word_emb, type_emb, pos_emb,
                                  emb_ln_s, emb_ln_b, p_ahi, p_alo);

    for (int l = 0; l < 2; l++) {
        const float* wq = Wq + (size_t)l * nDD;  const float* bql = bq + (size_t)l * Dx;
        const float* wk = Wk + (size_t)l * nDD;  const float* bkl = bk + (size_t)l * Dx;
        const float* wv = Wv + (size_t)l * nDD;  const float* bvl = bv + (size_t)l * Dx;
        const float* wo = Wo + (size_t)l * nDD;  const float* bol = bo + (size_t)l * Dx;
        const float* w1 = W1 + (size_t)l * nDF;  const float* b1l = b1 + (size_t)l * FFx;
        const float* w2 = W2 + (size_t)l * nDF;  const float* b2l = b2 + (size_t)l * Dx;
        const float* l1s = ln1_s + (size_t)l * Dx; const float* l1b = ln1_b + (size_t)l * Dx;
        const float* l2s = ln2_s + (size_t)l * Dx; const float* l2b = ln2_b + (size_t)l * Dx;

        // QKV: fused single launch (act planes current)
        split(wq, p_whi,           p_wlo,           nDD);
        split(wk, p_whi + nDD,     p_wlo + nDD,     nDD);
        split(wv, p_whi + 2 * nDD, p_wlo + 2 * nDD, nDD);
        qkv_gemm_kernel<<<dim3(Dx / 128, M / 128, 3), 256, SMEM_BYTES>>>(
            p_ahi, p_alo, p_whi, p_wlo, bql, bkl, bvl,
            p_qhi, p_qlo, p_khi, p_klo, p_vhi, p_vlo);

        // middle blocks: fused scores+softmax+PV
        mid_fused_kernel<<<dim3(NMID, NHx, Bx), 256, MID_SMEM>>>(
            p_qhi, p_qlo, p_khi, p_klo, p_vhi, p_vlo, rand_blk, attn_mask,
            p_ahi, p_alo);

        // edge blocks
        edge_scores_mma<<<dim3(NBx, NHx, Bx * 2), 256>>>(p_qhi, p_qlo, p_khi, p_klo,
                                                         attn_mask, p_sedge);
        softmax_split_kernel<<<Bx * NHx * 2 * BSx, 256, Sx * sizeof(float)>>>(
            p_sedge, p_peh, p_pel, Sx);
        zero_edge_ctx<<<(Bx * 2 * 64 * Dx + 255) / 256, 256>>>(p_ctx);
        edge_pv_mma<<<dim3(NHx, Bx * 2, 8), 256>>>(p_peh, p_pel, p_vhi, p_vlo, p_ctx);
        split_edge_kernel<<<(Bx * 2 * 64 * Dx + 255) / 256, 256>>>(p_ctx, p_ahi, p_alo);

        // O-projection + LN (LN emits act planes for FFN1)
        split(wo, p_whi, p_wlo, nDD);
        bgemm2_kernel<0><<<dim3(Dx / 128, M / 128), 256, SMEM_BYTES>>>(
            p_ahi, p_alo, p_whi, p_wlo, bol, p_res, nullptr, nullptr, M, Dx, Dx);
        add_ln_kernel<<<TOK, 256>>>(p_h, p_res, l1s, l1b, p_ahi, p_alo);

        // FFN
        split(w1, p_whi, p_wlo, nDF);
        bgemm2_kernel<3><<<dim3(FFx / 128, M / 128), 256, SMEM_BYTES>>>(
            p_ahi, p_alo, p_whi, p_wlo, b1l, nullptr, p_ffh, p_ffl, M, FFx, Dx);
        split(w2, p_whi, p_wlo, nDF);
        bgemm2_kernel<0><<<dim3(Dx / 128, M / 128), 256, SMEM_BYTES>>>(
            p_ffh, p_ffl, p_whi, p_wlo, b2l, p_res, nullptr, nullptr, M, Dx, FFx);
        add_ln_kernel<<<TOK, 256>>>(p_h, p_res, l2s, l2b, p_ahi, p_alo);
    }

    pooler_kernel<<<dim3((Dx + 127) / 128, Bx), 128>>>(p_h, pool_w, pool_b, out);
}

// round 12
// speedup vs baseline: 3.5273x; 1.2175x over previous
#include <cuda_runtime.h>
#include <cuda_bf16.h>
#include <cstdint>
#include <math.h>

#define Bx 2
#define Sx 4096
#define Dx 768
#define NHx 12
#define HDx 64
#define BSx 64
#define NBx 64
#define FFx 3072
#define Rx 3
#define NGx 8
#define NMID 62
#define TOK (Bx*Sx)

// ---------------- scratch ----------------
__device__ float g_h[(size_t)TOK*Dx];
__device__ float g_res[(size_t)TOK*Dx];
__device__ float g_ctx[(size_t)TOK*Dx];
__device__ float g_ff[(size_t)TOK*FFx];
__device__ float g_wt[(size_t)Dx*FFx];
__device__ float g_sedge[(size_t)Bx*NHx*2*BSx*Sx];
__device__ __nv_bfloat16 g_qhi[(size_t)TOK*Dx];
__device__ __nv_bfloat16 g_qlo[(size_t)TOK*Dx];
__device__ __nv_bfloat16 g_khi[(size_t)TOK*Dx];
__device__ __nv_bfloat16 g_klo[(size_t)TOK*Dx];
__device__ __nv_bfloat16 g_vhi[(size_t)TOK*Dx];
__device__ __nv_bfloat16 g_vlo[(size_t)TOK*Dx];
__device__ __nv_bfloat16 g_pedge_hi[(size_t)Bx*NHx*2*BSx*Sx];
__device__ __nv_bfloat16 g_pedge_lo[(size_t)Bx*NHx*2*BSx*Sx];

// ---------------- helpers ----------------
__device__ __forceinline__ float rna_tf32(float x) {
    uint32_t o;
    asm("cvt.rna.tf32.f32 %0, %1;" : "=r"(o) : "f"(x));
    return __uint_as_float(o);
}
__device__ __forceinline__ float fexp(float x) {
    x = fmaxf(x, -80.f);
    float t = fmaf(x, 1.4426950408889634f, 12582912.0f);
    float i = t - 12582912.0f;
    float f = fmaf(x, 1.4426950408889634f, -i);
    float pr = 1.5403530e-4f;
    pr = fmaf(pr, f, 1.3333558e-3f);
    pr = fmaf(pr, f, 9.6181291e-3f);
    pr = fmaf(pr, f, 5.5504109e-2f);
    pr = fmaf(pr, f, 2.4022651e-1f);
    pr = fmaf(pr, f, 6.9314718e-1f);
    pr = fmaf(pr, f, 1.0f);
    int ii = (int)i;
    float sc = __int_as_float((ii + 127) << 23);
    return pr * sc;
}

__device__ __forceinline__ float blk_sum(float v) {
    __shared__ float red[33];
    #pragma unroll
    for (int o = 16; o; o >>= 1) v += __shfl_down_sync(0xffffffffu, v, o);
    int lane = threadIdx.x & 31, w = threadIdx.x >> 5;
    __syncthreads();
    if (lane == 0) red[w] = v;
    __syncthreads();
    if (w == 0) {
        float x = (lane < ((blockDim.x + 31) >> 5)) ? red[lane] : 0.f;
        #pragma unroll
        for (int o = 16; o; o >>= 1) x += __shfl_down_sync(0xffffffffu, x, o);
        if (lane == 0) red[32] = x;
    }
    __syncthreads();
    return red[32];
}

__device__ __forceinline__ float blk_max(float v) {
    __shared__ float redm[33];
    #pragma unroll
    for (int o = 16; o; o >>= 1) v = fmaxf(v, __shfl_down_sync(0xffffffffu, v, o));
    int lane = threadIdx.x & 31, w = threadIdx.x >> 5;
    __syncthreads();
    if (lane == 0) redm[w] = v;
    __syncthreads();
    if (w == 0) {
        float x = (lane < ((blockDim.x + 31) >> 5)) ? redm[lane] : -3.4e38f;
        #pragma unroll
        for (int o = 16; o; o >>= 1) x = fmaxf(x, __shfl_down_sync(0xffffffffu, x, o));
        if (lane == 0) redm[32] = x;
    }
    __syncthreads();
    return redm[32];
}

__device__ __forceinline__ void split_store(float x, __nv_bfloat16* hi, __nv_bfloat16* lo) {
    __nv_bfloat16 h = __float2bfloat16_rn(x);
    *hi = h;
    *lo = __float2bfloat16_rn(x - __bfloat162float(h));
}
__device__ __forceinline__ void pack2(float x, float y, uint32_t& hi, uint32_t& lo) {
    __nv_bfloat16 h0 = __float2bfloat16_rn(x);
    __nv_bfloat16 h1 = __float2bfloat16_rn(y);
    __nv_bfloat16 l0 = __float2bfloat16_rn(x - __bfloat162float(h0));
    __nv_bfloat16 l1 = __float2bfloat16_rn(y - __bfloat162float(h1));
    __nv_bfloat162 hh = __halves2bfloat162(h0, h1);
    __nv_bfloat162 ll = __halves2bfloat162(l0, l1);
    hi = *(uint32_t*)&hh;
    lo = *(uint32_t*)&ll;
}

// ---------------- weight transpose + tf32 round: W[K][N] -> Wt[N][K] -------------
__global__ void trans_round_kernel(const float* __restrict__ in, float* __restrict__ out,
                                   int K, int N) {
    __shared__ float t[32][33];
    int n0 = blockIdx.x * 32, k0 = blockIdx.y * 32;
    int tx = threadIdx.x, ty = threadIdx.y;
    #pragma unroll
    for (int i = ty; i < 32; i += 8) t[i][tx] = in[(size_t)(k0 + i) * N + n0 + tx];
    __syncthreads();
    #pragma unroll
    for (int i = ty; i < 32; i += 8)
        out[(size_t)(n0 + i) * K + k0 + tx] = rna_tf32(t[tx][i]);
}

// ---------------- embeddings + LN (emits tf32-rounded fp32) ----------------
__global__ void embed_ln_kernel(const int* __restrict__ ids, const int* __restrict__ tt,
                                const float* __restrict__ wemb, const float* __restrict__ temb,
                                const float* __restrict__ pemb,
                                const float* __restrict__ lns, const float* __restrict__ lnb) {
    int tok = blockIdx.x;
    int pos = tok % Sx;
    const float* w = wemb + (size_t)ids[tok] * Dx;
    const float* t = temb + (size_t)tt[tok] * Dx;
    const float* p = pemb + (size_t)pos * Dx;
    __shared__ float buf[Dx];
    float ls = 0.f, lq = 0.f;
    for (int i = threadIdx.x; i < Dx; i += blockDim.x) {
        float x = w[i] + t[i] + p[i];
        buf[i] = x; ls += x; lq += x * x;
    }
    float sum = blk_sum(ls);
    float sq  = blk_sum(lq);
    float mu = sum * (1.f / Dx);
    float var = sq * (1.f / Dx) - mu * mu;
    float inv = rsqrtf(var + 1e-12f);
    for (int i = threadIdx.x; i < Dx; i += blockDim.x) {
        float y = lns[i] * (buf[i] - mu) * inv + lnb[i];
        g_h[(size_t)tok * Dx + i] = rna_tf32(y);
    }
}

// ---------------- residual add + LN ----------
__global__ void add_ln_kernel(float* __restrict__ h, const float* __restrict__ r,
                              const float* __restrict__ lns, const float* __restrict__ lnb) {
    int tok = blockIdx.x;
    __shared__ float buf[Dx];
    float ls = 0.f, lq = 0.f;
    for (int i = threadIdx.x; i < Dx; i += blockDim.x) {
        float x = h[(size_t)tok * Dx + i] + r[(size_t)tok * Dx + i];
        buf[i] = x; ls += x; lq += x * x;
    }
    float sum = blk_sum(ls);
    float sq  = blk_sum(lq);
    float mu = sum * (1.f / Dx);
    float var = sq * (1.f / Dx) - mu * mu;
    float inv = rsqrtf(var + 1e-12f);
    for (int i = threadIdx.x; i < Dx; i += blockDim.x) {
        float y = lns[i] * (buf[i] - mu) * inv + lnb[i];
        h[(size_t)tok * Dx + i] = rna_tf32(y);
    }
}

// ---------------- MMA primitives ----------------
__device__ __forceinline__ void ldsm_x4(uint32_t* r, uint32_t addr) {
    asm volatile("ldmatrix.sync.aligned.m8n8.x4.shared.b16 {%0,%1,%2,%3}, [%4];"
                 : "=r"(r[0]), "=r"(r[1]), "=r"(r[2]), "=r"(r[3]) : "r"(addr));
}
__device__ __forceinline__ void ldsm_x4t(uint32_t* r, uint32_t addr) {
    asm volatile("ldmatrix.sync.aligned.m8n8.x4.trans.shared.b16 {%0,%1,%2,%3}, [%4];"
                 : "=r"(r[0]), "=r"(r[1]), "=r"(r[2]), "=r"(r[3]) : "r"(addr));
}
__device__ __forceinline__ void mma_bf16(float* c, const uint32_t* a, uint32_t b0, uint32_t b1) {
    asm volatile("mma.sync.aligned.m16n8k16.row.col.f32.bf16.bf16.f32 "
                 "{%0,%1,%2,%3}, {%4,%5,%6,%7}, {%8,%9}, {%0,%1,%2,%3};"
                 : "+f"(c[0]), "+f"(c[1]), "+f"(c[2]), "+f"(c[3])
                 : "r"(a[0]), "r"(a[1]), "r"(a[2]), "r"(a[3]), "r"(b0), "r"(b1));
}
__device__ __forceinline__ void mma_tf32(float* c, const uint32_t* a, uint32_t b0, uint32_t b1) {
    asm volatile("mma.sync.aligned.m16n8k8.row.col.f32.tf32.tf32.f32 "
                 "{%0,%1,%2,%3}, {%4,%5,%6,%7}, {%8,%9}, {%0,%1,%2,%3};"
                 : "+f"(c[0]), "+f"(c[1]), "+f"(c[2]), "+f"(c[3])
                 : "r"(a[0]), "r"(a[1]), "r"(a[2]), "r"(a[3]), "r"(b0), "r"(b1));
}
__device__ __forceinline__ void cp16(void* dst, const void* src) {
    uint32_t d = (uint32_t)__cvta_generic_to_shared(dst);
    asm volatile("cp.async.cg.shared.global [%0], [%1], 16;" :: "r"(d), "l"(src));
}

// ---------------- TF32 dense GEMM ----------------
// C = act(A[M,K] @ Wt[N,K]^T + bias); A fp32 row-major (tf32-rounded), Wt fp32 [N][K].
// Tile 128x128x32; 256 threads = 8 warps (4M x 2N). MODE 0: fp32; 2: q/k/v planes; 3: GELU fp32.
#define TF_STRIDE 36
#define TF_STAGE (128 * TF_STRIDE * 2)
#define TF_OFF_B (128 * TF_STRIDE)
#define TF_SMEM_BYTES (2 * TF_STAGE * 4)

__device__ __forceinline__ void tf_load_stage(
    float* sm, int s, int k0, int tid, int m0, int n0,
    const float* __restrict__ A, const float* __restrict__ Bt, int K)
{
    float* st = sm + s * TF_STAGE;
    #pragma unroll
    for (int i = 0; i < 4; i++) {
        int idx = tid + i * 256;
        int r = idx >> 3, c = (idx & 7) * 4;
        cp16(st + r * TF_STRIDE + c, A + (size_t)(m0 + r) * K + k0 + c);
        cp16(st + TF_OFF_B + r * TF_STRIDE + c, Bt + (size_t)(n0 + r) * K + k0 + c);
    }
    asm volatile("cp.async.commit_group;");
}

template<int MODE>
__device__ __forceinline__ void tf_gemm_body(
    const float* __restrict__ A, const float* __restrict__ Bt,
    const float* __restrict__ bias, float* __restrict__ C,
    __nv_bfloat16* __restrict__ Chi, __nv_bfloat16* __restrict__ Clo,
    int M, int N, int K, int bxb, int byb, float* sm)
{
    const int tid = threadIdx.x;
    const int lane = tid & 31;
    const int wid = tid >> 5;
    const int warp_m = wid & 3;
    const int warp_n = wid >> 2;
    const int m0 = byb * 128;
    const int n0 = bxb * 128;

    float acc[2][8][4];
    #pragma unroll
    for (int mt = 0; mt < 2; mt++) {
        #pragma unroll
        for (int nt = 0; nt < 8; nt++) {
            acc[mt][nt][0] = 0.f; acc[mt][nt][1] = 0.f;
            acc[mt][nt][2] = 0.f; acc[mt][nt][3] = 0.f;
        }
    }

    const int phase = lane >> 3;
    const int rli = lane & 7;
    const int a_roff = (phase & 1) * 8 + rli;
    const int a_koff = (phase >> 1) * 4;
    const int b_roff = (phase >> 1) * 8 + rli;
    const int b_koff = (phase & 1) * 4;

    const int nk = K >> 5;
    tf_load_stage(sm, 0, 0, tid, m0, n0, A, Bt, K);

    for (int kt = 0; kt < nk; kt++) {
        const int s = kt & 1;
        asm volatile("cp.async.wait_group 0;");
        __syncthreads();
        if (kt + 1 < nk)
            tf_load_stage(sm, s ^ 1, (kt + 1) * 32, tid, m0, n0, A, Bt, K);

        float* stA = sm + s * TF_STAGE;
        float* stB = stA + TF_OFF_B;

        #pragma unroll
        for (int kk = 0; kk < 32; kk += 8) {
            uint32_t aa0[4], aa1[4];
            ldsm_x4(aa0, (uint32_t)__cvta_generic_to_shared(
                stA + (warp_m * 32 + a_roff) * TF_STRIDE + kk + a_koff));
            ldsm_x4(aa1, (uint32_t)__cvta_generic_to_shared(
                stA + (warp_m * 32 + 16 + a_roff) * TF_STRIDE + kk + a_koff));
            #pragma unroll
            for (int p = 0; p < 4; p++) {
                uint32_t bb[4];
                ldsm_x4(bb, (uint32_t)__cvta_generic_to_shared(
                    stB + (warp_n * 64 + p * 16 + b_roff) * TF_STRIDE + kk + b_koff));
                int nt0 = p * 2;
                int nt1 = p * 2 + 1;
                mma_tf32(acc[0][nt0], aa0, bb[0], bb[1]);
                mma_tf32(acc[0][nt1], aa0, bb[2], bb[3]);
                mma_tf32(acc[1][nt0], aa1, bb[0], bb[1]);
                mma_tf32(acc[1][nt1], aa1, bb[2], bb[3]);
            }
        }
    }

    const int grp = lane >> 2;
    const int tig = lane & 3;
    #pragma unroll
    for (int mt = 0; mt < 2; mt++) {
        #pragma unroll
        for (int nt = 0; nt < 8; nt++) {
            int col = n0 + warp_n * 64 + nt * 8 + tig * 2;
            float b0 = bias[col];
            float b1 = bias[col + 1];
            #pragma unroll
            for (int half = 0; half < 2; half++) {
                int row = m0 + warp_m * 32 + mt * 16 + grp + half * 8;
                float v0 = acc[mt][nt][half * 2 + 0] + b0;
                float v1 = acc[mt][nt][half * 2 + 1] + b1;
                if (MODE == 3) {
                    v0 = 0.5f * v0 * (1.f + erff(v0 * 0.70710678118654752f));
                    v1 = 0.5f * v1 * (1.f + erff(v1 * 0.70710678118654752f));
                }
                if (MODE == 2) {
                    __nv_bfloat16 h0 = __float2bfloat16_rn(v0);
                    __nv_bfloat16 h1 = __float2bfloat16_rn(v1);
                    __nv_bfloat16 l0 = __float2bfloat16_rn(v0 - __bfloat162float(h0));
                    __nv_bfloat16 l1 = __float2bfloat16_rn(v1 - __bfloat162float(h1));
                    *(__nv_bfloat162*)&Chi[(size_t)row * N + col] = __halves2bfloat162(h0, h1);
                    *(__nv_bfloat162*)&Clo[(size_t)row * N + col] = __halves2bfloat162(l0, l1);
                } else if (MODE == 3) {
                    C[(size_t)row * N + col]     = rna_tf32(v0);
                    C[(size_t)row * N + col + 1] = rna_tf32(v1);
                } else {
                    C[(size_t)row * N + col]     = v0;
                    C[(size_t)row * N + col + 1] = v1;
                }
            }
        }
    }
}

template<int MODE>
__global__ void __launch_bounds__(256, 2) tf_gemm_kernel(
    const float* __restrict__ A, const float* __restrict__ Bt,
    const float* __restrict__ bias, float* __restrict__ C,
    __nv_bfloat16* __restrict__ Chi, __nv_bfloat16* __restrict__ Clo,
    int M, int N, int K)
{
    extern __shared__ __align__(16) float sm[];
    tf_gemm_body<MODE>(A, Bt, bias, C, Chi, Clo, M, N, K, blockIdx.x, blockIdx.y, sm);
}

__global__ void __launch_bounds__(256, 2) tf_qkv_kernel(
    const float* __restrict__ A, const float* __restrict__ Bt,
    const float* __restrict__ bq, const float* __restrict__ bk, const float* __restrict__ bv,
    __nv_bfloat16* __restrict__ qhi, __nv_bfloat16* __restrict__ qlo,
    __nv_bfloat16* __restrict__ khi, __nv_bfloat16* __restrict__ klo,
    __nv_bfloat16* __restrict__ vhi, __nv_bfloat16* __restrict__ vlo)
{
    extern __shared__ __align__(16) float sm[];
    int z = blockIdx.z;
    size_t woff = (size_t)z * Dx * Dx;
    const float* bias = (z == 0) ? bq : (z == 1) ? bk : bv;
    __nv_bfloat16* chi = (z == 0) ? qhi : (z == 1) ? khi : vhi;
    __nv_bfloat16* clo = (z == 0) ? qlo : (z == 1) ? klo : vlo;
    tf_gemm_body<2>(A, Bt + woff, bias, nullptr, chi, clo,
                    TOK, Dx, Dx, blockIdx.x, blockIdx.y, sm);
}

// ---------------- attention helpers ----------------
__device__ __forceinline__ int mid_block_idx(int n, int g, const int* __restrict__ randb) {
    if (g == 0) return 0;
    if (g == 1) return NBx - 1;
    if (g < 5)  return n - 3 + g;
    return randb[(n - 1) * Rx + (g - 5)];
}

__device__ __forceinline__ void load_tile64(
    __nv_bfloat16 (*dst)[72], const __nv_bfloat16* __restrict__ src, int gstride, int tid)
{
    #pragma unroll
    for (int i = 0; i < 2; i++) {
        int idx = tid + i * 256;
        int r = idx >> 3, c = (idx & 7) * 8;
        *(uint4*)&dst[r][c] = *(const uint4*)(src + (size_t)r * gstride + c);
    }
}

// ---------------- fused middle-block attention (writes fp32 ctx) ----------------
#define SROW 516
#define MID_SMEM (64 * SROW * 4 + 4 * 64 * 72 * 2)

__global__ void __launch_bounds__(256, 1) mid_fused_kernel(
    const __nv_bfloat16* __restrict__ qhi, const __nv_bfloat16* __restrict__ qlo,
    const __nv_bfloat16* __restrict__ khi, const __nv_bfloat16* __restrict__ klo,
    const __nv_bfloat16* __restrict__ vhi, const __nv_bfloat16* __restrict__ vlo,
    const int* __restrict__ randb, const int* __restrict__ amask,
    float* __restrict__ ctx)
{
    extern __shared__ __align__(16) char smraw[];
    float (*Sf)[SROW] = (float(*)[SROW])smraw;
    __nv_bfloat16 (*Qh)[72] = (__nv_bfloat16(*)[72])(smraw + 64 * SROW * 4);
    __nv_bfloat16 (*Ql)[72] = (__nv_bfloat16(*)[72])(smraw + 64 * SROW * 4 + 9216);
    __nv_bfloat16 (*Kh)[72] = (__nv_bfloat16(*)[72])(smraw + 64 * SROW * 4 + 18432);
    __nv_bfloat16 (*Kl)[72] = (__nv_bfloat16(*)[72])(smraw + 64 * SROW * 4 + 27648);

    int n = blockIdx.x + 1, h = blockIdx.y, b = blockIdx.z;
    int tid = threadIdx.x, lane = tid & 31, wid = tid >> 5;
    int warp_m = wid & 3, warp_n = wid >> 2;

    const int tile = lane >> 3;
    const int rl = lane & 7;
    const int ldrow = (tile & 1) * 8 + rl;
    const int ldcol = (tile >> 1) * 8;
    const int b_ldk = (tile & 1) * 8 + rl;
    const int b_ldn = (tile >> 1) * 8;

    size_t qoff = ((size_t)b * Sx + n * 64) * Dx + h * 64;
    load_tile64(Qh, qhi + qoff, Dx, tid);
    load_tile64(Ql, qlo + qoff, Dx, tid);

    for (int g = 0; g < NGx; g++) {
        int kb = mid_block_idx(n, g, randb);
        size_t koff = ((size_t)b * Sx + kb * 64) * Dx + h * 64;
        __syncthreads();
        load_tile64(Kh, khi + koff, Dx, tid);
        load_tile64(Kl, klo + koff, Dx, tid);
        __syncthreads();

        float acc[4][4];
        #pragma unroll
        for (int j = 0; j < 4; j++) {
            acc[j][0] = 0.f; acc[j][1] = 0.f; acc[j][2] = 0.f; acc[j][3] = 0.f;
        }
        #pragma unroll
        for (int kk = 0; kk < 64; kk += 16) {
            uint32_t ah[4], al[4];
            ldsm_x4(ah, (uint32_t)__cvta_generic_to_shared(&Qh[warp_m * 16 + ldrow][ldcol + kk]));
            ldsm_x4(al, (uint32_t)__cvta_generic_to_shared(&Ql[warp_m * 16 + ldrow][ldcol + kk]));
            #pragma unroll
            for (int j2 = 0; j2 < 2; j2++) {
                int n0 = warp_n * 32 + j2 * 16;
                uint32_t bh[4], bl[4];
                ldsm_x4(bh, (uint32_t)__cvta_generic_to_shared(&Kh[n0 + ldrow][ldcol + kk]));
                ldsm_x4(bl, (uint32_t)__cvta_generic_to_shared(&Kl[n0 + ldrow][ldcol + kk]));
                mma_bf16(acc[j2 * 2 + 0], ah, bh[0], bh[2]);
                mma_bf16(acc[j2 * 2 + 0], ah, bl[0], bl[2]);
                mma_bf16(acc[j2 * 2 + 0], al, bh[0], bh[2]);
                mma_bf16(acc[j2 * 2 + 1], ah, bh[1], bh[3]);
                mma_bf16(acc[j2 * 2 + 1], ah, bl[1], bl[3]);
                mma_bf16(acc[j2 * 2 + 1], al, bh[1], bh[3]);
            }
        }
        int r0 = warp_m * 16 + (lane >> 2);
        int mask_base = b * Sx + kb * 64;
        #pragma unroll
        for (int j = 0; j < 4; j++) {
            int ki = warp_n * 32 + j * 8 + (lane & 3) * 2;
            float m0 = (1.0f - (float)amask[mask_base + ki]) * -1e9f;
            float m1 = (1.0f - (float)amask[mask_base + ki + 1]) * -1e9f;
            Sf[r0][g * 64 + ki]           = acc[j][0] * 0.125f + m0;
            Sf[r0][g * 64 + ki + 1]       = acc[j][1] * 0.125f + m1;
            Sf[r0 + 8][g * 64 + ki]       = acc[j][2] * 0.125f + m0;
            Sf[r0 + 8][g * 64 + ki + 1]   = acc[j][3] * 0.125f + m1;
        }
    }
    __syncthreads();

    for (int rr = 0; rr < 8; rr++) {
        int row = wid * 8 + rr;
        float v[16];
        float m = -3.4e38f;
        #pragma unroll
        for (int j = 0; j < 16; j++) {
            v[j] = Sf[row][lane + 32 * j];
            m = fmaxf(m, v[j]);
        }
        #pragma unroll
        for (int o = 16; o; o >>= 1) m = fmaxf(m, __shfl_xor_sync(0xffffffffu, m, o));
        float s = 0.f;
        #pragma unroll
        for (int j = 0; j < 16; j++) { v[j] = fexp(v[j] - m); s += v[j]; }
        #pragma unroll
        for (int o = 16; o; o >>= 1) s += __shfl_xor_sync(0xffffffffu, s, o);
        float inv = 1.f / s;
        #pragma unroll
        for (int j = 0; j < 16; j++) Sf[row][lane + 32 * j] = v[j] * inv;
    }
    __syncthreads();

    float acc[4][4];
    #pragma unroll
    for (int j = 0; j < 4; j++) {
        acc[j][0] = 0.f; acc[j][1] = 0.f; acc[j][2] = 0.f; acc[j][3] = 0.f;
    }
    int pr = warp_m * 16 + (lane >> 2);
    for (int g = 0; g < NGx; g++) {
        int kb = mid_block_idx(n, g, randb);
        size_t voff = ((size_t)b * Sx + kb * 64) * Dx + h * 64;
        __syncthreads();
        load_tile64(Kh, vhi + voff, Dx, tid);
        load_tile64(Kl, vlo + voff, Dx, tid);
        __syncthreads();
        #pragma unroll
        for (int kk = 0; kk < 64; kk += 16) {
            int cc = g * 64 + kk + (lane & 3) * 2;
            float2 p00 = *(const float2*)&Sf[pr][cc];
            float2 p10 = *(const float2*)&Sf[pr + 8][cc];
            float2 p01 = *(const float2*)&Sf[pr][cc + 8];
            float2 p11 = *(const float2*)&Sf[pr + 8][cc + 8];
            uint32_t ah[4], al[4];
            pack2(p00.x, p00.y, ah[0], al[0]);
            pack2(p10.x, p10.y, ah[1], al[1]);
            pack2(p01.x, p01.y, ah[2], al[2]);
            pack2(p11.x, p11.y, ah[3], al[3]);
            #pragma unroll
            for (int j2 = 0; j2 < 2; j2++) {
                int n0 = warp_n * 32 + j2 * 16;
                uint32_t bh4[4], bl4[4];
                ldsm_x4t(bh4, (uint32_t)__cvta_generic_to_shared(&Kh[kk + b_ldk][n0 + b_ldn]));
                ldsm_x4t(bl4, (uint32_t)__cvta_generic_to_shared(&Kl[kk + b_ldk][n0 + b_ldn]));
                mma_bf16(acc[j2 * 2 + 0], ah, bh4[0], bh4[1]);
                mma_bf16(acc[j2 * 2 + 0], ah, bl4[0], bl4[1]);
                mma_bf16(acc[j2 * 2 + 0], al, bh4[0], bh4[1]);
                mma_bf16(acc[j2 * 2 + 1], ah, bh4[2], bh4[3]);
                mma_bf16(acc[j2 * 2 + 1], ah, bl4[2], bl4[3]);
                mma_bf16(acc[j2 * 2 + 1], al, bh4[2], bh4[3]);
            }
        }
    }

    float* cbase = ctx + ((size_t)b * Sx + n * 64) * Dx + h * 64;
    #pragma unroll
    for (int j = 0; j < 4; j++) {
        int col = warp_n * 32 + j * 8 + (lane & 3) * 2;
        cbase[(size_t)pr * Dx + col]           = rna_tf32(acc[j][0]);
        cbase[(size_t)pr * Dx + col + 1]       = rna_tf32(acc[j][1]);
        cbase[(size_t)(pr + 8) * Dx + col]     = rna_tf32(acc[j][2]);
        cbase[(size_t)(pr + 8) * Dx + col + 1] = rna_tf32(acc[j][3]);
    }
}

// ---------------- edge scores ----------------
__device__ __forceinline__ void score_tile(
    const __nv_bfloat16 (*Qh)[72], const __nv_bfloat16 (*Ql)[72],
    const __nv_bfloat16 (*Kh)[72], const __nv_bfloat16 (*Kl)[72],
    const int* __restrict__ amask, int mask_base,
    float* __restrict__ out, int ostride, int ocol0,
    int lane, int warp_m, int warp_n)
{
    const int tile = lane >> 3;
    const int rl = lane & 7;
    const int ldrow = (tile & 1) * 8 + rl;
    const int ldcol = (tile >> 1) * 8;

    float acc[4][4];
    #pragma unroll
    for (int j = 0; j < 4; j++) {
        acc[j][0] = 0.f; acc[j][1] = 0.f; acc[j][2] = 0.f; acc[j][3] = 0.f;
    }

    #pragma unroll
    for (int kk = 0; kk < 64; kk += 16) {
        uint32_t ah[4], al[4];
        ldsm_x4(ah, (uint32_t)__cvta_generic_to_shared(&Qh[warp_m * 16 + ldrow][ldcol + kk]));
        ldsm_x4(al, (uint32_t)__cvta_generic_to_shared(&Ql[warp_m * 16 + ldrow][ldcol + kk]));
        #pragma unroll
        for (int j2 = 0; j2 < 2; j2++) {
            int n0 = warp_n * 32 + j2 * 16;
            uint32_t bh[4], bl[4];
            ldsm_x4(bh, (uint32_t)__cvta_generic_to_shared(&Kh[n0 + ldrow][ldcol + kk]));
            ldsm_x4(bl, (uint32_t)__cvta_generic_to_shared(&Kl[n0 + ldrow][ldcol + kk]));
            mma_bf16(acc[j2 * 2 + 0], ah, bh[0], bh[2]);
            mma_bf16(acc[j2 * 2 + 0], ah, bl[0], bl[2]);
            mma_bf16(acc[j2 * 2 + 0], al, bh[0], bh[2]);
            mma_bf16(acc[j2 * 2 + 1], ah, bh[1], bh[3]);
            mma_bf16(acc[j2 * 2 + 1], ah, bl[1], bl[3]);
            mma_bf16(acc[j2 * 2 + 1], al, bh[1], bh[3]);
        }
    }

    int r0 = warp_m * 16 + (lane >> 2);
    #pragma unroll
    for (int j = 0; j < 4; j++) {
        int ki = warp_n * 32 + j * 8 + (lane & 3) * 2;
        float m0 = (1.0f - (float)amask[mask_base + ki]) * -1e9f;
        float m1 = (1.0f - (float)amask[mask_base + ki + 1]) * -1e9f;
        out[(size_t)r0 * ostride + ocol0 + ki]           = acc[j][0] * 0.125f + m0;
        out[(size_t)r0 * ostride + ocol0 + ki + 1]       = acc[j][1] * 0.125f + m1;
        out[(size_t)(r0 + 8) * ostride + ocol0 + ki]     = acc[j][2] * 0.125f + m0;
        out[(size_t)(r0 + 8) * ostride + ocol0 + ki + 1] = acc[j][3] * 0.125f + m1;
    }
}

__device__ __forceinline__ void pv_tile(
    const __nv_bfloat16 (*Ph)[72], const __nv_bfloat16 (*Pl)[72],
    const __nv_bfloat16 (*Vh)[72], const __nv_bfloat16 (*Vl)[72],
    float acc[4][4], int lane, int warp_m, int warp_n)
{
    const int tile = lane >> 3;
    const int rl = lane & 7;
    const int ldrow = (tile & 1) * 8 + rl;
    const int ldcol = (tile >> 1) * 8;
    const int b_ldk = (tile & 1) * 8 + rl;
    const int b_ldn = (tile >> 1) * 8;

    #pragma unroll
    for (int kk = 0; kk < 64; kk += 16) {
        uint32_t ah[4], al[4];
        ldsm_x4(ah, (uint32_t)__cvta_generic_to_shared(&Ph[warp_m * 16 + ldrow][ldcol + kk]));
        ldsm_x4(al, (uint32_t)__cvta_generic_to_shared(&Pl[warp_m * 16 + ldrow][ldcol + kk]));
        #pragma unroll
        for (int j2 = 0; j2 < 2; j2++) {
            int n0 = warp_n * 32 + j2 * 16;
            uint32_t bh4[4], bl4[4];
            ldsm_x4t(bh4, (uint32_t)__cvta_generic_to_shared(&Vh[kk + b_ldk][n0 + b_ldn]));
            ldsm_x4t(bl4, (uint32_t)__cvta_generic_to_shared(&Vl[kk + b_ldk][n0 + b_ldn]));
            mma_bf16(acc[j2 * 2 + 0], ah, bh4[0], bh4[1]);
            mma_bf16(acc[j2 * 2 + 0], ah, bl4[0], bl4[1]);
            mma_bf16(acc[j2 * 2 + 0], al, bh4[0], bh4[1]);
            mma_bf16(acc[j2 * 2 + 1], ah, bh4[2], bh4[3]);
            mma_bf16(acc[j2 * 2 + 1], ah, bl4[2], bl4[3]);
            mma_bf16(acc[j2 * 2 + 1], al, bh4[2], bh4[3]);
        }
    }
}

__global__ void __launch_bounds__(256) edge_scores_mma(
    const __nv_bfloat16* __restrict__ qhi, const __nv_bfloat16* __restrict__ qlo,
    const __nv_bfloat16* __restrict__ khi, const __nv_bfloat16* __restrict__ klo,
    const int* __restrict__ amask, float* __restrict__ sedge)
{
    int kb = blockIdx.x, h = blockIdx.y;
    int e = blockIdx.z & 1, b = blockIdx.z >> 1;
    int qb = e ? (NBx - 1) : 0;
    __shared__ __nv_bfloat16 Qh[64][72], Ql[64][72], Kh[64][72], Kl[64][72];
    int tid = threadIdx.x, lane = tid & 31, wid = tid >> 5;
    int warp_m = wid & 3, warp_n = wid >> 2;

    size_t qoff = ((size_t)b * Sx + qb * 64) * Dx + h * 64;
    size_t koff = ((size_t)b * Sx + kb * 64) * Dx + h * 64;
    load_tile64(Qh, qhi + qoff, Dx, tid);
    load_tile64(Ql, qlo + qoff, Dx, tid);
    load_tile64(Kh, khi + koff, Dx, tid);
    load_tile64(Kl, klo + koff, Dx, tid);
    __syncthreads();

    float* out = sedge + ((size_t)((b * NHx + h) * 2 + e)) * (64 * Sx);
    score_tile(Qh, Ql, Kh, Kl, amask, b * Sx + kb * 64,
               out, Sx, kb * 64, lane, warp_m, warp_n);
}

__global__ void __launch_bounds__(256) edge_pv_mma(
    const __nv_bfloat16* __restrict__ phi, const __nv_bfloat16* __restrict__ plo,
    const __nv_bfloat16* __restrict__ vhi, const __nv_bfloat16* __restrict__ vlo,
    float* __restrict__ ctx)
{
    int h = blockIdx.x;
    int e = blockIdx.y & 1, b = blockIdx.y >> 1;
    int chunk = blockIdx.z;
    int qb = e ? (NBx - 1) : 0;
    __shared__ __nv_bfloat16 Ph[64][72], Pl[64][72], Vh[64][72], Vl[64][72];
    int tid = threadIdx.x, lane = tid & 31, wid = tid >> 5;
    int warp_m = wid & 3, warp_n = wid >> 2;

    const __nv_bfloat16* prow_h = phi + ((size_t)((b * NHx + h) * 2 + e)) * (64 * Sx);
    const __nv_bfloat16* prow_l = plo + ((size_t)((b * NHx + h) * 2 + e)) * (64 * Sx);

    float acc[4][4];
    #pragma unroll
    for (int j = 0; j < 4; j++) {
        acc[j][0] = 0.f; acc[j][1] = 0.f; acc[j][2] = 0.f; acc[j][3] = 0.f;
    }

    for (int c8 = 0; c8 < 8; c8++) {
        int kb = chunk * 8 + c8;
        size_t voff = ((size_t)b * Sx + kb * 64) * Dx + h * 64;
        __syncthreads();
        load_tile64(Ph, prow_h + kb * 64, Sx, tid);
        load_tile64(Pl, prow_l + kb * 64, Sx, tid);
        load_tile64(Vh, vhi + voff, Dx, tid);
        load_tile64(Vl, vlo + voff, Dx, tid);
        __syncthreads();
        pv_tile(Ph, Pl, Vh, Vl, acc, lane, warp_m, warp_n);
    }

    float* cbase = ctx + ((size_t)b * Sx + qb * 64) * Dx + h * 64;
    int r0 = warp_m * 16 + (lane >> 2);
    #pragma unroll
    for (int j = 0; j < 4; j++) {
        int col = warp_n * 32 + j * 8 + (lane & 3) * 2;
        atomicAdd(&cbase[(size_t)r0 * Dx + col],           acc[j][0]);
        atomicAdd(&cbase[(size_t)r0 * Dx + col + 1],       acc[j][1]);
        atomicAdd(&cbase[(size_t)(r0 + 8) * Dx + col],     acc[j][2]);
        atomicAdd(&cbase[(size_t)(r0 + 8) * Dx + col + 1], acc[j][3]);
    }
}

__global__ void zero_edge_ctx(float* __restrict__ ctx) {
    int i = blockIdx.x * 256 + threadIdx.x;
    if (i >= Bx * 2 * 64 * Dx) return;
    int col = i % Dx;
    int t = i / Dx;
    int row = t % 64;  t /= 64;
    int e = t & 1;
    int b = t >> 1;
    int blk = e ? (NBx - 1) : 0;
    ctx[((size_t)b * Sx + blk * 64 + row) * Dx + col] = 0.f;
}

// ---------------- row softmax -> bf16 hi/lo planes (edge) ----------------
__global__ void softmax_split_kernel(const float* __restrict__ s,
                                     __nv_bfloat16* __restrict__ phi,
                                     __nv_bfloat16* __restrict__ plo, int L) {
    extern __shared__ float buf[];
    size_t base = (size_t)blockIdx.x * L;
    float m = -3.4e38f;
    for (int i = threadIdx.x; i < L; i += blockDim.x) {
        float x = s[base + i];
        buf[i] = x;
        m = fmaxf(m, x);
    }
    m = blk_max(m);
    float lsum = 0.f;
    for (int i = threadIdx.x; i < L; i += blockDim.x) {
        float e = fexp(buf[i] - m);
        buf[i] = e;
        lsum += e;
    }
    float sum = blk_sum(lsum);
    float inv = 1.f / sum;
    for (int i = threadIdx.x; i < L; i += blockDim.x) {
        float p = buf[i] * inv;
        split_store(p, phi + base + i, plo + base + i);
    }
}

// ---------------- pooler ----------------
__global__ void pooler_kernel(const float* __restrict__ h, const float* __restrict__ pw,
                              const float* __restrict__ pb, float* __restrict__ out) {
    int j = blockIdx.x * blockDim.x + threadIdx.x;
    int b = blockIdx.y;
    if (j >= Dx) return;
    const float* hr = h + (size_t)b * Sx * Dx;
    float acc = pb[j];
    for (int kI = 0; kI < Dx; kI++) acc += hr[kI] * pw[(size_t)kI * Dx + j];
    out[b * Dx + j] = tanhf(acc);
}

// ---------------- host launcher ----------------
extern "C" void kernel_launch(void* const* d_in, const int* in_sizes, int n_in,
                              void* d_out, int out_size) {
    const int*   input_ids = (const int*)d_in[0];
    const int*   attn_mask = (const int*)d_in[1];
    const int*   tok_type  = (const int*)d_in[2];
    const int*   rand_blk  = (const int*)d_in[3];
    const float* word_emb  = (const float*)d_in[4];
    const float* type_emb  = (const float*)d_in[5];
    const float* pos_emb   = (const float*)d_in[6];
    const float* emb_ln_s  = (const float*)d_in[7];
    const float* emb_ln_b  = (const float*)d_in[8];
    const float* Wq = (const float*)d_in[9];  const float* bq = (const float*)d_in[10];
    const float* Wk = (const float*)d_in[11]; const float* bk = (const float*)d_in[12];
    const float* Wv = (const float*)d_in[13]; const float* bv = (const float*)d_in[14];
    const float* Wo = (const float*)d_in[15]; const float* bo = (const float*)d_in[16];
    const float* ln1_s = (const float*)d_in[17]; const float* ln1_b = (const float*)d_in[18];
    const float* W1 = (const float*)d_in[19]; const float* b1 = (const float*)d_in[20];
    const float* W2 = (const float*)d_in[21]; const float* b2 = (const float*)d_in[22];
    const float* ln2_s = (const float*)d_in[23]; const float* ln2_b = (const float*)d_in[24];
    const float* pool_w = (const float*)d_in[25]; const float* pool_b = (const float*)d_in[26];
    float* out = (float*)d_out;

    float *p_h = 0, *p_res = 0, *p_ctx = 0, *p_ff = 0, *p_wt = 0, *p_sedge = 0;
    __nv_bfloat16 *p_qhi = 0, *p_qlo = 0, *p_khi = 0, *p_klo = 0, *p_vhi = 0, *p_vlo = 0;
    __nv_bfloat16 *p_peh = 0, *p_pel = 0;
    cudaGetSymbolAddress((void**)&p_h,     g_h);
    cudaGetSymbolAddress((void**)&p_res,   g_res);
    cudaGetSymbolAddress((void**)&p_ctx,   g_ctx);
    cudaGetSymbolAddress((void**)&p_ff,    g_ff);
    cudaGetSymbolAddress((void**)&p_wt,    g_wt);
    cudaGetSymbolAddress((void**)&p_sedge, g_sedge);
    cudaGetSymbolAddress((void**)&p_qhi,   g_qhi);
    cudaGetSymbolAddress((void**)&p_qlo,   g_qlo);
    cudaGetSymbolAddress((void**)&p_khi,   g_khi);
    cudaGetSymbolAddress((void**)&p_klo,   g_klo);
    cudaGetSymbolAddress((void**)&p_vhi,   g_vhi);
    cudaGetSymbolAddress((void**)&p_vlo,   g_vlo);
    cudaGetSymbolAddress((void**)&p_peh,   g_pedge_hi);
    cudaGetSymbolAddress((void**)&p_pel,   g_pedge_lo);

    static bool attr_done = false;
    if (!attr_done) {
        cudaFuncSetAttribute(tf_gemm_kernel<0>, cudaFuncAttributeMaxDynamicSharedMemorySize, TF_SMEM_BYTES);
        cudaFuncSetAttribute(tf_gemm_kernel<3>, cudaFuncAttributeMaxDynamicSharedMemorySize, TF_SMEM_BYTES);
        cudaFuncSetAttribute(tf_qkv_kernel, cudaFuncAttributeMaxDynamicSharedMemorySize, TF_SMEM_BYTES);
        cudaFuncSetAttribute(mid_fused_kernel, cudaFuncAttributeMaxDynamicSharedMemorySize, MID_SMEM);
        attr_done = true;
    }

    const int M = TOK;
    const int nDD = Dx * Dx;

    embed_ln_kernel<<<TOK, 256>>>(input_ids, tok_type, word_emb, type_emb, pos_emb,
                                  emb_ln_s, emb_ln_b);

    for (int l = 0; l < 2; l++) {
        const float* wq = Wq + (size_t)l * nDD;  const float* bql = bq + (size_t)l * Dx;
        const float* wk = Wk + (size_t)l * nDD;  const float* bkl = bk + (size_t)l * Dx;
        const float* wv = Wv + (size_t)l * nDD;  const float* bvl = bv + (size_t)l * Dx;
        const float* wo = Wo + (size_t)l * nDD;  const float* bol = bo + (size_t)l * Dx;
        const float* w1 = W1 + (size_t)l * Dx * FFx; const float* b1l = b1 + (size_t)l * FFx;
        const float* w2 = W2 + (size_t)l * Dx * FFx; const float* b2l = b2 + (size_t)l * Dx;
        const float* l1s = ln1_s + (size_t)l * Dx; const float* l1b = ln1_b + (size_t)l * Dx;
        const float* l2s = ln2_s + (size_t)l * Dx; const float* l2b = ln2_b + (size_t)l * Dx;

        // QKV (tf32): transpose+round weights, fused GEMM, bf16 planes out
        trans_round_kernel<<<dim3(Dx / 32, Dx / 32), dim3(32, 8)>>>(wq, p_wt,           Dx, Dx);
        trans_round_kernel<<<dim3(Dx / 32, Dx / 32), dim3(32, 8)>>>(wk, p_wt + nDD,     Dx, Dx);
        trans_round_kernel<<<dim3(Dx / 32, Dx / 32), dim3(32, 8)>>>(wv, p_wt + 2 * nDD, Dx, Dx);
        tf_qkv_kernel<<<dim3(Dx / 128, M / 128, 3), 256, TF_SMEM_BYTES>>>(
            p_h, p_wt, bql, bkl, bvl, p_qhi, p_qlo, p_khi, p_klo, p_vhi, p_vlo);

        // middle blocks: fused scores+softmax+PV -> fp32 ctx
        mid_fused_kernel<<<dim3(NMID, NHx, Bx), 256, MID_SMEM>>>(
            p_qhi, p_qlo, p_khi, p_klo, p_vhi, p_vlo, rand_blk, attn_mask, p_ctx);

        // edge blocks
        edge_scores_mma<<<dim3(NBx, NHx, Bx * 2), 256>>>(p_qhi, p_qlo, p_khi, p_klo,
                                                         attn_mask, p_sedge);
        softmax_split_kernel<<<Bx * NHx * 2 * BSx, 256, Sx * sizeof(float)>>>(
            p_sedge, p_peh, p_pel, Sx);
        zero_edge_ctx<<<(Bx * 2 * 64 * Dx + 255) / 256, 256>>>(p_ctx);
        edge_pv_mma<<<dim3(NHx, Bx * 2, 8), 256>>>(p_peh, p_pel, p_vhi, p_vlo, p_ctx);

        // O-projection (tf32) + LN
        trans_round_kernel<<<dim3(Dx / 32, Dx / 32), dim3(32, 8)>>>(wo, p_wt, Dx, Dx);
        tf_gemm_kernel<0><<<dim3(Dx / 128, M / 128), 256, TF_SMEM_BYTES>>>(
            p_ctx, p_wt, bol, p_res, nullptr, nullptr, M, Dx, Dx);
        add_ln_kernel<<<TOK, 256>>>(p_h, p_res, l1s, l1b);

        // FFN (tf32)
        trans_round_kernel<<<dim3(FFx / 32, Dx / 32), dim3(32, 8)>>>(w1, p_wt, Dx, FFx);
        tf_gemm_kernel<3><<<dim3(FFx / 128, M / 128), 256, TF_SMEM_BYTES>>>(
            p_h, p_wt, b1l, p_ff, nullptr, nullptr, M, FFx, Dx);
        trans_round_kernel<<<dim3(Dx / 32, FFx / 32), dim3(32, 8)>>>(w2, p_wt, FFx, Dx);
        tf_gemm_kernel<0><<<dim3(Dx / 128, M / 128), 256, TF_SMEM_BYTES>>>(
            p_ff, p_wt, b2l, p_res, nullptr, nullptr, M, Dx, FFx);
        add_ln_kernel<<<TOK, 256>>>(p_h, p_res, l2s, l2b);
    }

    pooler_kernel<<<dim3((Dx + 127) / 128, Bx), 128>>>(p_h, pool_w, pool_b, out);
}

// round 13
// speedup vs baseline: 3.5567x; 1.0083x over previous
#include <cuda_runtime.h>
#include <cuda_bf16.h>
#include <cstdint>
#include <math.h>

#define Bx 2
#define Sx 4096
#define Dx 768
#define NHx 12
#define HDx 64
#define BSx 64
#define NBx 64
#define FFx 3072
#define Rx 3
#define NGx 8
#define NMID 62
#define TOK (Bx*Sx)

// ---------------- scratch ----------------
__device__ float g_h[(size_t)TOK*Dx];
__device__ float g_res[(size_t)TOK*Dx];
__device__ float g_ctx[(size_t)TOK*Dx];
__device__ float g_ff[(size_t)TOK*FFx];
__device__ float g_wt[(size_t)Dx*FFx];
__device__ float g_q[(size_t)TOK*Dx];
__device__ float g_k[(size_t)TOK*Dx];
__device__ float g_v[(size_t)TOK*Dx];
__device__ float g_sedge[(size_t)Bx*NHx*2*BSx*Sx];

// ---------------- helpers ----------------
__device__ __forceinline__ float rna_tf32(float x) {
    uint32_t o;
    asm("cvt.rna.tf32.f32 %0, %1;" : "=r"(o) : "f"(x));
    return __uint_as_float(o);
}
__device__ __forceinline__ float fexp(float x) {
    x = fmaxf(x, -80.f);
    float t = fmaf(x, 1.4426950408889634f, 12582912.0f);
    float i = t - 12582912.0f;
    float f = fmaf(x, 1.4426950408889634f, -i);
    float pr = 1.5403530e-4f;
    pr = fmaf(pr, f, 1.3333558e-3f);
    pr = fmaf(pr, f, 9.6181291e-3f);
    pr = fmaf(pr, f, 5.5504109e-2f);
    pr = fmaf(pr, f, 2.4022651e-1f);
    pr = fmaf(pr, f, 6.9314718e-1f);
    pr = fmaf(pr, f, 1.0f);
    int ii = (int)i;
    float sc = __int_as_float((ii + 127) << 23);
    return pr * sc;
}

__device__ __forceinline__ float blk_sum(float v) {
    __shared__ float red[33];
    #pragma unroll
    for (int o = 16; o; o >>= 1) v += __shfl_down_sync(0xffffffffu, v, o);
    int lane = threadIdx.x & 31, w = threadIdx.x >> 5;
    __syncthreads();
    if (lane == 0) red[w] = v;
    __syncthreads();
    if (w == 0) {
        float x = (lane < ((blockDim.x + 31) >> 5)) ? red[lane] : 0.f;
        #pragma unroll
        for (int o = 16; o; o >>= 1) x += __shfl_down_sync(0xffffffffu, x, o);
        if (lane == 0) red[32] = x;
    }
    __syncthreads();
    return red[32];
}

__device__ __forceinline__ float blk_max(float v) {
    __shared__ float redm[33];
    #pragma unroll
    for (int o = 16; o; o >>= 1) v = fmaxf(v, __shfl_down_sync(0xffffffffu, v, o));
    int lane = threadIdx.x & 31, w = threadIdx.x >> 5;
    __syncthreads();
    if (lane == 0) redm[w] = v;
    __syncthreads();
    if (w == 0) {
        float x = (lane < ((blockDim.x + 31) >> 5)) ? redm[lane] : -3.4e38f;
        #pragma unroll
        for (int o = 16; o; o >>= 1) x = fmaxf(x, __shfl_down_sync(0xffffffffu, x, o));
        if (lane == 0) redm[32] = x;
    }
    __syncthreads();
    return redm[32];
}

// ---------------- weight transpose + tf32 round: W[K][N] -> Wt[N][K] -------------
__global__ void trans_round_kernel(const float* __restrict__ in, float* __restrict__ out,
                                   int K, int N) {
    __shared__ float t[32][33];
    int n0 = blockIdx.x * 32, k0 = blockIdx.y * 32;
    int tx = threadIdx.x, ty = threadIdx.y;
    #pragma unroll
    for (int i = ty; i < 32; i += 8) t[i][tx] = in[(size_t)(k0 + i) * N + n0 + tx];
    __syncthreads();
    #pragma unroll
    for (int i = ty; i < 32; i += 8)
        out[(size_t)(n0 + i) * K + k0 + tx] = rna_tf32(t[tx][i]);
}

// ---------------- embeddings + LN ----------------
__global__ void embed_ln_kernel(const int* __restrict__ ids, const int* __restrict__ tt,
                                const float* __restrict__ wemb, const float* __restrict__ temb,
                                const float* __restrict__ pemb,
                                const float* __restrict__ lns, const float* __restrict__ lnb) {
    int tok = blockIdx.x;
    int pos = tok % Sx;
    const float* w = wemb + (size_t)ids[tok] * Dx;
    const float* t = temb + (size_t)tt[tok] * Dx;
    const float* p = pemb + (size_t)pos * Dx;
    __shared__ float buf[Dx];
    float ls = 0.f, lq = 0.f;
    for (int i = threadIdx.x; i < Dx; i += blockDim.x) {
        float x = w[i] + t[i] + p[i];
        buf[i] = x; ls += x; lq += x * x;
    }
    float sum = blk_sum(ls);
    float sq  = blk_sum(lq);
    float mu = sum * (1.f / Dx);
    float var = sq * (1.f / Dx) - mu * mu;
    float inv = rsqrtf(var + 1e-12f);
    for (int i = threadIdx.x; i < Dx; i += blockDim.x) {
        float y = lns[i] * (buf[i] - mu) * inv + lnb[i];
        g_h[(size_t)tok * Dx + i] = rna_tf32(y);
    }
}

__global__ void add_ln_kernel(float* __restrict__ h, const float* __restrict__ r,
                              const float* __restrict__ lns, const float* __restrict__ lnb) {
    int tok = blockIdx.x;
    __shared__ float buf[Dx];
    float ls = 0.f, lq = 0.f;
    for (int i = threadIdx.x; i < Dx; i += blockDim.x) {
        float x = h[(size_t)tok * Dx + i] + r[(size_t)tok * Dx + i];
        buf[i] = x; ls += x; lq += x * x;
    }
    float sum = blk_sum(ls);
    float sq  = blk_sum(lq);
    float mu = sum * (1.f / Dx);
    float var = sq * (1.f / Dx) - mu * mu;
    float inv = rsqrtf(var + 1e-12f);
    for (int i = threadIdx.x; i < Dx; i += blockDim.x) {
        float y = lns[i] * (buf[i] - mu) * inv + lnb[i];
        h[(size_t)tok * Dx + i] = rna_tf32(y);
    }
}

// ---------------- MMA primitives ----------------
__device__ __forceinline__ void ldsm_x4(uint32_t* r, uint32_t addr) {
    asm volatile("ldmatrix.sync.aligned.m8n8.x4.shared.b16 {%0,%1,%2,%3}, [%4];"
                 : "=r"(r[0]), "=r"(r[1]), "=r"(r[2]), "=r"(r[3]) : "r"(addr));
}
__device__ __forceinline__ void mma_tf32(float* c, const uint32_t* a, uint32_t b0, uint32_t b1) {
    asm volatile("mma.sync.aligned.m16n8k8.row.col.f32.tf32.tf32.f32 "
                 "{%0,%1,%2,%3}, {%4,%5,%6,%7}, {%8,%9}, {%0,%1,%2,%3};"
                 : "+f"(c[0]), "+f"(c[1]), "+f"(c[2]), "+f"(c[3])
                 : "r"(a[0]), "r"(a[1]), "r"(a[2]), "r"(a[3]), "r"(b0), "r"(b1));
}
__device__ __forceinline__ void mma_tf32f(float* c, const float* a, float b0, float b1) {
    mma_tf32(c, (const uint32_t*)a, __float_as_uint(b0), __float_as_uint(b1));
}
__device__ __forceinline__ void cp16(void* dst, const void* src) {
    uint32_t d = (uint32_t)__cvta_generic_to_shared(dst);
    asm volatile("cp.async.cg.shared.global [%0], [%1], 16;" :: "r"(d), "l"(src));
}

// ---------------- TF32 dense GEMM ----------------
// C = act(A[M,K] @ Wt[N,K]^T + bias). MODE 0: fp32; 3: GELU + rna; 4: rna fp32.
#define TF_STRIDE 36
#define TF_STAGE (128 * TF_STRIDE * 2)
#define TF_OFF_B (128 * TF_STRIDE)
#define TF_SMEM_BYTES (2 * TF_STAGE * 4)

__device__ __forceinline__ void tf_load_stage(
    float* sm, int s, int k0, int tid, int m0, int n0,
    const float* __restrict__ A, const float* __restrict__ Bt, int K)
{
    float* st = sm + s * TF_STAGE;
    #pragma unroll
    for (int i = 0; i < 4; i++) {
        int idx = tid + i * 256;
        int r = idx >> 3, c = (idx & 7) * 4;
        cp16(st + r * TF_STRIDE + c, A + (size_t)(m0 + r) * K + k0 + c);
        cp16(st + TF_OFF_B + r * TF_STRIDE + c, Bt + (size_t)(n0 + r) * K + k0 + c);
    }
    asm volatile("cp.async.commit_group;");
}

template<int MODE>
__device__ __forceinline__ void tf_gemm_body(
    const float* __restrict__ A, const float* __restrict__ Bt,
    const float* __restrict__ bias, float* __restrict__ C,
    int M, int N, int K, int bxb, int byb, float* sm)
{
    const int tid = threadIdx.x;
    const int lane = tid & 31;
    const int wid = tid >> 5;
    const int warp_m = wid & 3;
    const int warp_n = wid >> 2;
    const int m0 = byb * 128;
    const int n0 = bxb * 128;

    float acc[2][8][4];
    #pragma unroll
    for (int mt = 0; mt < 2; mt++) {
        #pragma unroll
        for (int nt = 0; nt < 8; nt++) {
            acc[mt][nt][0] = 0.f; acc[mt][nt][1] = 0.f;
            acc[mt][nt][2] = 0.f; acc[mt][nt][3] = 0.f;
        }
    }

    const int phase = lane >> 3;
    const int rli = lane & 7;
    const int a_roff = (phase & 1) * 8 + rli;
    const int a_koff = (phase >> 1) * 4;
    const int b_roff = (phase >> 1) * 8 + rli;
    const int b_koff = (phase & 1) * 4;

    const int nk = K >> 5;
    tf_load_stage(sm, 0, 0, tid, m0, n0, A, Bt, K);

    for (int kt = 0; kt < nk; kt++) {
        const int s = kt & 1;
        asm volatile("cp.async.wait_group 0;");
        __syncthreads();
        if (kt + 1 < nk)
            tf_load_stage(sm, s ^ 1, (kt + 1) * 32, tid, m0, n0, A, Bt, K);

        float* stA = sm + s * TF_STAGE;
        float* stB = stA + TF_OFF_B;

        #pragma unroll
        for (int kk = 0; kk < 32; kk += 8) {
            uint32_t aa0[4], aa1[4];
            ldsm_x4(aa0, (uint32_t)__cvta_generic_to_shared(
                stA + (warp_m * 32 + a_roff) * TF_STRIDE + kk + a_koff));
            ldsm_x4(aa1, (uint32_t)__cvta_generic_to_shared(
                stA + (warp_m * 32 + 16 + a_roff) * TF_STRIDE + kk + a_koff));
            #pragma unroll
            for (int p = 0; p < 4; p++) {
                uint32_t bb[4];
                ldsm_x4(bb, (uint32_t)__cvta_generic_to_shared(
                    stB + (warp_n * 64 + p * 16 + b_roff) * TF_STRIDE + kk + b_koff));
                int nt0 = p * 2;
                int nt1 = p * 2 + 1;
                mma_tf32(acc[0][nt0], aa0, bb[0], bb[1]);
                mma_tf32(acc[0][nt1], aa0, bb[2], bb[3]);
                mma_tf32(acc[1][nt0], aa1, bb[0], bb[1]);
                mma_tf32(acc[1][nt1], aa1, bb[2], bb[3]);
            }
        }
    }

    const int grp = lane >> 2;
    const int tig = lane & 3;
    #pragma unroll
    for (int mt = 0; mt < 2; mt++) {
        #pragma unroll
        for (int nt = 0; nt < 8; nt++) {
            int col = n0 + warp_n * 64 + nt * 8 + tig * 2;
            float b0 = bias[col];
            float b1 = bias[col + 1];
            #pragma unroll
            for (int half = 0; half < 2; half++) {
                int row = m0 + warp_m * 32 + mt * 16 + grp + half * 8;
                float v0 = acc[mt][nt][half * 2 + 0] + b0;
                float v1 = acc[mt][nt][half * 2 + 1] + b1;
                if (MODE == 3) {
                    v0 = 0.5f * v0 * (1.f + erff(v0 * 0.70710678118654752f));
                    v1 = 0.5f * v1 * (1.f + erff(v1 * 0.70710678118654752f));
                }
                if (MODE == 3 || MODE == 4) {
                    C[(size_t)row * N + col]     = rna_tf32(v0);
                    C[(size_t)row * N + col + 1] = rna_tf32(v1);
                } else {
                    C[(size_t)row * N + col]     = v0;
                    C[(size_t)row * N + col + 1] = v1;
                }
            }
        }
    }
}

template<int MODE>
__global__ void __launch_bounds__(256, 2) tf_gemm_kernel(
    const float* __restrict__ A, const float* __restrict__ Bt,
    const float* __restrict__ bias, float* __restrict__ C,
    int M, int N, int K)
{
    extern __shared__ __align__(16) float sm[];
    tf_gemm_body<MODE>(A, Bt, bias, C, M, N, K, blockIdx.x, blockIdx.y, sm);
}

__global__ void __launch_bounds__(256, 2) tf_qkv_kernel(
    const float* __restrict__ A, const float* __restrict__ Bt,
    const float* __restrict__ bq, const float* __restrict__ bk, const float* __restrict__ bv,
    float* __restrict__ q, float* __restrict__ k, float* __restrict__ v)
{
    extern __shared__ __align__(16) float sm[];
    int z = blockIdx.z;
    size_t woff = (size_t)z * Dx * Dx;
    const float* bias = (z == 0) ? bq : (z == 1) ? bk : bv;
    float* C = (z == 0) ? q : (z == 1) ? k : v;
    tf_gemm_body<4>(A, Bt + woff, bias, C, TOK, Dx, Dx, blockIdx.x, blockIdx.y, sm);
}

// ---------------- attention helpers ----------------
__device__ __forceinline__ int mid_block_idx(int n, int g, const int* __restrict__ randb) {
    if (g == 0) return 0;
    if (g == 1) return NBx - 1;
    if (g < 5)  return n - 3 + g;
    return randb[(n - 1) * Rx + (g - 5)];
}

#define FT_STRIDE 68
__device__ __forceinline__ void load_ftile(
    float (*dst)[FT_STRIDE], const float* __restrict__ src, int gstride, int tid)
{
    #pragma unroll
    for (int i = 0; i < 4; i++) {
        int idx = tid + i * 256;
        int r = idx >> 4, c = (idx & 15) * 4;
        *(float4*)&dst[r][c] = *(const float4*)(src + (size_t)r * gstride + c);
    }
}

// TF32 64x64 score tile: acc[j] covers n-tile j (8 keys); A rows = q, B = K^T.
// Per warp: 16 q-rows (warp_m), 32 keys (warp_n).
__device__ __forceinline__ void score_tile_tf(
    const float (*Qs)[FT_STRIDE], const float (*Ks)[FT_STRIDE],
    float acc[4][4], int lane, int warp_m, int warp_n)
{
    const int rq = warp_m * 16 + (lane >> 2);
    const int ck = lane & 3;
    #pragma unroll
    for (int kk = 0; kk < 64; kk += 8) {
        float a[4];
        a[0] = Qs[rq][kk + ck];
        a[1] = Qs[rq + 8][kk + ck];
        a[2] = Qs[rq][kk + 4 + ck];
        a[3] = Qs[rq + 8][kk + 4 + ck];
        #pragma unroll
        for (int j = 0; j < 4; j++) {
            int n0 = warp_n * 32 + j * 8 + (lane >> 2);
            float b0 = Ks[n0][kk + ck];
            float b1 = Ks[n0][kk + 4 + ck];
            mma_tf32f(acc[j], a, b0, b1);
        }
    }
}

// TF32 PV accumulate: P [64 rows x 64 keys at pcol0, stride pstride], V [64 key][64 d].
__device__ __forceinline__ void pv_tile_tf(
    const float* __restrict__ P, int pstride, int pcol0,
    const float (*Vs)[FT_STRIDE],
    float acc[4][4], int lane, int warp_m, int warp_n)
{
    const int rp = warp_m * 16 + (lane >> 2);
    const int ck = lane & 3;
    #pragma unroll
    for (int kk = 0; kk < 64; kk += 8) {
        float a[4];
        a[0] = P[(size_t)rp * pstride + pcol0 + kk + ck];
        a[1] = P[(size_t)(rp + 8) * pstride + pcol0 + kk + ck];
        a[2] = P[(size_t)rp * pstride + pcol0 + kk + 4 + ck];
        a[3] = P[(size_t)(rp + 8) * pstride + pcol0 + kk + 4 + ck];
        #pragma unroll
        for (int j = 0; j < 4; j++) {
            int n0 = warp_n * 32 + j * 8 + (lane >> 2);
            float b0 = Vs[kk + ck][n0];
            float b1 = Vs[kk + 4 + ck][n0];
            mma_tf32f(acc[j], a, b0, b1);
        }
    }
}

// ---------------- fused middle-block attention (tf32) ----------------
#define SROW 516
#define MID_SMEM (64 * SROW * 4 + 2 * 64 * FT_STRIDE * 4)

__global__ void __launch_bounds__(256, 1) mid_fused_kernel(
    const float* __restrict__ q, const float* __restrict__ k, const float* __restrict__ v,
    const int* __restrict__ randb, const int* __restrict__ amask,
    float* __restrict__ ctx)
{
    extern __shared__ __align__(16) char smraw[];
    float (*Sf)[SROW] = (float(*)[SROW])smraw;
    float (*Qs)[FT_STRIDE] = (float(*)[FT_STRIDE])(smraw + 64 * SROW * 4);
    float (*Ks)[FT_STRIDE] = (float(*)[FT_STRIDE])(smraw + 64 * SROW * 4 + 64 * FT_STRIDE * 4);

    int n = blockIdx.x + 1, h = blockIdx.y, b = blockIdx.z;
    int tid = threadIdx.x, lane = tid & 31, wid = tid >> 5;
    int warp_m = wid & 3, warp_n = wid >> 2;

    size_t qoff = ((size_t)b * Sx + n * 64) * Dx + h * 64;
    load_ftile(Qs, q + qoff, Dx, tid);

    // --- phase 1: scores ---
    for (int g = 0; g < NGx; g++) {
        int kb = mid_block_idx(n, g, randb);
        size_t koff = ((size_t)b * Sx + kb * 64) * Dx + h * 64;
        __syncthreads();
        load_ftile(Ks, k + koff, Dx, tid);
        __syncthreads();

        float acc[4][4];
        #pragma unroll
        for (int j = 0; j < 4; j++) {
            acc[j][0] = 0.f; acc[j][1] = 0.f; acc[j][2] = 0.f; acc[j][3] = 0.f;
        }
        score_tile_tf(Qs, Ks, acc, lane, warp_m, warp_n);

        int r0 = warp_m * 16 + (lane >> 2);
        int mask_base = b * Sx + kb * 64;
        #pragma unroll
        for (int j = 0; j < 4; j++) {
            int ki = warp_n * 32 + j * 8 + (lane & 3) * 2;
            float m0 = (1.0f - (float)amask[mask_base + ki]) * -1e9f;
            float m1 = (1.0f - (float)amask[mask_base + ki + 1]) * -1e9f;
            Sf[r0][g * 64 + ki]           = acc[j][0] * 0.125f + m0;
            Sf[r0][g * 64 + ki + 1]       = acc[j][1] * 0.125f + m1;
            Sf[r0 + 8][g * 64 + ki]       = acc[j][2] * 0.125f + m0;
            Sf[r0 + 8][g * 64 + ki + 1]   = acc[j][3] * 0.125f + m1;
        }
    }
    __syncthreads();

    // --- phase 2: softmax (rna-rounded for tf32 PV) ---
    for (int rr = 0; rr < 8; rr++) {
        int row = wid * 8 + rr;
        float vv[16];
        float m = -3.4e38f;
        #pragma unroll
        for (int j = 0; j < 16; j++) {
            vv[j] = Sf[row][lane + 32 * j];
            m = fmaxf(m, vv[j]);
        }
        #pragma unroll
        for (int o = 16; o; o >>= 1) m = fmaxf(m, __shfl_xor_sync(0xffffffffu, m, o));
        float s = 0.f;
        #pragma unroll
        for (int j = 0; j < 16; j++) { vv[j] = fexp(vv[j] - m); s += vv[j]; }
        #pragma unroll
        for (int o = 16; o; o >>= 1) s += __shfl_xor_sync(0xffffffffu, s, o);
        float inv = 1.f / s;
        #pragma unroll
        for (int j = 0; j < 16; j++) Sf[row][lane + 32 * j] = rna_tf32(vv[j] * inv);
    }
    __syncthreads();

    // --- phase 3: PV ---
    float acc[4][4];
    #pragma unroll
    for (int j = 0; j < 4; j++) {
        acc[j][0] = 0.f; acc[j][1] = 0.f; acc[j][2] = 0.f; acc[j][3] = 0.f;
    }
    for (int g = 0; g < NGx; g++) {
        int kb = mid_block_idx(n, g, randb);
        size_t voff = ((size_t)b * Sx + kb * 64) * Dx + h * 64;
        __syncthreads();
        load_ftile(Ks, v + voff, Dx, tid);
        __syncthreads();
        pv_tile_tf(&Sf[0][0], SROW, g * 64, Ks, acc, lane, warp_m, warp_n);
    }

    float* cbase = ctx + ((size_t)b * Sx + n * 64) * Dx + h * 64;
    int pr = warp_m * 16 + (lane >> 2);
    #pragma unroll
    for (int j = 0; j < 4; j++) {
        int col = warp_n * 32 + j * 8 + (lane & 3) * 2;
        cbase[(size_t)pr * Dx + col]           = rna_tf32(acc[j][0]);
        cbase[(size_t)pr * Dx + col + 1]       = rna_tf32(acc[j][1]);
        cbase[(size_t)(pr + 8) * Dx + col]     = rna_tf32(acc[j][2]);
        cbase[(size_t)(pr + 8) * Dx + col + 1] = rna_tf32(acc[j][3]);
    }
}

// ---------------- edge scores (tf32) ----------------
__global__ void __launch_bounds__(256) edge_scores_tf(
    const float* __restrict__ q, const float* __restrict__ k,
    const int* __restrict__ amask, float* __restrict__ sedge)
{
    int kb = blockIdx.x, h = blockIdx.y;
    int e = blockIdx.z & 1, b = blockIdx.z >> 1;
    int qb = e ? (NBx - 1) : 0;
    __shared__ float Qs[64][FT_STRIDE];
    __shared__ float Ks[64][FT_STRIDE];
    int tid = threadIdx.x, lane = tid & 31, wid = tid >> 5;
    int warp_m = wid & 3, warp_n = wid >> 2;

    size_t qoff = ((size_t)b * Sx + qb * 64) * Dx + h * 64;
    size_t koff = ((size_t)b * Sx + kb * 64) * Dx + h * 64;
    load_ftile(Qs, q + qoff, Dx, tid);
    load_ftile(Ks, k + koff, Dx, tid);
    __syncthreads();

    float acc[4][4];
    #pragma unroll
    for (int j = 0; j < 4; j++) {
        acc[j][0] = 0.f; acc[j][1] = 0.f; acc[j][2] = 0.f; acc[j][3] = 0.f;
    }
    score_tile_tf(Qs, Ks, acc, lane, warp_m, warp_n);

    float* out = sedge + ((size_t)((b * NHx + h) * 2 + e)) * (64 * Sx);
    int r0 = warp_m * 16 + (lane >> 2);
    int mask_base = b * Sx + kb * 64;
    #pragma unroll
    for (int j = 0; j < 4; j++) {
        int ki = warp_n * 32 + j * 8 + (lane & 3) * 2;
        float m0 = (1.0f - (float)amask[mask_base + ki]) * -1e9f;
        float m1 = (1.0f - (float)amask[mask_base + ki + 1]) * -1e9f;
        out[(size_t)r0 * Sx + kb * 64 + ki]           = acc[j][0] * 0.125f + m0;
        out[(size_t)r0 * Sx + kb * 64 + ki + 1]       = acc[j][1] * 0.125f + m1;
        out[(size_t)(r0 + 8) * Sx + kb * 64 + ki]     = acc[j][2] * 0.125f + m0;
        out[(size_t)(r0 + 8) * Sx + kb * 64 + ki + 1] = acc[j][3] * 0.125f + m1;
    }
}

// ---------------- edge softmax in place (rna) ----------------
__global__ void softmax_rna_kernel(float* __restrict__ s, int L) {
    extern __shared__ float buf[];
    size_t base = (size_t)blockIdx.x * L;
    float m = -3.4e38f;
    for (int i = threadIdx.x; i < L; i += blockDim.x) {
        float x = s[base + i];
        buf[i] = x;
        m = fmaxf(m, x);
    }
    m = blk_max(m);
    float lsum = 0.f;
    for (int i = threadIdx.x; i < L; i += blockDim.x) {
        float e = fexp(buf[i] - m);
        buf[i] = e;
        lsum += e;
    }
    float sum = blk_sum(lsum);
    float inv = 1.f / sum;
    for (int i = threadIdx.x; i < L; i += blockDim.x)
        s[base + i] = rna_tf32(buf[i] * inv);
}

// ---------------- edge PV (tf32, chunked atomic) ----------------
__global__ void __launch_bounds__(256) edge_pv_tf(
    const float* __restrict__ p, const float* __restrict__ v, float* __restrict__ ctx)
{
    int h = blockIdx.x;
    int e = blockIdx.y & 1, b = blockIdx.y >> 1;
    int chunk = blockIdx.z;
    int qb = e ? (NBx - 1) : 0;
    __shared__ float Ps[64][FT_STRIDE];
    __shared__ float Vs[64][FT_STRIDE];
    int tid = threadIdx.x, lane = tid & 31, wid = tid >> 5;
    int warp_m = wid & 3, warp_n = wid >> 2;

    const float* prow = p + ((size_t)((b * NHx + h) * 2 + e)) * (64 * Sx);

    float acc[4][4];
    #pragma unroll
    for (int j = 0; j < 4; j++) {
        acc[j][0] = 0.f; acc[j][1] = 0.f; acc[j][2] = 0.f; acc[j][3] = 0.f;
    }

    for (int c8 = 0; c8 < 8; c8++) {
        int kb = chunk * 8 + c8;
        size_t voff = ((size_t)b * Sx + kb * 64) * Dx + h * 64;
        __syncthreads();
        load_ftile(Ps, prow + kb * 64, Sx, tid);
        load_ftile(Vs, v + voff, Dx, tid);
        __syncthreads();
        pv_tile_tf(&Ps[0][0], FT_STRIDE, 0, Vs, acc, lane, warp_m, warp_n);
    }

    float* cbase = ctx + ((size_t)b * Sx + qb * 64) * Dx + h * 64;
    int r0 = warp_m * 16 + (lane >> 2);
    #pragma unroll
    for (int j = 0; j < 4; j++) {
        int col = warp_n * 32 + j * 8 + (lane & 3) * 2;
        atomicAdd(&cbase[(size_t)r0 * Dx + col],           acc[j][0]);
        atomicAdd(&cbase[(size_t)r0 * Dx + col + 1],       acc[j][1]);
        atomicAdd(&cbase[(size_t)(r0 + 8) * Dx + col],     acc[j][2]);
        atomicAdd(&cbase[(size_t)(r0 + 8) * Dx + col + 1], acc[j][3]);
    }
}

__global__ void zero_edge_ctx(float* __restrict__ ctx) {
    int i = blockIdx.x * 256 + threadIdx.x;
    if (i >= Bx * 2 * 64 * Dx) return;
    int col = i % Dx;
    int t = i / Dx;
    int row = t % 64;  t /= 64;
    int e = t & 1;
    int b = t >> 1;
    int blk = e ? (NBx - 1) : 0;
    ctx[((size_t)b * Sx + blk * 64 + row) * Dx + col] = 0.f;
}

// ---------------- pooler ----------------
__global__ void pooler_kernel(const float* __restrict__ h, const float* __restrict__ pw,
                              const float* __restrict__ pb, float* __restrict__ out) {
    int j = blockIdx.x * blockDim.x + threadIdx.x;
    int b = blockIdx.y;
    if (j >= Dx) return;
    const float* hr = h + (size_t)b * Sx * Dx;
    float acc = pb[j];
    for (int kI = 0; kI < Dx; kI++) acc += hr[kI] * pw[(size_t)kI * Dx + j];
    out[b * Dx + j] = tanhf(acc);
}

// ---------------- host launcher ----------------
extern "C" void kernel_launch(void* const* d_in, const int* in_sizes, int n_in,
                              void* d_out, int out_size) {
    const int*   input_ids = (const int*)d_in[0];
    const int*   attn_mask = (const int*)d_in[1];
    const int*   tok_type  = (const int*)d_in[2];
    const int*   rand_blk  = (const int*)d_in[3];
    const float* word_emb  = (const float*)d_in[4];
    const float* type_emb  = (const float*)d_in[5];
    const float* pos_emb   = (const float*)d_in[6];
    const float* emb_ln_s  = (const float*)d_in[7];
    const float* emb_ln_b  = (const float*)d_in[8];
    const float* Wq = (const float*)d_in[9];  const float* bq = (const float*)d_in[10];
    const float* Wk = (const float*)d_in[11]; const float* bk = (const float*)d_in[12];
    const float* Wv = (const float*)d_in[13]; const float* bv = (const float*)d_in[14];
    const float* Wo = (const float*)d_in[15]; const float* bo = (const float*)d_in[16];
    const float* ln1_s = (const float*)d_in[17]; const float* ln1_b = (const float*)d_in[18];
    const float* W1 = (const float*)d_in[19]; const float* b1 = (const float*)d_in[20];
    const float* W2 = (const float*)d_in[21]; const float* b2 = (const float*)d_in[22];
    const float* ln2_s = (const float*)d_in[23]; const float* ln2_b = (const float*)d_in[24];
    const float* pool_w = (const float*)d_in[25]; const float* pool_b = (const float*)d_in[26];
    float* out = (float*)d_out;

    float *p_h = 0, *p_res = 0, *p_ctx = 0, *p_ff = 0, *p_wt = 0, *p_sedge = 0;
    float *p_q = 0, *p_k = 0, *p_v = 0;
    cudaGetSymbolAddress((void**)&p_h,     g_h);
    cudaGetSymbolAddress((void**)&p_res,   g_res);
    cudaGetSymbolAddress((void**)&p_ctx,   g_ctx);
    cudaGetSymbolAddress((void**)&p_ff,    g_ff);
    cudaGetSymbolAddress((void**)&p_wt,    g_wt);
    cudaGetSymbolAddress((void**)&p_sedge, g_sedge);
    cudaGetSymbolAddress((void**)&p_q,     g_q);
    cudaGetSymbolAddress((void**)&p_k,     g_k);
    cudaGetSymbolAddress((void**)&p_v,     g_v);

    static bool attr_done = false;
    if (!attr_done) {
        cudaFuncSetAttribute(tf_gemm_kernel<0>, cudaFuncAttributeMaxDynamicSharedMemorySize, TF_SMEM_BYTES);
        cudaFuncSetAttribute(tf_gemm_kernel<3>, cudaFuncAttributeMaxDynamicSharedMemorySize, TF_SMEM_BYTES);
        cudaFuncSetAttribute(tf_qkv_kernel, cudaFuncAttributeMaxDynamicSharedMemorySize, TF_SMEM_BYTES);
        cudaFuncSetAttribute(mid_fused_kernel, cudaFuncAttributeMaxDynamicSharedMemorySize, MID_SMEM);
        attr_done = true;
    }

    const int M = TOK;
    const int nDD = Dx * Dx;

    embed_ln_kernel<<<TOK, 256>>>(input_ids, tok_type, word_emb, type_emb, pos_emb,
                                  emb_ln_s, emb_ln_b);

    for (int l = 0; l < 2; l++) {
        const float* wq = Wq + (size_t)l * nDD;  const float* bql = bq + (size_t)l * Dx;
        const float* wk = Wk + (size_t)l * nDD;  const float* bkl = bk + (size_t)l * Dx;
        const float* wv = Wv + (size_t)l * nDD;  const float* bvl = bv + (size_t)l * Dx;
        const float* wo = Wo + (size_t)l * nDD;  const float* bol = bo + (size_t)l * Dx;
        const float* w1 = W1 + (size_t)l * Dx * FFx; const float* b1l = b1 + (size_t)l * FFx;
        const float* w2 = W2 + (size_t)l * Dx * FFx; const float* b2l = b2 + (size_t)l * Dx;
        const float* l1s = ln1_s + (size_t)l * Dx; const float* l1b = ln1_b + (size_t)l * Dx;
        const float* l2s = ln2_s + (size_t)l * Dx; const float* l2b = ln2_b + (size_t)l * Dx;

        // QKV (tf32)
        trans_round_kernel<<<dim3(Dx / 32, Dx / 32), dim3(32, 8)>>>(wq, p_wt,           Dx, Dx);
        trans_round_kernel<<<dim3(Dx / 32, Dx / 32), dim3(32, 8)>>>(wk, p_wt + nDD,     Dx, Dx);
        trans_round_kernel<<<dim3(Dx / 32, Dx / 32), dim3(32, 8)>>>(wv, p_wt + 2 * nDD, Dx, Dx);
        tf_qkv_kernel<<<dim3(Dx / 128, M / 128, 3), 256, TF_SMEM_BYTES>>>(
            p_h, p_wt, bql, bkl, bvl, p_q, p_k, p_v);

        // middle blocks: fused scores+softmax+PV (tf32)
        mid_fused_kernel<<<dim3(NMID, NHx, Bx), 256, MID_SMEM>>>(
            p_q, p_k, p_v, rand_blk, attn_mask, p_ctx);

        // edge blocks (tf32)
        edge_scores_tf<<<dim3(NBx, NHx, Bx * 2), 256>>>(p_q, p_k, attn_mask, p_sedge);
        softmax_rna_kernel<<<Bx * NHx * 2 * BSx, 256, Sx * sizeof(float)>>>(p_sedge, Sx);
        zero_edge_ctx<<<(Bx * 2 * 64 * Dx + 255) / 256, 256>>>(p_ctx);
        edge_pv_tf<<<dim3(NHx, Bx * 2, 8), 256>>>(p_sedge, p_v, p_ctx);

        // O-projection (tf32) + LN
        trans_round_kernel<<<dim3(Dx / 32, Dx / 32), dim3(32, 8)>>>(wo, p_wt, Dx, Dx);
        tf_gemm_kernel<0><<<dim3(Dx / 128, M / 128), 256, TF_SMEM_BYTES>>>(
            p_ctx, p_wt, bol, p_res, M, Dx, Dx);
        add_ln_kernel<<<TOK, 256>>>(p_h, p_res, l1s, l1b);

        // FFN (tf32)
        trans_round_kernel<<<dim3(FFx / 32, Dx / 32), dim3(32, 8)>>>(w1, p_wt, Dx, FFx);
        tf_gemm_kernel<3><<<dim3(FFx / 128, M / 128), 256, TF_SMEM_BYTES>>>(
            p_h, p_wt, b1l, p_ff, M, FFx, Dx);
        trans_round_kernel<<<dim3(Dx / 32, FFx / 32), dim3(32, 8)>>>(w2, p_wt, FFx, Dx);
        tf_gemm_kernel<0><<<dim3(Dx / 128, M / 128), 256, TF_SMEM_BYTES>>>(
            p_ff, p_wt, b2l, p_res, M, Dx, FFx);
        add_ln_kernel<<<TOK, 256>>>(p_h, p_res, l2s, l2b);
    }

    pooler_kernel<<<dim3((Dx + 127) / 128, Bx), 128>>>(p_h, pool_w, pool_b, out);
}

// round 14
// speedup vs baseline: 3.5766x; 1.0056x over previous
#include <cuda_runtime.h>
#include <cuda_bf16.h>
#include <cstdint>
#include <math.h>

#define Bx 2
#define Sx 4096
#define Dx 768
#define NHx 12
#define HDx 64
#define BSx 64
#define NBx 64
#define FFx 3072
#define Rx 3
#define NGx 8
#define NMID 62
#define TOK (Bx*Sx)

// ---------------- scratch ----------------
__device__ float g_h[(size_t)TOK*Dx];
__device__ float g_res[(size_t)TOK*Dx];
__device__ float g_ctx[(size_t)TOK*Dx];
__device__ float g_ff[(size_t)TOK*FFx];
__device__ float g_wt[(size_t)Dx*FFx];
__device__ float g_q[(size_t)TOK*Dx];
__device__ float g_k[(size_t)TOK*Dx];
__device__ float g_v[(size_t)TOK*Dx];
__device__ float g_sedge[(size_t)Bx*NHx*2*BSx*Sx];

// ---------------- helpers ----------------
__device__ __forceinline__ float rna_tf32(float x) {
    uint32_t o;
    asm("cvt.rna.tf32.f32 %0, %1;" : "=r"(o) : "f"(x));
    return __uint_as_float(o);
}
__device__ __forceinline__ float fexp(float x) {
    x = fmaxf(x, -80.f);
    float t = fmaf(x, 1.4426950408889634f, 12582912.0f);
    float i = t - 12582912.0f;
    float f = fmaf(x, 1.4426950408889634f, -i);
    float pr = 1.5403530e-4f;
    pr = fmaf(pr, f, 1.3333558e-3f);
    pr = fmaf(pr, f, 9.6181291e-3f);
    pr = fmaf(pr, f, 5.5504109e-2f);
    pr = fmaf(pr, f, 2.4022651e-1f);
    pr = fmaf(pr, f, 6.9314718e-1f);
    pr = fmaf(pr, f, 1.0f);
    int ii = (int)i;
    float sc = __int_as_float((ii + 127) << 23);
    return pr * sc;
}

__device__ __forceinline__ float blk_sum(float v) {
    __shared__ float red[33];
    #pragma unroll
    for (int o = 16; o; o >>= 1) v += __shfl_down_sync(0xffffffffu, v, o);
    int lane = threadIdx.x & 31, w = threadIdx.x >> 5;
    __syncthreads();
    if (lane == 0) red[w] = v;
    __syncthreads();
    if (w == 0) {
        float x = (lane < ((blockDim.x + 31) >> 5)) ? red[lane] : 0.f;
        #pragma unroll
        for (int o = 16; o; o >>= 1) x += __shfl_down_sync(0xffffffffu, x, o);
        if (lane == 0) red[32] = x;
    }
    __syncthreads();
    return red[32];
}

__device__ __forceinline__ float blk_max(float v) {
    __shared__ float redm[33];
    #pragma unroll
    for (int o = 16; o; o >>= 1) v = fmaxf(v, __shfl_down_sync(0xffffffffu, v, o));
    int lane = threadIdx.x & 31, w = threadIdx.x >> 5;
    __syncthreads();
    if (lane == 0) redm[w] = v;
    __syncthreads();
    if (w == 0) {
        float x = (lane < ((blockDim.x + 31) >> 5)) ? redm[lane] : -3.4e38f;
        #pragma unroll
        for (int o = 16; o; o >>= 1) x = fmaxf(x, __shfl_down_sync(0xffffffffu, x, o));
        if (lane == 0) redm[32] = x;
    }
    __syncthreads();
    return redm[32];
}

// ---------------- weight transpose + tf32 round: W[K][N] -> Wt[N][K] -------------
// zstride: per-z offsets for batched QKV (0 for single).
__global__ void trans_round_kernel(const float* __restrict__ in, float* __restrict__ out,
                                   int K, int N, size_t zin, size_t zout) {
    __shared__ float t[32][33];
    in  += (size_t)blockIdx.z * zin;
    out += (size_t)blockIdx.z * zout;
    int n0 = blockIdx.x * 32, k0 = blockIdx.y * 32;
    int tx = threadIdx.x, ty = threadIdx.y;
    #pragma unroll
    for (int i = ty; i < 32; i += 8) t[i][tx] = in[(size_t)(k0 + i) * N + n0 + tx];
    __syncthreads();
    #pragma unroll
    for (int i = ty; i < 32; i += 8)
        out[(size_t)(n0 + i) * K + k0 + tx] = rna_tf32(t[tx][i]);
}

// ---------------- embeddings + LN ----------------
__global__ void embed_ln_kernel(const int* __restrict__ ids, const int* __restrict__ tt,
                                const float* __restrict__ wemb, const float* __restrict__ temb,
                                const float* __restrict__ pemb,
                                const float* __restrict__ lns, const float* __restrict__ lnb) {
    int tok = blockIdx.x;
    int pos = tok % Sx;
    const float* w = wemb + (size_t)ids[tok] * Dx;
    const float* t = temb + (size_t)tt[tok] * Dx;
    const float* p = pemb + (size_t)pos * Dx;
    __shared__ float buf[Dx];
    float ls = 0.f, lq = 0.f;
    for (int i = threadIdx.x; i < Dx; i += blockDim.x) {
        float x = w[i] + t[i] + p[i];
        buf[i] = x; ls += x; lq += x * x;
    }
    float sum = blk_sum(ls);
    float sq  = blk_sum(lq);
    float mu = sum * (1.f / Dx);
    float var = sq * (1.f / Dx) - mu * mu;
    float inv = rsqrtf(var + 1e-12f);
    for (int i = threadIdx.x; i < Dx; i += blockDim.x) {
        float y = lns[i] * (buf[i] - mu) * inv + lnb[i];
        g_h[(size_t)tok * Dx + i] = rna_tf32(y);
    }
}

__global__ void add_ln_kernel(float* __restrict__ h, const float* __restrict__ r,
                              const float* __restrict__ lns, const float* __restrict__ lnb) {
    int tok = blockIdx.x;
    __shared__ float buf[Dx];
    float ls = 0.f, lq = 0.f;
    for (int i = threadIdx.x; i < Dx; i += blockDim.x) {
        float x = h[(size_t)tok * Dx + i] + r[(size_t)tok * Dx + i];
        buf[i] = x; ls += x; lq += x * x;
    }
    float sum = blk_sum(ls);
    float sq  = blk_sum(lq);
    float mu = sum * (1.f / Dx);
    float var = sq * (1.f / Dx) - mu * mu;
    float inv = rsqrtf(var + 1e-12f);
    for (int i = threadIdx.x; i < Dx; i += blockDim.x) {
        float y = lns[i] * (buf[i] - mu) * inv + lnb[i];
        h[(size_t)tok * Dx + i] = rna_tf32(y);
    }
}

// ---------------- MMA primitives ----------------
__device__ __forceinline__ void ldsm_x4(uint32_t* r, uint32_t addr) {
    asm volatile("ldmatrix.sync.aligned.m8n8.x4.shared.b16 {%0,%1,%2,%3}, [%4];"
                 : "=r"(r[0]), "=r"(r[1]), "=r"(r[2]), "=r"(r[3]) : "r"(addr));
}
__device__ __forceinline__ void mma_tf32(float* c, const uint32_t* a, uint32_t b0, uint32_t b1) {
    asm volatile("mma.sync.aligned.m16n8k8.row.col.f32.tf32.tf32.f32 "
                 "{%0,%1,%2,%3}, {%4,%5,%6,%7}, {%8,%9}, {%0,%1,%2,%3};"
                 : "+f"(c[0]), "+f"(c[1]), "+f"(c[2]), "+f"(c[3])
                 : "r"(a[0]), "r"(a[1]), "r"(a[2]), "r"(a[3]), "r"(b0), "r"(b1));
}
__device__ __forceinline__ void cp16(void* dst, const void* src) {
    uint32_t d = (uint32_t)__cvta_generic_to_shared(dst);
    asm volatile("cp.async.cg.shared.global [%0], [%1], 16;" :: "r"(d), "l"(src));
}

// ---------------- TF32 dense GEMM ----------------
#define TF_STRIDE 36
#define TF_STAGE (128 * TF_STRIDE * 2)
#define TF_OFF_B (128 * TF_STRIDE)
#define TF_SMEM_BYTES (2 * TF_STAGE * 4)

__device__ __forceinline__ void tf_load_stage(
    float* sm, int s, int k0, int tid, int m0, int n0,
    const float* __restrict__ A, const float* __restrict__ Bt, int K)
{
    float* st = sm + s * TF_STAGE;
    #pragma unroll
    for (int i = 0; i < 4; i++) {
        int idx = tid + i * 256;
        int r = idx >> 3, c = (idx & 7) * 4;
        cp16(st + r * TF_STRIDE + c, A + (size_t)(m0 + r) * K + k0 + c);
        cp16(st + TF_OFF_B + r * TF_STRIDE + c, Bt + (size_t)(n0 + r) * K + k0 + c);
    }
    asm volatile("cp.async.commit_group;");
}

template<int MODE>
__device__ __forceinline__ void tf_gemm_body(
    const float* __restrict__ A, const float* __restrict__ Bt,
    const float* __restrict__ bias, float* __restrict__ C,
    int M, int N, int K, int bxb, int byb, float* sm)
{
    const int tid = threadIdx.x;
    const int lane = tid & 31;
    const int wid = tid >> 5;
    const int warp_m = wid & 3;
    const int warp_n = wid >> 2;
    const int m0 = byb * 128;
    const int n0 = bxb * 128;

    float acc[2][8][4];
    #pragma unroll
    for (int mt = 0; mt < 2; mt++) {
        #pragma unroll
        for (int nt = 0; nt < 8; nt++) {
            acc[mt][nt][0] = 0.f; acc[mt][nt][1] = 0.f;
            acc[mt][nt][2] = 0.f; acc[mt][nt][3] = 0.f;
        }
    }

    const int phase = lane >> 3;
    const int rli = lane & 7;
    const int a_roff = (phase & 1) * 8 + rli;
    const int a_koff = (phase >> 1) * 4;
    const int b_roff = (phase >> 1) * 8 + rli;
    const int b_koff = (phase & 1) * 4;

    const int nk = K >> 5;
    tf_load_stage(sm, 0, 0, tid, m0, n0, A, Bt, K);

    for (int kt = 0; kt < nk; kt++) {
        const int s = kt & 1;
        asm volatile("cp.async.wait_group 0;");
        __syncthreads();
        if (kt + 1 < nk)
            tf_load_stage(sm, s ^ 1, (kt + 1) * 32, tid, m0, n0, A, Bt, K);

        float* stA = sm + s * TF_STAGE;
        float* stB = stA + TF_OFF_B;

        #pragma unroll
        for (int kk = 0; kk < 32; kk += 8) {
            uint32_t aa0[4], aa1[4];
            ldsm_x4(aa0, (uint32_t)__cvta_generic_to_shared(
                stA + (warp_m * 32 + a_roff) * TF_STRIDE + kk + a_koff));
            ldsm_x4(aa1, (uint32_t)__cvta_generic_to_shared(
                stA + (warp_m * 32 + 16 + a_roff) * TF_STRIDE + kk + a_koff));
            #pragma unroll
            for (int p = 0; p < 4; p++) {
                uint32_t bb[4];
                ldsm_x4(bb, (uint32_t)__cvta_generic_to_shared(
                    stB + (warp_n * 64 + p * 16 + b_roff) * TF_STRIDE + kk + b_koff));
                int nt0 = p * 2;
                int nt1 = p * 2 + 1;
                mma_tf32(acc[0][nt0], aa0, bb[0], bb[1]);
                mma_tf32(acc[0][nt1], aa0, bb[2], bb[3]);
                mma_tf32(acc[1][nt0], aa1, bb[0], bb[1]);
                mma_tf32(acc[1][nt1], aa1, bb[2], bb[3]);
            }
        }
    }

    const int grp = lane >> 2;
    const int tig = lane & 3;
    #pragma unroll
    for (int mt = 0; mt < 2; mt++) {
        #pragma unroll
        for (int nt = 0; nt < 8; nt++) {
            int col = n0 + warp_n * 64 + nt * 8 + tig * 2;
            float b0 = bias[col];
            float b1 = bias[col + 1];
            #pragma unroll
            for (int half = 0; half < 2; half++) {
                int row = m0 + warp_m * 32 + mt * 16 + grp + half * 8;
                float v0 = acc[mt][nt][half * 2 + 0] + b0;
                float v1 = acc[mt][nt][half * 2 + 1] + b1;
                if (MODE == 3) {
                    v0 = 0.5f * v0 * (1.f + erff(v0 * 0.70710678118654752f));
                    v1 = 0.5f * v1 * (1.f + erff(v1 * 0.70710678118654752f));
                }
                if (MODE == 3 || MODE == 4) {
                    C[(size_t)row * N + col]     = rna_tf32(v0);
                    C[(size_t)row * N + col + 1] = rna_tf32(v1);
                } else {
                    C[(size_t)row * N + col]     = v0;
                    C[(size_t)row * N + col + 1] = v1;
                }
            }
        }
    }
}

template<int MODE>
__global__ void __launch_bounds__(256, 2) tf_gemm_kernel(
    const float* __restrict__ A, const float* __restrict__ Bt,
    const float* __restrict__ bias, float* __restrict__ C,
    int M, int N, int K)
{
    extern __shared__ __align__(16) float sm[];
    tf_gemm_body<MODE>(A, Bt, bias, C, M, N, K, blockIdx.x, blockIdx.y, sm);
}

__global__ void __launch_bounds__(256, 2) tf_qkv_kernel(
    const float* __restrict__ A, const float* __restrict__ Bt,
    const float* __restrict__ bq, const float* __restrict__ bk, const float* __restrict__ bv,
    float* __restrict__ q, float* __restrict__ k, float* __restrict__ v)
{
    extern __shared__ __align__(16) float sm[];
    int z = blockIdx.z;
    size_t woff = (size_t)z * Dx * Dx;
    const float* bias = (z == 0) ? bq : (z == 1) ? bk : bv;
    float* C = (z == 0) ? q : (z == 1) ? k : v;
    tf_gemm_body<4>(A, Bt + woff, bias, C, TOK, Dx, Dx, blockIdx.x, blockIdx.y, sm);
}

// ---------------- attention helpers ----------------
__device__ __forceinline__ int mid_block_idx(int n, int g, const int* __restrict__ randb) {
    if (g == 0) return 0;
    if (g == 1) return NBx - 1;
    if (g < 5)  return n - 3 + g;
    return randb[(n - 1) * Rx + (g - 5)];
}

#define FT_STRIDE 68
__device__ __forceinline__ void load_ftile(
    float (*dst)[FT_STRIDE], const float* __restrict__ src, int gstride, int tid)
{
    #pragma unroll
    for (int i = 0; i < 4; i++) {
        int idx = tid + i * 256;
        int r = idx >> 4, c = (idx & 15) * 4;
        *(float4*)&dst[r][c] = *(const float4*)(src + (size_t)r * gstride + c);
    }
}

// TF32 64x64 score tile via ldmatrix fragments (Q and K both k-contiguous).
__device__ __forceinline__ void score_tile_tf(
    const float (*Qs)[FT_STRIDE], const float (*Ks)[FT_STRIDE],
    float acc[4][4], int lane, int warp_m, int warp_n)
{
    const int phase = lane >> 3;
    const int rli = lane & 7;
    const int a_roff = (phase & 1) * 8 + rli;
    const int a_koff = (phase >> 1) * 4;
    const int b_roff = (phase >> 1) * 8 + rli;
    const int b_koff = (phase & 1) * 4;

    #pragma unroll
    for (int kk = 0; kk < 64; kk += 8) {
        uint32_t aa[4];
        ldsm_x4(aa, (uint32_t)__cvta_generic_to_shared(
            &Qs[warp_m * 16 + a_roff][kk + a_koff]));
        #pragma unroll
        for (int p = 0; p < 2; p++) {
            uint32_t bb[4];
            ldsm_x4(bb, (uint32_t)__cvta_generic_to_shared(
                &Ks[warp_n * 32 + p * 16 + b_roff][kk + b_koff]));
            mma_tf32(acc[p * 2 + 0], aa, bb[0], bb[1]);
            mma_tf32(acc[p * 2 + 1], aa, bb[2], bb[3]);
        }
    }
}

// TF32 PV: A = P (k-contiguous, ldmatrix), B = V [key][d] (n-contiguous, scalar loads).
__device__ __forceinline__ void pv_tile_tf(
    const float* __restrict__ P, int pstride, int pcol0,
    const float (*Vs)[FT_STRIDE],
    float acc[4][4], int lane, int warp_m, int warp_n)
{
    const int phase = lane >> 3;
    const int rli = lane & 7;
    const int a_roff = (phase & 1) * 8 + rli;
    const int a_koff = (phase >> 1) * 4;
    const int ck = lane & 3;
    const int nr = lane >> 2;

    #pragma unroll
    for (int kk = 0; kk < 64; kk += 8) {
        uint32_t aa[4];
        ldsm_x4(aa, (uint32_t)__cvta_generic_to_shared(
            P + (size_t)(warp_m * 16 + a_roff) * pstride + pcol0 + kk + a_koff));
        #pragma unroll
        for (int j = 0; j < 4; j++) {
            int n0 = warp_n * 32 + j * 8 + nr;
            uint32_t b0 = __float_as_uint(Vs[kk + ck][n0]);
            uint32_t b1 = __float_as_uint(Vs[kk + 4 + ck][n0]);
            mma_tf32(acc[j], aa, b0, b1);
        }
    }
}

// ---------------- fused middle-block attention (tf32) ----------------
#define SROW 516
#define MID_SMEM (64 * SROW * 4 + 2 * 64 * FT_STRIDE * 4)

__global__ void __launch_bounds__(256, 1) mid_fused_kernel(
    const float* __restrict__ q, const float* __restrict__ k, const float* __restrict__ v,
    const int* __restrict__ randb, const int* __restrict__ amask,
    float* __restrict__ ctx)
{
    extern __shared__ __align__(16) char smraw[];
    float (*Sf)[SROW] = (float(*)[SROW])smraw;
    float (*Qs)[FT_STRIDE] = (float(*)[FT_STRIDE])(smraw + 64 * SROW * 4);
    float (*Ks)[FT_STRIDE] = (float(*)[FT_STRIDE])(smraw + 64 * SROW * 4 + 64 * FT_STRIDE * 4);

    int n = blockIdx.x + 1, h = blockIdx.y, b = blockIdx.z;
    int tid = threadIdx.x, lane = tid & 31, wid = tid >> 5;
    int warp_m = wid & 3, warp_n = wid >> 2;

    size_t qoff = ((size_t)b * Sx + n * 64) * Dx + h * 64;
    load_ftile(Qs, q + qoff, Dx, tid);

    // --- phase 1: scores ---
    for (int g = 0; g < NGx; g++) {
        int kb = mid_block_idx(n, g, randb);
        size_t koff = ((size_t)b * Sx + kb * 64) * Dx + h * 64;
        __syncthreads();
        load_ftile(Ks, k + koff, Dx, tid);
        __syncthreads();

        float acc[4][4];
        #pragma unroll
        for (int j = 0; j < 4; j++) {
            acc[j][0] = 0.f; acc[j][1] = 0.f; acc[j][2] = 0.f; acc[j][3] = 0.f;
        }
        score_tile_tf(Qs, Ks, acc, lane, warp_m, warp_n);

        int r0 = warp_m * 16 + (lane >> 2);
        int mask_base = b * Sx + kb * 64;
        #pragma unroll
        for (int j = 0; j < 4; j++) {
            int ki = warp_n * 32 + j * 8 + (lane & 3) * 2;
            float m0 = (1.0f - (float)amask[mask_base + ki]) * -1e9f;
            float m1 = (1.0f - (float)amask[mask_base + ki + 1]) * -1e9f;
            Sf[r0][g * 64 + ki]           = acc[j][0] * 0.125f + m0;
            Sf[r0][g * 64 + ki + 1]       = acc[j][1] * 0.125f + m1;
            Sf[r0 + 8][g * 64 + ki]       = acc[j][2] * 0.125f + m0;
            Sf[r0 + 8][g * 64 + ki + 1]   = acc[j][3] * 0.125f + m1;
        }
    }
    __syncthreads();

    // --- phase 2: softmax (rna-rounded for tf32 PV) ---
    for (int rr = 0; rr < 8; rr++) {
        int row = wid * 8 + rr;
        float vv[16];
        float m = -3.4e38f;
        #pragma unroll
        for (int j = 0; j < 16; j++) {
            vv[j] = Sf[row][lane + 32 * j];
            m = fmaxf(m, vv[j]);
        }
        #pragma unroll
        for (int o = 16; o; o >>= 1) m = fmaxf(m, __shfl_xor_sync(0xffffffffu, m, o));
        float s = 0.f;
        #pragma unroll
        for (int j = 0; j < 16; j++) { vv[j] = fexp(vv[j] - m); s += vv[j]; }
        #pragma unroll
        for (int o = 16; o; o >>= 1) s += __shfl_xor_sync(0xffffffffu, s, o);
        float inv = 1.f / s;
        #pragma unroll
        for (int j = 0; j < 16; j++) Sf[row][lane + 32 * j] = rna_tf32(vv[j] * inv);
    }
    __syncthreads();

    // --- phase 3: PV ---
    float acc[4][4];
    #pragma unroll
    for (int j = 0; j < 4; j++) {
        acc[j][0] = 0.f; acc[j][1] = 0.f; acc[j][2] = 0.f; acc[j][3] = 0.f;
    }
    for (int g = 0; g < NGx; g++) {
        int kb = mid_block_idx(n, g, randb);
        size_t voff = ((size_t)b * Sx + kb * 64) * Dx + h * 64;
        __syncthreads();
        load_ftile(Ks, v + voff, Dx, tid);
        __syncthreads();
        pv_tile_tf(&Sf[0][0], SROW, g * 64, Ks, acc, lane, warp_m, warp_n);
    }

    float* cbase = ctx + ((size_t)b * Sx + n * 64) * Dx + h * 64;
    int pr = warp_m * 16 + (lane >> 2);
    #pragma unroll
    for (int j = 0; j < 4; j++) {
        int col = warp_n * 32 + j * 8 + (lane & 3) * 2;
        cbase[(size_t)pr * Dx + col]           = rna_tf32(acc[j][0]);
        cbase[(size_t)pr * Dx + col + 1]       = rna_tf32(acc[j][1]);
        cbase[(size_t)(pr + 8) * Dx + col]     = rna_tf32(acc[j][2]);
        cbase[(size_t)(pr + 8) * Dx + col + 1] = rna_tf32(acc[j][3]);
    }
}

// ---------------- edge scores (tf32) ----------------
__global__ void __launch_bounds__(256) edge_scores_tf(
    const float* __restrict__ q, const float* __restrict__ k,
    const int* __restrict__ amask, float* __restrict__ sedge)
{
    int kb = blockIdx.x, h = blockIdx.y;
    int e = blockIdx.z & 1, b = blockIdx.z >> 1;
    int qb = e ? (NBx - 1) : 0;
    __shared__ float Qs[64][FT_STRIDE];
    __shared__ float Ks[64][FT_STRIDE];
    int tid = threadIdx.x, lane = tid & 31, wid = tid >> 5;
    int warp_m = wid & 3, warp_n = wid >> 2;

    size_t qoff = ((size_t)b * Sx + qb * 64) * Dx + h * 64;
    size_t koff = ((size_t)b * Sx + kb * 64) * Dx + h * 64;
    load_ftile(Qs, q + qoff, Dx, tid);
    load_ftile(Ks, k + koff, Dx, tid);
    __syncthreads();

    float acc[4][4];
    #pragma unroll
    for (int j = 0; j < 4; j++) {
        acc[j][0] = 0.f; acc[j][1] = 0.f; acc[j][2] = 0.f; acc[j][3] = 0.f;
    }
    score_tile_tf(Qs, Ks, acc, lane, warp_m, warp_n);

    float* out = sedge + ((size_t)((b * NHx + h) * 2 + e)) * (64 * Sx);
    int r0 = warp_m * 16 + (lane >> 2);
    int mask_base = b * Sx + kb * 64;
    #pragma unroll
    for (int j = 0; j < 4; j++) {
        int ki = warp_n * 32 + j * 8 + (lane & 3) * 2;
        float m0 = (1.0f - (float)amask[mask_base + ki]) * -1e9f;
        float m1 = (1.0f - (float)amask[mask_base + ki + 1]) * -1e9f;
        out[(size_t)r0 * Sx + kb * 64 + ki]           = acc[j][0] * 0.125f + m0;
        out[(size_t)r0 * Sx + kb * 64 + ki + 1]       = acc[j][1] * 0.125f + m1;
        out[(size_t)(r0 + 8) * Sx + kb * 64 + ki]     = acc[j][2] * 0.125f + m0;
        out[(size_t)(r0 + 8) * Sx + kb * 64 + ki + 1] = acc[j][3] * 0.125f + m1;
    }
}

// ---------------- edge softmax in place (rna) ----------------
__global__ void softmax_rna_kernel(float* __restrict__ s, int L) {
    extern __shared__ float buf[];
    size_t base = (size_t)blockIdx.x * L;
    float m = -3.4e38f;
    for (int i = threadIdx.x; i < L; i += blockDim.x) {
        float x = s[base + i];
        buf[i] = x;
        m = fmaxf(m, x);
    }
    m = blk_max(m);
    float lsum = 0.f;
    for (int i = threadIdx.x; i < L; i += blockDim.x) {
        float e = fexp(buf[i] - m);
        buf[i] = e;
        lsum += e;
    }
    float sum = blk_sum(lsum);
    float inv = 1.f / sum;
    for (int i = threadIdx.x; i < L; i += blockDim.x)
        s[base + i] = rna_tf32(buf[i] * inv);
}

// ---------------- edge PV (tf32, chunked atomic) ----------------
__global__ void __launch_bounds__(256) edge_pv_tf(
    const float* __restrict__ p, const float* __restrict__ v, float* __restrict__ ctx)
{
    int h = blockIdx.x;
    int e = blockIdx.y & 1, b = blockIdx.y >> 1;
    int chunk = blockIdx.z;
    int qb = e ? (NBx - 1) : 0;
    __shared__ float Ps[64][FT_STRIDE];
    __shared__ float Vs[64][FT_STRIDE];
    int tid = threadIdx.x, lane = tid & 31, wid = tid >> 5;
    int warp_m = wid & 3, warp_n = wid >> 2;

    const float* prow = p + ((size_t)((b * NHx + h) * 2 + e)) * (64 * Sx);

    float acc[4][4];
    #pragma unroll
    for (int j = 0; j < 4; j++) {
        acc[j][0] = 0.f; acc[j][1] = 0.f; acc[j][2] = 0.f; acc[j][3] = 0.f;
    }

    for (int c8 = 0; c8 < 8; c8++) {
        int kb = chunk * 8 + c8;
        size_t voff = ((size_t)b * Sx + kb * 64) * Dx + h * 64;
        __syncthreads();
        load_ftile(Ps, prow + kb * 64, Sx, tid);
        load_ftile(Vs, v + voff, Dx, tid);
        __syncthreads();
        pv_tile_tf(&Ps[0][0], FT_STRIDE, 0, Vs, acc, lane, warp_m, warp_n);
    }

    float* cbase = ctx + ((size_t)b * Sx + qb * 64) * Dx + h * 64;
    int r0 = warp_m * 16 + (lane >> 2);
    #pragma unroll
    for (int j = 0; j < 4; j++) {
        int col = warp_n * 32 + j * 8 + (lane & 3) * 2;
        atomicAdd(&cbase[(size_t)r0 * Dx + col],           acc[j][0]);
        atomicAdd(&cbase[(size_t)r0 * Dx + col + 1],       acc[j][1]);
        atomicAdd(&cbase[(size_t)(r0 + 8) * Dx + col],     acc[j][2]);
        atomicAdd(&cbase[(size_t)(r0 + 8) * Dx + col + 1], acc[j][3]);
    }
}

__global__ void zero_edge_ctx(float* __restrict__ ctx) {
    int i = blockIdx.x * 256 + threadIdx.x;
    if (i >= Bx * 2 * 64 * Dx) return;
    int col = i % Dx;
    int t = i / Dx;
    int row = t % 64;  t /= 64;
    int e = t & 1;
    int b = t >> 1;
    int blk = e ? (NBx - 1) : 0;
    ctx[((size_t)b * Sx + blk * 64 + row) * Dx + col] = 0.f;
}

// ---------------- pooler ----------------
__global__ void pooler_kernel(const float* __restrict__ h, const float* __restrict__ pw,
                              const float* __restrict__ pb, float* __restrict__ out) {
    int j = blockIdx.x * blockDim.x + threadIdx.x;
    int b = blockIdx.y;
    if (j >= Dx) return;
    const float* hr = h + (size_t)b * Sx * Dx;
    float acc = pb[j];
    for (int kI = 0; kI < Dx; kI++) acc += hr[kI] * pw[(size_t)kI * Dx + j];
    out[b * Dx + j] = tanhf(acc);
}

// ---------------- host launcher ----------------
extern "C" void kernel_launch(void* const* d_in, const int* in_sizes, int n_in,
                              void* d_out, int out_size) {
    const int*   input_ids = (const int*)d_in[0];
    const int*   attn_mask = (const int*)d_in[1];
    const int*   tok_type  = (const int*)d_in[2];
    const int*   rand_blk  = (const int*)d_in[3];
    const float* word_emb  = (const float*)d_in[4];
    const float* type_emb  = (const float*)d_in[5];
    const float* pos_emb   = (const float*)d_in[6];
    const float* emb_ln_s  = (const float*)d_in[7];
    const float* emb_ln_b  = (const float*)d_in[8];
    const float* Wq = (const float*)d_in[9];  const float* bq = (const float*)d_in[10];
    const float* Wk = (const float*)d_in[11]; const float* bk = (const float*)d_in[12];
    const float* Wv = (const float*)d_in[13]; const float* bv = (const float*)d_in[14];
    const float* Wo = (const float*)d_in[15]; const float* bo = (const float*)d_in[16];
    const float* ln1_s = (const float*)d_in[17]; const float* ln1_b = (const float*)d_in[18];
    const float* W1 = (const float*)d_in[19]; const float* b1 = (const float*)d_in[20];
    const float* W2 = (const float*)d_in[21]; const float* b2 = (const float*)d_in[22];
    const float* ln2_s = (const float*)d_in[23]; const float* ln2_b = (const float*)d_in[24];
    const float* pool_w = (const float*)d_in[25]; const float* pool_b = (const float*)d_in[26];
    float* out = (float*)d_out;

    float *p_h = 0, *p_res = 0, *p_ctx = 0, *p_ff = 0, *p_wt = 0, *p_sedge = 0;
    float *p_q = 0, *p_k = 0, *p_v = 0;
    cudaGetSymbolAddress((void**)&p_h,     g_h);
    cudaGetSymbolAddress((void**)&p_res,   g_res);
    cudaGetSymbolAddress((void**)&p_ctx,   g_ctx);
    cudaGetSymbolAddress((void**)&p_ff,    g_ff);
    cudaGetSymbolAddress((void**)&p_wt,    g_wt);
    cudaGetSymbolAddress((void**)&p_sedge, g_sedge);
    cudaGetSymbolAddress((void**)&p_q,     g_q);
    cudaGetSymbolAddress((void**)&p_k,     g_k);
    cudaGetSymbolAddress((void**)&p_v,     g_v);

    static bool attr_done = false;
    if (!attr_done) {
        cudaFuncSetAttribute(tf_gemm_kernel<0>, cudaFuncAttributeMaxDynamicSharedMemorySize, TF_SMEM_BYTES);
        cudaFuncSetAttribute(tf_gemm_kernel<3>, cudaFuncAttributeMaxDynamicSharedMemorySize, TF_SMEM_BYTES);
        cudaFuncSetAttribute(tf_qkv_kernel, cudaFuncAttributeMaxDynamicSharedMemorySize, TF_SMEM_BYTES);
        cudaFuncSetAttribute(mid_fused_kernel, cudaFuncAttributeMaxDynamicSharedMemorySize, MID_SMEM);
        attr_done = true;
    }

    const int M = TOK;
    const int nDD = Dx * Dx;

    embed_ln_kernel<<<TOK, 256>>>(input_ids, tok_type, word_emb, type_emb, pos_emb,
                                  emb_ln_s, emb_ln_b);

    for (int l = 0; l < 2; l++) {
        const float* wq = Wq + (size_t)l * nDD;  const float* bql = bq + (size_t)l * Dx;
        const float* bkl = bk + (size_t)l * Dx;
        const float* bvl = bv + (size_t)l * Dx;
        const float* wo = Wo + (size_t)l * nDD;  const float* bol = bo + (size_t)l * Dx;
        const float* w1 = W1 + (size_t)l * Dx * FFx; const float* b1l = b1 + (size_t)l * FFx;
        const float* w2 = W2 + (size_t)l * Dx * FFx; const float* b2l = b2 + (size_t)l * Dx;
        const float* l1s = ln1_s + (size_t)l * Dx; const float* l1b = ln1_b + (size_t)l * Dx;
        const float* l2s = ln2_s + (size_t)l * Dx; const float* l2b = ln2_b + (size_t)l * Dx;

        // QKV (tf32); weights Wq/Wk/Wv are adjacent per layer? No — separate arrays.
        // batched z over q,k,v using matching layer offsets within each array:
        // use 3 separate launches replaced by one z-batched launch per weight array is
        // not possible (different base pointers) -> batch only over the layer-contiguous
        // stride within each array; keep one launch per array but grid.z merges K/V via
        // pointer arithmetic trick: Wq, Wk, Wv all have identical shape; we copy each to
        // its slot in p_wt with one launch each (cheap), kept as-is except z-batch on Wq
        // only when arrays happen to be contiguous — not guaranteed, so launch per array.
        trans_round_kernel<<<dim3(Dx / 32, Dx / 32, 1), dim3(32, 8)>>>(wq, p_wt, Dx, Dx, 0, 0);
        trans_round_kernel<<<dim3(Dx / 32, Dx / 32, 1), dim3(32, 8)>>>(Wk + (size_t)l * nDD, p_wt + nDD, Dx, Dx, 0, 0);
        trans_round_kernel<<<dim3(Dx / 32, Dx / 32, 1), dim3(32, 8)>>>(Wv + (size_t)l * nDD, p_wt + 2 * nDD, Dx, Dx, 0, 0);
        tf_qkv_kernel<<<dim3(Dx / 128, M / 128, 3), 256, TF_SMEM_BYTES>>>(
            p_h, p_wt, bql, bkl, bvl, p_q, p_k, p_v);

        // middle blocks: fused scores+softmax+PV (tf32, ldmatrix fragments)
        mid_fused_kernel<<<dim3(NMID, NHx, Bx), 256, MID_SMEM>>>(
            p_q, p_k, p_v, rand_blk, attn_mask, p_ctx);

        // edge blocks (tf32)
        edge_scores_tf<<<dim3(NBx, NHx, Bx * 2), 256>>>(p_q, p_k, attn_mask, p_sedge);
        softmax_rna_kernel<<<Bx * NHx * 2 * BSx, 256, Sx * sizeof(float)>>>(p_sedge, Sx);
        zero_edge_ctx<<<(Bx * 2 * 64 * Dx + 255) / 256, 256>>>(p_ctx);
        edge_pv_tf<<<dim3(NHx, Bx * 2, 8), 256>>>(p_sedge, p_v, p_ctx);

        // O-projection (tf32) + LN
        trans_round_kernel<<<dim3(Dx / 32, Dx / 32, 1), dim3(32, 8)>>>(wo, p_wt, Dx, Dx, 0, 0);
        tf_gemm_kernel<0><<<dim3(Dx / 128, M / 128), 256, TF_SMEM_BYTES>>>(
            p_ctx, p_wt, bol, p_res, M, Dx, Dx);
        add_ln_kernel<<<TOK, 256>>>(p_h, p_res, l1s, l1b);

        // FFN (tf32)
        trans_round_kernel<<<dim3(FFx / 32, Dx / 32, 1), dim3(32, 8)>>>(w1, p_wt, Dx, FFx, 0, 0);
        tf_gemm_kernel<3><<<dim3(FFx / 128, M / 128), 256, TF_SMEM_BYTES>>>(
            p_h, p_wt, b1l, p_ff, M, FFx, Dx);
        trans_round_kernel<<<dim3(Dx / 32, FFx / 32, 1), dim3(32, 8)>>>(w2, p_wt, FFx, Dx, 0, 0);
        tf_gemm_kernel<0><<<dim3(Dx / 128, M / 128), 256, TF_SMEM_BYTES>>>(
            p_ff, p_wt, b2l, p_res, M, Dx, FFx);
        add_ln_kernel<<<TOK, 256>>>(p_h, p_res, l2s, l2b);
    }

    pooler_kernel<<<dim3((Dx + 127) / 128, Bx), 128>>>(p_h, pool_w, pool_b, out);
}